// round 1
// baseline (speedup 1.0000x reference)
#include <cuda_runtime.h>
#include <cstdint>
#include <climits>

// ---------------- problem constants ----------------
constexpr int NQ = 40000;        // 200*200
constexpr int ED = 128;
constexpr int NV = 43520;        // sum of level sizes
constexpr int HEADS = 8;
constexpr int HD = 16;

// ---------------- scratch layout (floats) ----------------
constexpr size_t OFF_V    = 0;
constexpr size_t SZ_V     = (size_t)NV * ED;              // 5,570,560
constexpr size_t OFF_QIN  = OFF_V + SZ_V;
constexpr size_t SZ_Q     = (size_t)NQ * ED;              // 5,120,000
constexpr size_t OFF_OFF  = OFF_QIN + SZ_Q;
constexpr size_t SZ_OFF   = (size_t)NQ * 512;
constexpr size_t OFF_ATTN = OFF_OFF + SZ_OFF;
constexpr size_t SZ_ATTN  = (size_t)NQ * 256;
constexpr size_t OFF_AOUT = OFF_ATTN + SZ_ATTN;
constexpr size_t OFF_Q    = OFF_AOUT + SZ_Q;
constexpr size_t OFF_T1   = OFF_Q + SZ_Q;
constexpr size_t OFF_H1   = OFF_T1 + SZ_Q;
constexpr size_t SZ_H1    = (size_t)NQ * 128;
constexpr size_t OFF_H2   = OFF_H1 + SZ_H1;
constexpr size_t SZ_H2    = (size_t)NQ * 64;
constexpr size_t OFF_H3   = OFF_H2 + SZ_H2;
constexpr size_t SZ_H3    = (size_t)NQ * 48;
constexpr size_t OFF_H4   = OFF_H3 + SZ_H3;
constexpr size_t OFF_W1T  = OFF_H4 + SZ_H3;
constexpr size_t SZ_W1T   = 49 * 128 * 128;
constexpr size_t OFF_W2T  = OFF_W1T + SZ_W1T;
constexpr size_t SZ_W2T   = 9 * 128 * 64;
constexpr size_t OFF_W3T  = OFF_W2T + SZ_W2T;
constexpr size_t SZ_W3T   = 9 * 64 * 64;
constexpr size_t OFF_W4T  = OFF_W3T + SZ_W3T;
constexpr size_t SZ_W4T   = 9 * 48 * 64;
constexpr size_t OFF_PART = OFF_W4T + SZ_W4T;
constexpr size_t SZ_PART  = 64 * 128 * 2;
constexpr size_t OFF_SCALE= OFF_PART + SZ_PART;
constexpr size_t OFF_SHIFT= OFF_SCALE + 128;
constexpr size_t SCRATCH_TOTAL = OFF_SHIFT + 128;

__device__ float g_scratch[SCRATCH_TOTAL];
__device__ int   g_maxv;

// ---------------- elementwise helpers ----------------
__global__ void add2_kernel(float* __restrict__ o, const float* __restrict__ a,
                            const float* __restrict__ b, int n) {
    int i = blockIdx.x * blockDim.x + threadIdx.x;
    if (i < n) o[i] = a[i] + b[i];
}

__global__ void init_max_kernel(int* gm) { *gm = INT_MIN; }

__global__ void reduce_max_kernel(const int* __restrict__ p, int* gm) {
    int v = INT_MIN;
    for (int k = blockIdx.x * blockDim.x + threadIdx.x; k < NQ; k += gridDim.x * blockDim.x)
        v = max(v, p[k]);
    #pragma unroll
    for (int o = 16; o > 0; o >>= 1) v = max(v, __shfl_xor_sync(0xffffffffu, v, o));
    __shared__ int sm[8];
    int w = threadIdx.x >> 5;
    if ((threadIdx.x & 31) == 0) sm[w] = v;
    __syncthreads();
    if (threadIdx.x == 0) {
        int bv = sm[0];
        for (int i = 1; i < (int)(blockDim.x >> 5); i++) bv = max(bv, sm[i]);
        atomicMax(gm, bv);
    }
}

__global__ void write_mask_kernel(const int* __restrict__ p, const int* __restrict__ gm,
                                  float* __restrict__ out) {
    int i = blockIdx.x * blockDim.x + threadIdx.x;
    if (i < NQ) out[i] = (p[i] < *gm) ? 1.0f : 0.0f;
}

// ---------------- SGEMM, K = 128, 64x64 tile, 4x4 micro ----------------
// FLAGS: bit0 = relu, bit1 = residual add (R same shape as C)
template<int FLAGS>
__global__ void __launch_bounds__(256) sgemm128(
    const float* __restrict__ A, const float* __restrict__ B,
    const float* __restrict__ bias, const float* __restrict__ R,
    float* __restrict__ C, int M, int N)
{
    __shared__ float As[16][68];
    __shared__ float Bs[16][68];
    const int bm = blockIdx.x * 64, bn = blockIdx.y * 64;
    const int tid = threadIdx.x;
    const int arow = tid >> 2, acol = (tid & 3) * 4;
    const int brow = tid >> 4, bcol = (tid & 15) * 4;
    const int r0 = (tid >> 4) * 4, c0 = (tid & 15) * 4;

    float acc[4][4];
    #pragma unroll
    for (int i = 0; i < 4; i++)
        #pragma unroll
        for (int j = 0; j < 4; j++) acc[i][j] = 0.f;

    const float* Aptr = A + (size_t)(bm + arow) * 128 + acol;

    for (int k0 = 0; k0 < 128; k0 += 16) {
        float4 a = *(const float4*)(Aptr + k0);
        As[acol + 0][arow] = a.x; As[acol + 1][arow] = a.y;
        As[acol + 2][arow] = a.z; As[acol + 3][arow] = a.w;
        *(float4*)&Bs[brow][bcol] = *(const float4*)&B[(size_t)(k0 + brow) * N + bn + bcol];
        __syncthreads();
        #pragma unroll
        for (int k = 0; k < 16; k++) {
            float4 ra = *(const float4*)&As[k][r0];
            float4 rb = *(const float4*)&Bs[k][c0];
            float av[4] = {ra.x, ra.y, ra.z, ra.w};
            float bv[4] = {rb.x, rb.y, rb.z, rb.w};
            #pragma unroll
            for (int i = 0; i < 4; i++)
                #pragma unroll
                for (int j = 0; j < 4; j++)
                    acc[i][j] = fmaf(av[i], bv[j], acc[i][j]);
        }
        __syncthreads();
    }

    float4 bb = *(const float4*)&bias[bn + c0];
    float bvv[4] = {bb.x, bb.y, bb.z, bb.w};
    #pragma unroll
    for (int i = 0; i < 4; i++) {
        size_t row = (size_t)(bm + r0 + i);
        float v[4];
        #pragma unroll
        for (int j = 0; j < 4; j++) v[j] = acc[i][j] + bvv[j];
        if (FLAGS & 2) {
            float4 rr = *(const float4*)&R[row * N + bn + c0];
            v[0] += rr.x; v[1] += rr.y; v[2] += rr.z; v[3] += rr.w;
        }
        if (FLAGS & 1) {
            #pragma unroll
            for (int j = 0; j < 4; j++) v[j] = fmaxf(v[j], 0.f);
        }
        *(float4*)&C[row * N + bn + c0] = make_float4(v[0], v[1], v[2], v[3]);
    }
}

// ---------------- softmax over 32 per (query, head) ----------------
__global__ void softmax32_kernel(float* __restrict__ A) {
    int t = blockIdx.x * blockDim.x + threadIdx.x;
    if (t >= NQ * HEADS) return;
    float* a = A + (size_t)t * 32;
    float e[32];
    float m = -1e30f;
    #pragma unroll
    for (int k = 0; k < 32; k++) m = fmaxf(m, a[k]);
    float s = 0.f;
    #pragma unroll
    for (int k = 0; k < 32; k++) { e[k] = expf(a[k] - m); s += e[k]; }
    float inv = 1.f / s;
    #pragma unroll
    for (int k = 0; k < 32; k++) a[k] = e[k] * inv;
}

// ---------------- deformable attention sampling ----------------
__global__ void __launch_bounds__(256) deform_kernel(
    const float* __restrict__ V, const float* __restrict__ OFFS,
    const float* __restrict__ ATT, float* __restrict__ AOUT)
{
    int t = blockIdx.x * 256 + threadIdx.x;
    if (t >= NQ * HEADS) return;
    const int n = t >> 3, h = t & 7;
    const float rx = ((float)(n % 200) + 0.5f) * (1.f / 200.f);
    const float ry = ((float)(n / 200) + 0.5f) * (1.f / 200.f);
    const float* op = OFFS + (size_t)n * 512 + h * 64;
    const float* ap = ATT + (size_t)n * 256 + h * 32;

    float acc[16];
    #pragma unroll
    for (int d = 0; d < 16; d++) acc[d] = 0.f;

    const int stc[4] = {0, 32768, 40960, 43008};
    const int Wc[4]  = {256, 128, 64, 32};
    const int Hc[4]  = {128, 64, 32, 16};

    #pragma unroll
    for (int l = 0; l < 4; l++) {
        const int W = Wc[l], H = Hc[l], st = stc[l];
        const float Wf = (float)W, Hf = (float)H;
        for (int p = 0; p < 8; p++) {
            float ox = op[(l * 8 + p) * 2 + 0];
            float oy = op[(l * 8 + p) * 2 + 1];
            float aw = ap[l * 8 + p];
            float x = (rx + ox / Wf) * Wf - 0.5f;
            float y = (ry + oy / Hf) * Hf - 0.5f;
            float xf = floorf(x), yf = floorf(y);
            int x0 = (int)xf, y0 = (int)yf;
            float fx = x - xf, fy = y - yf;
            float wx[2] = {1.f - fx, fx};
            float wy[2] = {1.f - fy, fy};
            #pragma unroll
            for (int c = 0; c < 4; c++) {
                int xi = x0 + (c & 1), yi = y0 + (c >> 1);
                float wgt = wx[c & 1] * wy[c >> 1];
                if (xi >= 0 && xi < W && yi >= 0 && yi < H && wgt != 0.f) {
                    const float4* gp = (const float4*)(V + ((size_t)(st + yi * W + xi)) * 128 + h * 16);
                    float cw = aw * wgt;
                    float4 g0 = gp[0], g1 = gp[1], g2 = gp[2], g3 = gp[3];
                    acc[0]  += cw * g0.x; acc[1]  += cw * g0.y; acc[2]  += cw * g0.z; acc[3]  += cw * g0.w;
                    acc[4]  += cw * g1.x; acc[5]  += cw * g1.y; acc[6]  += cw * g1.z; acc[7]  += cw * g1.w;
                    acc[8]  += cw * g2.x; acc[9]  += cw * g2.y; acc[10] += cw * g2.z; acc[11] += cw * g2.w;
                    acc[12] += cw * g3.x; acc[13] += cw * g3.y; acc[14] += cw * g3.z; acc[15] += cw * g3.w;
                }
            }
        }
    }
    float4* o = (float4*)(AOUT + (size_t)n * 128 + h * 16);
    o[0] = make_float4(acc[0], acc[1], acc[2], acc[3]);
    o[1] = make_float4(acc[4], acc[5], acc[6], acc[7]);
    o[2] = make_float4(acc[8], acc[9], acc[10], acc[11]);
    o[3] = make_float4(acc[12], acc[13], acc[14], acc[15]);
}

// ---------------- layernorm over 128 per row ----------------
__global__ void ln_kernel(const float* __restrict__ X, const float* __restrict__ g,
                          const float* __restrict__ b, float* __restrict__ Y)
{
    int r = blockIdx.x;
    int t = threadIdx.x;
    float x = X[(size_t)r * 128 + t];
    float s = x;
    #pragma unroll
    for (int o = 16; o > 0; o >>= 1) s += __shfl_xor_sync(0xffffffffu, s, o);
    __shared__ float sm[4], sm2[4];
    int w = t >> 5, lane = t & 31;
    if (lane == 0) sm[w] = s;
    __syncthreads();
    float m = (sm[0] + sm[1] + sm[2] + sm[3]) * (1.f / 128.f);
    float d = x - m;
    float q = d * d;
    #pragma unroll
    for (int o = 16; o > 0; o >>= 1) q += __shfl_xor_sync(0xffffffffu, q, o);
    if (lane == 0) sm2[w] = q;
    __syncthreads();
    float var = (sm2[0] + sm2[1] + sm2[2] + sm2[3]) * (1.f / 128.f);
    Y[(size_t)r * 128 + t] = d * rsqrtf(var + 1e-5f) * g[t] + b[t];
}

// ---------------- weight reorder: OIHW -> [(ky*KS+kx)*CI + ci][co], padded cols ----------------
__global__ void wreorder_kernel(const float* __restrict__ W, float* __restrict__ Wt,
                                int CO, int CI, int KS, int stride, int total)
{
    int i = blockIdx.x * blockDim.x + threadIdx.x;
    if (i >= total) return;
    int col = i % stride;
    int row = i / stride;
    int ci = row % CI;
    int e = row / CI;
    int ky = e / KS, kx = e % KS;
    Wt[i] = (col < CO) ? W[((size_t)(col * CI + ci) * KS + ky) * KS + kx] : 0.f;
}

// ---------------- implicit-GEMM direct conv (NHWC, 200x200) ----------------
template<int KS, int PAD>
__global__ void __launch_bounds__(256) conv_igemm(
    const float* __restrict__ In, const float* __restrict__ Wt,
    float* __restrict__ Out, int CIN, int wt_stride, int COUT)
{
    __shared__ float As[16][68];
    __shared__ float Bs[16][68];
    const int bm = blockIdx.x * 64, bn = blockIdx.y * 64;
    const int tid = threadIdx.x;
    const int arow = tid >> 2, acol = (tid & 3) * 4;
    const int brow = tid >> 4, bcol = (tid & 15) * 4;
    const int r0 = (tid >> 4) * 4, c0 = (tid & 15) * 4;

    const int pm = bm + arow;
    const int py = pm / 200, px = pm % 200;

    float acc[4][4];
    #pragma unroll
    for (int i = 0; i < 4; i++)
        #pragma unroll
        for (int j = 0; j < 4; j++) acc[i][j] = 0.f;

    for (int e = 0; e < KS * KS; e++) {
        const int qy = py + e / KS - PAD;
        const int qx = px + e % KS - PAD;
        const bool val = (qy >= 0) && (qy < 200) && (qx >= 0) && (qx < 200);
        const float* ain = In + (size_t)(qy * 200 + qx) * CIN;
        for (int kc = 0; kc < CIN; kc += 16) {
            float4 a = val ? *(const float4*)&ain[kc + acol] : make_float4(0.f, 0.f, 0.f, 0.f);
            As[acol + 0][arow] = a.x; As[acol + 1][arow] = a.y;
            As[acol + 2][arow] = a.z; As[acol + 3][arow] = a.w;
            *(float4*)&Bs[brow][bcol] =
                *(const float4*)&Wt[(size_t)(e * CIN + kc + brow) * wt_stride + bn + bcol];
            __syncthreads();
            #pragma unroll
            for (int k = 0; k < 16; k++) {
                float4 ra = *(const float4*)&As[k][r0];
                float4 rb = *(const float4*)&Bs[k][c0];
                float av[4] = {ra.x, ra.y, ra.z, ra.w};
                float bv[4] = {rb.x, rb.y, rb.z, rb.w};
                #pragma unroll
                for (int i = 0; i < 4; i++)
                    #pragma unroll
                    for (int j = 0; j < 4; j++)
                        acc[i][j] = fmaf(av[i], bv[j], acc[i][j]);
            }
            __syncthreads();
        }
    }

    if (bn + c0 < COUT) {
        #pragma unroll
        for (int i = 0; i < 4; i++) {
            size_t row = (size_t)(bm + r0 + i);
            *(float4*)&Out[row * COUT + bn + c0] =
                make_float4(acc[i][0], acc[i][1], acc[i][2], acc[i][3]);
        }
    }
}

// ---------------- batchnorm (training-mode stats), deterministic 2-stage ----------------
__global__ void bn_stats_kernel(const float* __restrict__ X, float* __restrict__ part, int C)
{
    int c = threadIdx.x;         // blockDim.x == C
    int g = blockIdx.x;          // 64 blocks
    const int per = (NQ + 63) / 64;
    int p0 = g * per;
    int p1 = min(NQ, p0 + per);
    float s = 0.f, q = 0.f;
    for (int p = p0; p < p1; p++) {
        float x = X[(size_t)p * C + c];
        s += x; q += x * x;
    }
    part[(size_t)g * 2 * C + c] = s;
    part[(size_t)g * 2 * C + C + c] = q;
}

__global__ void bn_finalize_kernel(const float* __restrict__ part,
                                   const float* __restrict__ gamma, const float* __restrict__ beta,
                                   float* __restrict__ scale, float* __restrict__ shift, int C)
{
    int c = threadIdx.x;
    float s = 0.f, q = 0.f;
    for (int g = 0; g < 64; g++) {
        s += part[(size_t)g * 2 * C + c];
        q += part[(size_t)g * 2 * C + C + c];
    }
    const float invP = 1.f / (float)NQ;
    float m = s * invP;
    float v = q * invP - m * m;
    float sc = gamma[c] * rsqrtf(v + 1e-5f);
    scale[c] = sc;
    shift[c] = beta[c] - m * sc;
}

__global__ void bn_apply_kernel(float* __restrict__ X, const float* __restrict__ scale,
                                const float* __restrict__ shift, int C, int total)
{
    int i = blockIdx.x * blockDim.x + threadIdx.x;
    if (i < total) {
        int c = i % C;
        X[i] = fmaxf(0.f, fmaf(X[i], scale[c], shift[c]));
    }
}

// ---------------- head: 1x1 conv 48 -> 21, output NCHW ----------------
__global__ void head_conv_kernel(const float* __restrict__ H4, const float* __restrict__ Wo,
                                 const float* __restrict__ bo, float* __restrict__ out)
{
    int p = blockIdx.x * blockDim.x + threadIdx.x;
    if (p >= NQ) return;
    float x[48];
    const float4* hp = (const float4*)(H4 + (size_t)p * 48);
    #pragma unroll
    for (int i = 0; i < 12; i++) {
        float4 v = hp[i];
        x[i * 4 + 0] = v.x; x[i * 4 + 1] = v.y; x[i * 4 + 2] = v.z; x[i * 4 + 3] = v.w;
    }
    for (int co = 0; co < 21; co++) {
        float s = bo[co];
        const float* w = Wo + co * 48;
        #pragma unroll
        for (int ci = 0; ci < 48; ci++) s = fmaf(x[ci], w[ci], s);
        out[(size_t)co * NQ + p] = s;
    }
}

// ---------------- launch ----------------
extern "C" void kernel_launch(void* const* d_in, const int* in_sizes, int n_in,
                              void* d_out, int out_size)
{
    const float* value = (const float*)d_in[0];
    const float* bq    = (const float*)d_in[1];
    const float* bpos  = (const float*)d_in[2];
    const int*   proj  = (const int*)d_in[3];
    const float* Wv    = (const float*)d_in[4];
    const float* bv    = (const float*)d_in[5];
    const float* Woff  = (const float*)d_in[6];
    const float* boff  = (const float*)d_in[7];
    const float* Wattn = (const float*)d_in[8];
    const float* battn = (const float*)d_in[9];
    const float* Wout  = (const float*)d_in[10];
    const float* bout  = (const float*)d_in[11];
    const float* Wf1   = (const float*)d_in[12];
    const float* bf1   = (const float*)d_in[13];
    const float* Wf2   = (const float*)d_in[14];
    const float* bf2   = (const float*)d_in[15];
    const float* lng   = (const float*)d_in[16];
    const float* lnb   = (const float*)d_in[17];
    const float* cw1   = (const float*)d_in[18];
    const float* g1    = (const float*)d_in[19];
    const float* b1    = (const float*)d_in[20];
    const float* cw2   = (const float*)d_in[21];
    const float* g2    = (const float*)d_in[22];
    const float* b2    = (const float*)d_in[23];
    const float* cw3   = (const float*)d_in[24];
    const float* g3    = (const float*)d_in[25];
    const float* b3    = (const float*)d_in[26];
    const float* cw4   = (const float*)d_in[27];
    const float* g4    = (const float*)d_in[28];
    const float* b4    = (const float*)d_in[29];
    const float* objw  = (const float*)d_in[30];
    const float* objb  = (const float*)d_in[31];
    float* out = (float*)d_out;

    float* S = nullptr;
    cudaGetSymbolAddress((void**)&S, g_scratch);
    int* gm = nullptr;
    cudaGetSymbolAddress((void**)&gm, g_maxv);

    float* PV    = S + OFF_V;
    float* PQIN  = S + OFF_QIN;
    float* POFF  = S + OFF_OFF;
    float* PATTN = S + OFF_ATTN;
    float* PAOUT = S + OFF_AOUT;
    float* PQ    = S + OFF_Q;
    float* PT1   = S + OFF_T1;
    float* PH1   = S + OFF_H1;
    float* PH2   = S + OFF_H2;
    float* PH3   = S + OFF_H3;
    float* PH4   = S + OFF_H4;
    float* PW1T  = S + OFF_W1T;
    float* PW2T  = S + OFF_W2T;
    float* PW3T  = S + OFF_W3T;
    float* PW4T  = S + OFF_W4T;
    float* PPART = S + OFF_PART;
    float* PSCALE= S + OFF_SCALE;
    float* PSHIFT= S + OFF_SHIFT;

    // --- observed_masks ---
    init_max_kernel<<<1, 1>>>(gm);
    reduce_max_kernel<<<40, 256>>>(proj, gm);
    write_mask_kernel<<<(NQ + 255) / 256, 256>>>(proj, gm, out + 21 * NQ);

    // --- conv weight reorders (idempotent) ---
    wreorder_kernel<<<((int)SZ_W1T + 255) / 256, 256>>>(cw1, PW1T, 128, 128, 7, 128, (int)SZ_W1T);
    wreorder_kernel<<<((int)SZ_W2T + 255) / 256, 256>>>(cw2, PW2T, 64, 128, 3, 64, (int)SZ_W2T);
    wreorder_kernel<<<((int)SZ_W3T + 255) / 256, 256>>>(cw3, PW3T, 48, 64, 3, 64, (int)SZ_W3T);
    wreorder_kernel<<<((int)SZ_W4T + 255) / 256, 256>>>(cw4, PW4T, 48, 48, 3, 64, (int)SZ_W4T);

    // --- q init ---
    cudaMemcpyAsync(PQ, bq, (size_t)NQ * ED * sizeof(float), cudaMemcpyDeviceToDevice);

    // --- 2 encoder layers ---
    for (int i = 0; i < 2; i++) {
        add2_kernel<<<(NQ * ED + 255) / 256, 256>>>(PQIN, PQ, bpos, NQ * ED);
        sgemm128<0><<<dim3(NV / 64, 2), 256>>>(value, Wv + (size_t)i * 128 * 128, bv + i * 128,
                                               nullptr, PV, NV, 128);
        sgemm128<0><<<dim3(NQ / 64, 8), 256>>>(PQIN, Woff + (size_t)i * 128 * 512, boff + i * 512,
                                               nullptr, POFF, NQ, 512);
        sgemm128<0><<<dim3(NQ / 64, 4), 256>>>(PQIN, Wattn + (size_t)i * 128 * 256, battn + i * 256,
                                               nullptr, PATTN, NQ, 256);
        softmax32_kernel<<<(NQ * HEADS + 255) / 256, 256>>>(PATTN);
        deform_kernel<<<(NQ * HEADS + 255) / 256, 256>>>(PV, POFF, PATTN, PAOUT);
        sgemm128<2><<<dim3(NQ / 64, 2), 256>>>(PAOUT, Wout + (size_t)i * 128 * 128, bout + i * 128,
                                               PQ, PT1, NQ, 128);
        ln_kernel<<<NQ, 128>>>(PT1, lng + (i * 2 + 0) * 128, lnb + (i * 2 + 0) * 128, PQ);
        sgemm128<1><<<dim3(NQ / 64, 2), 256>>>(PQ, Wf1 + (size_t)i * 128 * 128, bf1 + i * 128,
                                               nullptr, PT1, NQ, 128);
        sgemm128<2><<<dim3(NQ / 64, 2), 256>>>(PT1, Wf2 + (size_t)i * 128 * 128, bf2 + i * 128,
                                               PQ, PAOUT, NQ, 128);
        ln_kernel<<<NQ, 128>>>(PAOUT, lng + (i * 2 + 1) * 128, lnb + (i * 2 + 1) * 128, PQ);
    }

    // --- conv head (NHWC implicit GEMM) ---
    conv_igemm<7, 3><<<dim3(NQ / 64, 2), 256>>>(PQ, PW1T, PH1, 128, 128, 128);
    bn_stats_kernel<<<64, 128>>>(PH1, PPART, 128);
    bn_finalize_kernel<<<1, 128>>>(PPART, g1, b1, PSCALE, PSHIFT, 128);
    bn_apply_kernel<<<(NQ * 128 + 255) / 256, 256>>>(PH1, PSCALE, PSHIFT, 128, NQ * 128);

    conv_igemm<3, 1><<<dim3(NQ / 64, 1), 256>>>(PH1, PW2T, PH2, 128, 64, 64);
    bn_stats_kernel<<<64, 64>>>(PH2, PPART, 64);
    bn_finalize_kernel<<<1, 64>>>(PPART, g2, b2, PSCALE, PSHIFT, 64);
    bn_apply_kernel<<<(NQ * 64 + 255) / 256, 256>>>(PH2, PSCALE, PSHIFT, 64, NQ * 64);

    conv_igemm<3, 1><<<dim3(NQ / 64, 1), 256>>>(PH2, PW3T, PH3, 64, 64, 48);
    bn_stats_kernel<<<64, 48>>>(PH3, PPART, 48);
    bn_finalize_kernel<<<1, 48>>>(PPART, g3, b3, PSCALE, PSHIFT, 48);
    bn_apply_kernel<<<(NQ * 48 + 255) / 256, 256>>>(PH3, PSCALE, PSHIFT, 48, NQ * 48);

    conv_igemm<3, 1><<<dim3(NQ / 64, 1), 256>>>(PH3, PW4T, PH4, 48, 64, 48);
    bn_stats_kernel<<<64, 48>>>(PH4, PPART, 48);
    bn_finalize_kernel<<<1, 48>>>(PPART, g4, b4, PSCALE, PSHIFT, 48);
    bn_apply_kernel<<<(NQ * 48 + 255) / 256, 256>>>(PH4, PSCALE, PSHIFT, 48, NQ * 48);

    head_conv_kernel<<<(NQ + 255) / 256, 256>>>(PH4, objw, objb, out);
}

// round 3
// speedup vs baseline: 1.2304x; 1.2304x over previous
#include <cuda_runtime.h>
#include <cuda_bf16.h>
#include <cstdint>
#include <climits>

// ---------------- problem constants ----------------
constexpr int NQ = 40000;        // 200*200
constexpr int ED = 128;
constexpr int NV = 43520;        // sum of level sizes
constexpr int HEADS = 8;

// ---------------- scratch layout (floats) ----------------
constexpr size_t OFF_V    = 0;
constexpr size_t SZ_V     = (size_t)NV * ED;
constexpr size_t OFF_QIN  = OFF_V + SZ_V;
constexpr size_t SZ_Q     = (size_t)NQ * ED;
constexpr size_t OFF_OFF  = OFF_QIN + SZ_Q;
constexpr size_t SZ_OFF   = (size_t)NQ * 512;
constexpr size_t OFF_ATTN = OFF_OFF + SZ_OFF;
constexpr size_t SZ_ATTN  = (size_t)NQ * 256;
constexpr size_t OFF_AOUT = OFF_ATTN + SZ_ATTN;
constexpr size_t OFF_Q    = OFF_AOUT + SZ_Q;
constexpr size_t OFF_T1   = OFF_Q + SZ_Q;
constexpr size_t OFF_H1   = OFF_T1 + SZ_Q;
constexpr size_t SZ_H1    = (size_t)NQ * 128;
constexpr size_t OFF_H2   = OFF_H1 + SZ_H1;
constexpr size_t SZ_H2    = (size_t)NQ * 64;
constexpr size_t OFF_H3   = OFF_H2 + SZ_H2;
constexpr size_t SZ_H3    = (size_t)NQ * 48;
constexpr size_t OFF_H4   = OFF_H3 + SZ_H3;
constexpr size_t OFF_W2T  = OFF_H4 + SZ_H3;
constexpr size_t SZ_W2T   = 9 * 128 * 64;
constexpr size_t OFF_W3T  = OFF_W2T + SZ_W2T;
constexpr size_t SZ_W3T   = 9 * 64 * 64;
constexpr size_t OFF_W4T  = OFF_W3T + SZ_W3T;
constexpr size_t SZ_W4T   = 9 * 48 * 64;
constexpr size_t OFF_PART = OFF_W4T + SZ_W4T;
constexpr size_t SZ_PART  = 64 * 128 * 2;
constexpr size_t OFF_SCALE= OFF_PART + SZ_PART;
constexpr size_t OFF_SHIFT= OFF_SCALE + 128;
constexpr size_t SCRATCH_TOTAL = OFF_SHIFT + 128;

__device__ float g_scratch[SCRATCH_TOTAL];
__device__ int   g_maxv;

// bf16 split buffers for tensor-core conv1
constexpr int W1CHUNKS = 98;                 // 49 positions * 2 halves of 128 ci
__device__ __align__(16) __nv_bfloat16 g_qhi[(size_t)NQ * 128];
__device__ __align__(16) __nv_bfloat16 g_qlo[(size_t)NQ * 128];
// weights stored [chunk][co(=n) 128][k 64]  (n-major so plain ldmatrix gives B frags)
__device__ __align__(16) __nv_bfloat16 g_whi[(size_t)W1CHUNKS * 128 * 64];
__device__ __align__(16) __nv_bfloat16 g_wlo[(size_t)W1CHUNKS * 128 * 64];

// ---------------- small helpers ----------------
__device__ __forceinline__ uint32_t smem_u32(const void* p) {
    return (uint32_t)__cvta_generic_to_shared(p);
}
__device__ __forceinline__ void cpasync16(uint32_t dst, const void* src, bool valid) {
    asm volatile("cp.async.cg.shared.global [%0], [%1], 16, %2;"
                 :: "r"(dst), "l"(src), "r"(valid ? 16u : 0u));
}
__device__ __forceinline__ void cp_commit() { asm volatile("cp.async.commit_group;"); }
__device__ __forceinline__ void cp_wait1()  { asm volatile("cp.async.wait_group 1;"); }

__device__ __forceinline__ void ldmx4(uint32_t* r, uint32_t addr) {
    asm volatile("ldmatrix.sync.aligned.m8n8.x4.shared.b16 {%0,%1,%2,%3}, [%4];"
                 : "=r"(r[0]), "=r"(r[1]), "=r"(r[2]), "=r"(r[3]) : "r"(addr));
}
__device__ __forceinline__ void ldmx2(uint32_t* r, uint32_t addr) {
    asm volatile("ldmatrix.sync.aligned.m8n8.x2.shared.b16 {%0,%1}, [%2];"
                 : "=r"(r[0]), "=r"(r[1]) : "r"(addr));
}
__device__ __forceinline__ void mma_bf16(float* c, const uint32_t* a, const uint32_t* b) {
    asm volatile("mma.sync.aligned.m16n8k16.row.col.f32.bf16.bf16.f32 "
                 "{%0,%1,%2,%3}, {%4,%5,%6,%7}, {%8,%9}, {%0,%1,%2,%3};"
                 : "+f"(c[0]), "+f"(c[1]), "+f"(c[2]), "+f"(c[3])
                 : "r"(a[0]), "r"(a[1]), "r"(a[2]), "r"(a[3]), "r"(b[0]), "r"(b[1]));
}

// ---------------- elementwise helpers ----------------
__global__ void add2_kernel(float* __restrict__ o, const float* __restrict__ a,
                            const float* __restrict__ b, int n) {
    int i = blockIdx.x * blockDim.x + threadIdx.x;
    if (i < n) o[i] = a[i] + b[i];
}

__global__ void init_max_kernel(int* gm) { *gm = INT_MIN; }

__global__ void reduce_max_kernel(const int* __restrict__ p, int* gm) {
    int v = INT_MIN;
    for (int k = blockIdx.x * blockDim.x + threadIdx.x; k < NQ; k += gridDim.x * blockDim.x)
        v = max(v, p[k]);
    #pragma unroll
    for (int o = 16; o > 0; o >>= 1) v = max(v, __shfl_xor_sync(0xffffffffu, v, o));
    __shared__ int sm[8];
    int w = threadIdx.x >> 5;
    if ((threadIdx.x & 31) == 0) sm[w] = v;
    __syncthreads();
    if (threadIdx.x == 0) {
        int bv = sm[0];
        for (int i = 1; i < (int)(blockDim.x >> 5); i++) bv = max(bv, sm[i]);
        atomicMax(gm, bv);
    }
}

__global__ void write_mask_kernel(const int* __restrict__ p, const int* __restrict__ gm,
                                  float* __restrict__ out) {
    int i = blockIdx.x * blockDim.x + threadIdx.x;
    if (i < NQ) out[i] = (p[i] < *gm) ? 1.0f : 0.0f;
}

// ---------------- SGEMM, K = 128, 64x64 tile, 4x4 micro ----------------
template<int FLAGS>   // bit0 relu, bit1 residual
__global__ void __launch_bounds__(256) sgemm128(
    const float* __restrict__ A, const float* __restrict__ B,
    const float* __restrict__ bias, const float* __restrict__ R,
    float* __restrict__ C, int M, int N)
{
    __shared__ float As[16][68];
    __shared__ float Bs[16][68];
    const int bm = blockIdx.x * 64, bn = blockIdx.y * 64;
    const int tid = threadIdx.x;
    const int arow = tid >> 2, acol = (tid & 3) * 4;
    const int brow = tid >> 4, bcol = (tid & 15) * 4;
    const int r0 = (tid >> 4) * 4, c0 = (tid & 15) * 4;

    float acc[4][4];
    #pragma unroll
    for (int i = 0; i < 4; i++)
        #pragma unroll
        for (int j = 0; j < 4; j++) acc[i][j] = 0.f;

    const float* Aptr = A + (size_t)(bm + arow) * 128 + acol;

    for (int k0 = 0; k0 < 128; k0 += 16) {
        float4 a = *(const float4*)(Aptr + k0);
        As[acol + 0][arow] = a.x; As[acol + 1][arow] = a.y;
        As[acol + 2][arow] = a.z; As[acol + 3][arow] = a.w;
        *(float4*)&Bs[brow][bcol] = *(const float4*)&B[(size_t)(k0 + brow) * N + bn + bcol];
        __syncthreads();
        #pragma unroll
        for (int k = 0; k < 16; k++) {
            float4 ra = *(const float4*)&As[k][r0];
            float4 rb = *(const float4*)&Bs[k][c0];
            float av[4] = {ra.x, ra.y, ra.z, ra.w};
            float bv[4] = {rb.x, rb.y, rb.z, rb.w};
            #pragma unroll
            for (int i = 0; i < 4; i++)
                #pragma unroll
                for (int j = 0; j < 4; j++)
                    acc[i][j] = fmaf(av[i], bv[j], acc[i][j]);
        }
        __syncthreads();
    }

    float4 bb = *(const float4*)&bias[bn + c0];
    float bvv[4] = {bb.x, bb.y, bb.z, bb.w};
    #pragma unroll
    for (int i = 0; i < 4; i++) {
        size_t row = (size_t)(bm + r0 + i);
        float v[4];
        #pragma unroll
        for (int j = 0; j < 4; j++) v[j] = acc[i][j] + bvv[j];
        if (FLAGS & 2) {
            float4 rr = *(const float4*)&R[row * N + bn + c0];
            v[0] += rr.x; v[1] += rr.y; v[2] += rr.z; v[3] += rr.w;
        }
        if (FLAGS & 1) {
            #pragma unroll
            for (int j = 0; j < 4; j++) v[j] = fmaxf(v[j], 0.f);
        }
        *(float4*)&C[row * N + bn + c0] = make_float4(v[0], v[1], v[2], v[3]);
    }
}

// ---------------- softmax over 32 per (query, head) ----------------
__global__ void softmax32_kernel(float* __restrict__ A) {
    int t = blockIdx.x * blockDim.x + threadIdx.x;
    if (t >= NQ * HEADS) return;
    float* a = A + (size_t)t * 32;
    float e[32];
    float m = -1e30f;
    #pragma unroll
    for (int k = 0; k < 32; k++) m = fmaxf(m, a[k]);
    float s = 0.f;
    #pragma unroll
    for (int k = 0; k < 32; k++) { e[k] = expf(a[k] - m); s += e[k]; }
    float inv = 1.f / s;
    #pragma unroll
    for (int k = 0; k < 32; k++) a[k] = e[k] * inv;
}

// ---------------- deformable attention sampling ----------------
__global__ void __launch_bounds__(256) deform_kernel(
    const float* __restrict__ V, const float* __restrict__ OFFS,
    const float* __restrict__ ATT, float* __restrict__ AOUT)
{
    int t = blockIdx.x * 256 + threadIdx.x;
    if (t >= NQ * HEADS) return;
    const int n = t >> 3, h = t & 7;
    const float rx = ((float)(n % 200) + 0.5f) * (1.f / 200.f);
    const float ry = ((float)(n / 200) + 0.5f) * (1.f / 200.f);
    const float* op = OFFS + (size_t)n * 512 + h * 64;
    const float* ap = ATT + (size_t)n * 256 + h * 32;

    float acc[16];
    #pragma unroll
    for (int d = 0; d < 16; d++) acc[d] = 0.f;

    const int stc[4] = {0, 32768, 40960, 43008};
    const int Wc[4]  = {256, 128, 64, 32};
    const int Hc[4]  = {128, 64, 32, 16};

    #pragma unroll
    for (int l = 0; l < 4; l++) {
        const int W = Wc[l], H = Hc[l], st = stc[l];
        const float Wf = (float)W, Hf = (float)H;
        for (int p = 0; p < 8; p++) {
            float ox = op[(l * 8 + p) * 2 + 0];
            float oy = op[(l * 8 + p) * 2 + 1];
            float aw = ap[l * 8 + p];
            float x = (rx + ox / Wf) * Wf - 0.5f;
            float y = (ry + oy / Hf) * Hf - 0.5f;
            float xf = floorf(x), yf = floorf(y);
            int x0 = (int)xf, y0 = (int)yf;
            float fx = x - xf, fy = y - yf;
            float wx[2] = {1.f - fx, fx};
            float wy[2] = {1.f - fy, fy};
            #pragma unroll
            for (int c = 0; c < 4; c++) {
                int xi = x0 + (c & 1), yi = y0 + (c >> 1);
                float wgt = wx[c & 1] * wy[c >> 1];
                if (xi >= 0 && xi < W && yi >= 0 && yi < H && wgt != 0.f) {
                    const float4* gp = (const float4*)(V + ((size_t)(st + yi * W + xi)) * 128 + h * 16);
                    float cw = aw * wgt;
                    float4 g0 = gp[0], g1 = gp[1], g2 = gp[2], g3 = gp[3];
                    acc[0]  += cw * g0.x; acc[1]  += cw * g0.y; acc[2]  += cw * g0.z; acc[3]  += cw * g0.w;
                    acc[4]  += cw * g1.x; acc[5]  += cw * g1.y; acc[6]  += cw * g1.z; acc[7]  += cw * g1.w;
                    acc[8]  += cw * g2.x; acc[9]  += cw * g2.y; acc[10] += cw * g2.z; acc[11] += cw * g2.w;
                    acc[12] += cw * g3.x; acc[13] += cw * g3.y; acc[14] += cw * g3.z; acc[15] += cw * g3.w;
                }
            }
        }
    }
    float4* o = (float4*)(AOUT + (size_t)n * 128 + h * 16);
    o[0] = make_float4(acc[0], acc[1], acc[2], acc[3]);
    o[1] = make_float4(acc[4], acc[5], acc[6], acc[7]);
    o[2] = make_float4(acc[8], acc[9], acc[10], acc[11]);
    o[3] = make_float4(acc[12], acc[13], acc[14], acc[15]);
}

// ---------------- layernorm over 128 per row ----------------
__global__ void ln_kernel(const float* __restrict__ X, const float* __restrict__ g,
                          const float* __restrict__ b, float* __restrict__ Y)
{
    int r = blockIdx.x;
    int t = threadIdx.x;
    float x = X[(size_t)r * 128 + t];
    float s = x;
    #pragma unroll
    for (int o = 16; o > 0; o >>= 1) s += __shfl_xor_sync(0xffffffffu, s, o);
    __shared__ float sm[4], sm2[4];
    int w = t >> 5, lane = t & 31;
    if (lane == 0) sm[w] = s;
    __syncthreads();
    float m = (sm[0] + sm[1] + sm[2] + sm[3]) * (1.f / 128.f);
    float d = x - m;
    float q = d * d;
    #pragma unroll
    for (int o = 16; o > 0; o >>= 1) q += __shfl_xor_sync(0xffffffffu, q, o);
    if (lane == 0) sm2[w] = q;
    __syncthreads();
    float var = (sm2[0] + sm2[1] + sm2[2] + sm2[3]) * (1.f / 128.f);
    Y[(size_t)r * 128 + t] = d * rsqrtf(var + 1e-5f) * g[t] + b[t];
}

// ---------------- bf16 split converters for conv1 ----------------
__global__ void qsplit_kernel(const float* __restrict__ X, __nv_bfloat16* __restrict__ hi,
                              __nv_bfloat16* __restrict__ lo, int n)
{
    int i = blockIdx.x * blockDim.x + threadIdx.x;
    if (i < n) {
        float v = X[i];
        __nv_bfloat16 h = __float2bfloat16(v);
        hi[i] = h;
        lo[i] = __float2bfloat16(v - __bfloat162float(h));
    }
}

__global__ void wsplit_kernel(const float* __restrict__ W, __nv_bfloat16* __restrict__ hi,
                              __nv_bfloat16* __restrict__ lo)
{
    int i = blockIdx.x * blockDim.x + threadIdx.x;  // [c][co][k]
    if (i >= W1CHUNKS * 128 * 64) return;
    int k  = i & 63;
    int co = (i >> 6) & 127;
    int c  = i >> 13;
    int e = c >> 1, ci = ((c & 1) << 6) + k;
    int ky = e / 7, kx = e % 7;
    float v = W[(((size_t)co * 128 + ci) * 7 + ky) * 7 + kx];
    __nv_bfloat16 h = __float2bfloat16(v);
    hi[i] = h;
    lo[i] = __float2bfloat16(v - __bfloat162float(h));
}

// ---------------- conv1 (7x7, 128->128) via mma.sync bf16x3 ----------------
// 128x128 output tile per CTA, K = 98 chunks of 64. 8 warps in 2(m) x 4(n).
// SMEM per buffer: Ahi, Alo (128 rows x 64 k), Bhi, Blo (128 n-rows x 64 k),
// all with 72-bf16 (144B) row stride. Double buffered via cp.async groups.
constexpr int ROWB = 144;                       // bytes per smem row
constexpr int TILE_B = 128 * ROWB;              // 18432 bytes per matrix tile
constexpr int BUF_B = 4 * TILE_B;               // Ahi, Alo, Bhi, Blo
constexpr int CONV1_SMEM = 2 * BUF_B;           // 147456

__global__ void __launch_bounds__(256, 1) conv1_mma_kernel(
    const __nv_bfloat16* __restrict__ qhi, const __nv_bfloat16* __restrict__ qlo,
    const __nv_bfloat16* __restrict__ whi, const __nv_bfloat16* __restrict__ wlo,
    float* __restrict__ Out)
{
    extern __shared__ char smem[];
    const int tid = threadIdx.x;
    const int wid = tid >> 5, lane = tid & 31;
    const int warp_m = wid >> 2, warp_n = wid & 3;
    const uint32_t sb = smem_u32(smem);
    const int bm = blockIdx.x * 128;

    // loader mapping: 2 threads per row, each covering 32 bf16 (64B = 4x16B)
    const int lrow = tid >> 1, lhalf = tid & 1;
    const int pm = bm + lrow;
    const int py = pm / 200, px = pm % 200;
    const bool prow_ok = pm < NQ;
    const uint32_t s_arow = sb + (uint32_t)lrow * ROWB + (uint32_t)lhalf * 64;
    const uint32_t s_brow = s_arow + 2 * TILE_B;

    // ldmatrix lane addressing
    const int ar = lane & 15, ak = lane >> 4;          // A: 16 rows x 2 k-segments
    const int br = lane & 7, bk = (lane >> 3) & 1;     // B: 8 rows x 2 k-segments
    const uint32_t a_base = sb + (uint32_t)(warp_m * 64 + ar) * ROWB + (uint32_t)ak * 16;
    const uint32_t b_base = sb + 2 * TILE_B + (uint32_t)(warp_n * 32 + br) * ROWB + (uint32_t)bk * 16;

    float acc[4][4][4];
    #pragma unroll
    for (int mt = 0; mt < 4; mt++)
        #pragma unroll
        for (int nt = 0; nt < 4; nt++)
            #pragma unroll
            for (int d = 0; d < 4; d++) acc[mt][nt][d] = 0.f;

    auto load_chunk = [&](int c, int buf) {
        const int e = c >> 1, ch = c & 1;
        const int qy = py + e / 7 - 3;
        const int qx = px + e % 7 - 3;
        const bool val = prow_ok && qy >= 0 && qy < 200 && qx >= 0 && qx < 200;
        const size_t aoff = (size_t)(val ? (qy * 200 + qx) : 0) * 128 + (size_t)ch * 64 + (size_t)lhalf * 32;
        const char* agh = (const char*)(qhi + aoff);
        const char* agl = (const char*)(qlo + aoff);
        const size_t boff = ((size_t)c * 128 + lrow) * 64 + (size_t)lhalf * 32;
        const char* bgh = (const char*)(whi + boff);
        const char* bgl = (const char*)(wlo + boff);
        const uint32_t sa = s_arow + (uint32_t)buf * BUF_B;
        const uint32_t sbr = s_brow + (uint32_t)buf * BUF_B;
        #pragma unroll
        for (int i = 0; i < 4; i++) {
            cpasync16(sa + i * 16,          agh + i * 16, val);
            cpasync16(sa + TILE_B + i * 16, agl + i * 16, val);
            cpasync16(sbr + i * 16,          bgh + i * 16, true);
            cpasync16(sbr + TILE_B + i * 16, bgl + i * 16, true);
        }
    };

    load_chunk(0, 0); cp_commit();
    load_chunk(1, 1); cp_commit();

    for (int c = 0; c < W1CHUNKS; c++) {
        const int buf = c & 1;
        cp_wait1();
        __syncthreads();

        const uint32_t ab = a_base + (uint32_t)buf * BUF_B;
        const uint32_t bb = b_base + (uint32_t)buf * BUF_B;
        #pragma unroll
        for (int ks = 0; ks < 4; ks++) {
            const uint32_t kbyte = (uint32_t)ks * 32;
            uint32_t bh[4][2], bl[4][2];
            #pragma unroll
            for (int nt = 0; nt < 4; nt++) {
                ldmx2(bh[nt], bb + (uint32_t)nt * 8 * ROWB + kbyte);
                ldmx2(bl[nt], bb + TILE_B + (uint32_t)nt * 8 * ROWB + kbyte);
            }
            #pragma unroll
            for (int mt = 0; mt < 4; mt++) {
                uint32_t ah[4], al[4];
                ldmx4(ah, ab + (uint32_t)mt * 16 * ROWB + kbyte);
                ldmx4(al, ab + TILE_B + (uint32_t)mt * 16 * ROWB + kbyte);
                #pragma unroll
                for (int nt = 0; nt < 4; nt++) {
                    mma_bf16(acc[mt][nt], ah, bh[nt]);
                    mma_bf16(acc[mt][nt], ah, bl[nt]);
                    mma_bf16(acc[mt][nt], al, bh[nt]);
                }
            }
        }
        __syncthreads();
        if (c + 2 < W1CHUNKS) load_chunk(c + 2, buf);
        cp_commit();
    }

    // epilogue: D[row][col], row = bm + warp_m*64 + mt*16 + lane/4 (+8)
    const int g = lane >> 2, tg = lane & 3;
    #pragma unroll
    for (int mt = 0; mt < 4; mt++) {
        const int r0 = bm + warp_m * 64 + mt * 16 + g;
        #pragma unroll
        for (int nt = 0; nt < 4; nt++) {
            const int col = warp_n * 32 + nt * 8 + tg * 2;
            if (r0 < NQ)
                *(float2*)&Out[(size_t)r0 * 128 + col] = make_float2(acc[mt][nt][0], acc[mt][nt][1]);
            if (r0 + 8 < NQ)
                *(float2*)&Out[(size_t)(r0 + 8) * 128 + col] = make_float2(acc[mt][nt][2], acc[mt][nt][3]);
        }
    }
}

// ---------------- weight reorder for fp32 convs 2-4 ----------------
__global__ void wreorder_kernel(const float* __restrict__ W, float* __restrict__ Wt,
                                int CO, int CI, int KS, int stride, int total)
{
    int i = blockIdx.x * blockDim.x + threadIdx.x;
    if (i >= total) return;
    int col = i % stride;
    int row = i / stride;
    int ci = row % CI;
    int e = row / CI;
    int ky = e / KS, kx = e % KS;
    Wt[i] = (col < CO) ? W[((size_t)(col * CI + ci) * KS + ky) * KS + kx] : 0.f;
}

// ---------------- implicit-GEMM direct conv (NHWC, 200x200), fp32 ----------------
template<int KS, int PAD>
__global__ void __launch_bounds__(256) conv_igemm(
    const float* __restrict__ In, const float* __restrict__ Wt,
    float* __restrict__ Out, int CIN, int wt_stride, int COUT)
{
    __shared__ float As[16][68];
    __shared__ float Bs[16][68];
    const int bm = blockIdx.x * 64, bn = blockIdx.y * 64;
    const int tid = threadIdx.x;
    const int arow = tid >> 2, acol = (tid & 3) * 4;
    const int brow = tid >> 4, bcol = (tid & 15) * 4;
    const int r0 = (tid >> 4) * 4, c0 = (tid & 15) * 4;

    const int pm = bm + arow;
    const int py = pm / 200, px = pm % 200;

    float acc[4][4];
    #pragma unroll
    for (int i = 0; i < 4; i++)
        #pragma unroll
        for (int j = 0; j < 4; j++) acc[i][j] = 0.f;

    for (int e = 0; e < KS * KS; e++) {
        const int qy = py + e / KS - PAD;
        const int qx = px + e % KS - PAD;
        const bool val = (qy >= 0) && (qy < 200) && (qx >= 0) && (qx < 200);
        const float* ain = In + (size_t)(qy * 200 + qx) * CIN;
        for (int kc = 0; kc < CIN; kc += 16) {
            float4 a = val ? *(const float4*)&ain[kc + acol] : make_float4(0.f, 0.f, 0.f, 0.f);
            As[acol + 0][arow] = a.x; As[acol + 1][arow] = a.y;
            As[acol + 2][arow] = a.z; As[acol + 3][arow] = a.w;
            *(float4*)&Bs[brow][bcol] =
                *(const float4*)&Wt[(size_t)(e * CIN + kc + brow) * wt_stride + bn + bcol];
            __syncthreads();
            #pragma unroll
            for (int k = 0; k < 16; k++) {
                float4 ra = *(const float4*)&As[k][r0];
                float4 rb = *(const float4*)&Bs[k][c0];
                float av[4] = {ra.x, ra.y, ra.z, ra.w};
                float bv[4] = {rb.x, rb.y, rb.z, rb.w};
                #pragma unroll
                for (int i = 0; i < 4; i++)
                    #pragma unroll
                    for (int j = 0; j < 4; j++)
                        acc[i][j] = fmaf(av[i], bv[j], acc[i][j]);
            }
            __syncthreads();
        }
    }

    if (bn + c0 < COUT) {
        #pragma unroll
        for (int i = 0; i < 4; i++) {
            size_t row = (size_t)(bm + r0 + i);
            *(float4*)&Out[row * COUT + bn + c0] =
                make_float4(acc[i][0], acc[i][1], acc[i][2], acc[i][3]);
        }
    }
}

// ---------------- batchnorm (training-mode stats), deterministic 2-stage ----------------
__global__ void bn_stats_kernel(const float* __restrict__ X, float* __restrict__ part, int C)
{
    int c = threadIdx.x;
    int g = blockIdx.x;
    const int per = (NQ + 63) / 64;
    int p0 = g * per;
    int p1 = min(NQ, p0 + per);
    float s = 0.f, q = 0.f;
    for (int p = p0; p < p1; p++) {
        float x = X[(size_t)p * C + c];
        s += x; q += x * x;
    }
    part[(size_t)g * 2 * C + c] = s;
    part[(size_t)g * 2 * C + C + c] = q;
}

__global__ void bn_finalize_kernel(const float* __restrict__ part,
                                   const float* __restrict__ gamma, const float* __restrict__ beta,
                                   float* __restrict__ scale, float* __restrict__ shift, int C)
{
    int c = threadIdx.x;
    float s = 0.f, q = 0.f;
    for (int g = 0; g < 64; g++) {
        s += part[(size_t)g * 2 * C + c];
        q += part[(size_t)g * 2 * C + C + c];
    }
    const float invP = 1.f / (float)NQ;
    float m = s * invP;
    float v = q * invP - m * m;
    float sc = gamma[c] * rsqrtf(v + 1e-5f);
    scale[c] = sc;
    shift[c] = beta[c] - m * sc;
}

__global__ void bn_apply_kernel(float* __restrict__ X, const float* __restrict__ scale,
                                const float* __restrict__ shift, int C, int total)
{
    int i = blockIdx.x * blockDim.x + threadIdx.x;
    if (i < total) {
        int c = i % C;
        X[i] = fmaxf(0.f, fmaf(X[i], scale[c], shift[c]));
    }
}

// ---------------- head: 1x1 conv 48 -> 21, output NCHW ----------------
__global__ void head_conv_kernel(const float* __restrict__ H4, const float* __restrict__ Wo,
                                 const float* __restrict__ bo, float* __restrict__ out)
{
    int p = blockIdx.x * blockDim.x + threadIdx.x;
    if (p >= NQ) return;
    float x[48];
    const float4* hp = (const float4*)(H4 + (size_t)p * 48);
    #pragma unroll
    for (int i = 0; i < 12; i++) {
        float4 v = hp[i];
        x[i * 4 + 0] = v.x; x[i * 4 + 1] = v.y; x[i * 4 + 2] = v.z; x[i * 4 + 3] = v.w;
    }
    for (int co = 0; co < 21; co++) {
        float s = bo[co];
        const float* w = Wo + co * 48;
        #pragma unroll
        for (int ci = 0; ci < 48; ci++) s = fmaf(x[ci], w[ci], s);
        out[(size_t)co * NQ + p] = s;
    }
}

// ---------------- launch ----------------
extern "C" void kernel_launch(void* const* d_in, const int* in_sizes, int n_in,
                              void* d_out, int out_size)
{
    const float* value = (const float*)d_in[0];
    const float* bq    = (const float*)d_in[1];
    const float* bpos  = (const float*)d_in[2];
    const int*   proj  = (const int*)d_in[3];
    const float* Wv    = (const float*)d_in[4];
    const float* bv    = (const float*)d_in[5];
    const float* Woff  = (const float*)d_in[6];
    const float* boff  = (const float*)d_in[7];
    const float* Wattn = (const float*)d_in[8];
    const float* battn = (const float*)d_in[9];
    const float* Wout  = (const float*)d_in[10];
    const float* bout  = (const float*)d_in[11];
    const float* Wf1   = (const float*)d_in[12];
    const float* bf1   = (const float*)d_in[13];
    const float* Wf2   = (const float*)d_in[14];
    const float* bf2   = (const float*)d_in[15];
    const float* lng   = (const float*)d_in[16];
    const float* lnb   = (const float*)d_in[17];
    const float* cw1   = (const float*)d_in[18];
    const float* g1    = (const float*)d_in[19];
    const float* b1    = (const float*)d_in[20];
    const float* cw2   = (const float*)d_in[21];
    const float* g2    = (const float*)d_in[22];
    const float* b2    = (const float*)d_in[23];
    const float* cw3   = (const float*)d_in[24];
    const float* g3    = (const float*)d_in[25];
    const float* b3    = (const float*)d_in[26];
    const float* cw4   = (const float*)d_in[27];
    const float* g4    = (const float*)d_in[28];
    const float* b4    = (const float*)d_in[29];
    const float* objw  = (const float*)d_in[30];
    const float* objb  = (const float*)d_in[31];
    float* out = (float*)d_out;

    float* S = nullptr;
    cudaGetSymbolAddress((void**)&S, g_scratch);
    int* gm = nullptr;
    cudaGetSymbolAddress((void**)&gm, g_maxv);
    __nv_bfloat16 *qhi = nullptr, *qlo = nullptr, *whi = nullptr, *wlo = nullptr;
    cudaGetSymbolAddress((void**)&qhi, g_qhi);
    cudaGetSymbolAddress((void**)&qlo, g_qlo);
    cudaGetSymbolAddress((void**)&whi, g_whi);
    cudaGetSymbolAddress((void**)&wlo, g_wlo);

    float* PV    = S + OFF_V;
    float* PQIN  = S + OFF_QIN;
    float* POFF  = S + OFF_OFF;
    float* PATTN = S + OFF_ATTN;
    float* PAOUT = S + OFF_AOUT;
    float* PQ    = S + OFF_Q;
    float* PT1   = S + OFF_T1;
    float* PH1   = S + OFF_H1;
    float* PH2   = S + OFF_H2;
    float* PH3   = S + OFF_H3;
    float* PH4   = S + OFF_H4;
    float* PW2T  = S + OFF_W2T;
    float* PW3T  = S + OFF_W3T;
    float* PW4T  = S + OFF_W4T;
    float* PPART = S + OFF_PART;
    float* PSCALE= S + OFF_SCALE;
    float* PSHIFT= S + OFF_SHIFT;

    cudaFuncSetAttribute(conv1_mma_kernel, cudaFuncAttributeMaxDynamicSharedMemorySize, CONV1_SMEM);

    // --- observed_masks ---
    init_max_kernel<<<1, 1>>>(gm);
    reduce_max_kernel<<<40, 256>>>(proj, gm);
    write_mask_kernel<<<(NQ + 255) / 256, 256>>>(proj, gm, out + 21 * NQ);

    // --- conv weight prep ---
    wsplit_kernel<<<(W1CHUNKS * 128 * 64 + 255) / 256, 256>>>(cw1, whi, wlo);
    wreorder_kernel<<<((int)SZ_W2T + 255) / 256, 256>>>(cw2, PW2T, 64, 128, 3, 64, (int)SZ_W2T);
    wreorder_kernel<<<((int)SZ_W3T + 255) / 256, 256>>>(cw3, PW3T, 48, 64, 3, 64, (int)SZ_W3T);
    wreorder_kernel<<<((int)SZ_W4T + 255) / 256, 256>>>(cw4, PW4T, 48, 48, 3, 64, (int)SZ_W4T);

    // --- q init ---
    cudaMemcpyAsync(PQ, bq, (size_t)NQ * ED * sizeof(float), cudaMemcpyDeviceToDevice);

    // --- 2 encoder layers ---
    for (int i = 0; i < 2; i++) {
        add2_kernel<<<(NQ * ED + 255) / 256, 256>>>(PQIN, PQ, bpos, NQ * ED);
        sgemm128<0><<<dim3(NV / 64, 2), 256>>>(value, Wv + (size_t)i * 128 * 128, bv + i * 128,
                                               nullptr, PV, NV, 128);
        sgemm128<0><<<dim3(NQ / 64, 8), 256>>>(PQIN, Woff + (size_t)i * 128 * 512, boff + i * 512,
                                               nullptr, POFF, NQ, 512);
        sgemm128<0><<<dim3(NQ / 64, 4), 256>>>(PQIN, Wattn + (size_t)i * 128 * 256, battn + i * 256,
                                               nullptr, PATTN, NQ, 256);
        softmax32_kernel<<<(NQ * HEADS + 255) / 256, 256>>>(PATTN);
        deform_kernel<<<(NQ * HEADS + 255) / 256, 256>>>(PV, POFF, PATTN, PAOUT);
        sgemm128<2><<<dim3(NQ / 64, 2), 256>>>(PAOUT, Wout + (size_t)i * 128 * 128, bout + i * 128,
                                               PQ, PT1, NQ, 128);
        ln_kernel<<<NQ, 128>>>(PT1, lng + (i * 2 + 0) * 128, lnb + (i * 2 + 0) * 128, PQ);
        sgemm128<1><<<dim3(NQ / 64, 2), 256>>>(PQ, Wf1 + (size_t)i * 128 * 128, bf1 + i * 128,
                                               nullptr, PT1, NQ, 128);
        sgemm128<2><<<dim3(NQ / 64, 2), 256>>>(PT1, Wf2 + (size_t)i * 128 * 128, bf2 + i * 128,
                                               PQ, PAOUT, NQ, 128);
        ln_kernel<<<NQ, 128>>>(PAOUT, lng + (i * 2 + 1) * 128, lnb + (i * 2 + 1) * 128, PQ);
    }

    // --- conv head ---
    // conv1: mma.sync bf16x3 implicit GEMM (313 CTAs of 128 pixels)
    qsplit_kernel<<<(NQ * 128 + 255) / 256, 256>>>(PQ, qhi, qlo, NQ * 128);
    conv1_mma_kernel<<<313, 256, CONV1_SMEM>>>(qhi, qlo, whi, wlo, PH1);
    bn_stats_kernel<<<64, 128>>>(PH1, PPART, 128);
    bn_finalize_kernel<<<1, 128>>>(PPART, g1, b1, PSCALE, PSHIFT, 128);
    bn_apply_kernel<<<(NQ * 128 + 255) / 256, 256>>>(PH1, PSCALE, PSHIFT, 128, NQ * 128);

    conv_igemm<3, 1><<<dim3(NQ / 64, 1), 256>>>(PH1, PW2T, PH2, 128, 64, 64);
    bn_stats_kernel<<<64, 64>>>(PH2, PPART, 64);
    bn_finalize_kernel<<<1, 64>>>(PPART, g2, b2, PSCALE, PSHIFT, 64);
    bn_apply_kernel<<<(NQ * 64 + 255) / 256, 256>>>(PH2, PSCALE, PSHIFT, 64, NQ * 64);

    conv_igemm<3, 1><<<dim3(NQ / 64, 1), 256>>>(PH2, PW3T, PH3, 64, 64, 48);
    bn_stats_kernel<<<64, 48>>>(PH3, PPART, 48);
    bn_finalize_kernel<<<1, 48>>>(PPART, g3, b3, PSCALE, PSHIFT, 48);
    bn_apply_kernel<<<(NQ * 48 + 255) / 256, 256>>>(PH3, PSCALE, PSHIFT, 48, NQ * 48);

    conv_igemm<3, 1><<<dim3(NQ / 64, 1), 256>>>(PH3, PW4T, PH4, 48, 64, 48);
    bn_stats_kernel<<<64, 48>>>(PH4, PPART, 48);
    bn_finalize_kernel<<<1, 48>>>(PPART, g4, b4, PSCALE, PSHIFT, 48);
    bn_apply_kernel<<<(NQ * 48 + 255) / 256, 256>>>(PH4, PSCALE, PSHIFT, 48, NQ * 48);

    head_conv_kernel<<<(NQ + 255) / 256, 256>>>(PH4, objw, objb, out);
}

// round 4
// speedup vs baseline: 1.3007x; 1.0571x over previous
#include <cuda_runtime.h>
#include <cuda_bf16.h>
#include <cstdint>
#include <climits>

// ---------------- problem constants ----------------
constexpr int NQ = 40000;        // 200*200
constexpr int ED = 128;
constexpr int NV = 43520;        // sum of level sizes
constexpr int HEADS = 8;

// ---------------- scratch layout (floats) ----------------
constexpr size_t OFF_V    = 0;
constexpr size_t SZ_V     = (size_t)NV * ED;
constexpr size_t OFF_OFF2 = OFF_V + SZ_V;
constexpr size_t SZ_OFF   = (size_t)NQ * 512;
constexpr size_t OFF_ATTN = OFF_OFF2 + SZ_OFF;
constexpr size_t SZ_ATTN  = (size_t)NQ * 256;
constexpr size_t OFF_Q    = OFF_ATTN + SZ_ATTN;
constexpr size_t SZ_Q     = (size_t)NQ * ED;
constexpr size_t OFF_T1   = OFF_Q + SZ_Q;
constexpr size_t OFF_T2   = OFF_T1 + SZ_Q;
constexpr size_t OFF_H1   = OFF_T2 + SZ_Q;
constexpr size_t SZ_H1    = (size_t)NQ * 128;
constexpr size_t OFF_H2   = OFF_H1 + SZ_H1;
constexpr size_t SZ_H2    = (size_t)NQ * 64;
constexpr size_t OFF_H3   = OFF_H2 + SZ_H2;
constexpr size_t SZ_H3    = (size_t)NQ * 48;
constexpr size_t OFF_H4   = OFF_H3 + SZ_H3;
constexpr size_t OFF_W2T  = OFF_H4 + SZ_H3;
constexpr size_t SZ_W2T   = 9 * 128 * 64;
constexpr size_t OFF_W3T  = OFF_W2T + SZ_W2T;
constexpr size_t SZ_W3T   = 9 * 64 * 64;
constexpr size_t OFF_W4T  = OFF_W3T + SZ_W3T;
constexpr size_t SZ_W4T   = 9 * 48 * 64;
constexpr size_t OFF_PART = OFF_W4T + SZ_W4T;
constexpr size_t SZ_PART  = 64 * 128 * 2;
constexpr size_t OFF_SCALE= OFF_PART + SZ_PART;
constexpr size_t OFF_SHIFT= OFF_SCALE + 128;
constexpr size_t SCRATCH_TOTAL = OFF_SHIFT + 128;

__device__ float g_scratch[SCRATCH_TOTAL];
__device__ int   g_maxv;

// ---------------- bf16 buffers ----------------
constexpr int W1CHUNKS = 98;                 // conv1: 49 taps * 2 ci-halves
__device__ __align__(16) __nv_bfloat16 g_s1h[(size_t)NQ * 128];
__device__ __align__(16) __nv_bfloat16 g_s1l[(size_t)NQ * 128];
__device__ __align__(16) __nv_bfloat16 g_s2h[(size_t)NQ * 128];
__device__ __align__(16) __nv_bfloat16 g_s2l[(size_t)NQ * 128];
__device__ __align__(16) __nv_bfloat16 g_vh[(size_t)NV * 128];
__device__ __align__(16) __nv_bfloat16 g_vl[(size_t)NV * 128];
// packed encoder weights: per layer 1280 cols x 128 k  ([n][k])
__device__ __align__(16) __nv_bfloat16 g_wph[(size_t)2 * 1280 * 128];
__device__ __align__(16) __nv_bfloat16 g_wpl[(size_t)2 * 1280 * 128];
// conv1 weights [chunk][co 128][k 64]
__device__ __align__(16) __nv_bfloat16 g_whi[(size_t)W1CHUNKS * 128 * 64];
__device__ __align__(16) __nv_bfloat16 g_wlo[(size_t)W1CHUNKS * 128 * 64];

// ---------------- small helpers ----------------
__device__ __forceinline__ uint32_t smem_u32(const void* p) {
    return (uint32_t)__cvta_generic_to_shared(p);
}
__device__ __forceinline__ void cpasync16(uint32_t dst, const void* src, bool valid) {
    asm volatile("cp.async.cg.shared.global [%0], [%1], 16, %2;"
                 :: "r"(dst), "l"(src), "r"(valid ? 16u : 0u));
}
__device__ __forceinline__ void cp_commit() { asm volatile("cp.async.commit_group;"); }
__device__ __forceinline__ void cp_wait1()  { asm volatile("cp.async.wait_group 1;"); }
__device__ __forceinline__ void cp_wait0()  { asm volatile("cp.async.wait_group 0;"); }

__device__ __forceinline__ void ldmx4(uint32_t* r, uint32_t addr) {
    asm volatile("ldmatrix.sync.aligned.m8n8.x4.shared.b16 {%0,%1,%2,%3}, [%4];"
                 : "=r"(r[0]), "=r"(r[1]), "=r"(r[2]), "=r"(r[3]) : "r"(addr));
}
__device__ __forceinline__ void ldmx2(uint32_t* r, uint32_t addr) {
    asm volatile("ldmatrix.sync.aligned.m8n8.x2.shared.b16 {%0,%1}, [%2];"
                 : "=r"(r[0]), "=r"(r[1]) : "r"(addr));
}
__device__ __forceinline__ void mma_bf16(float* c, const uint32_t* a, const uint32_t* b) {
    asm volatile("mma.sync.aligned.m16n8k16.row.col.f32.bf16.bf16.f32 "
                 "{%0,%1,%2,%3}, {%4,%5,%6,%7}, {%8,%9}, {%0,%1,%2,%3};"
                 : "+f"(c[0]), "+f"(c[1]), "+f"(c[2]), "+f"(c[3])
                 : "r"(a[0]), "r"(a[1]), "r"(a[2]), "r"(a[3]), "r"(b[0]), "r"(b[1]));
}
__device__ __forceinline__ void split2(float v, __nv_bfloat16& h, __nv_bfloat16& l) {
    h = __float2bfloat16(v);
    l = __float2bfloat16(v - __bfloat162float(h));
}

// ---------------- elementwise helpers ----------------
__global__ void init_max_kernel(int* gm) { *gm = INT_MIN; }

__global__ void reduce_max_kernel(const int* __restrict__ p, int* gm) {
    int v = INT_MIN;
    for (int k = blockIdx.x * blockDim.x + threadIdx.x; k < NQ; k += gridDim.x * blockDim.x)
        v = max(v, p[k]);
    #pragma unroll
    for (int o = 16; o > 0; o >>= 1) v = max(v, __shfl_xor_sync(0xffffffffu, v, o));
    __shared__ int sm[8];
    int w = threadIdx.x >> 5;
    if ((threadIdx.x & 31) == 0) sm[w] = v;
    __syncthreads();
    if (threadIdx.x == 0) {
        int bv = sm[0];
        for (int i = 1; i < (int)(blockDim.x >> 5); i++) bv = max(bv, sm[i]);
        atomicMax(gm, bv);
    }
}

__global__ void write_mask_kernel(const int* __restrict__ p, const int* __restrict__ gm,
                                  float* __restrict__ out) {
    int i = blockIdx.x * blockDim.x + threadIdx.x;
    if (i < NQ) out[i] = (p[i] < *gm) ? 1.0f : 0.0f;
}

// split(X) -> hi/lo
__global__ void split_kernel(const float* __restrict__ X, __nv_bfloat16* __restrict__ hi,
                             __nv_bfloat16* __restrict__ lo, int n)
{
    int i = blockIdx.x * blockDim.x + threadIdx.x;
    if (i < n) split2(X[i], hi[i], lo[i]);
}

// split(A+B) -> hi/lo
__global__ void add_split_kernel(const float* __restrict__ A, const float* __restrict__ B,
                                 __nv_bfloat16* __restrict__ hi, __nv_bfloat16* __restrict__ lo, int n)
{
    int i = blockIdx.x * blockDim.x + threadIdx.x;
    if (i < n) split2(A[i] + B[i], hi[i], lo[i]);
}

// pack encoder weight W [128][N] (k-major) -> hi/lo [N][128]
__global__ void packw_kernel(const float* __restrict__ W, __nv_bfloat16* __restrict__ hi,
                             __nv_bfloat16* __restrict__ lo, int N)
{
    int i = blockIdx.x * blockDim.x + threadIdx.x;
    if (i >= N * 128) return;
    int k = i & 127, n = i >> 7;
    split2(W[(size_t)k * N + n], hi[i], lo[i]);
}

// ---------------- generic bf16x3 GEMM: C[M,N] = A[M,128] * B[N,128]^T ----------------
// FLAGS: 1 relu, 2 residual, 4 write fp32 C, 8 write split C
constexpr int GROWB = 272;                   // smem row stride bytes (128 bf16 + pad)
constexpr int GTILE = 128 * GROWB;           // 34816
constexpr int GEMM_SMEM = 4 * GTILE;         // 139264

template<int FLAGS>
__global__ void __launch_bounds__(256, 1) gemm_mma(
    const __nv_bfloat16* __restrict__ Ah, const __nv_bfloat16* __restrict__ Al,
    const __nv_bfloat16* __restrict__ Bh, const __nv_bfloat16* __restrict__ Bl,
    const float* __restrict__ bias, const float* __restrict__ R,
    float* __restrict__ Cf, __nv_bfloat16* __restrict__ Ch, __nv_bfloat16* __restrict__ Cl,
    int M, int N)
{
    extern __shared__ char smem[];
    const int tid = threadIdx.x;
    const int wid = tid >> 5, lane = tid & 31;
    const int warp_m = wid >> 2, warp_n = wid & 3;
    const uint32_t sb = smem_u32(smem);
    const int bm = blockIdx.x * 128, bn = blockIdx.y * 128;

    // ---- load full K=128 tiles (Ahi, Alo, Bhi, Blo) ----
    {
        const int lrow = tid >> 1, lhalf = tid & 1;
        const bool aval = (bm + lrow) < M;
        const uint32_t sa = sb + (uint32_t)lrow * GROWB + (uint32_t)lhalf * 128;
        const char* agh = (const char*)(Ah + (size_t)(aval ? (bm + lrow) : 0) * 128 + lhalf * 64);
        const char* agl = (const char*)(Al + (size_t)(aval ? (bm + lrow) : 0) * 128 + lhalf * 64);
        const char* bgh = (const char*)(Bh + (size_t)(bn + lrow) * 128 + lhalf * 64);
        const char* bgl = (const char*)(Bl + (size_t)(bn + lrow) * 128 + lhalf * 64);
        #pragma unroll
        for (int i = 0; i < 8; i++) {
            cpasync16(sa + i * 16,             agh + i * 16, aval);
            cpasync16(sa + GTILE + i * 16,     agl + i * 16, aval);
            cpasync16(sa + 2 * GTILE + i * 16, bgh + i * 16, true);
            cpasync16(sa + 3 * GTILE + i * 16, bgl + i * 16, true);
        }
        cp_commit();
        cp_wait0();
        __syncthreads();
    }

    float acc[4][4][4];
    #pragma unroll
    for (int mt = 0; mt < 4; mt++)
        #pragma unroll
        for (int nt = 0; nt < 4; nt++)
            #pragma unroll
            for (int d = 0; d < 4; d++) acc[mt][nt][d] = 0.f;

    const uint32_t a_base = sb + (uint32_t)(warp_m * 64 + (lane & 15)) * GROWB + (uint32_t)(lane >> 4) * 16;
    const uint32_t b_base = sb + 2 * GTILE + (uint32_t)(warp_n * 32 + (lane & 7)) * GROWB
                          + (uint32_t)((lane >> 3) & 1) * 16;

    #pragma unroll
    for (int ks = 0; ks < 8; ks++) {
        const uint32_t kbyte = (uint32_t)ks * 32;
        uint32_t bh[4][2], bl[4][2];
        #pragma unroll
        for (int nt = 0; nt < 4; nt++) {
            ldmx2(bh[nt], b_base + (uint32_t)nt * 8 * GROWB + kbyte);
            ldmx2(bl[nt], b_base + GTILE + (uint32_t)nt * 8 * GROWB + kbyte);
        }
        #pragma unroll
        for (int mt = 0; mt < 4; mt++) {
            uint32_t ah[4], al[4];
            ldmx4(ah, a_base + (uint32_t)mt * 16 * GROWB + kbyte);
            ldmx4(al, a_base + GTILE + (uint32_t)mt * 16 * GROWB + kbyte);
            #pragma unroll
            for (int nt = 0; nt < 4; nt++) {
                mma_bf16(acc[mt][nt], ah, bh[nt]);
                mma_bf16(acc[mt][nt], ah, bl[nt]);
                mma_bf16(acc[mt][nt], al, bh[nt]);
            }
        }
    }

    // ---- epilogue ----
    const int g = lane >> 2, tg = lane & 3;
    #pragma unroll
    for (int mt = 0; mt < 4; mt++) {
        const int r0 = bm + warp_m * 64 + mt * 16 + g;
        #pragma unroll
        for (int nt = 0; nt < 4; nt++) {
            const int col = bn + warp_n * 32 + nt * 8 + tg * 2;
            float2 bb = *(const float2*)&bias[col];
            float v[4] = {acc[mt][nt][0] + bb.x, acc[mt][nt][1] + bb.y,
                          acc[mt][nt][2] + bb.x, acc[mt][nt][3] + bb.y};
            #pragma unroll
            for (int half = 0; half < 2; half++) {
                const int r = r0 + half * 8;
                if (r >= M) continue;
                float a0 = v[half * 2], a1 = v[half * 2 + 1];
                if (FLAGS & 2) {
                    float2 rr = *(const float2*)&R[(size_t)r * N + col];
                    a0 += rr.x; a1 += rr.y;
                }
                if (FLAGS & 1) { a0 = fmaxf(a0, 0.f); a1 = fmaxf(a1, 0.f); }
                if (FLAGS & 4)
                    *(float2*)&Cf[(size_t)r * N + col] = make_float2(a0, a1);
                if (FLAGS & 8) {
                    __nv_bfloat16 h0, l0, h1, l1;
                    split2(a0, h0, l0); split2(a1, h1, l1);
                    *(__nv_bfloat162*)&Ch[(size_t)r * N + col] = __nv_bfloat162(h0, h1);
                    *(__nv_bfloat162*)&Cl[(size_t)r * N + col] = __nv_bfloat162(l0, l1);
                }
            }
        }
    }
}

// ---------------- softmax over 32 per (query, head) ----------------
__global__ void softmax32_kernel(float* __restrict__ A) {
    int t = blockIdx.x * blockDim.x + threadIdx.x;
    if (t >= NQ * HEADS) return;
    float* a = A + (size_t)t * 32;
    float e[32];
    float m = -1e30f;
    #pragma unroll
    for (int k = 0; k < 32; k++) m = fmaxf(m, a[k]);
    float s = 0.f;
    #pragma unroll
    for (int k = 0; k < 32; k++) { e[k] = expf(a[k] - m); s += e[k]; }
    float inv = 1.f / s;
    #pragma unroll
    for (int k = 0; k < 32; k++) a[k] = e[k] * inv;
}

// ---------------- deformable attention sampling (split bf16 output) ----------------
__global__ void __launch_bounds__(256) deform_kernel(
    const float* __restrict__ V, const float* __restrict__ OFFS,
    const float* __restrict__ ATT,
    __nv_bfloat16* __restrict__ OH, __nv_bfloat16* __restrict__ OL)
{
    int t = blockIdx.x * 256 + threadIdx.x;
    if (t >= NQ * HEADS) return;
    const int n = t >> 3, h = t & 7;
    const float rx = ((float)(n % 200) + 0.5f) * (1.f / 200.f);
    const float ry = ((float)(n / 200) + 0.5f) * (1.f / 200.f);
    const float* op = OFFS + (size_t)n * 512 + h * 64;
    const float* ap = ATT + (size_t)n * 256 + h * 32;

    float acc[16];
    #pragma unroll
    for (int d = 0; d < 16; d++) acc[d] = 0.f;

    const int stc[4] = {0, 32768, 40960, 43008};
    const int Wc[4]  = {256, 128, 64, 32};
    const int Hc[4]  = {128, 64, 32, 16};

    #pragma unroll
    for (int l = 0; l < 4; l++) {
        const int W = Wc[l], H = Hc[l], st = stc[l];
        const float Wf = (float)W, Hf = (float)H;
        for (int p = 0; p < 8; p++) {
            float ox = op[(l * 8 + p) * 2 + 0];
            float oy = op[(l * 8 + p) * 2 + 1];
            float aw = ap[l * 8 + p];
            float x = (rx + ox / Wf) * Wf - 0.5f;
            float y = (ry + oy / Hf) * Hf - 0.5f;
            float xf = floorf(x), yf = floorf(y);
            int x0 = (int)xf, y0 = (int)yf;
            float fx = x - xf, fy = y - yf;
            float wx[2] = {1.f - fx, fx};
            float wy[2] = {1.f - fy, fy};
            #pragma unroll
            for (int c = 0; c < 4; c++) {
                int xi = x0 + (c & 1), yi = y0 + (c >> 1);
                float wgt = wx[c & 1] * wy[c >> 1];
                if (xi >= 0 && xi < W && yi >= 0 && yi < H && wgt != 0.f) {
                    const float4* gp = (const float4*)(V + ((size_t)(st + yi * W + xi)) * 128 + h * 16);
                    float cw = aw * wgt;
                    float4 g0 = gp[0], g1 = gp[1], g2 = gp[2], g3 = gp[3];
                    acc[0]  += cw * g0.x; acc[1]  += cw * g0.y; acc[2]  += cw * g0.z; acc[3]  += cw * g0.w;
                    acc[4]  += cw * g1.x; acc[5]  += cw * g1.y; acc[6]  += cw * g1.z; acc[7]  += cw * g1.w;
                    acc[8]  += cw * g2.x; acc[9]  += cw * g2.y; acc[10] += cw * g2.z; acc[11] += cw * g2.w;
                    acc[12] += cw * g3.x; acc[13] += cw * g3.y; acc[14] += cw * g3.z; acc[15] += cw * g3.w;
                }
            }
        }
    }
    __nv_bfloat162* oh = (__nv_bfloat162*)(OH + (size_t)n * 128 + h * 16);
    __nv_bfloat162* ol = (__nv_bfloat162*)(OL + (size_t)n * 128 + h * 16);
    #pragma unroll
    for (int d = 0; d < 8; d++) {
        __nv_bfloat16 h0, l0, h1, l1;
        split2(acc[d * 2], h0, l0); split2(acc[d * 2 + 1], h1, l1);
        oh[d] = __nv_bfloat162(h0, h1);
        ol[d] = __nv_bfloat162(l0, l1);
    }
}

// ---------------- layernorm over 128 per row ----------------
template<int SPLIT>
__global__ void ln_kernel(const float* __restrict__ X, const float* __restrict__ g,
                          const float* __restrict__ b, float* __restrict__ Y,
                          __nv_bfloat16* __restrict__ Yh, __nv_bfloat16* __restrict__ Yl)
{
    int r = blockIdx.x;
    int t = threadIdx.x;
    float x = X[(size_t)r * 128 + t];
    float s = x;
    #pragma unroll
    for (int o = 16; o > 0; o >>= 1) s += __shfl_xor_sync(0xffffffffu, s, o);
    __shared__ float sm[4], sm2[4];
    int w = t >> 5, lane = t & 31;
    if (lane == 0) sm[w] = s;
    __syncthreads();
    float m = (sm[0] + sm[1] + sm[2] + sm[3]) * (1.f / 128.f);
    float d = x - m;
    float q = d * d;
    #pragma unroll
    for (int o = 16; o > 0; o >>= 1) q += __shfl_xor_sync(0xffffffffu, q, o);
    if (lane == 0) sm2[w] = q;
    __syncthreads();
    float var = (sm2[0] + sm2[1] + sm2[2] + sm2[3]) * (1.f / 128.f);
    float y = d * rsqrtf(var + 1e-5f) * g[t] + b[t];
    Y[(size_t)r * 128 + t] = y;
    if (SPLIT) {
        __nv_bfloat16 hh, ll;
        split2(y, hh, ll);
        Yh[(size_t)r * 128 + t] = hh;
        Yl[(size_t)r * 128 + t] = ll;
    }
}

// ---------------- conv1 weight split ----------------
__global__ void wsplit_kernel(const float* __restrict__ W, __nv_bfloat16* __restrict__ hi,
                              __nv_bfloat16* __restrict__ lo)
{
    int i = blockIdx.x * blockDim.x + threadIdx.x;  // [c][co][k]
    if (i >= W1CHUNKS * 128 * 64) return;
    int k  = i & 63;
    int co = (i >> 6) & 127;
    int c  = i >> 13;
    int e = c >> 1, ci = ((c & 1) << 6) + k;
    int ky = e / 7, kx = e % 7;
    split2(W[(((size_t)co * 128 + ci) * 7 + ky) * 7 + kx], hi[i], lo[i]);
}

// ---------------- conv1 (7x7, 128->128) via mma.sync bf16x3 ----------------
constexpr int ROWB = 144;
constexpr int TILE_B = 128 * ROWB;
constexpr int BUF_B = 4 * TILE_B;
constexpr int CONV1_SMEM = 2 * BUF_B;

__global__ void __launch_bounds__(256, 1) conv1_mma_kernel(
    const __nv_bfloat16* __restrict__ qhi, const __nv_bfloat16* __restrict__ qlo,
    const __nv_bfloat16* __restrict__ whi, const __nv_bfloat16* __restrict__ wlo,
    float* __restrict__ Out)
{
    extern __shared__ char smem[];
    const int tid = threadIdx.x;
    const int wid = tid >> 5, lane = tid & 31;
    const int warp_m = wid >> 2, warp_n = wid & 3;
    const uint32_t sb = smem_u32(smem);
    const int bm = blockIdx.x * 128;

    const int lrow = tid >> 1, lhalf = tid & 1;
    const int pm = bm + lrow;
    const int py = pm / 200, px = pm % 200;
    const bool prow_ok = pm < NQ;
    const uint32_t s_arow = sb + (uint32_t)lrow * ROWB + (uint32_t)lhalf * 64;
    const uint32_t s_brow = s_arow + 2 * TILE_B;

    const int ar = lane & 15, ak = lane >> 4;
    const int br = lane & 7, bk = (lane >> 3) & 1;
    const uint32_t a_base = sb + (uint32_t)(warp_m * 64 + ar) * ROWB + (uint32_t)ak * 16;
    const uint32_t b_base = sb + 2 * TILE_B + (uint32_t)(warp_n * 32 + br) * ROWB + (uint32_t)bk * 16;

    float acc[4][4][4];
    #pragma unroll
    for (int mt = 0; mt < 4; mt++)
        #pragma unroll
        for (int nt = 0; nt < 4; nt++)
            #pragma unroll
            for (int d = 0; d < 4; d++) acc[mt][nt][d] = 0.f;

    auto load_chunk = [&](int c, int buf) {
        const int e = c >> 1, ch = c & 1;
        const int qy = py + e / 7 - 3;
        const int qx = px + e % 7 - 3;
        const bool val = prow_ok && qy >= 0 && qy < 200 && qx >= 0 && qx < 200;
        const size_t aoff = (size_t)(val ? (qy * 200 + qx) : 0) * 128 + (size_t)ch * 64 + (size_t)lhalf * 32;
        const char* agh = (const char*)(qhi + aoff);
        const char* agl = (const char*)(qlo + aoff);
        const size_t boff = ((size_t)c * 128 + lrow) * 64 + (size_t)lhalf * 32;
        const char* bgh = (const char*)(whi + boff);
        const char* bgl = (const char*)(wlo + boff);
        const uint32_t sa = s_arow + (uint32_t)buf * BUF_B;
        const uint32_t sbr = s_brow + (uint32_t)buf * BUF_B;
        #pragma unroll
        for (int i = 0; i < 4; i++) {
            cpasync16(sa + i * 16,          agh + i * 16, val);
            cpasync16(sa + TILE_B + i * 16, agl + i * 16, val);
            cpasync16(sbr + i * 16,          bgh + i * 16, true);
            cpasync16(sbr + TILE_B + i * 16, bgl + i * 16, true);
        }
    };

    load_chunk(0, 0); cp_commit();
    load_chunk(1, 1); cp_commit();

    for (int c = 0; c < W1CHUNKS; c++) {
        const int buf = c & 1;
        cp_wait1();
        __syncthreads();

        const uint32_t ab = a_base + (uint32_t)buf * BUF_B;
        const uint32_t bb = b_base + (uint32_t)buf * BUF_B;
        #pragma unroll
        for (int ks = 0; ks < 4; ks++) {
            const uint32_t kbyte = (uint32_t)ks * 32;
            uint32_t bh[4][2], bl[4][2];
            #pragma unroll
            for (int nt = 0; nt < 4; nt++) {
                ldmx2(bh[nt], bb + (uint32_t)nt * 8 * ROWB + kbyte);
                ldmx2(bl[nt], bb + TILE_B + (uint32_t)nt * 8 * ROWB + kbyte);
            }
            #pragma unroll
            for (int mt = 0; mt < 4; mt++) {
                uint32_t ah[4], al[4];
                ldmx4(ah, ab + (uint32_t)mt * 16 * ROWB + kbyte);
                ldmx4(al, ab + TILE_B + (uint32_t)mt * 16 * ROWB + kbyte);
                #pragma unroll
                for (int nt = 0; nt < 4; nt++) {
                    mma_bf16(acc[mt][nt], ah, bh[nt]);
                    mma_bf16(acc[mt][nt], ah, bl[nt]);
                    mma_bf16(acc[mt][nt], al, bh[nt]);
                }
            }
        }
        __syncthreads();
        if (c + 2 < W1CHUNKS) load_chunk(c + 2, buf);
        cp_commit();
    }

    const int g = lane >> 2, tg = lane & 3;
    #pragma unroll
    for (int mt = 0; mt < 4; mt++) {
        const int r0 = bm + warp_m * 64 + mt * 16 + g;
        #pragma unroll
        for (int nt = 0; nt < 4; nt++) {
            const int col = warp_n * 32 + nt * 8 + tg * 2;
            if (r0 < NQ)
                *(float2*)&Out[(size_t)r0 * 128 + col] = make_float2(acc[mt][nt][0], acc[mt][nt][1]);
            if (r0 + 8 < NQ)
                *(float2*)&Out[(size_t)(r0 + 8) * 128 + col] = make_float2(acc[mt][nt][2], acc[mt][nt][3]);
        }
    }
}

// ---------------- weight reorder for fp32 convs 2-4 ----------------
__global__ void wreorder_kernel(const float* __restrict__ W, float* __restrict__ Wt,
                                int CO, int CI, int KS, int stride, int total)
{
    int i = blockIdx.x * blockDim.x + threadIdx.x;
    if (i >= total) return;
    int col = i % stride;
    int row = i / stride;
    int ci = row % CI;
    int e = row / CI;
    int ky = e / KS, kx = e % KS;
    Wt[i] = (col < CO) ? W[((size_t)(col * CI + ci) * KS + ky) * KS + kx] : 0.f;
}

// ---------------- implicit-GEMM direct conv (NHWC, 200x200), fp32 ----------------
template<int KS, int PAD>
__global__ void __launch_bounds__(256) conv_igemm(
    const float* __restrict__ In, const float* __restrict__ Wt,
    float* __restrict__ Out, int CIN, int wt_stride, int COUT)
{
    __shared__ float As[16][68];
    __shared__ float Bs[16][68];
    const int bm = blockIdx.x * 64, bn = blockIdx.y * 64;
    const int tid = threadIdx.x;
    const int arow = tid >> 2, acol = (tid & 3) * 4;
    const int brow = tid >> 4, bcol = (tid & 15) * 4;
    const int r0 = (tid >> 4) * 4, c0 = (tid & 15) * 4;

    const int pm = bm + arow;
    const int py = pm / 200, px = pm % 200;

    float acc[4][4];
    #pragma unroll
    for (int i = 0; i < 4; i++)
        #pragma unroll
        for (int j = 0; j < 4; j++) acc[i][j] = 0.f;

    for (int e = 0; e < KS * KS; e++) {
        const int qy = py + e / KS - PAD;
        const int qx = px + e % KS - PAD;
        const bool val = (qy >= 0) && (qy < 200) && (qx >= 0) && (qx < 200);
        const float* ain = In + (size_t)(qy * 200 + qx) * CIN;
        for (int kc = 0; kc < CIN; kc += 16) {
            float4 a = val ? *(const float4*)&ain[kc + acol] : make_float4(0.f, 0.f, 0.f, 0.f);
            As[acol + 0][arow] = a.x; As[acol + 1][arow] = a.y;
            As[acol + 2][arow] = a.z; As[acol + 3][arow] = a.w;
            *(float4*)&Bs[brow][bcol] =
                *(const float4*)&Wt[(size_t)(e * CIN + kc + brow) * wt_stride + bn + bcol];
            __syncthreads();
            #pragma unroll
            for (int k = 0; k < 16; k++) {
                float4 ra = *(const float4*)&As[k][r0];
                float4 rb = *(const float4*)&Bs[k][c0];
                float av[4] = {ra.x, ra.y, ra.z, ra.w};
                float bv[4] = {rb.x, rb.y, rb.z, rb.w};
                #pragma unroll
                for (int i = 0; i < 4; i++)
                    #pragma unroll
                    for (int j = 0; j < 4; j++)
                        acc[i][j] = fmaf(av[i], bv[j], acc[i][j]);
            }
            __syncthreads();
        }
    }

    if (bn + c0 < COUT) {
        #pragma unroll
        for (int i = 0; i < 4; i++) {
            size_t row = (size_t)(bm + r0 + i);
            *(float4*)&Out[row * COUT + bn + c0] =
                make_float4(acc[i][0], acc[i][1], acc[i][2], acc[i][3]);
        }
    }
}

// ---------------- batchnorm (training-mode stats), deterministic 2-stage ----------------
__global__ void bn_stats_kernel(const float* __restrict__ X, float* __restrict__ part, int C)
{
    int c = threadIdx.x;
    int g = blockIdx.x;
    const int per = (NQ + 63) / 64;
    int p0 = g * per;
    int p1 = min(NQ, p0 + per);
    float s = 0.f, q = 0.f;
    for (int p = p0; p < p1; p++) {
        float x = X[(size_t)p * C + c];
        s += x; q += x * x;
    }
    part[(size_t)g * 2 * C + c] = s;
    part[(size_t)g * 2 * C + C + c] = q;
}

__global__ void bn_finalize_kernel(const float* __restrict__ part,
                                   const float* __restrict__ gamma, const float* __restrict__ beta,
                                   float* __restrict__ scale, float* __restrict__ shift, int C)
{
    int c = threadIdx.x;
    float s = 0.f, q = 0.f;
    for (int g = 0; g < 64; g++) {
        s += part[(size_t)g * 2 * C + c];
        q += part[(size_t)g * 2 * C + C + c];
    }
    const float invP = 1.f / (float)NQ;
    float m = s * invP;
    float v = q * invP - m * m;
    float sc = gamma[c] * rsqrtf(v + 1e-5f);
    scale[c] = sc;
    shift[c] = beta[c] - m * sc;
}

__global__ void bn_apply_kernel(float* __restrict__ X, const float* __restrict__ scale,
                                const float* __restrict__ shift, int C, int total)
{
    int i = blockIdx.x * blockDim.x + threadIdx.x;
    if (i < total) {
        int c = i % C;
        X[i] = fmaxf(0.f, fmaf(X[i], scale[c], shift[c]));
    }
}

// ---------------- head: 1x1 conv 48 -> 21, output NCHW ----------------
__global__ void head_conv_kernel(const float* __restrict__ H4, const float* __restrict__ Wo,
                                 const float* __restrict__ bo, float* __restrict__ out)
{
    int p = blockIdx.x * blockDim.x + threadIdx.x;
    if (p >= NQ) return;
    float x[48];
    const float4* hp = (const float4*)(H4 + (size_t)p * 48);
    #pragma unroll
    for (int i = 0; i < 12; i++) {
        float4 v = hp[i];
        x[i * 4 + 0] = v.x; x[i * 4 + 1] = v.y; x[i * 4 + 2] = v.z; x[i * 4 + 3] = v.w;
    }
    for (int co = 0; co < 21; co++) {
        float s = bo[co];
        const float* w = Wo + co * 48;
        #pragma unroll
        for (int ci = 0; ci < 48; ci++) s = fmaf(x[ci], w[ci], s);
        out[(size_t)co * NQ + p] = s;
    }
}

// ---------------- launch ----------------
extern "C" void kernel_launch(void* const* d_in, const int* in_sizes, int n_in,
                              void* d_out, int out_size)
{
    const float* value = (const float*)d_in[0];
    const float* bq    = (const float*)d_in[1];
    const float* bpos  = (const float*)d_in[2];
    const int*   proj  = (const int*)d_in[3];
    const float* Wv    = (const float*)d_in[4];
    const float* bv    = (const float*)d_in[5];
    const float* Woff  = (const float*)d_in[6];
    const float* boff  = (const float*)d_in[7];
    const float* Wattn = (const float*)d_in[8];
    const float* battn = (const float*)d_in[9];
    const float* Wout  = (const float*)d_in[10];
    const float* bout  = (const float*)d_in[11];
    const float* Wf1   = (const float*)d_in[12];
    const float* bf1   = (const float*)d_in[13];
    const float* Wf2   = (const float*)d_in[14];
    const float* bf2   = (const float*)d_in[15];
    const float* lng   = (const float*)d_in[16];
    const float* lnb   = (const float*)d_in[17];
    const float* cw1   = (const float*)d_in[18];
    const float* g1    = (const float*)d_in[19];
    const float* b1    = (const float*)d_in[20];
    const float* cw2   = (const float*)d_in[21];
    const float* g2    = (const float*)d_in[22];
    const float* b2    = (const float*)d_in[23];
    const float* cw3   = (const float*)d_in[24];
    const float* g3    = (const float*)d_in[25];
    const float* b3    = (const float*)d_in[26];
    const float* cw4   = (const float*)d_in[27];
    const float* g4    = (const float*)d_in[28];
    const float* b4    = (const float*)d_in[29];
    const float* objw  = (const float*)d_in[30];
    const float* objb  = (const float*)d_in[31];
    float* out = (float*)d_out;

    float* S = nullptr;
    cudaGetSymbolAddress((void**)&S, g_scratch);
    int* gm = nullptr;
    cudaGetSymbolAddress((void**)&gm, g_maxv);
    __nv_bfloat16 *s1h, *s1l, *s2h, *s2l, *vh, *vl, *wph, *wpl, *whi, *wlo;
    cudaGetSymbolAddress((void**)&s1h, g_s1h);
    cudaGetSymbolAddress((void**)&s1l, g_s1l);
    cudaGetSymbolAddress((void**)&s2h, g_s2h);
    cudaGetSymbolAddress((void**)&s2l, g_s2l);
    cudaGetSymbolAddress((void**)&vh,  g_vh);
    cudaGetSymbolAddress((void**)&vl,  g_vl);
    cudaGetSymbolAddress((void**)&wph, g_wph);
    cudaGetSymbolAddress((void**)&wpl, g_wpl);
    cudaGetSymbolAddress((void**)&whi, g_whi);
    cudaGetSymbolAddress((void**)&wlo, g_wlo);

    float* PV    = S + OFF_V;
    float* POFF  = S + OFF_OFF2;
    float* PATTN = S + OFF_ATTN;
    float* PQ    = S + OFF_Q;
    float* PT1   = S + OFF_T1;
    float* PT2   = S + OFF_T2;
    float* PH1   = S + OFF_H1;
    float* PH2   = S + OFF_H2;
    float* PH3   = S + OFF_H3;
    float* PH4   = S + OFF_H4;
    float* PW2T  = S + OFF_W2T;
    float* PW3T  = S + OFF_W3T;
    float* PW4T  = S + OFF_W4T;
    float* PPART = S + OFF_PART;
    float* PSCALE= S + OFF_SCALE;
    float* PSHIFT= S + OFF_SHIFT;

    cudaFuncSetAttribute(conv1_mma_kernel, cudaFuncAttributeMaxDynamicSharedMemorySize, CONV1_SMEM);
    cudaFuncSetAttribute(gemm_mma<4>,  cudaFuncAttributeMaxDynamicSharedMemorySize, GEMM_SMEM);
    cudaFuncSetAttribute(gemm_mma<6>,  cudaFuncAttributeMaxDynamicSharedMemorySize, GEMM_SMEM);
    cudaFuncSetAttribute(gemm_mma<9>,  cudaFuncAttributeMaxDynamicSharedMemorySize, GEMM_SMEM);

    // --- observed_masks ---
    init_max_kernel<<<1, 1>>>(gm);
    reduce_max_kernel<<<40, 256>>>(proj, gm);
    write_mask_kernel<<<(NQ + 255) / 256, 256>>>(proj, gm, out + 21 * NQ);

    // --- weight prep ---
    wsplit_kernel<<<(W1CHUNKS * 128 * 64 + 255) / 256, 256>>>(cw1, whi, wlo);
    wreorder_kernel<<<((int)SZ_W2T + 255) / 256, 256>>>(cw2, PW2T, 64, 128, 3, 64, (int)SZ_W2T);
    wreorder_kernel<<<((int)SZ_W3T + 255) / 256, 256>>>(cw3, PW3T, 48, 64, 3, 64, (int)SZ_W3T);
    wreorder_kernel<<<((int)SZ_W4T + 255) / 256, 256>>>(cw4, PW4T, 48, 48, 3, 64, (int)SZ_W4T);
    for (int i = 0; i < 2; i++) {
        size_t LB = (size_t)i * 1280 * 128;
        packw_kernel<<<(128 * 128 + 255) / 256, 256>>>(Wv   + (size_t)i * 128 * 128, wph + LB,               wpl + LB,               128);
        packw_kernel<<<(512 * 128 + 255) / 256, 256>>>(Woff + (size_t)i * 128 * 512, wph + LB + 128 * 128,   wpl + LB + 128 * 128,   512);
        packw_kernel<<<(256 * 128 + 255) / 256, 256>>>(Wattn+ (size_t)i * 128 * 256, wph + LB + 640 * 128,   wpl + LB + 640 * 128,   256);
        packw_kernel<<<(128 * 128 + 255) / 256, 256>>>(Wout + (size_t)i * 128 * 128, wph + LB + 896 * 128,   wpl + LB + 896 * 128,   128);
        packw_kernel<<<(128 * 128 + 255) / 256, 256>>>(Wf1  + (size_t)i * 128 * 128, wph + LB + 1024 * 128,  wpl + LB + 1024 * 128,  128);
        packw_kernel<<<(128 * 128 + 255) / 256, 256>>>(Wf2  + (size_t)i * 128 * 128, wph + LB + 1152 * 128,  wpl + LB + 1152 * 128,  128);
    }
    split_kernel<<<(NV * 128 + 255) / 256, 256>>>(value, vh, vl, NV * 128);

    // --- q init ---
    cudaMemcpyAsync(PQ, bq, (size_t)NQ * ED * sizeof(float), cudaMemcpyDeviceToDevice);

    // --- 2 encoder layers (all GEMMs via bf16x3 mma) ---
    for (int i = 0; i < 2; i++) {
        size_t LB = (size_t)i * 1280 * 128;
        add_split_kernel<<<(NQ * ED + 255) / 256, 256>>>(PQ, bpos, s1h, s1l, NQ * ED);
        gemm_mma<4><<<dim3(340, 1), 256, GEMM_SMEM>>>(vh, vl, wph + LB, wpl + LB,
                                                      bv + i * 128, nullptr, PV, nullptr, nullptr, NV, 128);
        gemm_mma<4><<<dim3(313, 4), 256, GEMM_SMEM>>>(s1h, s1l, wph + LB + 128 * 128, wpl + LB + 128 * 128,
                                                      boff + i * 512, nullptr, POFF, nullptr, nullptr, NQ, 512);
        gemm_mma<4><<<dim3(313, 2), 256, GEMM_SMEM>>>(s1h, s1l, wph + LB + 640 * 128, wpl + LB + 640 * 128,
                                                      battn + i * 256, nullptr, PATTN, nullptr, nullptr, NQ, 256);
        softmax32_kernel<<<(NQ * HEADS + 255) / 256, 256>>>(PATTN);
        deform_kernel<<<(NQ * HEADS + 255) / 256, 256>>>(PV, POFF, PATTN, s2h, s2l);
        gemm_mma<6><<<dim3(313, 1), 256, GEMM_SMEM>>>(s2h, s2l, wph + LB + 896 * 128, wpl + LB + 896 * 128,
                                                      bout + i * 128, PQ, PT1, nullptr, nullptr, NQ, 128);
        ln_kernel<1><<<NQ, 128>>>(PT1, lng + (i * 2 + 0) * 128, lnb + (i * 2 + 0) * 128, PQ, s1h, s1l);
        gemm_mma<9><<<dim3(313, 1), 256, GEMM_SMEM>>>(s1h, s1l, wph + LB + 1024 * 128, wpl + LB + 1024 * 128,
                                                      bf1 + i * 128, nullptr, nullptr, s2h, s2l, NQ, 128);
        gemm_mma<6><<<dim3(313, 1), 256, GEMM_SMEM>>>(s2h, s2l, wph + LB + 1152 * 128, wpl + LB + 1152 * 128,
                                                      bf2 + i * 128, PQ, PT2, nullptr, nullptr, NQ, 128);
        ln_kernel<0><<<NQ, 128>>>(PT2, lng + (i * 2 + 1) * 128, lnb + (i * 2 + 1) * 128, PQ, nullptr, nullptr);
    }

    // --- conv head ---
    split_kernel<<<(NQ * 128 + 255) / 256, 256>>>(PQ, s1h, s1l, NQ * 128);
    conv1_mma_kernel<<<313, 256, CONV1_SMEM>>>(s1h, s1l, whi, wlo, PH1);
    bn_stats_kernel<<<64, 128>>>(PH1, PPART, 128);
    bn_finalize_kernel<<<1, 128>>>(PPART, g1, b1, PSCALE, PSHIFT, 128);
    bn_apply_kernel<<<(NQ * 128 + 255) / 256, 256>>>(PH1, PSCALE, PSHIFT, 128, NQ * 128);

    conv_igemm<3, 1><<<dim3(NQ / 64, 1), 256>>>(PH1, PW2T, PH2, 128, 64, 64);
    bn_stats_kernel<<<64, 64>>>(PH2, PPART, 64);
    bn_finalize_kernel<<<1, 64>>>(PPART, g2, b2, PSCALE, PSHIFT, 64);
    bn_apply_kernel<<<(NQ * 64 + 255) / 256, 256>>>(PH2, PSCALE, PSHIFT, 64, NQ * 64);

    conv_igemm<3, 1><<<dim3(NQ / 64, 1), 256>>>(PH2, PW3T, PH3, 64, 64, 48);
    bn_stats_kernel<<<64, 48>>>(PH3, PPART, 48);
    bn_finalize_kernel<<<1, 48>>>(PPART, g3, b3, PSCALE, PSHIFT, 48);
    bn_apply_kernel<<<(NQ * 48 + 255) / 256, 256>>>(PH3, PSCALE, PSHIFT, 48, NQ * 48);

    conv_igemm<3, 1><<<dim3(NQ / 64, 1), 256>>>(PH3, PW4T, PH4, 48, 64, 48);
    bn_stats_kernel<<<64, 48>>>(PH4, PPART, 48);
    bn_finalize_kernel<<<1, 48>>>(PPART, g4, b4, PSCALE, PSHIFT, 48);
    bn_apply_kernel<<<(NQ * 48 + 255) / 256, 256>>>(PH4, PSCALE, PSHIFT, 48, NQ * 48);

    head_conv_kernel<<<(NQ + 255) / 256, 256>>>(PH4, objw, objb, out);
}

// round 5
// speedup vs baseline: 1.3704x; 1.0536x over previous
#include <cuda_runtime.h>
#include <cuda_bf16.h>
#include <cstdint>
#include <climits>

// ---------------- problem constants ----------------
constexpr int NQ = 40000;        // 200*200
constexpr int ED = 128;
constexpr int NV = 43520;        // sum of level sizes
constexpr int HEADS = 8;

// ---------------- scratch layout (floats) ----------------
constexpr size_t OFF_V    = 0;
constexpr size_t SZ_V     = (size_t)NV * ED;
constexpr size_t OFF_OA   = OFF_V + SZ_V;          // combined offsets+attn, NQ x 768
constexpr size_t SZ_OA    = (size_t)NQ * 768;
constexpr size_t OFF_Q    = OFF_OA + SZ_OA;
constexpr size_t SZ_Q     = (size_t)NQ * ED;
constexpr size_t OFF_T1   = OFF_Q + SZ_Q;
constexpr size_t OFF_T2   = OFF_T1 + SZ_Q;
constexpr size_t OFF_H1   = OFF_T2 + SZ_Q;
constexpr size_t SZ_H1    = (size_t)NQ * 128;
constexpr size_t OFF_H2   = OFF_H1 + SZ_H1;
constexpr size_t SZ_H2    = (size_t)NQ * 64;
constexpr size_t OFF_H3   = OFF_H2 + SZ_H2;
constexpr size_t SZ_H3    = (size_t)NQ * 48;
constexpr size_t OFF_H4   = OFF_H3 + SZ_H3;
constexpr size_t OFF_PART = OFF_H4 + SZ_H3;
constexpr size_t SZ_PART  = 64 * 128 * 2;
constexpr size_t OFF_SCALE= OFF_PART + SZ_PART;
constexpr size_t OFF_SHIFT= OFF_SCALE + 128;
constexpr size_t OFF_BIAS = OFF_SHIFT + 128;       // 2 layers x 768 packed bias
constexpr size_t SCRATCH_TOTAL = OFF_BIAS + 2 * 768;

__device__ float g_scratch[SCRATCH_TOTAL];
__device__ int   g_maxv;

// ---------------- bf16 buffers ----------------
constexpr int W1CHUNKS = 98;                 // conv1: 49 taps * 2 ci-halves
__device__ __align__(16) __nv_bfloat16 g_s1h[(size_t)NQ * 128];
__device__ __align__(16) __nv_bfloat16 g_s1l[(size_t)NQ * 128];
__device__ __align__(16) __nv_bfloat16 g_s2h[(size_t)NQ * 128];
__device__ __align__(16) __nv_bfloat16 g_s2l[(size_t)NQ * 128];
__device__ __align__(16) __nv_bfloat16 g_vh[(size_t)NV * 128];
__device__ __align__(16) __nv_bfloat16 g_vl[(size_t)NV * 128];
// packed encoder weights: per layer 1280 cols x 128 k  ([n][k])
__device__ __align__(16) __nv_bfloat16 g_wph[(size_t)2 * 1280 * 128];
__device__ __align__(16) __nv_bfloat16 g_wpl[(size_t)2 * 1280 * 128];
// conv1 weights [chunk][co 128][k 64]
__device__ __align__(16) __nv_bfloat16 g_whi[(size_t)W1CHUNKS * 128 * 64];
__device__ __align__(16) __nv_bfloat16 g_wlo[(size_t)W1CHUNKS * 128 * 64];
// convs 2-4 weights: [chunk][co 64][k 64]; conv2 @0 (18 ch), conv3 @73728 (9), conv4 @110592 (9)
constexpr int WC2_OFF = 0, WC3_OFF = 73728, WC4_OFF = 110592, WC_TOTAL = 147456;
__device__ __align__(16) __nv_bfloat16 g_wch[WC_TOTAL];
__device__ __align__(16) __nv_bfloat16 g_wcl[WC_TOTAL];

// ---------------- small helpers ----------------
__device__ __forceinline__ uint32_t smem_u32(const void* p) {
    return (uint32_t)__cvta_generic_to_shared(p);
}
__device__ __forceinline__ void cpasync16(uint32_t dst, const void* src, bool valid) {
    asm volatile("cp.async.cg.shared.global [%0], [%1], 16, %2;"
                 :: "r"(dst), "l"(src), "r"(valid ? 16u : 0u));
}
__device__ __forceinline__ void cp_commit() { asm volatile("cp.async.commit_group;"); }
__device__ __forceinline__ void cp_wait1()  { asm volatile("cp.async.wait_group 1;"); }
__device__ __forceinline__ void cp_wait0()  { asm volatile("cp.async.wait_group 0;"); }

__device__ __forceinline__ void ldmx4(uint32_t* r, uint32_t addr) {
    asm volatile("ldmatrix.sync.aligned.m8n8.x4.shared.b16 {%0,%1,%2,%3}, [%4];"
                 : "=r"(r[0]), "=r"(r[1]), "=r"(r[2]), "=r"(r[3]) : "r"(addr));
}
__device__ __forceinline__ void ldmx2(uint32_t* r, uint32_t addr) {
    asm volatile("ldmatrix.sync.aligned.m8n8.x2.shared.b16 {%0,%1}, [%2];"
                 : "=r"(r[0]), "=r"(r[1]) : "r"(addr));
}
__device__ __forceinline__ void mma_bf16(float* c, const uint32_t* a, const uint32_t* b) {
    asm volatile("mma.sync.aligned.m16n8k16.row.col.f32.bf16.bf16.f32 "
                 "{%0,%1,%2,%3}, {%4,%5,%6,%7}, {%8,%9}, {%0,%1,%2,%3};"
                 : "+f"(c[0]), "+f"(c[1]), "+f"(c[2]), "+f"(c[3])
                 : "r"(a[0]), "r"(a[1]), "r"(a[2]), "r"(a[3]), "r"(b[0]), "r"(b[1]));
}
__device__ __forceinline__ void split2(float v, __nv_bfloat16& h, __nv_bfloat16& l) {
    h = __float2bfloat16(v);
    l = __float2bfloat16(v - __bfloat162float(h));
}

// ---------------- elementwise helpers ----------------
__global__ void init_max_kernel(int* gm) { *gm = INT_MIN; }

__global__ void reduce_max_kernel(const int* __restrict__ p, int* gm) {
    int v = INT_MIN;
    for (int k = blockIdx.x * blockDim.x + threadIdx.x; k < NQ; k += gridDim.x * blockDim.x)
        v = max(v, p[k]);
    #pragma unroll
    for (int o = 16; o > 0; o >>= 1) v = max(v, __shfl_xor_sync(0xffffffffu, v, o));
    __shared__ int sm[8];
    int w = threadIdx.x >> 5;
    if ((threadIdx.x & 31) == 0) sm[w] = v;
    __syncthreads();
    if (threadIdx.x == 0) {
        int bv = sm[0];
        for (int i = 1; i < (int)(blockDim.x >> 5); i++) bv = max(bv, sm[i]);
        atomicMax(gm, bv);
    }
}

__global__ void write_mask_kernel(const int* __restrict__ p, const int* __restrict__ gm,
                                  float* __restrict__ out) {
    int i = blockIdx.x * blockDim.x + threadIdx.x;
    if (i < NQ) out[i] = (p[i] < *gm) ? 1.0f : 0.0f;
}

__global__ void split_kernel(const float* __restrict__ X, __nv_bfloat16* __restrict__ hi,
                             __nv_bfloat16* __restrict__ lo, int n)
{
    int i = blockIdx.x * blockDim.x + threadIdx.x;
    if (i < n) split2(X[i], hi[i], lo[i]);
}

__global__ void add_split_kernel(const float* __restrict__ A, const float* __restrict__ B,
                                 __nv_bfloat16* __restrict__ hi, __nv_bfloat16* __restrict__ lo, int n)
{
    int i = blockIdx.x * blockDim.x + threadIdx.x;
    if (i < n) split2(A[i] + B[i], hi[i], lo[i]);
}

// pack encoder weight W [128][N] (k-major) -> hi/lo [N][128]
__global__ void packw_kernel(const float* __restrict__ W, __nv_bfloat16* __restrict__ hi,
                             __nv_bfloat16* __restrict__ lo, int N)
{
    int i = blockIdx.x * blockDim.x + threadIdx.x;
    if (i >= N * 128) return;
    int k = i & 127, n = i >> 7;
    split2(W[(size_t)k * N + n], hi[i], lo[i]);
}

// pack boff||battn -> 768
__global__ void packbias_kernel(const float* __restrict__ boff, const float* __restrict__ battn,
                                float* __restrict__ dst)
{
    int i = threadIdx.x + blockIdx.x * blockDim.x;
    if (i < 768) dst[i] = (i < 512) ? boff[i] : battn[i - 512];
}

// pack conv 3x3 weight OIHW -> [chunk][co 64][k 64] hi/lo, zero-padded
__global__ void packcw_kernel(const float* __restrict__ W, __nv_bfloat16* __restrict__ hi,
                              __nv_bfloat16* __restrict__ lo, int CO, int CI, int CIN_CH, int total)
{
    int i = blockIdx.x * blockDim.x + threadIdx.x;
    if (i >= total) return;
    int k = i & 63, co = (i >> 6) & 63, c = i >> 12;
    int e = c / CIN_CH, cih = c % CIN_CH;
    int ci = cih * 64 + k;
    float v = (co < CO && ci < CI) ? W[(((size_t)co * CI + ci) * 3 + e / 3) * 3 + e % 3] : 0.f;
    split2(v, hi[i], lo[i]);
}

// ---------------- generic bf16x3 GEMM: C[M,N] = A[M,128] * B[N,128]^T ----------------
// FLAGS: 1 relu, 2 residual, 4 write fp32 C, 8 write split C
constexpr int GROWB = 272;
constexpr int GTILE = 128 * GROWB;
constexpr int GEMM_SMEM = 4 * GTILE;

template<int FLAGS>
__global__ void __launch_bounds__(256, 1) gemm_mma(
    const __nv_bfloat16* __restrict__ Ah, const __nv_bfloat16* __restrict__ Al,
    const __nv_bfloat16* __restrict__ Bh, const __nv_bfloat16* __restrict__ Bl,
    const float* __restrict__ bias, const float* __restrict__ R,
    float* __restrict__ Cf, __nv_bfloat16* __restrict__ Ch, __nv_bfloat16* __restrict__ Cl,
    int M, int N)
{
    extern __shared__ char smem[];
    const int tid = threadIdx.x;
    const int wid = tid >> 5, lane = tid & 31;
    const int warp_m = wid >> 2, warp_n = wid & 3;
    const uint32_t sb = smem_u32(smem);
    const int bm = blockIdx.x * 128, bn = blockIdx.y * 128;

    {
        const int lrow = tid >> 1, lhalf = tid & 1;
        const bool aval = (bm + lrow) < M;
        const uint32_t sa = sb + (uint32_t)lrow * GROWB + (uint32_t)lhalf * 128;
        const char* agh = (const char*)(Ah + (size_t)(aval ? (bm + lrow) : 0) * 128 + lhalf * 64);
        const char* agl = (const char*)(Al + (size_t)(aval ? (bm + lrow) : 0) * 128 + lhalf * 64);
        const char* bgh = (const char*)(Bh + (size_t)(bn + lrow) * 128 + lhalf * 64);
        const char* bgl = (const char*)(Bl + (size_t)(bn + lrow) * 128 + lhalf * 64);
        #pragma unroll
        for (int i = 0; i < 8; i++) {
            cpasync16(sa + i * 16,             agh + i * 16, aval);
            cpasync16(sa + GTILE + i * 16,     agl + i * 16, aval);
            cpasync16(sa + 2 * GTILE + i * 16, bgh + i * 16, true);
            cpasync16(sa + 3 * GTILE + i * 16, bgl + i * 16, true);
        }
        cp_commit();
        cp_wait0();
        __syncthreads();
    }

    float acc[4][4][4];
    #pragma unroll
    for (int mt = 0; mt < 4; mt++)
        #pragma unroll
        for (int nt = 0; nt < 4; nt++)
            #pragma unroll
            for (int d = 0; d < 4; d++) acc[mt][nt][d] = 0.f;

    const uint32_t a_base = sb + (uint32_t)(warp_m * 64 + (lane & 15)) * GROWB + (uint32_t)(lane >> 4) * 16;
    const uint32_t b_base = sb + 2 * GTILE + (uint32_t)(warp_n * 32 + (lane & 7)) * GROWB
                          + (uint32_t)((lane >> 3) & 1) * 16;

    #pragma unroll
    for (int ks = 0; ks < 8; ks++) {
        const uint32_t kbyte = (uint32_t)ks * 32;
        uint32_t bh[4][2], bl[4][2];
        #pragma unroll
        for (int nt = 0; nt < 4; nt++) {
            ldmx2(bh[nt], b_base + (uint32_t)nt * 8 * GROWB + kbyte);
            ldmx2(bl[nt], b_base + GTILE + (uint32_t)nt * 8 * GROWB + kbyte);
        }
        #pragma unroll
        for (int mt = 0; mt < 4; mt++) {
            uint32_t ah[4], al[4];
            ldmx4(ah, a_base + (uint32_t)mt * 16 * GROWB + kbyte);
            ldmx4(al, a_base + GTILE + (uint32_t)mt * 16 * GROWB + kbyte);
            #pragma unroll
            for (int nt = 0; nt < 4; nt++) {
                mma_bf16(acc[mt][nt], ah, bh[nt]);
                mma_bf16(acc[mt][nt], ah, bl[nt]);
                mma_bf16(acc[mt][nt], al, bh[nt]);
            }
        }
    }

    const int g = lane >> 2, tg = lane & 3;
    #pragma unroll
    for (int mt = 0; mt < 4; mt++) {
        const int r0 = bm + warp_m * 64 + mt * 16 + g;
        #pragma unroll
        for (int nt = 0; nt < 4; nt++) {
            const int col = bn + warp_n * 32 + nt * 8 + tg * 2;
            float2 bb = *(const float2*)&bias[col];
            float v[4] = {acc[mt][nt][0] + bb.x, acc[mt][nt][1] + bb.y,
                          acc[mt][nt][2] + bb.x, acc[mt][nt][3] + bb.y};
            #pragma unroll
            for (int half = 0; half < 2; half++) {
                const int r = r0 + half * 8;
                if (r >= M) continue;
                float a0 = v[half * 2], a1 = v[half * 2 + 1];
                if (FLAGS & 2) {
                    float2 rr = *(const float2*)&R[(size_t)r * N + col];
                    a0 += rr.x; a1 += rr.y;
                }
                if (FLAGS & 1) { a0 = fmaxf(a0, 0.f); a1 = fmaxf(a1, 0.f); }
                if (FLAGS & 4)
                    *(float2*)&Cf[(size_t)r * N + col] = make_float2(a0, a1);
                if (FLAGS & 8) {
                    __nv_bfloat16 h0, l0, h1, l1;
                    split2(a0, h0, l0); split2(a1, h1, l1);
                    *(__nv_bfloat162*)&Ch[(size_t)r * N + col] = __nv_bfloat162(h0, h1);
                    *(__nv_bfloat162*)&Cl[(size_t)r * N + col] = __nv_bfloat162(l0, l1);
                }
            }
        }
    }
}

// ---------------- softmax over 32, reading combined NQx768 buffer ----------------
__global__ void softmax32_kernel(float* __restrict__ A) {
    int t = blockIdx.x * blockDim.x + threadIdx.x;
    if (t >= NQ * HEADS) return;
    const int n = t >> 3, h = t & 7;
    float* a = A + (size_t)n * 768 + 512 + h * 32;
    float e[32];
    float m = -1e30f;
    #pragma unroll
    for (int k = 0; k < 32; k++) m = fmaxf(m, a[k]);
    float s = 0.f;
    #pragma unroll
    for (int k = 0; k < 32; k++) { e[k] = expf(a[k] - m); s += e[k]; }
    float inv = 1.f / s;
    #pragma unroll
    for (int k = 0; k < 32; k++) a[k] = e[k] * inv;
}

// ---------------- deformable attention sampling (combined buffer, split out) ----------------
__global__ void __launch_bounds__(256) deform_kernel(
    const float* __restrict__ V, const float* __restrict__ OA,
    __nv_bfloat16* __restrict__ OH, __nv_bfloat16* __restrict__ OL)
{
    int t = blockIdx.x * 256 + threadIdx.x;
    if (t >= NQ * HEADS) return;
    const int n = t >> 3, h = t & 7;
    const float rx = ((float)(n % 200) + 0.5f) * (1.f / 200.f);
    const float ry = ((float)(n / 200) + 0.5f) * (1.f / 200.f);
    const float* op = OA + (size_t)n * 768 + h * 64;
    const float* ap = OA + (size_t)n * 768 + 512 + h * 32;

    float acc[16];
    #pragma unroll
    for (int d = 0; d < 16; d++) acc[d] = 0.f;

    const int stc[4] = {0, 32768, 40960, 43008};
    const int Wc[4]  = {256, 128, 64, 32};
    const int Hc[4]  = {128, 64, 32, 16};

    #pragma unroll
    for (int l = 0; l < 4; l++) {
        const int W = Wc[l], H = Hc[l], st = stc[l];
        const float Wf = (float)W, Hf = (float)H;
        for (int p = 0; p < 8; p++) {
            float ox = op[(l * 8 + p) * 2 + 0];
            float oy = op[(l * 8 + p) * 2 + 1];
            float aw = ap[l * 8 + p];
            float x = (rx + ox / Wf) * Wf - 0.5f;
            float y = (ry + oy / Hf) * Hf - 0.5f;
            float xf = floorf(x), yf = floorf(y);
            int x0 = (int)xf, y0 = (int)yf;
            float fx = x - xf, fy = y - yf;
            float wx[2] = {1.f - fx, fx};
            float wy[2] = {1.f - fy, fy};
            #pragma unroll
            for (int c = 0; c < 4; c++) {
                int xi = x0 + (c & 1), yi = y0 + (c >> 1);
                float wgt = wx[c & 1] * wy[c >> 1];
                if (xi >= 0 && xi < W && yi >= 0 && yi < H && wgt != 0.f) {
                    const float4* gp = (const float4*)(V + ((size_t)(st + yi * W + xi)) * 128 + h * 16);
                    float cw = aw * wgt;
                    float4 g0 = gp[0], g1 = gp[1], g2 = gp[2], g3 = gp[3];
                    acc[0]  += cw * g0.x; acc[1]  += cw * g0.y; acc[2]  += cw * g0.z; acc[3]  += cw * g0.w;
                    acc[4]  += cw * g1.x; acc[5]  += cw * g1.y; acc[6]  += cw * g1.z; acc[7]  += cw * g1.w;
                    acc[8]  += cw * g2.x; acc[9]  += cw * g2.y; acc[10] += cw * g2.z; acc[11] += cw * g2.w;
                    acc[12] += cw * g3.x; acc[13] += cw * g3.y; acc[14] += cw * g3.z; acc[15] += cw * g3.w;
                }
            }
        }
    }
    __nv_bfloat162* oh = (__nv_bfloat162*)(OH + (size_t)n * 128 + h * 16);
    __nv_bfloat162* ol = (__nv_bfloat162*)(OL + (size_t)n * 128 + h * 16);
    #pragma unroll
    for (int d = 0; d < 8; d++) {
        __nv_bfloat16 h0, l0, h1, l1;
        split2(acc[d * 2], h0, l0); split2(acc[d * 2 + 1], h1, l1);
        oh[d] = __nv_bfloat162(h0, h1);
        ol[d] = __nv_bfloat162(l0, l1);
    }
}

// ---------------- layernorm over 128 per row ----------------
template<int SPLIT>
__global__ void ln_kernel(const float* __restrict__ X, const float* __restrict__ g,
                          const float* __restrict__ b, float* __restrict__ Y,
                          __nv_bfloat16* __restrict__ Yh, __nv_bfloat16* __restrict__ Yl)
{
    int r = blockIdx.x;
    int t = threadIdx.x;
    float x = X[(size_t)r * 128 + t];
    float s = x;
    #pragma unroll
    for (int o = 16; o > 0; o >>= 1) s += __shfl_xor_sync(0xffffffffu, s, o);
    __shared__ float sm[4], sm2[4];
    int w = t >> 5, lane = t & 31;
    if (lane == 0) sm[w] = s;
    __syncthreads();
    float m = (sm[0] + sm[1] + sm[2] + sm[3]) * (1.f / 128.f);
    float d = x - m;
    float q = d * d;
    #pragma unroll
    for (int o = 16; o > 0; o >>= 1) q += __shfl_xor_sync(0xffffffffu, q, o);
    if (lane == 0) sm2[w] = q;
    __syncthreads();
    float var = (sm2[0] + sm2[1] + sm2[2] + sm2[3]) * (1.f / 128.f);
    float y = d * rsqrtf(var + 1e-5f) * g[t] + b[t];
    Y[(size_t)r * 128 + t] = y;
    if (SPLIT) {
        __nv_bfloat16 hh, ll;
        split2(y, hh, ll);
        Yh[(size_t)r * 128 + t] = hh;
        Yl[(size_t)r * 128 + t] = ll;
    }
}

// ---------------- conv1 weight split ----------------
__global__ void wsplit_kernel(const float* __restrict__ W, __nv_bfloat16* __restrict__ hi,
                              __nv_bfloat16* __restrict__ lo)
{
    int i = blockIdx.x * blockDim.x + threadIdx.x;
    if (i >= W1CHUNKS * 128 * 64) return;
    int k  = i & 63;
    int co = (i >> 6) & 127;
    int c  = i >> 13;
    int e = c >> 1, ci = ((c & 1) << 6) + k;
    int ky = e / 7, kx = e % 7;
    split2(W[(((size_t)co * 128 + ci) * 7 + ky) * 7 + kx], hi[i], lo[i]);
}

// ---------------- conv1 (7x7, 128->128) via mma.sync bf16x3 ----------------
constexpr int ROWB = 144;
constexpr int TILE_B = 128 * ROWB;
constexpr int BUF_B = 4 * TILE_B;
constexpr int CONV1_SMEM = 2 * BUF_B;

__global__ void __launch_bounds__(256, 1) conv1_mma_kernel(
    const __nv_bfloat16* __restrict__ qhi, const __nv_bfloat16* __restrict__ qlo,
    const __nv_bfloat16* __restrict__ whi, const __nv_bfloat16* __restrict__ wlo,
    float* __restrict__ Out)
{
    extern __shared__ char smem[];
    const int tid = threadIdx.x;
    const int wid = tid >> 5, lane = tid & 31;
    const int warp_m = wid >> 2, warp_n = wid & 3;
    const uint32_t sb = smem_u32(smem);
    const int bm = blockIdx.x * 128;

    const int lrow = tid >> 1, lhalf = tid & 1;
    const int pm = bm + lrow;
    const int py = pm / 200, px = pm % 200;
    const bool prow_ok = pm < NQ;
    const uint32_t s_arow = sb + (uint32_t)lrow * ROWB + (uint32_t)lhalf * 64;
    const uint32_t s_brow = s_arow + 2 * TILE_B;

    const uint32_t a_base = sb + (uint32_t)(warp_m * 64 + (lane & 15)) * ROWB + (uint32_t)(lane >> 4) * 16;
    const uint32_t b_base = sb + 2 * TILE_B + (uint32_t)(warp_n * 32 + (lane & 7)) * ROWB
                          + (uint32_t)((lane >> 3) & 1) * 16;

    float acc[4][4][4];
    #pragma unroll
    for (int mt = 0; mt < 4; mt++)
        #pragma unroll
        for (int nt = 0; nt < 4; nt++)
            #pragma unroll
            for (int d = 0; d < 4; d++) acc[mt][nt][d] = 0.f;

    auto load_chunk = [&](int c, int buf) {
        const int e = c >> 1, ch = c & 1;
        const int qy = py + e / 7 - 3;
        const int qx = px + e % 7 - 3;
        const bool val = prow_ok && qy >= 0 && qy < 200 && qx >= 0 && qx < 200;
        const size_t aoff = (size_t)(val ? (qy * 200 + qx) : 0) * 128 + (size_t)ch * 64 + (size_t)lhalf * 32;
        const char* agh = (const char*)(qhi + aoff);
        const char* agl = (const char*)(qlo + aoff);
        const size_t boff = ((size_t)c * 128 + lrow) * 64 + (size_t)lhalf * 32;
        const char* bgh = (const char*)(whi + boff);
        const char* bgl = (const char*)(wlo + boff);
        const uint32_t sa = s_arow + (uint32_t)buf * BUF_B;
        const uint32_t sbr = s_brow + (uint32_t)buf * BUF_B;
        #pragma unroll
        for (int i = 0; i < 4; i++) {
            cpasync16(sa + i * 16,          agh + i * 16, val);
            cpasync16(sa + TILE_B + i * 16, agl + i * 16, val);
            cpasync16(sbr + i * 16,          bgh + i * 16, true);
            cpasync16(sbr + TILE_B + i * 16, bgl + i * 16, true);
        }
    };

    load_chunk(0, 0); cp_commit();
    load_chunk(1, 1); cp_commit();

    for (int c = 0; c < W1CHUNKS; c++) {
        const int buf = c & 1;
        cp_wait1();
        __syncthreads();

        const uint32_t ab = a_base + (uint32_t)buf * BUF_B;
        const uint32_t bb = b_base + (uint32_t)buf * BUF_B;
        #pragma unroll
        for (int ks = 0; ks < 4; ks++) {
            const uint32_t kbyte = (uint32_t)ks * 32;
            uint32_t bh[4][2], bl[4][2];
            #pragma unroll
            for (int nt = 0; nt < 4; nt++) {
                ldmx2(bh[nt], bb + (uint32_t)nt * 8 * ROWB + kbyte);
                ldmx2(bl[nt], bb + TILE_B + (uint32_t)nt * 8 * ROWB + kbyte);
            }
            #pragma unroll
            for (int mt = 0; mt < 4; mt++) {
                uint32_t ah[4], al[4];
                ldmx4(ah, ab + (uint32_t)mt * 16 * ROWB + kbyte);
                ldmx4(al, ab + TILE_B + (uint32_t)mt * 16 * ROWB + kbyte);
                #pragma unroll
                for (int nt = 0; nt < 4; nt++) {
                    mma_bf16(acc[mt][nt], ah, bh[nt]);
                    mma_bf16(acc[mt][nt], ah, bl[nt]);
                    mma_bf16(acc[mt][nt], al, bh[nt]);
                }
            }
        }
        __syncthreads();
        if (c + 2 < W1CHUNKS) load_chunk(c + 2, buf);
        cp_commit();
    }

    const int g = lane >> 2, tg = lane & 3;
    #pragma unroll
    for (int mt = 0; mt < 4; mt++) {
        const int r0 = bm + warp_m * 64 + mt * 16 + g;
        #pragma unroll
        for (int nt = 0; nt < 4; nt++) {
            const int col = warp_n * 32 + nt * 8 + tg * 2;
            if (r0 < NQ)
                *(float2*)&Out[(size_t)r0 * 128 + col] = make_float2(acc[mt][nt][0], acc[mt][nt][1]);
            if (r0 + 8 < NQ)
                *(float2*)&Out[(size_t)(r0 + 8) * 128 + col] = make_float2(acc[mt][nt][2], acc[mt][nt][3]);
        }
    }
}

// ---------------- convs 2-4 (3x3) via mma.sync bf16x3, 128x64 tile ----------------
constexpr int CATILE = 128 * ROWB;            // 18432
constexpr int CBTILE = 64 * ROWB;             // 9216
constexpr int CBUF = 2 * CATILE + 2 * CBTILE; // 55296
constexpr int CONV_SMEM = 2 * CBUF;           // 110592

template<int CHUNKS, int CIN_CH, int CST>
__global__ void __launch_bounds__(256, 2) conv_mma_kernel(
    const __nv_bfloat16* __restrict__ inh, const __nv_bfloat16* __restrict__ inl,
    const __nv_bfloat16* __restrict__ wh, const __nv_bfloat16* __restrict__ wl,
    float* __restrict__ Out, int COUT)
{
    extern __shared__ char smem[];
    const int tid = threadIdx.x;
    const int wid = tid >> 5, lane = tid & 31;
    const int warp_m = wid >> 1, warp_n = wid & 1;  // 4 x 2
    const uint32_t sb = smem_u32(smem);
    const int bm = blockIdx.x * 128;

    const int lrow = tid >> 1, lhalf = tid & 1;     // A loader: 2 threads/row
    const int pm = bm + lrow;
    const int py = pm / 200, px = pm % 200;
    const bool prow_ok = pm < NQ;
    const uint32_t s_arow = sb + (uint32_t)lrow * ROWB + (uint32_t)lhalf * 64;
    const int brow = tid >> 2, bq = tid & 3;        // B loader: 4 threads/row
    const uint32_t s_brow = sb + 2 * CATILE + (uint32_t)brow * ROWB + (uint32_t)bq * 32;

    const uint32_t a_base = sb + (uint32_t)(warp_m * 32 + (lane & 15)) * ROWB + (uint32_t)(lane >> 4) * 16;
    const uint32_t b_base = sb + 2 * CATILE + (uint32_t)(warp_n * 32 + (lane & 7)) * ROWB
                          + (uint32_t)((lane >> 3) & 1) * 16;

    float acc[2][4][4];
    #pragma unroll
    for (int mt = 0; mt < 2; mt++)
        #pragma unroll
        for (int nt = 0; nt < 4; nt++)
            #pragma unroll
            for (int d = 0; d < 4; d++) acc[mt][nt][d] = 0.f;

    auto load_chunk = [&](int c, int buf) {
        const int e = c / CIN_CH, cih = c % CIN_CH;
        const int qy = py + e / 3 - 1;
        const int qx = px + e % 3 - 1;
        const bool val = prow_ok && qy >= 0 && qy < 200 && qx >= 0 && qx < 200;
        const size_t aoff = (size_t)(val ? (qy * 200 + qx) : 0) * CST + (size_t)cih * 64 + (size_t)lhalf * 32;
        const char* agh = (const char*)(inh + aoff);
        const char* agl = (const char*)(inl + aoff);
        const size_t boff = ((size_t)c * 64 + brow) * 64 + (size_t)bq * 16;
        const char* bgh = (const char*)(wh + boff);
        const char* bgl = (const char*)(wl + boff);
        const uint32_t sa = s_arow + (uint32_t)buf * CBUF;
        const uint32_t sbr = s_brow + (uint32_t)buf * CBUF;
        #pragma unroll
        for (int i = 0; i < 4; i++) {
            cpasync16(sa + i * 16,           agh + i * 16, val);
            cpasync16(sa + CATILE + i * 16,  agl + i * 16, val);
        }
        #pragma unroll
        for (int i = 0; i < 2; i++) {
            cpasync16(sbr + i * 16,          bgh + i * 16, true);
            cpasync16(sbr + CBTILE + i * 16, bgl + i * 16, true);
        }
    };

    load_chunk(0, 0); cp_commit();
    load_chunk(1, 1); cp_commit();

    for (int c = 0; c < CHUNKS; c++) {
        const int buf = c & 1;
        cp_wait1();
        __syncthreads();

        const uint32_t ab = a_base + (uint32_t)buf * CBUF;
        const uint32_t bb = b_base + (uint32_t)buf * CBUF;
        #pragma unroll
        for (int ks = 0; ks < 4; ks++) {
            const uint32_t kbyte = (uint32_t)ks * 32;
            uint32_t bh[4][2], bl[4][2];
            #pragma unroll
            for (int nt = 0; nt < 4; nt++) {
                ldmx2(bh[nt], bb + (uint32_t)nt * 8 * ROWB + kbyte);
                ldmx2(bl[nt], bb + CBTILE + (uint32_t)nt * 8 * ROWB + kbyte);
            }
            #pragma unroll
            for (int mt = 0; mt < 2; mt++) {
                uint32_t ah[4], al[4];
                ldmx4(ah, ab + (uint32_t)mt * 16 * ROWB + kbyte);
                ldmx4(al, ab + CATILE + (uint32_t)mt * 16 * ROWB + kbyte);
                #pragma unroll
                for (int nt = 0; nt < 4; nt++) {
                    mma_bf16(acc[mt][nt], ah, bh[nt]);
                    mma_bf16(acc[mt][nt], ah, bl[nt]);
                    mma_bf16(acc[mt][nt], al, bh[nt]);
                }
            }
        }
        __syncthreads();
        if (c + 2 < CHUNKS) load_chunk(c + 2, buf);
        cp_commit();
    }

    const int g = lane >> 2, tg = lane & 3;
    #pragma unroll
    for (int mt = 0; mt < 2; mt++) {
        const int r0 = bm + warp_m * 32 + mt * 16 + g;
        #pragma unroll
        for (int nt = 0; nt < 4; nt++) {
            const int col = warp_n * 32 + nt * 8 + tg * 2;
            if (col >= COUT) continue;
            if (r0 < NQ)
                *(float2*)&Out[(size_t)r0 * COUT + col] = make_float2(acc[mt][nt][0], acc[mt][nt][1]);
            if (r0 + 8 < NQ)
                *(float2*)&Out[(size_t)(r0 + 8) * COUT + col] = make_float2(acc[mt][nt][2], acc[mt][nt][3]);
        }
    }
}

// ---------------- batchnorm ----------------
__global__ void bn_stats_kernel(const float* __restrict__ X, float* __restrict__ part, int C)
{
    int c = threadIdx.x;
    int g = blockIdx.x;
    const int per = (NQ + 63) / 64;
    int p0 = g * per;
    int p1 = min(NQ, p0 + per);
    float s = 0.f, q = 0.f;
    for (int p = p0; p < p1; p++) {
        float x = X[(size_t)p * C + c];
        s += x; q += x * x;
    }
    part[(size_t)g * 2 * C + c] = s;
    part[(size_t)g * 2 * C + C + c] = q;
}

__global__ void bn_finalize_kernel(const float* __restrict__ part,
                                   const float* __restrict__ gamma, const float* __restrict__ beta,
                                   float* __restrict__ scale, float* __restrict__ shift, int C)
{
    int c = threadIdx.x;
    float s = 0.f, q = 0.f;
    for (int g = 0; g < 64; g++) {
        s += part[(size_t)g * 2 * C + c];
        q += part[(size_t)g * 2 * C + C + c];
    }
    const float invP = 1.f / (float)NQ;
    float m = s * invP;
    float v = q * invP - m * m;
    float sc = gamma[c] * rsqrtf(v + 1e-5f);
    scale[c] = sc;
    shift[c] = beta[c] - m * sc;
}

// BN+ReLU, write bf16 split into padded-stride buffer
__global__ void bn_apply_split_kernel(const float* __restrict__ X, const float* __restrict__ scale,
                                      const float* __restrict__ shift,
                                      __nv_bfloat16* __restrict__ hi, __nv_bfloat16* __restrict__ lo,
                                      int C, int CST, int total)
{
    int i = blockIdx.x * blockDim.x + threadIdx.x;
    if (i >= total) return;
    int c = i % CST;
    int p = i / CST;
    float v = 0.f;
    if (c < C) v = fmaxf(0.f, fmaf(X[(size_t)p * C + c], scale[c], shift[c]));
    split2(v, hi[i], lo[i]);
}

__global__ void bn_apply_kernel(float* __restrict__ X, const float* __restrict__ scale,
                                const float* __restrict__ shift, int C, int total)
{
    int i = blockIdx.x * blockDim.x + threadIdx.x;
    if (i < total) {
        int c = i % C;
        X[i] = fmaxf(0.f, fmaf(X[i], scale[c], shift[c]));
    }
}

// ---------------- head: 1x1 conv 48 -> 21, output NCHW ----------------
__global__ void head_conv_kernel(const float* __restrict__ H4, const float* __restrict__ Wo,
                                 const float* __restrict__ bo, float* __restrict__ out)
{
    int p = blockIdx.x * blockDim.x + threadIdx.x;
    if (p >= NQ) return;
    float x[48];
    const float4* hp = (const float4*)(H4 + (size_t)p * 48);
    #pragma unroll
    for (int i = 0; i < 12; i++) {
        float4 v = hp[i];
        x[i * 4 + 0] = v.x; x[i * 4 + 1] = v.y; x[i * 4 + 2] = v.z; x[i * 4 + 3] = v.w;
    }
    for (int co = 0; co < 21; co++) {
        float s = bo[co];
        const float* w = Wo + co * 48;
        #pragma unroll
        for (int ci = 0; ci < 48; ci++) s = fmaf(x[ci], w[ci], s);
        out[(size_t)co * NQ + p] = s;
    }
}

// ---------------- launch ----------------
extern "C" void kernel_launch(void* const* d_in, const int* in_sizes, int n_in,
                              void* d_out, int out_size)
{
    const float* value = (const float*)d_in[0];
    const float* bq    = (const float*)d_in[1];
    const float* bpos  = (const float*)d_in[2];
    const int*   proj  = (const int*)d_in[3];
    const float* Wv    = (const float*)d_in[4];
    const float* bv    = (const float*)d_in[5];
    const float* Woff  = (const float*)d_in[6];
    const float* boff  = (const float*)d_in[7];
    const float* Wattn = (const float*)d_in[8];
    const float* battn = (const float*)d_in[9];
    const float* Wout  = (const float*)d_in[10];
    const float* bout  = (const float*)d_in[11];
    const float* Wf1   = (const float*)d_in[12];
    const float* bf1   = (const float*)d_in[13];
    const float* Wf2   = (const float*)d_in[14];
    const float* bf2   = (const float*)d_in[15];
    const float* lng   = (const float*)d_in[16];
    const float* lnb   = (const float*)d_in[17];
    const float* cw1   = (const float*)d_in[18];
    const float* g1    = (const float*)d_in[19];
    const float* b1    = (const float*)d_in[20];
    const float* cw2   = (const float*)d_in[21];
    const float* g2    = (const float*)d_in[22];
    const float* b2    = (const float*)d_in[23];
    const float* cw3   = (const float*)d_in[24];
    const float* g3    = (const float*)d_in[25];
    const float* b3    = (const float*)d_in[26];
    const float* cw4   = (const float*)d_in[27];
    const float* g4    = (const float*)d_in[28];
    const float* b4    = (const float*)d_in[29];
    const float* objw  = (const float*)d_in[30];
    const float* objb  = (const float*)d_in[31];
    float* out = (float*)d_out;

    float* S = nullptr;
    cudaGetSymbolAddress((void**)&S, g_scratch);
    int* gm = nullptr;
    cudaGetSymbolAddress((void**)&gm, g_maxv);
    __nv_bfloat16 *s1h, *s1l, *s2h, *s2l, *vh, *vl, *wph, *wpl, *whi, *wlo, *wch, *wcl;
    cudaGetSymbolAddress((void**)&s1h, g_s1h);
    cudaGetSymbolAddress((void**)&s1l, g_s1l);
    cudaGetSymbolAddress((void**)&s2h, g_s2h);
    cudaGetSymbolAddress((void**)&s2l, g_s2l);
    cudaGetSymbolAddress((void**)&vh,  g_vh);
    cudaGetSymbolAddress((void**)&vl,  g_vl);
    cudaGetSymbolAddress((void**)&wph, g_wph);
    cudaGetSymbolAddress((void**)&wpl, g_wpl);
    cudaGetSymbolAddress((void**)&whi, g_whi);
    cudaGetSymbolAddress((void**)&wlo, g_wlo);
    cudaGetSymbolAddress((void**)&wch, g_wch);
    cudaGetSymbolAddress((void**)&wcl, g_wcl);

    float* PV    = S + OFF_V;
    float* POA   = S + OFF_OA;
    float* PQ    = S + OFF_Q;
    float* PT1   = S + OFF_T1;
    float* PT2   = S + OFF_T2;
    float* PH1   = S + OFF_H1;
    float* PH2   = S + OFF_H2;
    float* PH3   = S + OFF_H3;
    float* PH4   = S + OFF_H4;
    float* PPART = S + OFF_PART;
    float* PSCALE= S + OFF_SCALE;
    float* PSHIFT= S + OFF_SHIFT;
    float* PBIAS = S + OFF_BIAS;

    cudaFuncSetAttribute(conv1_mma_kernel, cudaFuncAttributeMaxDynamicSharedMemorySize, CONV1_SMEM);
    cudaFuncSetAttribute(gemm_mma<4>,  cudaFuncAttributeMaxDynamicSharedMemorySize, GEMM_SMEM);
    cudaFuncSetAttribute(gemm_mma<6>,  cudaFuncAttributeMaxDynamicSharedMemorySize, GEMM_SMEM);
    cudaFuncSetAttribute(gemm_mma<9>,  cudaFuncAttributeMaxDynamicSharedMemorySize, GEMM_SMEM);
    cudaFuncSetAttribute((conv_mma_kernel<18, 2, 128>), cudaFuncAttributeMaxDynamicSharedMemorySize, CONV_SMEM);
    cudaFuncSetAttribute((conv_mma_kernel<9, 1, 64>),   cudaFuncAttributeMaxDynamicSharedMemorySize, CONV_SMEM);

    // --- observed_masks ---
    init_max_kernel<<<1, 1>>>(gm);
    reduce_max_kernel<<<40, 256>>>(proj, gm);
    write_mask_kernel<<<(NQ + 255) / 256, 256>>>(proj, gm, out + 21 * NQ);

    // --- weight prep ---
    wsplit_kernel<<<(W1CHUNKS * 128 * 64 + 255) / 256, 256>>>(cw1, whi, wlo);
    packcw_kernel<<<(18 * 4096 + 255) / 256, 256>>>(cw2, wch + WC2_OFF, wcl + WC2_OFF, 64, 128, 2, 18 * 4096);
    packcw_kernel<<<(9 * 4096 + 255) / 256, 256>>>(cw3, wch + WC3_OFF, wcl + WC3_OFF, 48, 64, 1, 9 * 4096);
    packcw_kernel<<<(9 * 4096 + 255) / 256, 256>>>(cw4, wch + WC4_OFF, wcl + WC4_OFF, 48, 48, 1, 9 * 4096);
    for (int i = 0; i < 2; i++) {
        size_t LB = (size_t)i * 1280 * 128;
        packw_kernel<<<(128 * 128 + 255) / 256, 256>>>(Wv   + (size_t)i * 128 * 128, wph + LB,              wpl + LB,              128);
        packw_kernel<<<(512 * 128 + 255) / 256, 256>>>(Woff + (size_t)i * 128 * 512, wph + LB + 128 * 128,  wpl + LB + 128 * 128,  512);
        packw_kernel<<<(256 * 128 + 255) / 256, 256>>>(Wattn+ (size_t)i * 128 * 256, wph + LB + 640 * 128,  wpl + LB + 640 * 128,  256);
        packw_kernel<<<(128 * 128 + 255) / 256, 256>>>(Wout + (size_t)i * 128 * 128, wph + LB + 896 * 128,  wpl + LB + 896 * 128,  128);
        packw_kernel<<<(128 * 128 + 255) / 256, 256>>>(Wf1  + (size_t)i * 128 * 128, wph + LB + 1024 * 128, wpl + LB + 1024 * 128, 128);
        packw_kernel<<<(128 * 128 + 255) / 256, 256>>>(Wf2  + (size_t)i * 128 * 128, wph + LB + 1152 * 128, wpl + LB + 1152 * 128, 128);
        packbias_kernel<<<3, 256>>>(boff + i * 512, battn + i * 256, PBIAS + i * 768);
    }
    split_kernel<<<(NV * 128 + 255) / 256, 256>>>(value, vh, vl, NV * 128);

    // --- q init ---
    cudaMemcpyAsync(PQ, bq, (size_t)NQ * ED * sizeof(float), cudaMemcpyDeviceToDevice);

    // --- 2 encoder layers ---
    for (int i = 0; i < 2; i++) {
        size_t LB = (size_t)i * 1280 * 128;
        add_split_kernel<<<(NQ * ED + 255) / 256, 256>>>(PQ, bpos, s1h, s1l, NQ * ED);
        gemm_mma<4><<<dim3(340, 1), 256, GEMM_SMEM>>>(vh, vl, wph + LB, wpl + LB,
                                                      bv + i * 128, nullptr, PV, nullptr, nullptr, NV, 128);
        // combined Woff+Wattn: N = 768
        gemm_mma<4><<<dim3(313, 6), 256, GEMM_SMEM>>>(s1h, s1l, wph + LB + 128 * 128, wpl + LB + 128 * 128,
                                                      PBIAS + i * 768, nullptr, POA, nullptr, nullptr, NQ, 768);
        softmax32_kernel<<<(NQ * HEADS + 255) / 256, 256>>>(POA);
        deform_kernel<<<(NQ * HEADS + 255) / 256, 256>>>(PV, POA, s2h, s2l);
        gemm_mma<6><<<dim3(313, 1), 256, GEMM_SMEM>>>(s2h, s2l, wph + LB + 896 * 128, wpl + LB + 896 * 128,
                                                      bout + i * 128, PQ, PT1, nullptr, nullptr, NQ, 128);
        ln_kernel<1><<<NQ, 128>>>(PT1, lng + (i * 2 + 0) * 128, lnb + (i * 2 + 0) * 128, PQ, s1h, s1l);
        gemm_mma<9><<<dim3(313, 1), 256, GEMM_SMEM>>>(s1h, s1l, wph + LB + 1024 * 128, wpl + LB + 1024 * 128,
                                                      bf1 + i * 128, nullptr, nullptr, s2h, s2l, NQ, 128);
        gemm_mma<6><<<dim3(313, 1), 256, GEMM_SMEM>>>(s2h, s2l, wph + LB + 1152 * 128, wpl + LB + 1152 * 128,
                                                      bf2 + i * 128, PQ, PT2, nullptr, nullptr, NQ, 128);
        if (i == 0)
            ln_kernel<0><<<NQ, 128>>>(PT2, lng + 1 * 128, lnb + 1 * 128, PQ, nullptr, nullptr);
        else
            ln_kernel<1><<<NQ, 128>>>(PT2, lng + 3 * 128, lnb + 3 * 128, PQ, s1h, s1l);
    }

    // --- conv head (all mma) ---
    conv1_mma_kernel<<<313, 256, CONV1_SMEM>>>(s1h, s1l, whi, wlo, PH1);
    bn_stats_kernel<<<64, 128>>>(PH1, PPART, 128);
    bn_finalize_kernel<<<1, 128>>>(PPART, g1, b1, PSCALE, PSHIFT, 128);
    bn_apply_split_kernel<<<(NQ * 128 + 255) / 256, 256>>>(PH1, PSCALE, PSHIFT, s1h, s1l, 128, 128, NQ * 128);

    conv_mma_kernel<18, 2, 128><<<313, 256, CONV_SMEM>>>(s1h, s1l, wch + WC2_OFF, wcl + WC2_OFF, PH2, 64);
    bn_stats_kernel<<<64, 64>>>(PH2, PPART, 64);
    bn_finalize_kernel<<<1, 64>>>(PPART, g2, b2, PSCALE, PSHIFT, 64);
    bn_apply_split_kernel<<<(NQ * 64 + 255) / 256, 256>>>(PH2, PSCALE, PSHIFT, s2h, s2l, 64, 64, NQ * 64);

    conv_mma_kernel<9, 1, 64><<<313, 256, CONV_SMEM>>>(s2h, s2l, wch + WC3_OFF, wcl + WC3_OFF, PH3, 48);
    bn_stats_kernel<<<64, 48>>>(PH3, PPART, 48);
    bn_finalize_kernel<<<1, 48>>>(PPART, g3, b3, PSCALE, PSHIFT, 48);
    bn_apply_split_kernel<<<(NQ * 64 + 255) / 256, 256>>>(PH3, PSCALE, PSHIFT, s1h, s1l, 48, 64, NQ * 64);

    conv_mma_kernel<9, 1, 64><<<313, 256, CONV_SMEM>>>(s1h, s1l, wch + WC4_OFF, wcl + WC4_OFF, PH4, 48);
    bn_stats_kernel<<<64, 48>>>(PH4, PPART, 48);
    bn_finalize_kernel<<<1, 48>>>(PPART, g4, b4, PSCALE, PSHIFT, 48);
    bn_apply_kernel<<<(NQ * 48 + 255) / 256, 256>>>(PH4, PSCALE, PSHIFT, 48, NQ * 48);

    head_conv_kernel<<<(NQ + 255) / 256, 256>>>(PH4, objw, objb, out);
}

// round 6
// speedup vs baseline: 1.6018x; 1.1688x over previous
#include <cuda_runtime.h>
#include <cuda_bf16.h>
#include <cuda_fp16.h>
#include <cstdint>
#include <climits>

// ---------------- problem constants ----------------
constexpr int NQ = 40000;        // 200*200
constexpr int ED = 128;
constexpr int NV = 43520;        // sum of level sizes
constexpr int HEADS = 8;

// ---------------- scratch layout (floats) ----------------
constexpr size_t OFF_OA   = 0;                     // combined offsets+attn, NQ x 768
constexpr size_t SZ_OA    = (size_t)NQ * 768;
constexpr size_t OFF_Q    = OFF_OA + SZ_OA;
constexpr size_t SZ_Q     = (size_t)NQ * ED;
constexpr size_t OFF_T1   = OFF_Q + SZ_Q;
constexpr size_t OFF_T2   = OFF_T1 + SZ_Q;
constexpr size_t OFF_H1   = OFF_T2 + SZ_Q;
constexpr size_t SZ_H1    = (size_t)NQ * 128;
constexpr size_t OFF_H2   = OFF_H1 + SZ_H1;
constexpr size_t SZ_H2    = (size_t)NQ * 64;
constexpr size_t OFF_H3   = OFF_H2 + SZ_H2;
constexpr size_t SZ_H3    = (size_t)NQ * 48;
constexpr size_t OFF_H4   = OFF_H3 + SZ_H3;
constexpr size_t OFF_PART = OFF_H4 + SZ_H3;
constexpr size_t SZ_PART  = 64 * 128 * 2;
constexpr size_t OFF_SCALE= OFF_PART + SZ_PART;
constexpr size_t OFF_SHIFT= OFF_SCALE + 128;
constexpr size_t OFF_BIAS = OFF_SHIFT + 128;       // 2 layers x 768 packed bias
constexpr size_t SCRATCH_TOTAL = OFF_BIAS + 2 * 768;

__device__ float g_scratch[SCRATCH_TOTAL];
__device__ int   g_maxv;

// ---------------- bf16 / fp16 buffers ----------------
constexpr int W1CHUNKS = 98;                 // conv1: 49 taps * 2 ci-halves
__device__ __align__(16) __nv_bfloat16 g_s1h[(size_t)NQ * 128];
__device__ __align__(16) __nv_bfloat16 g_s1l[(size_t)NQ * 128];
__device__ __align__(16) __nv_bfloat16 g_s2h[(size_t)NQ * 128];
__device__ __align__(16) __nv_bfloat16 g_s2l[(size_t)NQ * 128];
__device__ __align__(16) __nv_bfloat16 g_vh[(size_t)NV * 128];
__device__ __align__(16) __nv_bfloat16 g_vl[(size_t)NV * 128];
__device__ __align__(16) __half        g_vx[(size_t)NV * 128];   // fp16 V for deform
// packed encoder weights: per layer 1280 cols x 128 k  ([n][k])
__device__ __align__(16) __nv_bfloat16 g_wph[(size_t)2 * 1280 * 128];
__device__ __align__(16) __nv_bfloat16 g_wpl[(size_t)2 * 1280 * 128];
// conv1 weights [chunk][co 128][k 64]
__device__ __align__(16) __nv_bfloat16 g_whi[(size_t)W1CHUNKS * 128 * 64];
__device__ __align__(16) __nv_bfloat16 g_wlo[(size_t)W1CHUNKS * 128 * 64];
// convs 2-4 weights
constexpr int WC2_OFF = 0, WC3_OFF = 73728, WC4_OFF = 110592, WC_TOTAL = 147456;
__device__ __align__(16) __nv_bfloat16 g_wch[WC_TOTAL];
__device__ __align__(16) __nv_bfloat16 g_wcl[WC_TOTAL];

// ---------------- small helpers ----------------
__device__ __forceinline__ uint32_t smem_u32(const void* p) {
    return (uint32_t)__cvta_generic_to_shared(p);
}
__device__ __forceinline__ void cpasync16(uint32_t dst, const void* src, bool valid) {
    asm volatile("cp.async.cg.shared.global [%0], [%1], 16, %2;"
                 :: "r"(dst), "l"(src), "r"(valid ? 16u : 0u));
}
__device__ __forceinline__ void cp_commit() { asm volatile("cp.async.commit_group;"); }
__device__ __forceinline__ void cp_wait1()  { asm volatile("cp.async.wait_group 1;"); }
__device__ __forceinline__ void cp_wait0()  { asm volatile("cp.async.wait_group 0;"); }

__device__ __forceinline__ void ldmx4(uint32_t* r, uint32_t addr) {
    asm volatile("ldmatrix.sync.aligned.m8n8.x4.shared.b16 {%0,%1,%2,%3}, [%4];"
                 : "=r"(r[0]), "=r"(r[1]), "=r"(r[2]), "=r"(r[3]) : "r"(addr));
}
__device__ __forceinline__ void ldmx2(uint32_t* r, uint32_t addr) {
    asm volatile("ldmatrix.sync.aligned.m8n8.x2.shared.b16 {%0,%1}, [%2];"
                 : "=r"(r[0]), "=r"(r[1]) : "r"(addr));
}
__device__ __forceinline__ void mma_bf16(float* c, const uint32_t* a, const uint32_t* b) {
    asm volatile("mma.sync.aligned.m16n8k16.row.col.f32.bf16.bf16.f32 "
                 "{%0,%1,%2,%3}, {%4,%5,%6,%7}, {%8,%9}, {%0,%1,%2,%3};"
                 : "+f"(c[0]), "+f"(c[1]), "+f"(c[2]), "+f"(c[3])
                 : "r"(a[0]), "r"(a[1]), "r"(a[2]), "r"(a[3]), "r"(b[0]), "r"(b[1]));
}
__device__ __forceinline__ void split2(float v, __nv_bfloat16& h, __nv_bfloat16& l) {
    h = __float2bfloat16(v);
    l = __float2bfloat16(v - __bfloat162float(h));
}

// ---------------- elementwise helpers ----------------
__global__ void init_max_kernel(int* gm) { *gm = INT_MIN; }

__global__ void reduce_max_kernel(const int* __restrict__ p, int* gm) {
    int v = INT_MIN;
    for (int k = blockIdx.x * blockDim.x + threadIdx.x; k < NQ; k += gridDim.x * blockDim.x)
        v = max(v, p[k]);
    #pragma unroll
    for (int o = 16; o > 0; o >>= 1) v = max(v, __shfl_xor_sync(0xffffffffu, v, o));
    __shared__ int sm[8];
    int w = threadIdx.x >> 5;
    if ((threadIdx.x & 31) == 0) sm[w] = v;
    __syncthreads();
    if (threadIdx.x == 0) {
        int bv = sm[0];
        for (int i = 1; i < (int)(blockDim.x >> 5); i++) bv = max(bv, sm[i]);
        atomicMax(gm, bv);
    }
}

__global__ void write_mask_kernel(const int* __restrict__ p, const int* __restrict__ gm,
                                  float* __restrict__ out) {
    int i = blockIdx.x * blockDim.x + threadIdx.x;
    if (i < NQ) out[i] = (p[i] < *gm) ? 1.0f : 0.0f;
}

__global__ void split_kernel(const float* __restrict__ X, __nv_bfloat16* __restrict__ hi,
                             __nv_bfloat16* __restrict__ lo, int n)
{
    int i = blockIdx.x * blockDim.x + threadIdx.x;
    if (i < n) split2(X[i], hi[i], lo[i]);
}

__global__ void add_split_kernel(const float* __restrict__ A, const float* __restrict__ B,
                                 __nv_bfloat16* __restrict__ hi, __nv_bfloat16* __restrict__ lo, int n)
{
    int i = blockIdx.x * blockDim.x + threadIdx.x;
    if (i < n) split2(A[i] + B[i], hi[i], lo[i]);
}

// pack encoder weight W [128][N] (k-major) -> hi/lo [N][128]
__global__ void packw_kernel(const float* __restrict__ W, __nv_bfloat16* __restrict__ hi,
                             __nv_bfloat16* __restrict__ lo, int N)
{
    int i = blockIdx.x * blockDim.x + threadIdx.x;
    if (i >= N * 128) return;
    int k = i & 127, n = i >> 7;
    split2(W[(size_t)k * N + n], hi[i], lo[i]);
}

__global__ void packbias_kernel(const float* __restrict__ boff, const float* __restrict__ battn,
                                float* __restrict__ dst)
{
    int i = threadIdx.x + blockIdx.x * blockDim.x;
    if (i < 768) dst[i] = (i < 512) ? boff[i] : battn[i - 512];
}

__global__ void packcw_kernel(const float* __restrict__ W, __nv_bfloat16* __restrict__ hi,
                              __nv_bfloat16* __restrict__ lo, int CO, int CI, int CIN_CH, int total)
{
    int i = blockIdx.x * blockDim.x + threadIdx.x;
    if (i >= total) return;
    int k = i & 63, co = (i >> 6) & 63, c = i >> 12;
    int e = c / CIN_CH, cih = c % CIN_CH;
    int ci = cih * 64 + k;
    float v = (co < CO && ci < CI) ? W[(((size_t)co * CI + ci) * 3 + e / 3) * 3 + e % 3] : 0.f;
    split2(v, hi[i], lo[i]);
}

// ---------------- generic bf16x3 GEMM: C[M,N] = A[M,128] * B[N,128]^T ----------------
// FLAGS: 1 relu, 2 residual, 4 write fp32 C, 8 write split C, 16 write fp16 C
constexpr int GROWB = 272;
constexpr int GTILE = 128 * GROWB;
constexpr int GEMM_SMEM = 4 * GTILE;

template<int FLAGS>
__global__ void __launch_bounds__(256, 1) gemm_mma(
    const __nv_bfloat16* __restrict__ Ah, const __nv_bfloat16* __restrict__ Al,
    const __nv_bfloat16* __restrict__ Bh, const __nv_bfloat16* __restrict__ Bl,
    const float* __restrict__ bias, const float* __restrict__ R,
    float* __restrict__ Cf, __nv_bfloat16* __restrict__ Ch, __nv_bfloat16* __restrict__ Cl,
    __half* __restrict__ Cx, int M, int N)
{
    extern __shared__ char smem[];
    const int tid = threadIdx.x;
    const int wid = tid >> 5, lane = tid & 31;
    const int warp_m = wid >> 2, warp_n = wid & 3;
    const uint32_t sb = smem_u32(smem);
    const int bm = blockIdx.x * 128, bn = blockIdx.y * 128;

    {
        const int lrow = tid >> 1, lhalf = tid & 1;
        const bool aval = (bm + lrow) < M;
        const uint32_t sa = sb + (uint32_t)lrow * GROWB + (uint32_t)lhalf * 128;
        const char* agh = (const char*)(Ah + (size_t)(aval ? (bm + lrow) : 0) * 128 + lhalf * 64);
        const char* agl = (const char*)(Al + (size_t)(aval ? (bm + lrow) : 0) * 128 + lhalf * 64);
        const char* bgh = (const char*)(Bh + (size_t)(bn + lrow) * 128 + lhalf * 64);
        const char* bgl = (const char*)(Bl + (size_t)(bn + lrow) * 128 + lhalf * 64);
        #pragma unroll
        for (int i = 0; i < 8; i++) {
            cpasync16(sa + i * 16,             agh + i * 16, aval);
            cpasync16(sa + GTILE + i * 16,     agl + i * 16, aval);
            cpasync16(sa + 2 * GTILE + i * 16, bgh + i * 16, true);
            cpasync16(sa + 3 * GTILE + i * 16, bgl + i * 16, true);
        }
        cp_commit();
        cp_wait0();
        __syncthreads();
    }

    float acc[4][4][4];
    #pragma unroll
    for (int mt = 0; mt < 4; mt++)
        #pragma unroll
        for (int nt = 0; nt < 4; nt++)
            #pragma unroll
            for (int d = 0; d < 4; d++) acc[mt][nt][d] = 0.f;

    const uint32_t a_base = sb + (uint32_t)(warp_m * 64 + (lane & 15)) * GROWB + (uint32_t)(lane >> 4) * 16;
    const uint32_t b_base = sb + 2 * GTILE + (uint32_t)(warp_n * 32 + (lane & 7)) * GROWB
                          + (uint32_t)((lane >> 3) & 1) * 16;

    #pragma unroll
    for (int ks = 0; ks < 8; ks++) {
        const uint32_t kbyte = (uint32_t)ks * 32;
        uint32_t bh[4][2], bl[4][2];
        #pragma unroll
        for (int nt = 0; nt < 4; nt++) {
            ldmx2(bh[nt], b_base + (uint32_t)nt * 8 * GROWB + kbyte);
            ldmx2(bl[nt], b_base + GTILE + (uint32_t)nt * 8 * GROWB + kbyte);
        }
        #pragma unroll
        for (int mt = 0; mt < 4; mt++) {
            uint32_t ah[4], al[4];
            ldmx4(ah, a_base + (uint32_t)mt * 16 * GROWB + kbyte);
            ldmx4(al, a_base + GTILE + (uint32_t)mt * 16 * GROWB + kbyte);
            #pragma unroll
            for (int nt = 0; nt < 4; nt++) {
                mma_bf16(acc[mt][nt], ah, bh[nt]);
                mma_bf16(acc[mt][nt], ah, bl[nt]);
                mma_bf16(acc[mt][nt], al, bh[nt]);
            }
        }
    }

    const int g = lane >> 2, tg = lane & 3;
    #pragma unroll
    for (int mt = 0; mt < 4; mt++) {
        const int r0 = bm + warp_m * 64 + mt * 16 + g;
        #pragma unroll
        for (int nt = 0; nt < 4; nt++) {
            const int col = bn + warp_n * 32 + nt * 8 + tg * 2;
            float2 bb = *(const float2*)&bias[col];
            float v[4] = {acc[mt][nt][0] + bb.x, acc[mt][nt][1] + bb.y,
                          acc[mt][nt][2] + bb.x, acc[mt][nt][3] + bb.y};
            #pragma unroll
            for (int half = 0; half < 2; half++) {
                const int r = r0 + half * 8;
                if (r >= M) continue;
                float a0 = v[half * 2], a1 = v[half * 2 + 1];
                if (FLAGS & 2) {
                    float2 rr = *(const float2*)&R[(size_t)r * N + col];
                    a0 += rr.x; a1 += rr.y;
                }
                if (FLAGS & 1) { a0 = fmaxf(a0, 0.f); a1 = fmaxf(a1, 0.f); }
                if (FLAGS & 4)
                    *(float2*)&Cf[(size_t)r * N + col] = make_float2(a0, a1);
                if (FLAGS & 8) {
                    __nv_bfloat16 h0, l0, h1, l1;
                    split2(a0, h0, l0); split2(a1, h1, l1);
                    *(__nv_bfloat162*)&Ch[(size_t)r * N + col] = __nv_bfloat162(h0, h1);
                    *(__nv_bfloat162*)&Cl[(size_t)r * N + col] = __nv_bfloat162(l0, l1);
                }
                if (FLAGS & 16)
                    *(__half2*)&Cx[(size_t)r * N + col] = __floats2half2_rn(a0, a1);
            }
        }
    }
}

// ---------------- deformable attention sampling (fp16 V, fused softmax) ----------------
__global__ void __launch_bounds__(256) deform_kernel(
    const __half* __restrict__ VX, const float* __restrict__ OA,
    __nv_bfloat16* __restrict__ OH, __nv_bfloat16* __restrict__ OL)
{
    int t = blockIdx.x * 256 + threadIdx.x;
    if (t >= NQ * HEADS) return;
    const int n = t >> 3, h = t & 7;
    const float rx = ((float)(n % 200) + 0.5f) * (1.f / 200.f);
    const float ry = ((float)(n / 200) + 0.5f) * (1.f / 200.f);
    const float* op = OA + (size_t)n * 768 + h * 64;
    const float* ap = OA + (size_t)n * 768 + 512 + h * 32;

    // in-register softmax over the 32 logits
    float e[32];
    {
        float m = -1e30f;
        #pragma unroll
        for (int k = 0; k < 32; k++) { e[k] = ap[k]; m = fmaxf(m, e[k]); }
        float s = 0.f;
        #pragma unroll
        for (int k = 0; k < 32; k++) { e[k] = expf(e[k] - m); s += e[k]; }
        float inv = 1.f / s;
        #pragma unroll
        for (int k = 0; k < 32; k++) e[k] *= inv;
    }

    float acc[16];
    #pragma unroll
    for (int d = 0; d < 16; d++) acc[d] = 0.f;

    const int stc[4] = {0, 32768, 40960, 43008};
    const int Wc[4]  = {256, 128, 64, 32};
    const int Hc[4]  = {128, 64, 32, 16};

    #pragma unroll
    for (int l = 0; l < 4; l++) {
        const int W = Wc[l], H = Hc[l], st = stc[l];
        const float Wf = (float)W, Hf = (float)H;
        for (int p = 0; p < 8; p++) {
            float ox = op[(l * 8 + p) * 2 + 0];
            float oy = op[(l * 8 + p) * 2 + 1];
            float aw = e[l * 8 + p];
            float x = (rx + ox / Wf) * Wf - 0.5f;
            float y = (ry + oy / Hf) * Hf - 0.5f;
            float xf = floorf(x), yf = floorf(y);
            int x0 = (int)xf, y0 = (int)yf;
            float fx = x - xf, fy = y - yf;
            float wx[2] = {1.f - fx, fx};
            float wy[2] = {1.f - fy, fy};
            #pragma unroll
            for (int c = 0; c < 4; c++) {
                int xi = x0 + (c & 1), yi = y0 + (c >> 1);
                float wgt = wx[c & 1] * wy[c >> 1];
                if (xi >= 0 && xi < W && yi >= 0 && yi < H && wgt != 0.f) {
                    const __half2* gp = (const __half2*)(VX + ((size_t)(st + yi * W + xi)) * 128 + h * 16);
                    float cw = aw * wgt;
                    #pragma unroll
                    for (int d = 0; d < 8; d++) {
                        float2 g2 = __half22float2(gp[d]);
                        acc[d * 2 + 0] += cw * g2.x;
                        acc[d * 2 + 1] += cw * g2.y;
                    }
                }
            }
        }
    }
    __nv_bfloat162* oh = (__nv_bfloat162*)(OH + (size_t)n * 128 + h * 16);
    __nv_bfloat162* ol = (__nv_bfloat162*)(OL + (size_t)n * 128 + h * 16);
    #pragma unroll
    for (int d = 0; d < 8; d++) {
        __nv_bfloat16 h0, l0, h1, l1;
        split2(acc[d * 2], h0, l0); split2(acc[d * 2 + 1], h1, l1);
        oh[d] = __nv_bfloat162(h0, h1);
        ol[d] = __nv_bfloat162(l0, l1);
    }
}

// ---------------- layernorm over 128 per row ----------------
// MODE: 0 = fp32 only, 1 = + split(y), 2 = + split(y + pos)
template<int MODE>
__global__ void ln_kernel(const float* __restrict__ X, const float* __restrict__ g,
                          const float* __restrict__ b, float* __restrict__ Y,
                          __nv_bfloat16* __restrict__ Yh, __nv_bfloat16* __restrict__ Yl,
                          const float* __restrict__ pos)
{
    int r = blockIdx.x;
    int t = threadIdx.x;
    float x = X[(size_t)r * 128 + t];
    float s = x;
    #pragma unroll
    for (int o = 16; o > 0; o >>= 1) s += __shfl_xor_sync(0xffffffffu, s, o);
    __shared__ float sm[4], sm2[4];
    int w = t >> 5, lane = t & 31;
    if (lane == 0) sm[w] = s;
    __syncthreads();
    float m = (sm[0] + sm[1] + sm[2] + sm[3]) * (1.f / 128.f);
    float d = x - m;
    float q = d * d;
    #pragma unroll
    for (int o = 16; o > 0; o >>= 1) q += __shfl_xor_sync(0xffffffffu, q, o);
    if (lane == 0) sm2[w] = q;
    __syncthreads();
    float var = (sm2[0] + sm2[1] + sm2[2] + sm2[3]) * (1.f / 128.f);
    float y = d * rsqrtf(var + 1e-5f) * g[t] + b[t];
    Y[(size_t)r * 128 + t] = y;
    if (MODE >= 1) {
        float z = (MODE == 2) ? (y + pos[(size_t)r * 128 + t]) : y;
        __nv_bfloat16 hh, ll;
        split2(z, hh, ll);
        Yh[(size_t)r * 128 + t] = hh;
        Yl[(size_t)r * 128 + t] = ll;
    }
}

// ---------------- conv1 weight split ----------------
__global__ void wsplit_kernel(const float* __restrict__ W, __nv_bfloat16* __restrict__ hi,
                              __nv_bfloat16* __restrict__ lo)
{
    int i = blockIdx.x * blockDim.x + threadIdx.x;
    if (i >= W1CHUNKS * 128 * 64) return;
    int k  = i & 63;
    int co = (i >> 6) & 127;
    int c  = i >> 13;
    int e = c >> 1, ci = ((c & 1) << 6) + k;
    int ky = e / 7, kx = e % 7;
    split2(W[(((size_t)co * 128 + ci) * 7 + ky) * 7 + kx], hi[i], lo[i]);
}

// ---------------- conv1 (7x7, 128->128) via mma.sync bf16x3 ----------------
constexpr int ROWB = 144;
constexpr int TILE_B = 128 * ROWB;
constexpr int BUF_B = 4 * TILE_B;
constexpr int CONV1_SMEM = 2 * BUF_B;

__global__ void __launch_bounds__(256, 1) conv1_mma_kernel(
    const __nv_bfloat16* __restrict__ qhi, const __nv_bfloat16* __restrict__ qlo,
    const __nv_bfloat16* __restrict__ whi, const __nv_bfloat16* __restrict__ wlo,
    float* __restrict__ Out)
{
    extern __shared__ char smem[];
    const int tid = threadIdx.x;
    const int wid = tid >> 5, lane = tid & 31;
    const int warp_m = wid >> 2, warp_n = wid & 3;
    const uint32_t sb = smem_u32(smem);
    const int bm = blockIdx.x * 128;

    const int lrow = tid >> 1, lhalf = tid & 1;
    const int pm = bm + lrow;
    const int py = pm / 200, px = pm % 200;
    const bool prow_ok = pm < NQ;
    const uint32_t s_arow = sb + (uint32_t)lrow * ROWB + (uint32_t)lhalf * 64;
    const uint32_t s_brow = s_arow + 2 * TILE_B;

    const uint32_t a_base = sb + (uint32_t)(warp_m * 64 + (lane & 15)) * ROWB + (uint32_t)(lane >> 4) * 16;
    const uint32_t b_base = sb + 2 * TILE_B + (uint32_t)(warp_n * 32 + (lane & 7)) * ROWB
                          + (uint32_t)((lane >> 3) & 1) * 16;

    float acc[4][4][4];
    #pragma unroll
    for (int mt = 0; mt < 4; mt++)
        #pragma unroll
        for (int nt = 0; nt < 4; nt++)
            #pragma unroll
            for (int d = 0; d < 4; d++) acc[mt][nt][d] = 0.f;

    auto load_chunk = [&](int c, int buf) {
        const int e = c >> 1, ch = c & 1;
        const int qy = py + e / 7 - 3;
        const int qx = px + e % 7 - 3;
        const bool val = prow_ok && qy >= 0 && qy < 200 && qx >= 0 && qx < 200;
        const size_t aoff = (size_t)(val ? (qy * 200 + qx) : 0) * 128 + (size_t)ch * 64 + (size_t)lhalf * 32;
        const char* agh = (const char*)(qhi + aoff);
        const char* agl = (const char*)(qlo + aoff);
        const size_t boff = ((size_t)c * 128 + lrow) * 64 + (size_t)lhalf * 32;
        const char* bgh = (const char*)(whi + boff);
        const char* bgl = (const char*)(wlo + boff);
        const uint32_t sa = s_arow + (uint32_t)buf * BUF_B;
        const uint32_t sbr = s_brow + (uint32_t)buf * BUF_B;
        #pragma unroll
        for (int i = 0; i < 4; i++) {
            cpasync16(sa + i * 16,          agh + i * 16, val);
            cpasync16(sa + TILE_B + i * 16, agl + i * 16, val);
            cpasync16(sbr + i * 16,          bgh + i * 16, true);
            cpasync16(sbr + TILE_B + i * 16, bgl + i * 16, true);
        }
    };

    load_chunk(0, 0); cp_commit();
    load_chunk(1, 1); cp_commit();

    for (int c = 0; c < W1CHUNKS; c++) {
        const int buf = c & 1;
        cp_wait1();
        __syncthreads();

        const uint32_t ab = a_base + (uint32_t)buf * BUF_B;
        const uint32_t bb = b_base + (uint32_t)buf * BUF_B;
        #pragma unroll
        for (int ks = 0; ks < 4; ks++) {
            const uint32_t kbyte = (uint32_t)ks * 32;
            uint32_t bh[4][2], bl[4][2];
            #pragma unroll
            for (int nt = 0; nt < 4; nt++) {
                ldmx2(bh[nt], bb + (uint32_t)nt * 8 * ROWB + kbyte);
                ldmx2(bl[nt], bb + TILE_B + (uint32_t)nt * 8 * ROWB + kbyte);
            }
            #pragma unroll
            for (int mt = 0; mt < 4; mt++) {
                uint32_t ah[4], al[4];
                ldmx4(ah, ab + (uint32_t)mt * 16 * ROWB + kbyte);
                ldmx4(al, ab + TILE_B + (uint32_t)mt * 16 * ROWB + kbyte);
                #pragma unroll
                for (int nt = 0; nt < 4; nt++) {
                    mma_bf16(acc[mt][nt], ah, bh[nt]);
                    mma_bf16(acc[mt][nt], ah, bl[nt]);
                    mma_bf16(acc[mt][nt], al, bh[nt]);
                }
            }
        }
        __syncthreads();
        if (c + 2 < W1CHUNKS) load_chunk(c + 2, buf);
        cp_commit();
    }

    const int g = lane >> 2, tg = lane & 3;
    #pragma unroll
    for (int mt = 0; mt < 4; mt++) {
        const int r0 = bm + warp_m * 64 + mt * 16 + g;
        #pragma unroll
        for (int nt = 0; nt < 4; nt++) {
            const int col = warp_n * 32 + nt * 8 + tg * 2;
            if (r0 < NQ)
                *(float2*)&Out[(size_t)r0 * 128 + col] = make_float2(acc[mt][nt][0], acc[mt][nt][1]);
            if (r0 + 8 < NQ)
                *(float2*)&Out[(size_t)(r0 + 8) * 128 + col] = make_float2(acc[mt][nt][2], acc[mt][nt][3]);
        }
    }
}

// ---------------- convs 2-4 (3x3) via mma.sync bf16x3, 128x64 tile ----------------
constexpr int CATILE = 128 * ROWB;
constexpr int CBTILE = 64 * ROWB;
constexpr int CBUF = 2 * CATILE + 2 * CBTILE;
constexpr int CONV_SMEM = 2 * CBUF;

template<int CHUNKS, int CIN_CH, int CST>
__global__ void __launch_bounds__(256, 2) conv_mma_kernel(
    const __nv_bfloat16* __restrict__ inh, const __nv_bfloat16* __restrict__ inl,
    const __nv_bfloat16* __restrict__ wh, const __nv_bfloat16* __restrict__ wl,
    float* __restrict__ Out, int COUT)
{
    extern __shared__ char smem[];
    const int tid = threadIdx.x;
    const int wid = tid >> 5, lane = tid & 31;
    const int warp_m = wid >> 1, warp_n = wid & 1;
    const uint32_t sb = smem_u32(smem);
    const int bm = blockIdx.x * 128;

    const int lrow = tid >> 1, lhalf = tid & 1;
    const int pm = bm + lrow;
    const int py = pm / 200, px = pm % 200;
    const bool prow_ok = pm < NQ;
    const uint32_t s_arow = sb + (uint32_t)lrow * ROWB + (uint32_t)lhalf * 64;
    const int brow = tid >> 2, bq = tid & 3;
    const uint32_t s_brow = sb + 2 * CATILE + (uint32_t)brow * ROWB + (uint32_t)bq * 32;

    const uint32_t a_base = sb + (uint32_t)(warp_m * 32 + (lane & 15)) * ROWB + (uint32_t)(lane >> 4) * 16;
    const uint32_t b_base = sb + 2 * CATILE + (uint32_t)(warp_n * 32 + (lane & 7)) * ROWB
                          + (uint32_t)((lane >> 3) & 1) * 16;

    float acc[2][4][4];
    #pragma unroll
    for (int mt = 0; mt < 2; mt++)
        #pragma unroll
        for (int nt = 0; nt < 4; nt++)
            #pragma unroll
            for (int d = 0; d < 4; d++) acc[mt][nt][d] = 0.f;

    auto load_chunk = [&](int c, int buf) {
        const int e = c / CIN_CH, cih = c % CIN_CH;
        const int qy = py + e / 3 - 1;
        const int qx = px + e % 3 - 1;
        const bool val = prow_ok && qy >= 0 && qy < 200 && qx >= 0 && qx < 200;
        const size_t aoff = (size_t)(val ? (qy * 200 + qx) : 0) * CST + (size_t)cih * 64 + (size_t)lhalf * 32;
        const char* agh = (const char*)(inh + aoff);
        const char* agl = (const char*)(inl + aoff);
        const size_t boff = ((size_t)c * 64 + brow) * 64 + (size_t)bq * 16;
        const char* bgh = (const char*)(wh + boff);
        const char* bgl = (const char*)(wl + boff);
        const uint32_t sa = s_arow + (uint32_t)buf * CBUF;
        const uint32_t sbr = s_brow + (uint32_t)buf * CBUF;
        #pragma unroll
        for (int i = 0; i < 4; i++) {
            cpasync16(sa + i * 16,           agh + i * 16, val);
            cpasync16(sa + CATILE + i * 16,  agl + i * 16, val);
        }
        #pragma unroll
        for (int i = 0; i < 2; i++) {
            cpasync16(sbr + i * 16,          bgh + i * 16, true);
            cpasync16(sbr + CBTILE + i * 16, bgl + i * 16, true);
        }
    };

    load_chunk(0, 0); cp_commit();
    load_chunk(1, 1); cp_commit();

    for (int c = 0; c < CHUNKS; c++) {
        const int buf = c & 1;
        cp_wait1();
        __syncthreads();

        const uint32_t ab = a_base + (uint32_t)buf * CBUF;
        const uint32_t bb = b_base + (uint32_t)buf * CBUF;
        #pragma unroll
        for (int ks = 0; ks < 4; ks++) {
            const uint32_t kbyte = (uint32_t)ks * 32;
            uint32_t bh[4][2], bl[4][2];
            #pragma unroll
            for (int nt = 0; nt < 4; nt++) {
                ldmx2(bh[nt], bb + (uint32_t)nt * 8 * ROWB + kbyte);
                ldmx2(bl[nt], bb + CBTILE + (uint32_t)nt * 8 * ROWB + kbyte);
            }
            #pragma unroll
            for (int mt = 0; mt < 2; mt++) {
                uint32_t ah[4], al[4];
                ldmx4(ah, ab + (uint32_t)mt * 16 * ROWB + kbyte);
                ldmx4(al, ab + CATILE + (uint32_t)mt * 16 * ROWB + kbyte);
                #pragma unroll
                for (int nt = 0; nt < 4; nt++) {
                    mma_bf16(acc[mt][nt], ah, bh[nt]);
                    mma_bf16(acc[mt][nt], ah, bl[nt]);
                    mma_bf16(acc[mt][nt], al, bh[nt]);
                }
            }
        }
        __syncthreads();
        if (c + 2 < CHUNKS) load_chunk(c + 2, buf);
        cp_commit();
    }

    const int g = lane >> 2, tg = lane & 3;
    #pragma unroll
    for (int mt = 0; mt < 2; mt++) {
        const int r0 = bm + warp_m * 32 + mt * 16 + g;
        #pragma unroll
        for (int nt = 0; nt < 4; nt++) {
            const int col = warp_n * 32 + nt * 8 + tg * 2;
            if (col >= COUT) continue;
            if (r0 < NQ)
                *(float2*)&Out[(size_t)r0 * COUT + col] = make_float2(acc[mt][nt][0], acc[mt][nt][1]);
            if (r0 + 8 < NQ)
                *(float2*)&Out[(size_t)(r0 + 8) * COUT + col] = make_float2(acc[mt][nt][2], acc[mt][nt][3]);
        }
    }
}

// ---------------- batchnorm ----------------
__global__ void bn_stats_kernel(const float* __restrict__ X, float* __restrict__ part, int C)
{
    int c = threadIdx.x;
    int g = blockIdx.x;
    const int per = (NQ + 63) / 64;
    int p0 = g * per;
    int p1 = min(NQ, p0 + per);
    float s = 0.f, q = 0.f;
    for (int p = p0; p < p1; p++) {
        float x = X[(size_t)p * C + c];
        s += x; q += x * x;
    }
    part[(size_t)g * 2 * C + c] = s;
    part[(size_t)g * 2 * C + C + c] = q;
}

__global__ void bn_finalize_kernel(const float* __restrict__ part,
                                   const float* __restrict__ gamma, const float* __restrict__ beta,
                                   float* __restrict__ scale, float* __restrict__ shift, int C)
{
    int c = threadIdx.x;
    float s = 0.f, q = 0.f;
    for (int g = 0; g < 64; g++) {
        s += part[(size_t)g * 2 * C + c];
        q += part[(size_t)g * 2 * C + C + c];
    }
    const float invP = 1.f / (float)NQ;
    float m = s * invP;
    float v = q * invP - m * m;
    float sc = gamma[c] * rsqrtf(v + 1e-5f);
    scale[c] = sc;
    shift[c] = beta[c] - m * sc;
}

__global__ void bn_apply_split_kernel(const float* __restrict__ X, const float* __restrict__ scale,
                                      const float* __restrict__ shift,
                                      __nv_bfloat16* __restrict__ hi, __nv_bfloat16* __restrict__ lo,
                                      int C, int CST, int total)
{
    int i = blockIdx.x * blockDim.x + threadIdx.x;
    if (i >= total) return;
    int c = i % CST;
    int p = i / CST;
    float v = 0.f;
    if (c < C) v = fmaxf(0.f, fmaf(X[(size_t)p * C + c], scale[c], shift[c]));
    split2(v, hi[i], lo[i]);
}

// ---------------- head: fused BN4+ReLU + 1x1 conv 48 -> 21, output NCHW ----------------
__global__ void head_conv_kernel(const float* __restrict__ H4raw, const float* __restrict__ scale,
                                 const float* __restrict__ shift,
                                 const float* __restrict__ Wo, const float* __restrict__ bo,
                                 float* __restrict__ out)
{
    int p = blockIdx.x * blockDim.x + threadIdx.x;
    if (p >= NQ) return;
    float x[48];
    const float4* hp = (const float4*)(H4raw + (size_t)p * 48);
    #pragma unroll
    for (int i = 0; i < 12; i++) {
        float4 v = hp[i];
        x[i * 4 + 0] = v.x; x[i * 4 + 1] = v.y; x[i * 4 + 2] = v.z; x[i * 4 + 3] = v.w;
    }
    #pragma unroll
    for (int ci = 0; ci < 48; ci++)
        x[ci] = fmaxf(0.f, fmaf(x[ci], scale[ci], shift[ci]));
    for (int co = 0; co < 21; co++) {
        float s = bo[co];
        const float* w = Wo + co * 48;
        #pragma unroll
        for (int ci = 0; ci < 48; ci++) s = fmaf(x[ci], w[ci], s);
        out[(size_t)co * NQ + p] = s;
    }
}

// ---------------- launch ----------------
extern "C" void kernel_launch(void* const* d_in, const int* in_sizes, int n_in,
                              void* d_out, int out_size)
{
    const float* value = (const float*)d_in[0];
    const float* bq    = (const float*)d_in[1];
    const float* bpos  = (const float*)d_in[2];
    const int*   proj  = (const int*)d_in[3];
    const float* Wv    = (const float*)d_in[4];
    const float* bv    = (const float*)d_in[5];
    const float* Woff  = (const float*)d_in[6];
    const float* boff  = (const float*)d_in[7];
    const float* Wattn = (const float*)d_in[8];
    const float* battn = (const float*)d_in[9];
    const float* Wout  = (const float*)d_in[10];
    const float* bout  = (const float*)d_in[11];
    const float* Wf1   = (const float*)d_in[12];
    const float* bf1   = (const float*)d_in[13];
    const float* Wf2   = (const float*)d_in[14];
    const float* bf2   = (const float*)d_in[15];
    const float* lng   = (const float*)d_in[16];
    const float* lnb   = (const float*)d_in[17];
    const float* cw1   = (const float*)d_in[18];
    const float* g1    = (const float*)d_in[19];
    const float* b1    = (const float*)d_in[20];
    const float* cw2   = (const float*)d_in[21];
    const float* g2    = (const float*)d_in[22];
    const float* b2    = (const float*)d_in[23];
    const float* cw3   = (const float*)d_in[24];
    const float* g3    = (const float*)d_in[25];
    const float* b3    = (const float*)d_in[26];
    const float* cw4   = (const float*)d_in[27];
    const float* g4    = (const float*)d_in[28];
    const float* b4    = (const float*)d_in[29];
    const float* objw  = (const float*)d_in[30];
    const float* objb  = (const float*)d_in[31];
    float* out = (float*)d_out;

    float* S = nullptr;
    cudaGetSymbolAddress((void**)&S, g_scratch);
    int* gm = nullptr;
    cudaGetSymbolAddress((void**)&gm, g_maxv);
    __nv_bfloat16 *s1h, *s1l, *s2h, *s2l, *vh, *vl, *wph, *wpl, *whi, *wlo, *wch, *wcl;
    __half* vx;
    cudaGetSymbolAddress((void**)&s1h, g_s1h);
    cudaGetSymbolAddress((void**)&s1l, g_s1l);
    cudaGetSymbolAddress((void**)&s2h, g_s2h);
    cudaGetSymbolAddress((void**)&s2l, g_s2l);
    cudaGetSymbolAddress((void**)&vh,  g_vh);
    cudaGetSymbolAddress((void**)&vl,  g_vl);
    cudaGetSymbolAddress((void**)&vx,  g_vx);
    cudaGetSymbolAddress((void**)&wph, g_wph);
    cudaGetSymbolAddress((void**)&wpl, g_wpl);
    cudaGetSymbolAddress((void**)&whi, g_whi);
    cudaGetSymbolAddress((void**)&wlo, g_wlo);
    cudaGetSymbolAddress((void**)&wch, g_wch);
    cudaGetSymbolAddress((void**)&wcl, g_wcl);

    float* POA   = S + OFF_OA;
    float* PQ    = S + OFF_Q;
    float* PT1   = S + OFF_T1;
    float* PT2   = S + OFF_T2;
    float* PH1   = S + OFF_H1;
    float* PH2   = S + OFF_H2;
    float* PH3   = S + OFF_H3;
    float* PH4   = S + OFF_H4;
    float* PPART = S + OFF_PART;
    float* PSCALE= S + OFF_SCALE;
    float* PSHIFT= S + OFF_SHIFT;
    float* PBIAS = S + OFF_BIAS;

    cudaFuncSetAttribute(conv1_mma_kernel, cudaFuncAttributeMaxDynamicSharedMemorySize, CONV1_SMEM);
    cudaFuncSetAttribute(gemm_mma<4>,  cudaFuncAttributeMaxDynamicSharedMemorySize, GEMM_SMEM);
    cudaFuncSetAttribute(gemm_mma<6>,  cudaFuncAttributeMaxDynamicSharedMemorySize, GEMM_SMEM);
    cudaFuncSetAttribute(gemm_mma<9>,  cudaFuncAttributeMaxDynamicSharedMemorySize, GEMM_SMEM);
    cudaFuncSetAttribute(gemm_mma<16>, cudaFuncAttributeMaxDynamicSharedMemorySize, GEMM_SMEM);
    cudaFuncSetAttribute((conv_mma_kernel<18, 2, 128>), cudaFuncAttributeMaxDynamicSharedMemorySize, CONV_SMEM);
    cudaFuncSetAttribute((conv_mma_kernel<9, 1, 64>),   cudaFuncAttributeMaxDynamicSharedMemorySize, CONV_SMEM);

    // --- observed_masks ---
    init_max_kernel<<<1, 1>>>(gm);
    reduce_max_kernel<<<40, 256>>>(proj, gm);
    write_mask_kernel<<<(NQ + 255) / 256, 256>>>(proj, gm, out + 21 * NQ);

    // --- weight prep ---
    wsplit_kernel<<<(W1CHUNKS * 128 * 64 + 255) / 256, 256>>>(cw1, whi, wlo);
    packcw_kernel<<<(18 * 4096 + 255) / 256, 256>>>(cw2, wch + WC2_OFF, wcl + WC2_OFF, 64, 128, 2, 18 * 4096);
    packcw_kernel<<<(9 * 4096 + 255) / 256, 256>>>(cw3, wch + WC3_OFF, wcl + WC3_OFF, 48, 64, 1, 9 * 4096);
    packcw_kernel<<<(9 * 4096 + 255) / 256, 256>>>(cw4, wch + WC4_OFF, wcl + WC4_OFF, 48, 48, 1, 9 * 4096);
    for (int i = 0; i < 2; i++) {
        size_t LB = (size_t)i * 1280 * 128;
        packw_kernel<<<(128 * 128 + 255) / 256, 256>>>(Wv   + (size_t)i * 128 * 128, wph + LB,              wpl + LB,              128);
        packw_kernel<<<(512 * 128 + 255) / 256, 256>>>(Woff + (size_t)i * 128 * 512, wph + LB + 128 * 128,  wpl + LB + 128 * 128,  512);
        packw_kernel<<<(256 * 128 + 255) / 256, 256>>>(Wattn+ (size_t)i * 128 * 256, wph + LB + 640 * 128,  wpl + LB + 640 * 128,  256);
        packw_kernel<<<(128 * 128 + 255) / 256, 256>>>(Wout + (size_t)i * 128 * 128, wph + LB + 896 * 128,  wpl + LB + 896 * 128,  128);
        packw_kernel<<<(128 * 128 + 255) / 256, 256>>>(Wf1  + (size_t)i * 128 * 128, wph + LB + 1024 * 128, wpl + LB + 1024 * 128, 128);
        packw_kernel<<<(128 * 128 + 255) / 256, 256>>>(Wf2  + (size_t)i * 128 * 128, wph + LB + 1152 * 128, wpl + LB + 1152 * 128, 128);
        packbias_kernel<<<3, 256>>>(boff + i * 512, battn + i * 256, PBIAS + i * 768);
    }
    split_kernel<<<(NV * 128 + 255) / 256, 256>>>(value, vh, vl, NV * 128);

    // --- q init ---
    cudaMemcpyAsync(PQ, bq, (size_t)NQ * ED * sizeof(float), cudaMemcpyDeviceToDevice);

    // --- 2 encoder layers ---
    // layer 0 needs split(q + pos) up-front; layer 1 gets it fused into layer 0's final LN
    add_split_kernel<<<(NQ * ED + 255) / 256, 256>>>(PQ, bpos, s1h, s1l, NQ * ED);
    for (int i = 0; i < 2; i++) {
        size_t LB = (size_t)i * 1280 * 128;
        // V projection -> fp16 V for deform
        gemm_mma<16><<<dim3(340, 1), 256, GEMM_SMEM>>>(vh, vl, wph + LB, wpl + LB,
                                                       bv + i * 128, nullptr, nullptr, nullptr, nullptr, vx, NV, 128);
        // combined Woff+Wattn: N = 768 (attn logits, softmax fused in deform)
        gemm_mma<4><<<dim3(313, 6), 256, GEMM_SMEM>>>(s1h, s1l, wph + LB + 128 * 128, wpl + LB + 128 * 128,
                                                      PBIAS + i * 768, nullptr, POA, nullptr, nullptr, nullptr, NQ, 768);
        deform_kernel<<<(NQ * HEADS + 255) / 256, 256>>>(vx, POA, s2h, s2l);
        gemm_mma<6><<<dim3(313, 1), 256, GEMM_SMEM>>>(s2h, s2l, wph + LB + 896 * 128, wpl + LB + 896 * 128,
                                                      bout + i * 128, PQ, PT1, nullptr, nullptr, nullptr, NQ, 128);
        ln_kernel<1><<<NQ, 128>>>(PT1, lng + (i * 2 + 0) * 128, lnb + (i * 2 + 0) * 128, PQ, s1h, s1l, nullptr);
        gemm_mma<9><<<dim3(313, 1), 256, GEMM_SMEM>>>(s1h, s1l, wph + LB + 1024 * 128, wpl + LB + 1024 * 128,
                                                      bf1 + i * 128, nullptr, nullptr, s2h, s2l, nullptr, NQ, 128);
        gemm_mma<6><<<dim3(313, 1), 256, GEMM_SMEM>>>(s2h, s2l, wph + LB + 1152 * 128, wpl + LB + 1152 * 128,
                                                      bf2 + i * 128, PQ, PT2, nullptr, nullptr, nullptr, NQ, 128);
        if (i == 0)
            ln_kernel<2><<<NQ, 128>>>(PT2, lng + 1 * 128, lnb + 1 * 128, PQ, s1h, s1l, bpos);  // split(q+pos) for layer 1
        else
            ln_kernel<1><<<NQ, 128>>>(PT2, lng + 3 * 128, lnb + 3 * 128, PQ, s1h, s1l, nullptr); // split(q) for conv1
    }

    // --- conv head (all mma) ---
    conv1_mma_kernel<<<313, 256, CONV1_SMEM>>>(s1h, s1l, whi, wlo, PH1);
    bn_stats_kernel<<<64, 128>>>(PH1, PPART, 128);
    bn_finalize_kernel<<<1, 128>>>(PPART, g1, b1, PSCALE, PSHIFT, 128);
    bn_apply_split_kernel<<<(NQ * 128 + 255) / 256, 256>>>(PH1, PSCALE, PSHIFT, s1h, s1l, 128, 128, NQ * 128);

    conv_mma_kernel<18, 2, 128><<<313, 256, CONV_SMEM>>>(s1h, s1l, wch + WC2_OFF, wcl + WC2_OFF, PH2, 64);
    bn_stats_kernel<<<64, 64>>>(PH2, PPART, 64);
    bn_finalize_kernel<<<1, 64>>>(PPART, g2, b2, PSCALE, PSHIFT, 64);
    bn_apply_split_kernel<<<(NQ * 64 + 255) / 256, 256>>>(PH2, PSCALE, PSHIFT, s2h, s2l, 64, 64, NQ * 64);

    conv_mma_kernel<9, 1, 64><<<313, 256, CONV_SMEM>>>(s2h, s2l, wch + WC3_OFF, wcl + WC3_OFF, PH3, 48);
    bn_stats_kernel<<<64, 48>>>(PH3, PPART, 48);
    bn_finalize_kernel<<<1, 48>>>(PPART, g3, b3, PSCALE, PSHIFT, 48);
    bn_apply_split_kernel<<<(NQ * 64 + 255) / 256, 256>>>(PH3, PSCALE, PSHIFT, s1h, s1l, 48, 64, NQ * 64);

    conv_mma_kernel<9, 1, 64><<<313, 256, CONV_SMEM>>>(s1h, s1l, wch + WC4_OFF, wcl + WC4_OFF, PH4, 48);
    bn_stats_kernel<<<64, 48>>>(PH4, PPART, 48);
    bn_finalize_kernel<<<1, 48>>>(PPART, g4, b4, PSCALE, PSHIFT, 48);
    head_conv_kernel<<<(NQ + 255) / 256, 256>>>(PH4, PSCALE, PSHIFT, objw, objb, out);
}

// round 7
// speedup vs baseline: 2.3210x; 1.4490x over previous
#include <cuda_runtime.h>
#include <cuda_bf16.h>
#include <cuda_fp16.h>
#include <cstdint>
#include <climits>

// ---------------- problem constants ----------------
constexpr int NQ = 40000;        // 200*200
constexpr int ED = 128;
constexpr int NV = 43520;        // sum of level sizes
constexpr int HEADS = 8;

// ---------------- scratch layout (floats) ----------------
constexpr size_t OFF_OA   = 0;                     // combined offsets+attn, NQ x 768
constexpr size_t SZ_OA    = (size_t)NQ * 768;
constexpr size_t OFF_Q    = OFF_OA + SZ_OA;
constexpr size_t SZ_Q     = (size_t)NQ * ED;
constexpr size_t OFF_T1   = OFF_Q + SZ_Q;
constexpr size_t OFF_T2   = OFF_T1 + SZ_Q;
constexpr size_t OFF_H1   = OFF_T2 + SZ_Q;
constexpr size_t SZ_H1    = (size_t)NQ * 128;
constexpr size_t OFF_H2   = OFF_H1 + SZ_H1;
constexpr size_t SZ_H2    = (size_t)NQ * 64;
constexpr size_t OFF_H3   = OFF_H2 + SZ_H2;
constexpr size_t SZ_H3    = (size_t)NQ * 48;
constexpr size_t OFF_H4   = OFF_H3 + SZ_H3;
constexpr size_t OFF_PART = OFF_H4 + SZ_H3;
constexpr size_t SZ_PART  = 64 * 128 * 2;
constexpr size_t OFF_SCALE= OFF_PART + SZ_PART;
constexpr size_t OFF_SHIFT= OFF_SCALE + 128;
constexpr size_t OFF_BIAS = OFF_SHIFT + 128;       // 2 layers x 768 packed bias
constexpr size_t SCRATCH_TOTAL = OFF_BIAS + 2 * 768;

__device__ float g_scratch[SCRATCH_TOTAL];
__device__ int   g_maxv;

// ---------------- bf16 / fp16 buffers ----------------
constexpr int W1CHUNKS = 98;                 // conv1: 49 taps * 2 ci-halves
__device__ __align__(16) __nv_bfloat16 g_s1h[(size_t)NQ * 128];
__device__ __align__(16) __nv_bfloat16 g_s1l[(size_t)NQ * 128];
__device__ __align__(16) __nv_bfloat16 g_s2h[(size_t)NQ * 128];
__device__ __align__(16) __nv_bfloat16 g_s2l[(size_t)NQ * 128];
__device__ __align__(16) __half        g_vx[(size_t)NV * 128];   // fp16 V for deform
__device__ __align__(16) __nv_bfloat16 g_vh[(size_t)NV * 128];
__device__ __align__(16) __nv_bfloat16 g_vl[(size_t)NV * 128];
__device__ __align__(16) __half        g_q16[(size_t)NQ * 128];  // fp16 q for conv1
// packed encoder weights: per layer 1280 cols x 128 k  ([n][k])
__device__ __align__(16) __nv_bfloat16 g_wph[(size_t)2 * 1280 * 128];
__device__ __align__(16) __nv_bfloat16 g_wpl[(size_t)2 * 1280 * 128];
// conv1 weights [chunk][co 128][k 64] fp16
__device__ __align__(16) __half g_w16[(size_t)W1CHUNKS * 128 * 64];
// convs 2-4 weights
constexpr int WC2_OFF = 0, WC3_OFF = 73728, WC4_OFF = 110592, WC_TOTAL = 147456;
__device__ __align__(16) __nv_bfloat16 g_wch[WC_TOTAL];
__device__ __align__(16) __nv_bfloat16 g_wcl[WC_TOTAL];

// ---------------- small helpers ----------------
__device__ __forceinline__ uint32_t smem_u32(const void* p) {
    return (uint32_t)__cvta_generic_to_shared(p);
}
__device__ __forceinline__ void cpasync16(uint32_t dst, const void* src, bool valid) {
    asm volatile("cp.async.cg.shared.global [%0], [%1], 16, %2;"
                 :: "r"(dst), "l"(src), "r"(valid ? 16u : 0u));
}
__device__ __forceinline__ void cp_commit() { asm volatile("cp.async.commit_group;"); }
__device__ __forceinline__ void cp_wait1()  { asm volatile("cp.async.wait_group 1;"); }
__device__ __forceinline__ void cp_wait0()  { asm volatile("cp.async.wait_group 0;"); }

__device__ __forceinline__ void ldmx4(uint32_t* r, uint32_t addr) {
    asm volatile("ldmatrix.sync.aligned.m8n8.x4.shared.b16 {%0,%1,%2,%3}, [%4];"
                 : "=r"(r[0]), "=r"(r[1]), "=r"(r[2]), "=r"(r[3]) : "r"(addr));
}
__device__ __forceinline__ void ldmx2(uint32_t* r, uint32_t addr) {
    asm volatile("ldmatrix.sync.aligned.m8n8.x2.shared.b16 {%0,%1}, [%2];"
                 : "=r"(r[0]), "=r"(r[1]) : "r"(addr));
}
__device__ __forceinline__ void mma_bf16(float* c, const uint32_t* a, const uint32_t* b) {
    asm volatile("mma.sync.aligned.m16n8k16.row.col.f32.bf16.bf16.f32 "
                 "{%0,%1,%2,%3}, {%4,%5,%6,%7}, {%8,%9}, {%0,%1,%2,%3};"
                 : "+f"(c[0]), "+f"(c[1]), "+f"(c[2]), "+f"(c[3])
                 : "r"(a[0]), "r"(a[1]), "r"(a[2]), "r"(a[3]), "r"(b[0]), "r"(b[1]));
}
__device__ __forceinline__ void mma_f16(float* c, const uint32_t* a, const uint32_t* b) {
    asm volatile("mma.sync.aligned.m16n8k16.row.col.f32.f16.f16.f32 "
                 "{%0,%1,%2,%3}, {%4,%5,%6,%7}, {%8,%9}, {%0,%1,%2,%3};"
                 : "+f"(c[0]), "+f"(c[1]), "+f"(c[2]), "+f"(c[3])
                 : "r"(a[0]), "r"(a[1]), "r"(a[2]), "r"(a[3]), "r"(b[0]), "r"(b[1]));
}
__device__ __forceinline__ void split2(float v, __nv_bfloat16& h, __nv_bfloat16& l) {
    h = __float2bfloat16(v);
    l = __float2bfloat16(v - __bfloat162float(h));
}

// ---------------- elementwise helpers ----------------
__global__ void init_max_kernel(int* gm) { *gm = INT_MIN; }

__global__ void reduce_max_kernel(const int* __restrict__ p, int* gm) {
    int v = INT_MIN;
    for (int k = blockIdx.x * blockDim.x + threadIdx.x; k < NQ; k += gridDim.x * blockDim.x)
        v = max(v, p[k]);
    #pragma unroll
    for (int o = 16; o > 0; o >>= 1) v = max(v, __shfl_xor_sync(0xffffffffu, v, o));
    __shared__ int sm[8];
    int w = threadIdx.x >> 5;
    if ((threadIdx.x & 31) == 0) sm[w] = v;
    __syncthreads();
    if (threadIdx.x == 0) {
        int bv = sm[0];
        for (int i = 1; i < (int)(blockDim.x >> 5); i++) bv = max(bv, sm[i]);
        atomicMax(gm, bv);
    }
}

__global__ void write_mask_kernel(const int* __restrict__ p, const int* __restrict__ gm,
                                  float* __restrict__ out) {
    int i = blockIdx.x * blockDim.x + threadIdx.x;
    if (i < NQ) out[i] = (p[i] < *gm) ? 1.0f : 0.0f;
}

__global__ void split_kernel(const float* __restrict__ X, __nv_bfloat16* __restrict__ hi,
                             __nv_bfloat16* __restrict__ lo, int n)
{
    int i = blockIdx.x * blockDim.x + threadIdx.x;
    if (i < n) split2(X[i], hi[i], lo[i]);
}

__global__ void add_split_kernel(const float* __restrict__ A, const float* __restrict__ B,
                                 __nv_bfloat16* __restrict__ hi, __nv_bfloat16* __restrict__ lo, int n)
{
    int i = blockIdx.x * blockDim.x + threadIdx.x;
    if (i < n) split2(A[i] + B[i], hi[i], lo[i]);
}

// pack encoder weight W [128][N] (k-major) -> hi/lo [N][128]
__global__ void packw_kernel(const float* __restrict__ W, __nv_bfloat16* __restrict__ hi,
                             __nv_bfloat16* __restrict__ lo, int N)
{
    int i = blockIdx.x * blockDim.x + threadIdx.x;
    if (i >= N * 128) return;
    int k = i & 127, n = i >> 7;
    split2(W[(size_t)k * N + n], hi[i], lo[i]);
}

__global__ void packbias_kernel(const float* __restrict__ boff, const float* __restrict__ battn,
                                float* __restrict__ dst)
{
    int i = threadIdx.x + blockIdx.x * blockDim.x;
    if (i < 768) dst[i] = (i < 512) ? boff[i] : battn[i - 512];
}

__global__ void packcw_kernel(const float* __restrict__ W, __nv_bfloat16* __restrict__ hi,
                              __nv_bfloat16* __restrict__ lo, int CO, int CI, int CIN_CH, int total)
{
    int i = blockIdx.x * blockDim.x + threadIdx.x;
    if (i >= total) return;
    int k = i & 63, co = (i >> 6) & 63, c = i >> 12;
    int e = c / CIN_CH, cih = c % CIN_CH;
    int ci = cih * 64 + k;
    float v = (co < CO && ci < CI) ? W[(((size_t)co * CI + ci) * 3 + e / 3) * 3 + e % 3] : 0.f;
    split2(v, hi[i], lo[i]);
}

// conv1 weight -> fp16 [chunk][co][k]
__global__ void wsplit16_kernel(const float* __restrict__ W, __half* __restrict__ w16)
{
    int i = blockIdx.x * blockDim.x + threadIdx.x;
    if (i >= W1CHUNKS * 128 * 64) return;
    int k  = i & 63;
    int co = (i >> 6) & 127;
    int c  = i >> 13;
    int e = c >> 1, ci = ((c & 1) << 6) + k;
    int ky = e / 7, kx = e % 7;
    w16[i] = __float2half_rn(W[(((size_t)co * 128 + ci) * 7 + ky) * 7 + kx]);
}

// ---------------- generic bf16x3 GEMM: C[M,N] = A[M,128] * B[N,128]^T ----------------
// FLAGS: 1 relu, 2 residual, 4 write fp32 C, 8 write split C, 16 write fp16 C
constexpr int GROWB = 272;
constexpr int GTILE = 128 * GROWB;
constexpr int GEMM_SMEM = 4 * GTILE;

template<int FLAGS>
__global__ void __launch_bounds__(256, 1) gemm_mma(
    const __nv_bfloat16* __restrict__ Ah, const __nv_bfloat16* __restrict__ Al,
    const __nv_bfloat16* __restrict__ Bh, const __nv_bfloat16* __restrict__ Bl,
    const float* __restrict__ bias, const float* __restrict__ R,
    float* __restrict__ Cf, __nv_bfloat16* __restrict__ Ch, __nv_bfloat16* __restrict__ Cl,
    __half* __restrict__ Cx, int M, int N)
{
    extern __shared__ char smem[];
    const int tid = threadIdx.x;
    const int wid = tid >> 5, lane = tid & 31;
    const int warp_m = wid >> 2, warp_n = wid & 3;
    const uint32_t sb = smem_u32(smem);
    const int bm = blockIdx.x * 128, bn = blockIdx.y * 128;

    {
        const int lrow = tid >> 1, lhalf = tid & 1;
        const bool aval = (bm + lrow) < M;
        const uint32_t sa = sb + (uint32_t)lrow * GROWB + (uint32_t)lhalf * 128;
        const char* agh = (const char*)(Ah + (size_t)(aval ? (bm + lrow) : 0) * 128 + lhalf * 64);
        const char* agl = (const char*)(Al + (size_t)(aval ? (bm + lrow) : 0) * 128 + lhalf * 64);
        const char* bgh = (const char*)(Bh + (size_t)(bn + lrow) * 128 + lhalf * 64);
        const char* bgl = (const char*)(Bl + (size_t)(bn + lrow) * 128 + lhalf * 64);
        #pragma unroll
        for (int i = 0; i < 8; i++) {
            cpasync16(sa + i * 16,             agh + i * 16, aval);
            cpasync16(sa + GTILE + i * 16,     agl + i * 16, aval);
            cpasync16(sa + 2 * GTILE + i * 16, bgh + i * 16, true);
            cpasync16(sa + 3 * GTILE + i * 16, bgl + i * 16, true);
        }
        cp_commit();
        cp_wait0();
        __syncthreads();
    }

    float acc[4][4][4];
    #pragma unroll
    for (int mt = 0; mt < 4; mt++)
        #pragma unroll
        for (int nt = 0; nt < 4; nt++)
            #pragma unroll
            for (int d = 0; d < 4; d++) acc[mt][nt][d] = 0.f;

    const uint32_t a_base = sb + (uint32_t)(warp_m * 64 + (lane & 15)) * GROWB + (uint32_t)(lane >> 4) * 16;
    const uint32_t b_base = sb + 2 * GTILE + (uint32_t)(warp_n * 32 + (lane & 7)) * GROWB
                          + (uint32_t)((lane >> 3) & 1) * 16;

    #pragma unroll
    for (int ks = 0; ks < 8; ks++) {
        const uint32_t kbyte = (uint32_t)ks * 32;
        uint32_t bh[4][2], bl[4][2];
        #pragma unroll
        for (int nt = 0; nt < 4; nt++) {
            ldmx2(bh[nt], b_base + (uint32_t)nt * 8 * GROWB + kbyte);
            ldmx2(bl[nt], b_base + GTILE + (uint32_t)nt * 8 * GROWB + kbyte);
        }
        #pragma unroll
        for (int mt = 0; mt < 4; mt++) {
            uint32_t ah[4], al[4];
            ldmx4(ah, a_base + (uint32_t)mt * 16 * GROWB + kbyte);
            ldmx4(al, a_base + GTILE + (uint32_t)mt * 16 * GROWB + kbyte);
            #pragma unroll
            for (int nt = 0; nt < 4; nt++) {
                mma_bf16(acc[mt][nt], ah, bh[nt]);
                mma_bf16(acc[mt][nt], ah, bl[nt]);
                mma_bf16(acc[mt][nt], al, bh[nt]);
            }
        }
    }

    const int g = lane >> 2, tg = lane & 3;
    #pragma unroll
    for (int mt = 0; mt < 4; mt++) {
        const int r0 = bm + warp_m * 64 + mt * 16 + g;
        #pragma unroll
        for (int nt = 0; nt < 4; nt++) {
            const int col = bn + warp_n * 32 + nt * 8 + tg * 2;
            float2 bb = *(const float2*)&bias[col];
            float v[4] = {acc[mt][nt][0] + bb.x, acc[mt][nt][1] + bb.y,
                          acc[mt][nt][2] + bb.x, acc[mt][nt][3] + bb.y};
            #pragma unroll
            for (int half = 0; half < 2; half++) {
                const int r = r0 + half * 8;
                if (r >= M) continue;
                float a0 = v[half * 2], a1 = v[half * 2 + 1];
                if (FLAGS & 2) {
                    float2 rr = *(const float2*)&R[(size_t)r * N + col];
                    a0 += rr.x; a1 += rr.y;
                }
                if (FLAGS & 1) { a0 = fmaxf(a0, 0.f); a1 = fmaxf(a1, 0.f); }
                if (FLAGS & 4)
                    *(float2*)&Cf[(size_t)r * N + col] = make_float2(a0, a1);
                if (FLAGS & 8) {
                    __nv_bfloat16 h0, l0, h1, l1;
                    split2(a0, h0, l0); split2(a1, h1, l1);
                    *(__nv_bfloat162*)&Ch[(size_t)r * N + col] = __nv_bfloat162(h0, h1);
                    *(__nv_bfloat162*)&Cl[(size_t)r * N + col] = __nv_bfloat162(l0, l1);
                }
                if (FLAGS & 16)
                    *(__half2*)&Cx[(size_t)r * N + col] = __floats2half2_rn(a0, a1);
            }
        }
    }
}

// ---------------- deformable attention sampling (fp16 V, fused softmax, uint4 loads) ----------------
__global__ void __launch_bounds__(256) deform_kernel(
    const __half* __restrict__ VX, const float* __restrict__ OA,
    __nv_bfloat16* __restrict__ OH, __nv_bfloat16* __restrict__ OL)
{
    int t = blockIdx.x * 256 + threadIdx.x;
    if (t >= NQ * HEADS) return;
    const int n = t >> 3, h = t & 7;
    const float rx = ((float)(n % 200) + 0.5f) * (1.f / 200.f);
    const float ry = ((float)(n / 200) + 0.5f) * (1.f / 200.f);
    const float* op = OA + (size_t)n * 768 + h * 64;
    const float* ap = OA + (size_t)n * 768 + 512 + h * 32;

    // in-register softmax over the 32 logits
    float e[32];
    {
        float m = -1e30f;
        #pragma unroll
        for (int k = 0; k < 32; k++) { e[k] = ap[k]; m = fmaxf(m, e[k]); }
        float s = 0.f;
        #pragma unroll
        for (int k = 0; k < 32; k++) { e[k] = expf(e[k] - m); s += e[k]; }
        float inv = 1.f / s;
        #pragma unroll
        for (int k = 0; k < 32; k++) e[k] *= inv;
    }

    float acc[16];
    #pragma unroll
    for (int d = 0; d < 16; d++) acc[d] = 0.f;

    const int stc[4] = {0, 32768, 40960, 43008};
    const int Wc[4]  = {256, 128, 64, 32};
    const int Hc[4]  = {128, 64, 32, 16};

    #pragma unroll
    for (int l = 0; l < 4; l++) {
        const int W = Wc[l], H = Hc[l], st = stc[l];
        const float Wf = (float)W, Hf = (float)H;
        for (int p = 0; p < 8; p++) {
            float ox = op[(l * 8 + p) * 2 + 0];
            float oy = op[(l * 8 + p) * 2 + 1];
            float aw = e[l * 8 + p];
            float x = (rx + ox / Wf) * Wf - 0.5f;
            float y = (ry + oy / Hf) * Hf - 0.5f;
            float xf = floorf(x), yf = floorf(y);
            int x0 = (int)xf, y0 = (int)yf;
            float fx = x - xf, fy = y - yf;
            float wx[2] = {1.f - fx, fx};
            float wy[2] = {1.f - fy, fy};
            #pragma unroll
            for (int c = 0; c < 4; c++) {
                int xi = x0 + (c & 1), yi = y0 + (c >> 1);
                float wgt = wx[c & 1] * wy[c >> 1];
                if (xi >= 0 && xi < W && yi >= 0 && yi < H && wgt != 0.f) {
                    const uint4* gp = (const uint4*)(VX + ((size_t)(st + yi * W + xi)) * 128 + h * 16);
                    uint4 u0 = gp[0];
                    uint4 u1 = gp[1];
                    uint32_t wv[8] = {u0.x, u0.y, u0.z, u0.w, u1.x, u1.y, u1.z, u1.w};
                    float cw = aw * wgt;
                    #pragma unroll
                    for (int d = 0; d < 8; d++) {
                        float2 g2 = __half22float2(*(const __half2*)&wv[d]);
                        acc[d * 2 + 0] += cw * g2.x;
                        acc[d * 2 + 1] += cw * g2.y;
                    }
                }
            }
        }
    }
    __nv_bfloat162* oh = (__nv_bfloat162*)(OH + (size_t)n * 128 + h * 16);
    __nv_bfloat162* ol = (__nv_bfloat162*)(OL + (size_t)n * 128 + h * 16);
    #pragma unroll
    for (int d = 0; d < 8; d++) {
        __nv_bfloat16 h0, l0, h1, l1;
        split2(acc[d * 2], h0, l0); split2(acc[d * 2 + 1], h1, l1);
        oh[d] = __nv_bfloat162(h0, h1);
        ol[d] = __nv_bfloat162(l0, l1);
    }
}

// ---------------- layernorm over 128 per row ----------------
// MODE: 0 fp32 only, 1 + split(y), 2 + split(y + pos), 3 + fp16(y)
template<int MODE>
__global__ void ln_kernel(const float* __restrict__ X, const float* __restrict__ g,
                          const float* __restrict__ b, float* __restrict__ Y,
                          __nv_bfloat16* __restrict__ Yh, __nv_bfloat16* __restrict__ Yl,
                          __half* __restrict__ Yx, const float* __restrict__ pos)
{
    int r = blockIdx.x;
    int t = threadIdx.x;
    float x = X[(size_t)r * 128 + t];
    float s = x;
    #pragma unroll
    for (int o = 16; o > 0; o >>= 1) s += __shfl_xor_sync(0xffffffffu, s, o);
    __shared__ float sm[4], sm2[4];
    int w = t >> 5, lane = t & 31;
    if (lane == 0) sm[w] = s;
    __syncthreads();
    float m = (sm[0] + sm[1] + sm[2] + sm[3]) * (1.f / 128.f);
    float d = x - m;
    float q = d * d;
    #pragma unroll
    for (int o = 16; o > 0; o >>= 1) q += __shfl_xor_sync(0xffffffffu, q, o);
    if (lane == 0) sm2[w] = q;
    __syncthreads();
    float var = (sm2[0] + sm2[1] + sm2[2] + sm2[3]) * (1.f / 128.f);
    float y = d * rsqrtf(var + 1e-5f) * g[t] + b[t];
    Y[(size_t)r * 128 + t] = y;
    if (MODE == 1 || MODE == 2) {
        float z = (MODE == 2) ? (y + pos[(size_t)r * 128 + t]) : y;
        __nv_bfloat16 hh, ll;
        split2(z, hh, ll);
        Yh[(size_t)r * 128 + t] = hh;
        Yl[(size_t)r * 128 + t] = ll;
    }
    if (MODE == 3)
        Yx[(size_t)r * 128 + t] = __float2half_rn(y);
}

// ---------------- conv1 (7x7, 128->128) via mma.sync fp16 single ----------------
constexpr int ROWB = 144;
constexpr int C1TILE = 128 * ROWB;     // 18432
constexpr int C1BUF  = 2 * C1TILE;     // A + B
constexpr int CONV1_SMEM = 2 * C1BUF;  // 73728

__global__ void __launch_bounds__(256, 2) conv1_f16_kernel(
    const __half* __restrict__ q16, const __half* __restrict__ w16,
    float* __restrict__ Out)
{
    extern __shared__ char smem[];
    const int tid = threadIdx.x;
    const int wid = tid >> 5, lane = tid & 31;
    const int warp_m = wid >> 2, warp_n = wid & 3;
    const uint32_t sb = smem_u32(smem);
    const int bm = blockIdx.x * 128;

    const int lrow = tid >> 1, lhalf = tid & 1;
    const int pm = bm + lrow;
    const int py = pm / 200, px = pm % 200;
    const bool prow_ok = pm < NQ;
    const uint32_t s_arow = sb + (uint32_t)lrow * ROWB + (uint32_t)lhalf * 64;
    const uint32_t s_brow = s_arow + C1TILE;

    const uint32_t a_base = sb + (uint32_t)(warp_m * 64 + (lane & 15)) * ROWB + (uint32_t)(lane >> 4) * 16;
    const uint32_t b_base = sb + C1TILE + (uint32_t)(warp_n * 32 + (lane & 7)) * ROWB
                          + (uint32_t)((lane >> 3) & 1) * 16;

    float acc[4][4][4];
    #pragma unroll
    for (int mt = 0; mt < 4; mt++)
        #pragma unroll
        for (int nt = 0; nt < 4; nt++)
            #pragma unroll
            for (int d = 0; d < 4; d++) acc[mt][nt][d] = 0.f;

    auto load_chunk = [&](int c, int buf) {
        const int e = c >> 1, ch = c & 1;
        const int qy = py + e / 7 - 3;
        const int qx = px + e % 7 - 3;
        const bool val = prow_ok && qy >= 0 && qy < 200 && qx >= 0 && qx < 200;
        const size_t aoff = (size_t)(val ? (qy * 200 + qx) : 0) * 128 + (size_t)ch * 64 + (size_t)lhalf * 32;
        const char* ag = (const char*)(q16 + aoff);
        const size_t boff = ((size_t)c * 128 + lrow) * 64 + (size_t)lhalf * 32;
        const char* bg = (const char*)(w16 + boff);
        const uint32_t sa = s_arow + (uint32_t)buf * C1BUF;
        const uint32_t sbr = s_brow + (uint32_t)buf * C1BUF;
        #pragma unroll
        for (int i = 0; i < 4; i++) {
            cpasync16(sa + i * 16,  ag + i * 16, val);
            cpasync16(sbr + i * 16, bg + i * 16, true);
        }
    };

    load_chunk(0, 0); cp_commit();
    load_chunk(1, 1); cp_commit();

    for (int c = 0; c < W1CHUNKS; c++) {
        const int buf = c & 1;
        cp_wait1();
        __syncthreads();

        const uint32_t ab = a_base + (uint32_t)buf * C1BUF;
        const uint32_t bb = b_base + (uint32_t)buf * C1BUF;
        #pragma unroll
        for (int ks = 0; ks < 4; ks++) {
            const uint32_t kbyte = (uint32_t)ks * 32;
            uint32_t bfr[4][2];
            #pragma unroll
            for (int nt = 0; nt < 4; nt++)
                ldmx2(bfr[nt], bb + (uint32_t)nt * 8 * ROWB + kbyte);
            #pragma unroll
            for (int mt = 0; mt < 4; mt++) {
                uint32_t afr[4];
                ldmx4(afr, ab + (uint32_t)mt * 16 * ROWB + kbyte);
                #pragma unroll
                for (int nt = 0; nt < 4; nt++)
                    mma_f16(acc[mt][nt], afr, bfr[nt]);
            }
        }
        __syncthreads();
        if (c + 2 < W1CHUNKS) load_chunk(c + 2, buf);
        cp_commit();
    }

    const int g = lane >> 2, tg = lane & 3;
    #pragma unroll
    for (int mt = 0; mt < 4; mt++) {
        const int r0 = bm + warp_m * 64 + mt * 16 + g;
        #pragma unroll
        for (int nt = 0; nt < 4; nt++) {
            const int col = warp_n * 32 + nt * 8 + tg * 2;
            if (r0 < NQ)
                *(float2*)&Out[(size_t)r0 * 128 + col] = make_float2(acc[mt][nt][0], acc[mt][nt][1]);
            if (r0 + 8 < NQ)
                *(float2*)&Out[(size_t)(r0 + 8) * 128 + col] = make_float2(acc[mt][nt][2], acc[mt][nt][3]);
        }
    }
}

// ---------------- convs 2-4 (3x3) via mma.sync bf16x3, 128x64 tile ----------------
constexpr int CATILE = 128 * ROWB;
constexpr int CBTILE = 64 * ROWB;
constexpr int CBUF = 2 * CATILE + 2 * CBTILE;
constexpr int CONV_SMEM = 2 * CBUF;

template<int CHUNKS, int CIN_CH, int CST>
__global__ void __launch_bounds__(256, 2) conv_mma_kernel(
    const __nv_bfloat16* __restrict__ inh, const __nv_bfloat16* __restrict__ inl,
    const __nv_bfloat16* __restrict__ wh, const __nv_bfloat16* __restrict__ wl,
    float* __restrict__ Out, int COUT)
{
    extern __shared__ char smem[];
    const int tid = threadIdx.x;
    const int wid = tid >> 5, lane = tid & 31;
    const int warp_m = wid >> 1, warp_n = wid & 1;
    const uint32_t sb = smem_u32(smem);
    const int bm = blockIdx.x * 128;

    const int lrow = tid >> 1, lhalf = tid & 1;
    const int pm = bm + lrow;
    const int py = pm / 200, px = pm % 200;
    const bool prow_ok = pm < NQ;
    const uint32_t s_arow = sb + (uint32_t)lrow * ROWB + (uint32_t)lhalf * 64;
    const int brow = tid >> 2, bq = tid & 3;
    const uint32_t s_brow = sb + 2 * CATILE + (uint32_t)brow * ROWB + (uint32_t)bq * 32;

    const uint32_t a_base = sb + (uint32_t)(warp_m * 32 + (lane & 15)) * ROWB + (uint32_t)(lane >> 4) * 16;
    const uint32_t b_base = sb + 2 * CATILE + (uint32_t)(warp_n * 32 + (lane & 7)) * ROWB
                          + (uint32_t)((lane >> 3) & 1) * 16;

    float acc[2][4][4];
    #pragma unroll
    for (int mt = 0; mt < 2; mt++)
        #pragma unroll
        for (int nt = 0; nt < 4; nt++)
            #pragma unroll
            for (int d = 0; d < 4; d++) acc[mt][nt][d] = 0.f;

    auto load_chunk = [&](int c, int buf) {
        const int e = c / CIN_CH, cih = c % CIN_CH;
        const int qy = py + e / 3 - 1;
        const int qx = px + e % 3 - 1;
        const bool val = prow_ok && qy >= 0 && qy < 200 && qx >= 0 && qx < 200;
        const size_t aoff = (size_t)(val ? (qy * 200 + qx) : 0) * CST + (size_t)cih * 64 + (size_t)lhalf * 32;
        const char* agh = (const char*)(inh + aoff);
        const char* agl = (const char*)(inl + aoff);
        const size_t boff = ((size_t)c * 64 + brow) * 64 + (size_t)bq * 16;
        const char* bgh = (const char*)(wh + boff);
        const char* bgl = (const char*)(wl + boff);
        const uint32_t sa = s_arow + (uint32_t)buf * CBUF;
        const uint32_t sbr = s_brow + (uint32_t)buf * CBUF;
        #pragma unroll
        for (int i = 0; i < 4; i++) {
            cpasync16(sa + i * 16,           agh + i * 16, val);
            cpasync16(sa + CATILE + i * 16,  agl + i * 16, val);
        }
        #pragma unroll
        for (int i = 0; i < 2; i++) {
            cpasync16(sbr + i * 16,          bgh + i * 16, true);
            cpasync16(sbr + CBTILE + i * 16, bgl + i * 16, true);
        }
    };

    load_chunk(0, 0); cp_commit();
    load_chunk(1, 1); cp_commit();

    for (int c = 0; c < CHUNKS; c++) {
        const int buf = c & 1;
        cp_wait1();
        __syncthreads();

        const uint32_t ab = a_base + (uint32_t)buf * CBUF;
        const uint32_t bb = b_base + (uint32_t)buf * CBUF;
        #pragma unroll
        for (int ks = 0; ks < 4; ks++) {
            const uint32_t kbyte = (uint32_t)ks * 32;
            uint32_t bh[4][2], bl[4][2];
            #pragma unroll
            for (int nt = 0; nt < 4; nt++) {
                ldmx2(bh[nt], bb + (uint32_t)nt * 8 * ROWB + kbyte);
                ldmx2(bl[nt], bb + CBTILE + (uint32_t)nt * 8 * ROWB + kbyte);
            }
            #pragma unroll
            for (int mt = 0; mt < 2; mt++) {
                uint32_t ah[4], al[4];
                ldmx4(ah, ab + (uint32_t)mt * 16 * ROWB + kbyte);
                ldmx4(al, ab + CATILE + (uint32_t)mt * 16 * ROWB + kbyte);
                #pragma unroll
                for (int nt = 0; nt < 4; nt++) {
                    mma_bf16(acc[mt][nt], ah, bh[nt]);
                    mma_bf16(acc[mt][nt], ah, bl[nt]);
                    mma_bf16(acc[mt][nt], al, bh[nt]);
                }
            }
        }
        __syncthreads();
        if (c + 2 < CHUNKS) load_chunk(c + 2, buf);
        cp_commit();
    }

    const int g = lane >> 2, tg = lane & 3;
    #pragma unroll
    for (int mt = 0; mt < 2; mt++) {
        const int r0 = bm + warp_m * 32 + mt * 16 + g;
        #pragma unroll
        for (int nt = 0; nt < 4; nt++) {
            const int col = warp_n * 32 + nt * 8 + tg * 2;
            if (col >= COUT) continue;
            if (r0 < NQ)
                *(float2*)&Out[(size_t)r0 * COUT + col] = make_float2(acc[mt][nt][0], acc[mt][nt][1]);
            if (r0 + 8 < NQ)
                *(float2*)&Out[(size_t)(r0 + 8) * COUT + col] = make_float2(acc[mt][nt][2], acc[mt][nt][3]);
        }
    }
}

// ---------------- batchnorm ----------------
__global__ void bn_stats_kernel(const float* __restrict__ X, float* __restrict__ part, int C)
{
    int c = threadIdx.x;
    int g = blockIdx.x;
    const int per = (NQ + 63) / 64;
    int p0 = g * per;
    int p1 = min(NQ, p0 + per);
    float s = 0.f, q = 0.f;
    for (int p = p0; p < p1; p++) {
        float x = X[(size_t)p * C + c];
        s += x; q += x * x;
    }
    part[(size_t)g * 2 * C + c] = s;
    part[(size_t)g * 2 * C + C + c] = q;
}

__global__ void bn_finalize_kernel(const float* __restrict__ part,
                                   const float* __restrict__ gamma, const float* __restrict__ beta,
                                   float* __restrict__ scale, float* __restrict__ shift, int C)
{
    int c = threadIdx.x;
    float s = 0.f, q = 0.f;
    for (int g = 0; g < 64; g++) {
        s += part[(size_t)g * 2 * C + c];
        q += part[(size_t)g * 2 * C + C + c];
    }
    const float invP = 1.f / (float)NQ;
    float m = s * invP;
    float v = q * invP - m * m;
    float sc = gamma[c] * rsqrtf(v + 1e-5f);
    scale[c] = sc;
    shift[c] = beta[c] - m * sc;
}

__global__ void bn_apply_split_kernel(const float* __restrict__ X, const float* __restrict__ scale,
                                      const float* __restrict__ shift,
                                      __nv_bfloat16* __restrict__ hi, __nv_bfloat16* __restrict__ lo,
                                      int C, int CST, int total)
{
    int i = blockIdx.x * blockDim.x + threadIdx.x;
    if (i >= total) return;
    int c = i % CST;
    int p = i / CST;
    float v = 0.f;
    if (c < C) v = fmaxf(0.f, fmaf(X[(size_t)p * C + c], scale[c], shift[c]));
    split2(v, hi[i], lo[i]);
}

// ---------------- head: fused BN4+ReLU + 1x1 conv 48 -> 21, output NCHW ----------------
__global__ void head_conv_kernel(const float* __restrict__ H4raw, const float* __restrict__ scale,
                                 const float* __restrict__ shift,
                                 const float* __restrict__ Wo, const float* __restrict__ bo,
                                 float* __restrict__ out)
{
    int p = blockIdx.x * blockDim.x + threadIdx.x;
    if (p >= NQ) return;
    float x[48];
    const float4* hp = (const float4*)(H4raw + (size_t)p * 48);
    #pragma unroll
    for (int i = 0; i < 12; i++) {
        float4 v = hp[i];
        x[i * 4 + 0] = v.x; x[i * 4 + 1] = v.y; x[i * 4 + 2] = v.z; x[i * 4 + 3] = v.w;
    }
    #pragma unroll
    for (int ci = 0; ci < 48; ci++)
        x[ci] = fmaxf(0.f, fmaf(x[ci], scale[ci], shift[ci]));
    for (int co = 0; co < 21; co++) {
        float s = bo[co];
        const float* w = Wo + co * 48;
        #pragma unroll
        for (int ci = 0; ci < 48; ci++) s = fmaf(x[ci], w[ci], s);
        out[(size_t)co * NQ + p] = s;
    }
}

// ---------------- launch ----------------
extern "C" void kernel_launch(void* const* d_in, const int* in_sizes, int n_in,
                              void* d_out, int out_size)
{
    const float* value = (const float*)d_in[0];
    const float* bq    = (const float*)d_in[1];
    const float* bpos  = (const float*)d_in[2];
    const int*   proj  = (const int*)d_in[3];
    const float* Wv    = (const float*)d_in[4];
    const float* bv    = (const float*)d_in[5];
    const float* Woff  = (const float*)d_in[6];
    const float* boff  = (const float*)d_in[7];
    const float* Wattn = (const float*)d_in[8];
    const float* battn = (const float*)d_in[9];
    const float* Wout  = (const float*)d_in[10];
    const float* bout  = (const float*)d_in[11];
    const float* Wf1   = (const float*)d_in[12];
    const float* bf1   = (const float*)d_in[13];
    const float* Wf2   = (const float*)d_in[14];
    const float* bf2   = (const float*)d_in[15];
    const float* lng   = (const float*)d_in[16];
    const float* lnb   = (const float*)d_in[17];
    const float* cw1   = (const float*)d_in[18];
    const float* g1    = (const float*)d_in[19];
    const float* b1    = (const float*)d_in[20];
    const float* cw2   = (const float*)d_in[21];
    const float* g2    = (const float*)d_in[22];
    const float* b2    = (const float*)d_in[23];
    const float* cw3   = (const float*)d_in[24];
    const float* g3    = (const float*)d_in[25];
    const float* b3    = (const float*)d_in[26];
    const float* cw4   = (const float*)d_in[27];
    const float* g4    = (const float*)d_in[28];
    const float* b4    = (const float*)d_in[29];
    const float* objw  = (const float*)d_in[30];
    const float* objb  = (const float*)d_in[31];
    float* out = (float*)d_out;

    float* S = nullptr;
    cudaGetSymbolAddress((void**)&S, g_scratch);
    int* gm = nullptr;
    cudaGetSymbolAddress((void**)&gm, g_maxv);
    __nv_bfloat16 *s1h, *s1l, *s2h, *s2l, *vh, *vl, *wph, *wpl, *wch, *wcl;
    __half *vx, *q16, *w16;
    cudaGetSymbolAddress((void**)&s1h, g_s1h);
    cudaGetSymbolAddress((void**)&s1l, g_s1l);
    cudaGetSymbolAddress((void**)&s2h, g_s2h);
    cudaGetSymbolAddress((void**)&s2l, g_s2l);
    cudaGetSymbolAddress((void**)&vh,  g_vh);
    cudaGetSymbolAddress((void**)&vl,  g_vl);
    cudaGetSymbolAddress((void**)&vx,  g_vx);
    cudaGetSymbolAddress((void**)&q16, g_q16);
    cudaGetSymbolAddress((void**)&w16, g_w16);
    cudaGetSymbolAddress((void**)&wph, g_wph);
    cudaGetSymbolAddress((void**)&wpl, g_wpl);
    cudaGetSymbolAddress((void**)&wch, g_wch);
    cudaGetSymbolAddress((void**)&wcl, g_wcl);

    float* POA   = S + OFF_OA;
    float* PQ    = S + OFF_Q;
    float* PT1   = S + OFF_T1;
    float* PT2   = S + OFF_T2;
    float* PH1   = S + OFF_H1;
    float* PH2   = S + OFF_H2;
    float* PH3   = S + OFF_H3;
    float* PH4   = S + OFF_H4;
    float* PPART = S + OFF_PART;
    float* PSCALE= S + OFF_SCALE;
    float* PSHIFT= S + OFF_SHIFT;
    float* PBIAS = S + OFF_BIAS;

    cudaFuncSetAttribute(conv1_f16_kernel, cudaFuncAttributeMaxDynamicSharedMemorySize, CONV1_SMEM);
    cudaFuncSetAttribute(gemm_mma<4>,  cudaFuncAttributeMaxDynamicSharedMemorySize, GEMM_SMEM);
    cudaFuncSetAttribute(gemm_mma<6>,  cudaFuncAttributeMaxDynamicSharedMemorySize, GEMM_SMEM);
    cudaFuncSetAttribute(gemm_mma<9>,  cudaFuncAttributeMaxDynamicSharedMemorySize, GEMM_SMEM);
    cudaFuncSetAttribute(gemm_mma<16>, cudaFuncAttributeMaxDynamicSharedMemorySize, GEMM_SMEM);
    cudaFuncSetAttribute((conv_mma_kernel<18, 2, 128>), cudaFuncAttributeMaxDynamicSharedMemorySize, CONV_SMEM);
    cudaFuncSetAttribute((conv_mma_kernel<9, 1, 64>),   cudaFuncAttributeMaxDynamicSharedMemorySize, CONV_SMEM);

    // --- observed_masks ---
    init_max_kernel<<<1, 1>>>(gm);
    reduce_max_kernel<<<40, 256>>>(proj, gm);
    write_mask_kernel<<<(NQ + 255) / 256, 256>>>(proj, gm, out + 21 * NQ);

    // --- weight prep ---
    wsplit16_kernel<<<(W1CHUNKS * 128 * 64 + 255) / 256, 256>>>(cw1, w16);
    packcw_kernel<<<(18 * 4096 + 255) / 256, 256>>>(cw2, wch + WC2_OFF, wcl + WC2_OFF, 64, 128, 2, 18 * 4096);
    packcw_kernel<<<(9 * 4096 + 255) / 256, 256>>>(cw3, wch + WC3_OFF, wcl + WC3_OFF, 48, 64, 1, 9 * 4096);
    packcw_kernel<<<(9 * 4096 + 255) / 256, 256>>>(cw4, wch + WC4_OFF, wcl + WC4_OFF, 48, 48, 1, 9 * 4096);
    for (int i = 0; i < 2; i++) {
        size_t LB = (size_t)i * 1280 * 128;
        packw_kernel<<<(128 * 128 + 255) / 256, 256>>>(Wv   + (size_t)i * 128 * 128, wph + LB,              wpl + LB,              128);
        packw_kernel<<<(512 * 128 + 255) / 256, 256>>>(Woff + (size_t)i * 128 * 512, wph + LB + 128 * 128,  wpl + LB + 128 * 128,  512);
        packw_kernel<<<(256 * 128 + 255) / 256, 256>>>(Wattn+ (size_t)i * 128 * 256, wph + LB + 640 * 128,  wpl + LB + 640 * 128,  256);
        packw_kernel<<<(128 * 128 + 255) / 256, 256>>>(Wout + (size_t)i * 128 * 128, wph + LB + 896 * 128,  wpl + LB + 896 * 128,  128);
        packw_kernel<<<(128 * 128 + 255) / 256, 256>>>(Wf1  + (size_t)i * 128 * 128, wph + LB + 1024 * 128, wpl + LB + 1024 * 128, 128);
        packw_kernel<<<(128 * 128 + 255) / 256, 256>>>(Wf2  + (size_t)i * 128 * 128, wph + LB + 1152 * 128, wpl + LB + 1152 * 128, 128);
        packbias_kernel<<<3, 256>>>(boff + i * 512, battn + i * 256, PBIAS + i * 768);
    }
    split_kernel<<<(NV * 128 + 255) / 256, 256>>>(value, vh, vl, NV * 128);

    // --- q init ---
    cudaMemcpyAsync(PQ, bq, (size_t)NQ * ED * sizeof(float), cudaMemcpyDeviceToDevice);

    // --- 2 encoder layers ---
    add_split_kernel<<<(NQ * ED + 255) / 256, 256>>>(PQ, bpos, s1h, s1l, NQ * ED);
    for (int i = 0; i < 2; i++) {
        size_t LB = (size_t)i * 1280 * 128;
        // V projection -> fp16 V for deform
        gemm_mma<16><<<dim3(340, 1), 256, GEMM_SMEM>>>(vh, vl, wph + LB, wpl + LB,
                                                       bv + i * 128, nullptr, nullptr, nullptr, nullptr, vx, NV, 128);
        // combined Woff+Wattn: N = 768 (attn logits, softmax fused in deform)
        gemm_mma<4><<<dim3(313, 6), 256, GEMM_SMEM>>>(s1h, s1l, wph + LB + 128 * 128, wpl + LB + 128 * 128,
                                                      PBIAS + i * 768, nullptr, POA, nullptr, nullptr, nullptr, NQ, 768);
        deform_kernel<<<(NQ * HEADS + 255) / 256, 256>>>(vx, POA, s2h, s2l);
        gemm_mma<6><<<dim3(313, 1), 256, GEMM_SMEM>>>(s2h, s2l, wph + LB + 896 * 128, wpl + LB + 896 * 128,
                                                      bout + i * 128, PQ, PT1, nullptr, nullptr, nullptr, NQ, 128);
        ln_kernel<1><<<NQ, 128>>>(PT1, lng + (i * 2 + 0) * 128, lnb + (i * 2 + 0) * 128, PQ, s1h, s1l, nullptr, nullptr);
        gemm_mma<9><<<dim3(313, 1), 256, GEMM_SMEM>>>(s1h, s1l, wph + LB + 1024 * 128, wpl + LB + 1024 * 128,
                                                      bf1 + i * 128, nullptr, nullptr, s2h, s2l, nullptr, NQ, 128);
        gemm_mma<6><<<dim3(313, 1), 256, GEMM_SMEM>>>(s2h, s2l, wph + LB + 1152 * 128, wpl + LB + 1152 * 128,
                                                      bf2 + i * 128, PQ, PT2, nullptr, nullptr, nullptr, NQ, 128);
        if (i == 0)
            ln_kernel<2><<<NQ, 128>>>(PT2, lng + 1 * 128, lnb + 1 * 128, PQ, s1h, s1l, nullptr, bpos);  // split(q+pos) for layer 1
        else
            ln_kernel<3><<<NQ, 128>>>(PT2, lng + 3 * 128, lnb + 3 * 128, PQ, nullptr, nullptr, q16, nullptr); // fp16(q) for conv1
    }

    // --- conv head ---
    conv1_f16_kernel<<<313, 256, CONV1_SMEM>>>(q16, w16, PH1);
    bn_stats_kernel<<<64, 128>>>(PH1, PPART, 128);
    bn_finalize_kernel<<<1, 128>>>(PPART, g1, b1, PSCALE, PSHIFT, 128);
    bn_apply_split_kernel<<<(NQ * 128 + 255) / 256, 256>>>(PH1, PSCALE, PSHIFT, s1h, s1l, 128, 128, NQ * 128);

    conv_mma_kernel<18, 2, 128><<<313, 256, CONV_SMEM>>>(s1h, s1l, wch + WC2_OFF, wcl + WC2_OFF, PH2, 64);
    bn_stats_kernel<<<64, 64>>>(PH2, PPART, 64);
    bn_finalize_kernel<<<1, 64>>>(PPART, g2, b2, PSCALE, PSHIFT, 64);
    bn_apply_split_kernel<<<(NQ * 64 + 255) / 256, 256>>>(PH2, PSCALE, PSHIFT, s2h, s2l, 64, 64, NQ * 64);

    conv_mma_kernel<9, 1, 64><<<313, 256, CONV_SMEM>>>(s2h, s2l, wch + WC3_OFF, wcl + WC3_OFF, PH3, 48);
    bn_stats_kernel<<<64, 48>>>(PH3, PPART, 48);
    bn_finalize_kernel<<<1, 48>>>(PPART, g3, b3, PSCALE, PSHIFT, 48);
    bn_apply_split_kernel<<<(NQ * 64 + 255) / 256, 256>>>(PH3, PSCALE, PSHIFT, s1h, s1l, 48, 64, NQ * 64);

    conv_mma_kernel<9, 1, 64><<<313, 256, CONV_SMEM>>>(s1h, s1l, wch + WC4_OFF, wcl + WC4_OFF, PH4, 48);
    bn_stats_kernel<<<64, 48>>>(PH4, PPART, 48);
    bn_finalize_kernel<<<1, 48>>>(PPART, g4, b4, PSCALE, PSHIFT, 48);
    head_conv_kernel<<<(NQ + 255) / 256, 256>>>(PH4, PSCALE, PSHIFT, objw, objb, out);
}

// round 8
// speedup vs baseline: 2.5314x; 1.0906x over previous
#include <cuda_runtime.h>
#include <cuda_bf16.h>
#include <cuda_fp16.h>
#include <cstdint>
#include <climits>

// ---------------- problem constants ----------------
constexpr int NQ = 40000;        // 200*200
constexpr int ED = 128;
constexpr int NV = 43520;        // sum of level sizes
constexpr int HEADS = 8;

// ---------------- scratch layout (floats) ----------------
constexpr size_t OFF_OA   = 0;                     // combined offsets+attn, NQ x 768
constexpr size_t SZ_OA    = (size_t)NQ * 768;
constexpr size_t OFF_Q    = OFF_OA + SZ_OA;
constexpr size_t SZ_Q     = (size_t)NQ * ED;
constexpr size_t OFF_T1   = OFF_Q + SZ_Q;
constexpr size_t OFF_T2   = OFF_T1 + SZ_Q;
constexpr size_t OFF_H1   = OFF_T2 + SZ_Q;
constexpr size_t SZ_H1    = (size_t)NQ * 128;
constexpr size_t OFF_H2   = OFF_H1 + SZ_H1;
constexpr size_t SZ_H2    = (size_t)NQ * 64;
constexpr size_t OFF_H3   = OFF_H2 + SZ_H2;
constexpr size_t SZ_H3    = (size_t)NQ * 48;
constexpr size_t OFF_H4   = OFF_H3 + SZ_H3;
constexpr size_t OFF_PART = OFF_H4 + SZ_H3;
constexpr size_t SZ_PART  = 64 * 128 * 2;
constexpr size_t OFF_SCALE= OFF_PART + SZ_PART;
constexpr size_t OFF_SHIFT= OFF_SCALE + 128;
constexpr size_t OFF_BIAS = OFF_SHIFT + 128;       // 2 layers x 768 packed bias
constexpr size_t SCRATCH_TOTAL = OFF_BIAS + 2 * 768;

__device__ float g_scratch[SCRATCH_TOTAL];
__device__ int   g_maxv;

// ---------------- bf16 / fp16 buffers ----------------
constexpr int W1CHUNKS = 98;                 // conv1: 49 taps * 2 ci-halves
__device__ __align__(16) __nv_bfloat16 g_s1h[(size_t)NQ * 128];
__device__ __align__(16) __nv_bfloat16 g_s1l[(size_t)NQ * 128];
__device__ __align__(16) __nv_bfloat16 g_s2h[(size_t)NQ * 128];
__device__ __align__(16) __nv_bfloat16 g_s2l[(size_t)NQ * 128];
__device__ __align__(16) __half        g_vx[(size_t)NV * 128];    // fp16 V for deform
__device__ __align__(16) __nv_bfloat16 g_vh[(size_t)NV * 128];
__device__ __align__(16) __nv_bfloat16 g_vl[(size_t)NV * 128];
__device__ __align__(16) __half        g_q16[(size_t)NQ * 128];   // fp16 q for conv1
__device__ __align__(16) __half        g_qp16[(size_t)NQ * 128];  // fp16 q+pos for OA gemm
// packed encoder weights (bf16x3 path): per layer 1280 cols x 128 k ([n][k])
__device__ __align__(16) __nv_bfloat16 g_wph[(size_t)2 * 1280 * 128];
__device__ __align__(16) __nv_bfloat16 g_wpl[(size_t)2 * 1280 * 128];
// OA weights fp16: per layer 768 x 128
__device__ __align__(16) __half g_woa16[(size_t)2 * 768 * 128];
// conv1 weights [chunk][co 128][k 64] fp16
__device__ __align__(16) __half g_w16[(size_t)W1CHUNKS * 128 * 64];
// convs 2-4 weights
constexpr int WC2_OFF = 0, WC3_OFF = 73728, WC4_OFF = 110592, WC_TOTAL = 147456;
__device__ __align__(16) __nv_bfloat16 g_wch[WC_TOTAL];
__device__ __align__(16) __nv_bfloat16 g_wcl[WC_TOTAL];

// ---------------- small helpers ----------------
__device__ __forceinline__ uint32_t smem_u32(const void* p) {
    return (uint32_t)__cvta_generic_to_shared(p);
}
__device__ __forceinline__ void cpasync16(uint32_t dst, const void* src, bool valid) {
    asm volatile("cp.async.cg.shared.global [%0], [%1], 16, %2;"
                 :: "r"(dst), "l"(src), "r"(valid ? 16u : 0u));
}
__device__ __forceinline__ void cp_commit() { asm volatile("cp.async.commit_group;"); }
__device__ __forceinline__ void cp_wait1()  { asm volatile("cp.async.wait_group 1;"); }
__device__ __forceinline__ void cp_wait0()  { asm volatile("cp.async.wait_group 0;"); }

__device__ __forceinline__ void ldmx4(uint32_t* r, uint32_t addr) {
    asm volatile("ldmatrix.sync.aligned.m8n8.x4.shared.b16 {%0,%1,%2,%3}, [%4];"
                 : "=r"(r[0]), "=r"(r[1]), "=r"(r[2]), "=r"(r[3]) : "r"(addr));
}
__device__ __forceinline__ void ldmx2(uint32_t* r, uint32_t addr) {
    asm volatile("ldmatrix.sync.aligned.m8n8.x2.shared.b16 {%0,%1}, [%2];"
                 : "=r"(r[0]), "=r"(r[1]) : "r"(addr));
}
__device__ __forceinline__ void mma_bf16(float* c, const uint32_t* a, const uint32_t* b) {
    asm volatile("mma.sync.aligned.m16n8k16.row.col.f32.bf16.bf16.f32 "
                 "{%0,%1,%2,%3}, {%4,%5,%6,%7}, {%8,%9}, {%0,%1,%2,%3};"
                 : "+f"(c[0]), "+f"(c[1]), "+f"(c[2]), "+f"(c[3])
                 : "r"(a[0]), "r"(a[1]), "r"(a[2]), "r"(a[3]), "r"(b[0]), "r"(b[1]));
}
__device__ __forceinline__ void mma_f16(float* c, const uint32_t* a, const uint32_t* b) {
    asm volatile("mma.sync.aligned.m16n8k16.row.col.f32.f16.f16.f32 "
                 "{%0,%1,%2,%3}, {%4,%5,%6,%7}, {%8,%9}, {%0,%1,%2,%3};"
                 : "+f"(c[0]), "+f"(c[1]), "+f"(c[2]), "+f"(c[3])
                 : "r"(a[0]), "r"(a[1]), "r"(a[2]), "r"(a[3]), "r"(b[0]), "r"(b[1]));
}
__device__ __forceinline__ void split2(float v, __nv_bfloat16& h, __nv_bfloat16& l) {
    h = __float2bfloat16(v);
    l = __float2bfloat16(v - __bfloat162float(h));
}

// ---------------- elementwise helpers ----------------
__global__ void init_max_kernel(int* gm) { *gm = INT_MIN; }

__global__ void reduce_max_kernel(const int* __restrict__ p, int* gm) {
    int v = INT_MIN;
    for (int k = blockIdx.x * blockDim.x + threadIdx.x; k < NQ; k += gridDim.x * blockDim.x)
        v = max(v, p[k]);
    #pragma unroll
    for (int o = 16; o > 0; o >>= 1) v = max(v, __shfl_xor_sync(0xffffffffu, v, o));
    __shared__ int sm[8];
    int w = threadIdx.x >> 5;
    if ((threadIdx.x & 31) == 0) sm[w] = v;
    __syncthreads();
    if (threadIdx.x == 0) {
        int bv = sm[0];
        for (int i = 1; i < (int)(blockDim.x >> 5); i++) bv = max(bv, sm[i]);
        atomicMax(gm, bv);
    }
}

__global__ void write_mask_kernel(const int* __restrict__ p, const int* __restrict__ gm,
                                  float* __restrict__ out) {
    int i = blockIdx.x * blockDim.x + threadIdx.x;
    if (i < NQ) out[i] = (p[i] < *gm) ? 1.0f : 0.0f;
}

__global__ void split_kernel(const float* __restrict__ X, __nv_bfloat16* __restrict__ hi,
                             __nv_bfloat16* __restrict__ lo, int n)
{
    int i = blockIdx.x * blockDim.x + threadIdx.x;
    if (i < n) split2(X[i], hi[i], lo[i]);
}

// q+pos -> fp16
__global__ void add_f16_kernel(const float* __restrict__ A, const float* __restrict__ B,
                               __half* __restrict__ o, int n)
{
    int i = blockIdx.x * blockDim.x + threadIdx.x;
    if (i < n) o[i] = __float2half_rn(A[i] + B[i]);
}

// pack encoder weight W [128][N] (k-major) -> hi/lo [N][128]
__global__ void packw_kernel(const float* __restrict__ W, __nv_bfloat16* __restrict__ hi,
                             __nv_bfloat16* __restrict__ lo, int N)
{
    int i = blockIdx.x * blockDim.x + threadIdx.x;
    if (i >= N * 128) return;
    int k = i & 127, n = i >> 7;
    split2(W[(size_t)k * N + n], hi[i], lo[i]);
}

// pack weight W [128][N] -> fp16 [N][128]
__global__ void packwf16_kernel(const float* __restrict__ W, __half* __restrict__ o, int N)
{
    int i = blockIdx.x * blockDim.x + threadIdx.x;
    if (i >= N * 128) return;
    int k = i & 127, n = i >> 7;
    o[i] = __float2half_rn(W[(size_t)k * N + n]);
}

__global__ void packbias_kernel(const float* __restrict__ boff, const float* __restrict__ battn,
                                float* __restrict__ dst)
{
    int i = threadIdx.x + blockIdx.x * blockDim.x;
    if (i < 768) dst[i] = (i < 512) ? boff[i] : battn[i - 512];
}

__global__ void packcw_kernel(const float* __restrict__ W, __nv_bfloat16* __restrict__ hi,
                              __nv_bfloat16* __restrict__ lo, int CO, int CI, int CIN_CH, int total)
{
    int i = blockIdx.x * blockDim.x + threadIdx.x;
    if (i >= total) return;
    int k = i & 63, co = (i >> 6) & 63, c = i >> 12;
    int e = c / CIN_CH, cih = c % CIN_CH;
    int ci = cih * 64 + k;
    float v = (co < CO && ci < CI) ? W[(((size_t)co * CI + ci) * 3 + e / 3) * 3 + e % 3] : 0.f;
    split2(v, hi[i], lo[i]);
}

// conv1 weight -> fp16 [chunk][co][k]
__global__ void wsplit16_kernel(const float* __restrict__ W, __half* __restrict__ w16)
{
    int i = blockIdx.x * blockDim.x + threadIdx.x;
    if (i >= W1CHUNKS * 128 * 64) return;
    int k  = i & 63;
    int co = (i >> 6) & 127;
    int c  = i >> 13;
    int e = c >> 1, ci = ((c & 1) << 6) + k;
    int ky = e / 7, kx = e % 7;
    w16[i] = __float2half_rn(W[(((size_t)co * 128 + ci) * 7 + ky) * 7 + kx]);
}

// ---------------- generic bf16x3 GEMM: C[M,N] = A[M,128] * B[N,128]^T ----------------
// FLAGS: 1 relu, 2 residual, 4 write fp32 C, 8 write split C, 16 write fp16 C
constexpr int GROWB = 272;
constexpr int GTILE = 128 * GROWB;
constexpr int GEMM_SMEM = 4 * GTILE;

template<int FLAGS>
__global__ void __launch_bounds__(256, 1) gemm_mma(
    const __nv_bfloat16* __restrict__ Ah, const __nv_bfloat16* __restrict__ Al,
    const __nv_bfloat16* __restrict__ Bh, const __nv_bfloat16* __restrict__ Bl,
    const float* __restrict__ bias, const float* __restrict__ R,
    float* __restrict__ Cf, __nv_bfloat16* __restrict__ Ch, __nv_bfloat16* __restrict__ Cl,
    __half* __restrict__ Cx, int M, int N)
{
    extern __shared__ char smem[];
    const int tid = threadIdx.x;
    const int wid = tid >> 5, lane = tid & 31;
    const int warp_m = wid >> 2, warp_n = wid & 3;
    const uint32_t sb = smem_u32(smem);
    const int bm = blockIdx.x * 128, bn = blockIdx.y * 128;

    {
        const int lrow = tid >> 1, lhalf = tid & 1;
        const bool aval = (bm + lrow) < M;
        const uint32_t sa = sb + (uint32_t)lrow * GROWB + (uint32_t)lhalf * 128;
        const char* agh = (const char*)(Ah + (size_t)(aval ? (bm + lrow) : 0) * 128 + lhalf * 64);
        const char* agl = (const char*)(Al + (size_t)(aval ? (bm + lrow) : 0) * 128 + lhalf * 64);
        const char* bgh = (const char*)(Bh + (size_t)(bn + lrow) * 128 + lhalf * 64);
        const char* bgl = (const char*)(Bl + (size_t)(bn + lrow) * 128 + lhalf * 64);
        #pragma unroll
        for (int i = 0; i < 8; i++) {
            cpasync16(sa + i * 16,             agh + i * 16, aval);
            cpasync16(sa + GTILE + i * 16,     agl + i * 16, aval);
            cpasync16(sa + 2 * GTILE + i * 16, bgh + i * 16, true);
            cpasync16(sa + 3 * GTILE + i * 16, bgl + i * 16, true);
        }
        cp_commit();
        cp_wait0();
        __syncthreads();
    }

    float acc[4][4][4];
    #pragma unroll
    for (int mt = 0; mt < 4; mt++)
        #pragma unroll
        for (int nt = 0; nt < 4; nt++)
            #pragma unroll
            for (int d = 0; d < 4; d++) acc[mt][nt][d] = 0.f;

    const uint32_t a_base = sb + (uint32_t)(warp_m * 64 + (lane & 15)) * GROWB + (uint32_t)(lane >> 4) * 16;
    const uint32_t b_base = sb + 2 * GTILE + (uint32_t)(warp_n * 32 + (lane & 7)) * GROWB
                          + (uint32_t)((lane >> 3) & 1) * 16;

    #pragma unroll
    for (int ks = 0; ks < 8; ks++) {
        const uint32_t kbyte = (uint32_t)ks * 32;
        uint32_t bh[4][2], bl[4][2];
        #pragma unroll
        for (int nt = 0; nt < 4; nt++) {
            ldmx2(bh[nt], b_base + (uint32_t)nt * 8 * GROWB + kbyte);
            ldmx2(bl[nt], b_base + GTILE + (uint32_t)nt * 8 * GROWB + kbyte);
        }
        #pragma unroll
        for (int mt = 0; mt < 4; mt++) {
            uint32_t ah[4], al[4];
            ldmx4(ah, a_base + (uint32_t)mt * 16 * GROWB + kbyte);
            ldmx4(al, a_base + GTILE + (uint32_t)mt * 16 * GROWB + kbyte);
            #pragma unroll
            for (int nt = 0; nt < 4; nt++) {
                mma_bf16(acc[mt][nt], ah, bh[nt]);
                mma_bf16(acc[mt][nt], ah, bl[nt]);
                mma_bf16(acc[mt][nt], al, bh[nt]);
            }
        }
    }

    const int g = lane >> 2, tg = lane & 3;
    #pragma unroll
    for (int mt = 0; mt < 4; mt++) {
        const int r0 = bm + warp_m * 64 + mt * 16 + g;
        #pragma unroll
        for (int nt = 0; nt < 4; nt++) {
            const int col = bn + warp_n * 32 + nt * 8 + tg * 2;
            float2 bb = *(const float2*)&bias[col];
            float v[4] = {acc[mt][nt][0] + bb.x, acc[mt][nt][1] + bb.y,
                          acc[mt][nt][2] + bb.x, acc[mt][nt][3] + bb.y};
            #pragma unroll
            for (int half = 0; half < 2; half++) {
                const int r = r0 + half * 8;
                if (r >= M) continue;
                float a0 = v[half * 2], a1 = v[half * 2 + 1];
                if (FLAGS & 2) {
                    float2 rr = *(const float2*)&R[(size_t)r * N + col];
                    a0 += rr.x; a1 += rr.y;
                }
                if (FLAGS & 1) { a0 = fmaxf(a0, 0.f); a1 = fmaxf(a1, 0.f); }
                if (FLAGS & 4)
                    *(float2*)&Cf[(size_t)r * N + col] = make_float2(a0, a1);
                if (FLAGS & 8) {
                    __nv_bfloat16 h0, l0, h1, l1;
                    split2(a0, h0, l0); split2(a1, h1, l1);
                    *(__nv_bfloat162*)&Ch[(size_t)r * N + col] = __nv_bfloat162(h0, h1);
                    *(__nv_bfloat162*)&Cl[(size_t)r * N + col] = __nv_bfloat162(l0, l1);
                }
                if (FLAGS & 16)
                    *(__half2*)&Cx[(size_t)r * N + col] = __floats2half2_rn(a0, a1);
            }
        }
    }
}

// ---------------- fp16 single GEMM (OA): C[M,N] = A[M,128] * B[N,128]^T + bias ----------------
constexpr int F16GEMM_SMEM = 2 * GTILE;   // A + B

__global__ void __launch_bounds__(256, 2) gemm_f16_kernel(
    const __half* __restrict__ A, const __half* __restrict__ B,
    const float* __restrict__ bias, float* __restrict__ Cf, int M, int N)
{
    extern __shared__ char smem[];
    const int tid = threadIdx.x;
    const int wid = tid >> 5, lane = tid & 31;
    const int warp_m = wid >> 2, warp_n = wid & 3;
    const uint32_t sb = smem_u32(smem);
    const int bm = blockIdx.x * 128, bn = blockIdx.y * 128;

    {
        const int lrow = tid >> 1, lhalf = tid & 1;
        const bool aval = (bm + lrow) < M;
        const uint32_t sa = sb + (uint32_t)lrow * GROWB + (uint32_t)lhalf * 128;
        const char* ag = (const char*)(A + (size_t)(aval ? (bm + lrow) : 0) * 128 + lhalf * 64);
        const char* bg = (const char*)(B + (size_t)(bn + lrow) * 128 + lhalf * 64);
        #pragma unroll
        for (int i = 0; i < 8; i++) {
            cpasync16(sa + i * 16,         ag + i * 16, aval);
            cpasync16(sa + GTILE + i * 16, bg + i * 16, true);
        }
        cp_commit();
        cp_wait0();
        __syncthreads();
    }

    float acc[4][4][4];
    #pragma unroll
    for (int mt = 0; mt < 4; mt++)
        #pragma unroll
        for (int nt = 0; nt < 4; nt++)
            #pragma unroll
            for (int d = 0; d < 4; d++) acc[mt][nt][d] = 0.f;

    const uint32_t a_base = sb + (uint32_t)(warp_m * 64 + (lane & 15)) * GROWB + (uint32_t)(lane >> 4) * 16;
    const uint32_t b_base = sb + GTILE + (uint32_t)(warp_n * 32 + (lane & 7)) * GROWB
                          + (uint32_t)((lane >> 3) & 1) * 16;

    #pragma unroll
    for (int ks = 0; ks < 8; ks++) {
        const uint32_t kbyte = (uint32_t)ks * 32;
        uint32_t bfr[4][2];
        #pragma unroll
        for (int nt = 0; nt < 4; nt++)
            ldmx2(bfr[nt], b_base + (uint32_t)nt * 8 * GROWB + kbyte);
        #pragma unroll
        for (int mt = 0; mt < 4; mt++) {
            uint32_t afr[4];
            ldmx4(afr, a_base + (uint32_t)mt * 16 * GROWB + kbyte);
            #pragma unroll
            for (int nt = 0; nt < 4; nt++)
                mma_f16(acc[mt][nt], afr, bfr[nt]);
        }
    }

    const int g = lane >> 2, tg = lane & 3;
    #pragma unroll
    for (int mt = 0; mt < 4; mt++) {
        const int r0 = bm + warp_m * 64 + mt * 16 + g;
        #pragma unroll
        for (int nt = 0; nt < 4; nt++) {
            const int col = bn + warp_n * 32 + nt * 8 + tg * 2;
            float2 bb = *(const float2*)&bias[col];
            #pragma unroll
            for (int half = 0; half < 2; half++) {
                const int r = r0 + half * 8;
                if (r >= M) continue;
                *(float2*)&Cf[(size_t)r * N + col] =
                    make_float2(acc[mt][nt][half * 2] + bb.x, acc[mt][nt][half * 2 + 1] + bb.y);
            }
        }
    }
}

// ---------------- deformable attention sampling (fp16 V, fused softmax, uint4 loads) ----------------
__global__ void __launch_bounds__(256) deform_kernel(
    const __half* __restrict__ VX, const float* __restrict__ OA,
    __nv_bfloat16* __restrict__ OH, __nv_bfloat16* __restrict__ OL)
{
    int t = blockIdx.x * 256 + threadIdx.x;
    if (t >= NQ * HEADS) return;
    const int n = t >> 3, h = t & 7;
    const float rx = ((float)(n % 200) + 0.5f) * (1.f / 200.f);
    const float ry = ((float)(n / 200) + 0.5f) * (1.f / 200.f);
    const float* op = OA + (size_t)n * 768 + h * 64;
    const float* ap = OA + (size_t)n * 768 + 512 + h * 32;

    float e[32];
    {
        float m = -1e30f;
        #pragma unroll
        for (int k = 0; k < 32; k++) { e[k] = ap[k]; m = fmaxf(m, e[k]); }
        float s = 0.f;
        #pragma unroll
        for (int k = 0; k < 32; k++) { e[k] = expf(e[k] - m); s += e[k]; }
        float inv = 1.f / s;
        #pragma unroll
        for (int k = 0; k < 32; k++) e[k] *= inv;
    }

    float acc[16];
    #pragma unroll
    for (int d = 0; d < 16; d++) acc[d] = 0.f;

    const int stc[4] = {0, 32768, 40960, 43008};
    const int Wc[4]  = {256, 128, 64, 32};
    const int Hc[4]  = {128, 64, 32, 16};

    #pragma unroll
    for (int l = 0; l < 4; l++) {
        const int W = Wc[l], H = Hc[l], st = stc[l];
        const float Wf = (float)W, Hf = (float)H;
        for (int p = 0; p < 8; p++) {
            float ox = op[(l * 8 + p) * 2 + 0];
            float oy = op[(l * 8 + p) * 2 + 1];
            float aw = e[l * 8 + p];
            float x = (rx + ox / Wf) * Wf - 0.5f;
            float y = (ry + oy / Hf) * Hf - 0.5f;
            float xf = floorf(x), yf = floorf(y);
            int x0 = (int)xf, y0 = (int)yf;
            float fx = x - xf, fy = y - yf;
            float wx[2] = {1.f - fx, fx};
            float wy[2] = {1.f - fy, fy};
            #pragma unroll
            for (int c = 0; c < 4; c++) {
                int xi = x0 + (c & 1), yi = y0 + (c >> 1);
                float wgt = wx[c & 1] * wy[c >> 1];
                if (xi >= 0 && xi < W && yi >= 0 && yi < H && wgt != 0.f) {
                    const uint4* gp = (const uint4*)(VX + ((size_t)(st + yi * W + xi)) * 128 + h * 16);
                    uint4 u0 = gp[0];
                    uint4 u1 = gp[1];
                    uint32_t wv[8] = {u0.x, u0.y, u0.z, u0.w, u1.x, u1.y, u1.z, u1.w};
                    float cw = aw * wgt;
                    #pragma unroll
                    for (int d = 0; d < 8; d++) {
                        float2 g2 = __half22float2(*(const __half2*)&wv[d]);
                        acc[d * 2 + 0] += cw * g2.x;
                        acc[d * 2 + 1] += cw * g2.y;
                    }
                }
            }
        }
    }
    __nv_bfloat162* oh = (__nv_bfloat162*)(OH + (size_t)n * 128 + h * 16);
    __nv_bfloat162* ol = (__nv_bfloat162*)(OL + (size_t)n * 128 + h * 16);
    #pragma unroll
    for (int d = 0; d < 8; d++) {
        __nv_bfloat16 h0, l0, h1, l1;
        split2(acc[d * 2], h0, l0); split2(acc[d * 2 + 1], h1, l1);
        oh[d] = __nv_bfloat162(h0, h1);
        ol[d] = __nv_bfloat162(l0, l1);
    }
}

// ---------------- layernorm over 128 per row ----------------
// MODE: 0 fp32 only, 1 + split(y), 3 + fp16(y), 4 + fp16(y + pos)
template<int MODE>
__global__ void ln_kernel(const float* __restrict__ X, const float* __restrict__ g,
                          const float* __restrict__ b, float* __restrict__ Y,
                          __nv_bfloat16* __restrict__ Yh, __nv_bfloat16* __restrict__ Yl,
                          __half* __restrict__ Yx, const float* __restrict__ pos)
{
    int r = blockIdx.x;
    int t = threadIdx.x;
    float x = X[(size_t)r * 128 + t];
    float s = x;
    #pragma unroll
    for (int o = 16; o > 0; o >>= 1) s += __shfl_xor_sync(0xffffffffu, s, o);
    __shared__ float sm[4], sm2[4];
    int w = t >> 5, lane = t & 31;
    if (lane == 0) sm[w] = s;
    __syncthreads();
    float m = (sm[0] + sm[1] + sm[2] + sm[3]) * (1.f / 128.f);
    float d = x - m;
    float q = d * d;
    #pragma unroll
    for (int o = 16; o > 0; o >>= 1) q += __shfl_xor_sync(0xffffffffu, q, o);
    if (lane == 0) sm2[w] = q;
    __syncthreads();
    float var = (sm2[0] + sm2[1] + sm2[2] + sm2[3]) * (1.f / 128.f);
    float y = d * rsqrtf(var + 1e-5f) * g[t] + b[t];
    Y[(size_t)r * 128 + t] = y;
    if (MODE == 1) {
        __nv_bfloat16 hh, ll;
        split2(y, hh, ll);
        Yh[(size_t)r * 128 + t] = hh;
        Yl[(size_t)r * 128 + t] = ll;
    }
    if (MODE == 3)
        Yx[(size_t)r * 128 + t] = __float2half_rn(y);
    if (MODE == 4)
        Yx[(size_t)r * 128 + t] = __float2half_rn(y + pos[(size_t)r * 128 + t]);
}

// ---------------- conv1 (7x7, 128->128) via mma.sync fp16 single ----------------
constexpr int ROWB = 144;
constexpr int C1TILE = 128 * ROWB;     // 18432
constexpr int C1BUF  = 2 * C1TILE;     // A + B
constexpr int CONV1_SMEM = 2 * C1BUF;  // 73728

__global__ void __launch_bounds__(256, 2) conv1_f16_kernel(
    const __half* __restrict__ q16, const __half* __restrict__ w16,
    float* __restrict__ Out)
{
    extern __shared__ char smem[];
    const int tid = threadIdx.x;
    const int wid = tid >> 5, lane = tid & 31;
    const int warp_m = wid >> 2, warp_n = wid & 3;
    const uint32_t sb = smem_u32(smem);
    const int bm = blockIdx.x * 128;

    const int lrow = tid >> 1, lhalf = tid & 1;
    const int pm = bm + lrow;
    const int py = pm / 200, px = pm % 200;
    const bool prow_ok = pm < NQ;
    const uint32_t s_arow = sb + (uint32_t)lrow * ROWB + (uint32_t)lhalf * 64;
    const uint32_t s_brow = s_arow + C1TILE;

    const uint32_t a_base = sb + (uint32_t)(warp_m * 64 + (lane & 15)) * ROWB + (uint32_t)(lane >> 4) * 16;
    const uint32_t b_base = sb + C1TILE + (uint32_t)(warp_n * 32 + (lane & 7)) * ROWB
                          + (uint32_t)((lane >> 3) & 1) * 16;

    float acc[4][4][4];
    #pragma unroll
    for (int mt = 0; mt < 4; mt++)
        #pragma unroll
        for (int nt = 0; nt < 4; nt++)
            #pragma unroll
            for (int d = 0; d < 4; d++) acc[mt][nt][d] = 0.f;

    auto load_chunk = [&](int c, int buf) {
        const int e = c >> 1, ch = c & 1;
        const int qy = py + e / 7 - 3;
        const int qx = px + e % 7 - 3;
        const bool val = prow_ok && qy >= 0 && qy < 200 && qx >= 0 && qx < 200;
        const size_t aoff = (size_t)(val ? (qy * 200 + qx) : 0) * 128 + (size_t)ch * 64 + (size_t)lhalf * 32;
        const char* ag = (const char*)(q16 + aoff);
        const size_t boff = ((size_t)c * 128 + lrow) * 64 + (size_t)lhalf * 32;
        const char* bg = (const char*)(w16 + boff);
        const uint32_t sa = s_arow + (uint32_t)buf * C1BUF;
        const uint32_t sbr = s_brow + (uint32_t)buf * C1BUF;
        #pragma unroll
        for (int i = 0; i < 4; i++) {
            cpasync16(sa + i * 16,  ag + i * 16, val);
            cpasync16(sbr + i * 16, bg + i * 16, true);
        }
    };

    load_chunk(0, 0); cp_commit();
    load_chunk(1, 1); cp_commit();

    for (int c = 0; c < W1CHUNKS; c++) {
        const int buf = c & 1;
        cp_wait1();
        __syncthreads();

        const uint32_t ab = a_base + (uint32_t)buf * C1BUF;
        const uint32_t bb = b_base + (uint32_t)buf * C1BUF;
        #pragma unroll
        for (int ks = 0; ks < 4; ks++) {
            const uint32_t kbyte = (uint32_t)ks * 32;
            uint32_t bfr[4][2];
            #pragma unroll
            for (int nt = 0; nt < 4; nt++)
                ldmx2(bfr[nt], bb + (uint32_t)nt * 8 * ROWB + kbyte);
            #pragma unroll
            for (int mt = 0; mt < 4; mt++) {
                uint32_t afr[4];
                ldmx4(afr, ab + (uint32_t)mt * 16 * ROWB + kbyte);
                #pragma unroll
                for (int nt = 0; nt < 4; nt++)
                    mma_f16(acc[mt][nt], afr, bfr[nt]);
            }
        }
        __syncthreads();
        if (c + 2 < W1CHUNKS) load_chunk(c + 2, buf);
        cp_commit();
    }

    const int g = lane >> 2, tg = lane & 3;
    #pragma unroll
    for (int mt = 0; mt < 4; mt++) {
        const int r0 = bm + warp_m * 64 + mt * 16 + g;
        #pragma unroll
        for (int nt = 0; nt < 4; nt++) {
            const int col = warp_n * 32 + nt * 8 + tg * 2;
            if (r0 < NQ)
                *(float2*)&Out[(size_t)r0 * 128 + col] = make_float2(acc[mt][nt][0], acc[mt][nt][1]);
            if (r0 + 8 < NQ)
                *(float2*)&Out[(size_t)(r0 + 8) * 128 + col] = make_float2(acc[mt][nt][2], acc[mt][nt][3]);
        }
    }
}

// ---------------- convs 2-4 (3x3) via mma.sync bf16x3, 128x64 tile ----------------
constexpr int CATILE = 128 * ROWB;
constexpr int CBTILE = 64 * ROWB;
constexpr int CBUF = 2 * CATILE + 2 * CBTILE;
constexpr int CONV_SMEM = 2 * CBUF;

template<int CHUNKS, int CIN_CH, int CST>
__global__ void __launch_bounds__(256, 2) conv_mma_kernel(
    const __nv_bfloat16* __restrict__ inh, const __nv_bfloat16* __restrict__ inl,
    const __nv_bfloat16* __restrict__ wh, const __nv_bfloat16* __restrict__ wl,
    float* __restrict__ Out, int COUT)
{
    extern __shared__ char smem[];
    const int tid = threadIdx.x;
    const int wid = tid >> 5, lane = tid & 31;
    const int warp_m = wid >> 1, warp_n = wid & 1;
    const uint32_t sb = smem_u32(smem);
    const int bm = blockIdx.x * 128;

    const int lrow = tid >> 1, lhalf = tid & 1;
    const int pm = bm + lrow;
    const int py = pm / 200, px = pm % 200;
    const bool prow_ok = pm < NQ;
    const uint32_t s_arow = sb + (uint32_t)lrow * ROWB + (uint32_t)lhalf * 64;
    const int brow = tid >> 2, bq = tid & 3;
    const uint32_t s_brow = sb + 2 * CATILE + (uint32_t)brow * ROWB + (uint32_t)bq * 32;

    const uint32_t a_base = sb + (uint32_t)(warp_m * 32 + (lane & 15)) * ROWB + (uint32_t)(lane >> 4) * 16;
    const uint32_t b_base = sb + 2 * CATILE + (uint32_t)(warp_n * 32 + (lane & 7)) * ROWB
                          + (uint32_t)((lane >> 3) & 1) * 16;

    float acc[2][4][4];
    #pragma unroll
    for (int mt = 0; mt < 2; mt++)
        #pragma unroll
        for (int nt = 0; nt < 4; nt++)
            #pragma unroll
            for (int d = 0; d < 4; d++) acc[mt][nt][d] = 0.f;

    auto load_chunk = [&](int c, int buf) {
        const int e = c / CIN_CH, cih = c % CIN_CH;
        const int qy = py + e / 3 - 1;
        const int qx = px + e % 3 - 1;
        const bool val = prow_ok && qy >= 0 && qy < 200 && qx >= 0 && qx < 200;
        const size_t aoff = (size_t)(val ? (qy * 200 + qx) : 0) * CST + (size_t)cih * 64 + (size_t)lhalf * 32;
        const char* agh = (const char*)(inh + aoff);
        const char* agl = (const char*)(inl + aoff);
        const size_t boff = ((size_t)c * 64 + brow) * 64 + (size_t)bq * 16;
        const char* bgh = (const char*)(wh + boff);
        const char* bgl = (const char*)(wl + boff);
        const uint32_t sa = s_arow + (uint32_t)buf * CBUF;
        const uint32_t sbr = s_brow + (uint32_t)buf * CBUF;
        #pragma unroll
        for (int i = 0; i < 4; i++) {
            cpasync16(sa + i * 16,           agh + i * 16, val);
            cpasync16(sa + CATILE + i * 16,  agl + i * 16, val);
        }
        #pragma unroll
        for (int i = 0; i < 2; i++) {
            cpasync16(sbr + i * 16,          bgh + i * 16, true);
            cpasync16(sbr + CBTILE + i * 16, bgl + i * 16, true);
        }
    };

    load_chunk(0, 0); cp_commit();
    load_chunk(1, 1); cp_commit();

    for (int c = 0; c < CHUNKS; c++) {
        const int buf = c & 1;
        cp_wait1();
        __syncthreads();

        const uint32_t ab = a_base + (uint32_t)buf * CBUF;
        const uint32_t bb = b_base + (uint32_t)buf * CBUF;
        #pragma unroll
        for (int ks = 0; ks < 4; ks++) {
            const uint32_t kbyte = (uint32_t)ks * 32;
            uint32_t bh[4][2], bl[4][2];
            #pragma unroll
            for (int nt = 0; nt < 4; nt++) {
                ldmx2(bh[nt], bb + (uint32_t)nt * 8 * ROWB + kbyte);
                ldmx2(bl[nt], bb + CBTILE + (uint32_t)nt * 8 * ROWB + kbyte);
            }
            #pragma unroll
            for (int mt = 0; mt < 2; mt++) {
                uint32_t ah[4], al[4];
                ldmx4(ah, ab + (uint32_t)mt * 16 * ROWB + kbyte);
                ldmx4(al, ab + CATILE + (uint32_t)mt * 16 * ROWB + kbyte);
                #pragma unroll
                for (int nt = 0; nt < 4; nt++) {
                    mma_bf16(acc[mt][nt], ah, bh[nt]);
                    mma_bf16(acc[mt][nt], ah, bl[nt]);
                    mma_bf16(acc[mt][nt], al, bh[nt]);
                }
            }
        }
        __syncthreads();
        if (c + 2 < CHUNKS) load_chunk(c + 2, buf);
        cp_commit();
    }

    const int g = lane >> 2, tg = lane & 3;
    #pragma unroll
    for (int mt = 0; mt < 2; mt++) {
        const int r0 = bm + warp_m * 32 + mt * 16 + g;
        #pragma unroll
        for (int nt = 0; nt < 4; nt++) {
            const int col = warp_n * 32 + nt * 8 + tg * 2;
            if (col >= COUT) continue;
            if (r0 < NQ)
                *(float2*)&Out[(size_t)r0 * COUT + col] = make_float2(acc[mt][nt][0], acc[mt][nt][1]);
            if (r0 + 8 < NQ)
                *(float2*)&Out[(size_t)(r0 + 8) * COUT + col] = make_float2(acc[mt][nt][2], acc[mt][nt][3]);
        }
    }
}

// ---------------- batchnorm ----------------
__global__ void bn_stats_kernel(const float* __restrict__ X, float* __restrict__ part, int C)
{
    int c = threadIdx.x;
    int g = blockIdx.x;
    const int per = (NQ + 63) / 64;
    int p0 = g * per;
    int p1 = min(NQ, p0 + per);
    float s = 0.f, q = 0.f;
    for (int p = p0; p < p1; p++) {
        float x = X[(size_t)p * C + c];
        s += x; q += x * x;
    }
    part[(size_t)g * 2 * C + c] = s;
    part[(size_t)g * 2 * C + C + c] = q;
}

__global__ void bn_finalize_kernel(const float* __restrict__ part,
                                   const float* __restrict__ gamma, const float* __restrict__ beta,
                                   float* __restrict__ scale, float* __restrict__ shift, int C)
{
    int c = threadIdx.x;
    float s = 0.f, q = 0.f;
    for (int g = 0; g < 64; g++) {
        s += part[(size_t)g * 2 * C + c];
        q += part[(size_t)g * 2 * C + C + c];
    }
    const float invP = 1.f / (float)NQ;
    float m = s * invP;
    float v = q * invP - m * m;
    float sc = gamma[c] * rsqrtf(v + 1e-5f);
    scale[c] = sc;
    shift[c] = beta[c] - m * sc;
}

__global__ void bn_apply_split_kernel(const float* __restrict__ X, const float* __restrict__ scale,
                                      const float* __restrict__ shift,
                                      __nv_bfloat16* __restrict__ hi, __nv_bfloat16* __restrict__ lo,
                                      int C, int CST, int total)
{
    int i = blockIdx.x * blockDim.x + threadIdx.x;
    if (i >= total) return;
    int c = i % CST;
    int p = i / CST;
    float v = 0.f;
    if (c < C) v = fmaxf(0.f, fmaf(X[(size_t)p * C + c], scale[c], shift[c]));
    split2(v, hi[i], lo[i]);
}

// ---------------- head: fused BN4+ReLU + 1x1 conv 48 -> 21, output NCHW ----------------
__global__ void head_conv_kernel(const float* __restrict__ H4raw, const float* __restrict__ scale,
                                 const float* __restrict__ shift,
                                 const float* __restrict__ Wo, const float* __restrict__ bo,
                                 float* __restrict__ out)
{
    int p = blockIdx.x * blockDim.x + threadIdx.x;
    if (p >= NQ) return;
    float x[48];
    const float4* hp = (const float4*)(H4raw + (size_t)p * 48);
    #pragma unroll
    for (int i = 0; i < 12; i++) {
        float4 v = hp[i];
        x[i * 4 + 0] = v.x; x[i * 4 + 1] = v.y; x[i * 4 + 2] = v.z; x[i * 4 + 3] = v.w;
    }
    #pragma unroll
    for (int ci = 0; ci < 48; ci++)
        x[ci] = fmaxf(0.f, fmaf(x[ci], scale[ci], shift[ci]));
    for (int co = 0; co < 21; co++) {
        float s = bo[co];
        const float* w = Wo + co * 48;
        #pragma unroll
        for (int ci = 0; ci < 48; ci++) s = fmaf(x[ci], w[ci], s);
        out[(size_t)co * NQ + p] = s;
    }
}

// ---------------- launch ----------------
extern "C" void kernel_launch(void* const* d_in, const int* in_sizes, int n_in,
                              void* d_out, int out_size)
{
    const float* value = (const float*)d_in[0];
    const float* bq    = (const float*)d_in[1];
    const float* bpos  = (const float*)d_in[2];
    const int*   proj  = (const int*)d_in[3];
    const float* Wv    = (const float*)d_in[4];
    const float* bv    = (const float*)d_in[5];
    const float* Woff  = (const float*)d_in[6];
    const float* boff  = (const float*)d_in[7];
    const float* Wattn = (const float*)d_in[8];
    const float* battn = (const float*)d_in[9];
    const float* Wout  = (const float*)d_in[10];
    const float* bout  = (const float*)d_in[11];
    const float* Wf1   = (const float*)d_in[12];
    const float* bf1   = (const float*)d_in[13];
    const float* Wf2   = (const float*)d_in[14];
    const float* bf2   = (const float*)d_in[15];
    const float* lng   = (const float*)d_in[16];
    const float* lnb   = (const float*)d_in[17];
    const float* cw1   = (const float*)d_in[18];
    const float* g1    = (const float*)d_in[19];
    const float* b1    = (const float*)d_in[20];
    const float* cw2   = (const float*)d_in[21];
    const float* g2    = (const float*)d_in[22];
    const float* b2    = (const float*)d_in[23];
    const float* cw3   = (const float*)d_in[24];
    const float* g3    = (const float*)d_in[25];
    const float* b3    = (const float*)d_in[26];
    const float* cw4   = (const float*)d_in[27];
    const float* g4    = (const float*)d_in[28];
    const float* b4    = (const float*)d_in[29];
    const float* objw  = (const float*)d_in[30];
    const float* objb  = (const float*)d_in[31];
    float* out = (float*)d_out;

    float* S = nullptr;
    cudaGetSymbolAddress((void**)&S, g_scratch);
    int* gm = nullptr;
    cudaGetSymbolAddress((void**)&gm, g_maxv);
    __nv_bfloat16 *s1h, *s1l, *s2h, *s2l, *vh, *vl, *wph, *wpl, *wch, *wcl;
    __half *vx, *q16, *qp16, *w16, *woa16;
    cudaGetSymbolAddress((void**)&s1h, g_s1h);
    cudaGetSymbolAddress((void**)&s1l, g_s1l);
    cudaGetSymbolAddress((void**)&s2h, g_s2h);
    cudaGetSymbolAddress((void**)&s2l, g_s2l);
    cudaGetSymbolAddress((void**)&vh,  g_vh);
    cudaGetSymbolAddress((void**)&vl,  g_vl);
    cudaGetSymbolAddress((void**)&vx,  g_vx);
    cudaGetSymbolAddress((void**)&q16, g_q16);
    cudaGetSymbolAddress((void**)&qp16, g_qp16);
    cudaGetSymbolAddress((void**)&w16, g_w16);
    cudaGetSymbolAddress((void**)&woa16, g_woa16);
    cudaGetSymbolAddress((void**)&wph, g_wph);
    cudaGetSymbolAddress((void**)&wpl, g_wpl);
    cudaGetSymbolAddress((void**)&wch, g_wch);
    cudaGetSymbolAddress((void**)&wcl, g_wcl);

    float* POA   = S + OFF_OA;
    float* PQ    = S + OFF_Q;
    float* PT1   = S + OFF_T1;
    float* PT2   = S + OFF_T2;
    float* PH1   = S + OFF_H1;
    float* PH2   = S + OFF_H2;
    float* PH3   = S + OFF_H3;
    float* PH4   = S + OFF_H4;
    float* PPART = S + OFF_PART;
    float* PSCALE= S + OFF_SCALE;
    float* PSHIFT= S + OFF_SHIFT;
    float* PBIAS = S + OFF_BIAS;

    cudaFuncSetAttribute(conv1_f16_kernel, cudaFuncAttributeMaxDynamicSharedMemorySize, CONV1_SMEM);
    cudaFuncSetAttribute(gemm_f16_kernel,  cudaFuncAttributeMaxDynamicSharedMemorySize, F16GEMM_SMEM);
    cudaFuncSetAttribute(gemm_mma<6>,  cudaFuncAttributeMaxDynamicSharedMemorySize, GEMM_SMEM);
    cudaFuncSetAttribute(gemm_mma<9>,  cudaFuncAttributeMaxDynamicSharedMemorySize, GEMM_SMEM);
    cudaFuncSetAttribute(gemm_mma<16>, cudaFuncAttributeMaxDynamicSharedMemorySize, GEMM_SMEM);
    cudaFuncSetAttribute((conv_mma_kernel<18, 2, 128>), cudaFuncAttributeMaxDynamicSharedMemorySize, CONV_SMEM);
    cudaFuncSetAttribute((conv_mma_kernel<9, 1, 64>),   cudaFuncAttributeMaxDynamicSharedMemorySize, CONV_SMEM);

    // --- observed_masks ---
    init_max_kernel<<<1, 1>>>(gm);
    reduce_max_kernel<<<40, 256>>>(proj, gm);
    write_mask_kernel<<<(NQ + 255) / 256, 256>>>(proj, gm, out + 21 * NQ);

    // --- weight prep ---
    wsplit16_kernel<<<(W1CHUNKS * 128 * 64 + 255) / 256, 256>>>(cw1, w16);
    packcw_kernel<<<(18 * 4096 + 255) / 256, 256>>>(cw2, wch + WC2_OFF, wcl + WC2_OFF, 64, 128, 2, 18 * 4096);
    packcw_kernel<<<(9 * 4096 + 255) / 256, 256>>>(cw3, wch + WC3_OFF, wcl + WC3_OFF, 48, 64, 1, 9 * 4096);
    packcw_kernel<<<(9 * 4096 + 255) / 256, 256>>>(cw4, wch + WC4_OFF, wcl + WC4_OFF, 48, 48, 1, 9 * 4096);
    for (int i = 0; i < 2; i++) {
        size_t LB = (size_t)i * 1280 * 128;
        size_t LO = (size_t)i * 768 * 128;
        packw_kernel<<<(128 * 128 + 255) / 256, 256>>>(Wv   + (size_t)i * 128 * 128, wph + LB,              wpl + LB,              128);
        packwf16_kernel<<<(512 * 128 + 255) / 256, 256>>>(Woff + (size_t)i * 128 * 512, woa16 + LO,             512);
        packwf16_kernel<<<(256 * 128 + 255) / 256, 256>>>(Wattn+ (size_t)i * 128 * 256, woa16 + LO + 512 * 128, 256);
        packw_kernel<<<(128 * 128 + 255) / 256, 256>>>(Wout + (size_t)i * 128 * 128, wph + LB + 896 * 128,  wpl + LB + 896 * 128,  128);
        packw_kernel<<<(128 * 128 + 255) / 256, 256>>>(Wf1  + (size_t)i * 128 * 128, wph + LB + 1024 * 128, wpl + LB + 1024 * 128, 128);
        packw_kernel<<<(128 * 128 + 255) / 256, 256>>>(Wf2  + (size_t)i * 128 * 128, wph + LB + 1152 * 128, wpl + LB + 1152 * 128, 128);
        packbias_kernel<<<3, 256>>>(boff + i * 512, battn + i * 256, PBIAS + i * 768);
    }
    split_kernel<<<(NV * 128 + 255) / 256, 256>>>(value, vh, vl, NV * 128);

    // --- q init ---
    cudaMemcpyAsync(PQ, bq, (size_t)NQ * ED * sizeof(float), cudaMemcpyDeviceToDevice);

    // --- 2 encoder layers ---
    add_f16_kernel<<<(NQ * ED + 255) / 256, 256>>>(PQ, bpos, qp16, NQ * ED);
    for (int i = 0; i < 2; i++) {
        size_t LB = (size_t)i * 1280 * 128;
        size_t LO = (size_t)i * 768 * 128;
        // V projection -> fp16 V for deform (bf16x3 for accuracy on the value path)
        gemm_mma<16><<<dim3(340, 1), 256, GEMM_SMEM>>>(vh, vl, wph + LB, wpl + LB,
                                                       bv + i * 128, nullptr, nullptr, nullptr, nullptr, vx, NV, 128);
        // combined Woff+Wattn: fp16 single-MMA GEMM (offsets/logits only)
        gemm_f16_kernel<<<dim3(313, 6), 256, F16GEMM_SMEM>>>(qp16, woa16 + LO, PBIAS + i * 768, POA, NQ, 768);
        deform_kernel<<<(NQ * HEADS + 255) / 256, 256>>>(vx, POA, s2h, s2l);
        gemm_mma<6><<<dim3(313, 1), 256, GEMM_SMEM>>>(s2h, s2l, wph + LB + 896 * 128, wpl + LB + 896 * 128,
                                                      bout + i * 128, PQ, PT1, nullptr, nullptr, nullptr, NQ, 128);
        ln_kernel<1><<<NQ, 128>>>(PT1, lng + (i * 2 + 0) * 128, lnb + (i * 2 + 0) * 128, PQ, s1h, s1l, nullptr, nullptr);
        gemm_mma<9><<<dim3(313, 1), 256, GEMM_SMEM>>>(s1h, s1l, wph + LB + 1024 * 128, wpl + LB + 1024 * 128,
                                                      bf1 + i * 128, nullptr, nullptr, s2h, s2l, nullptr, NQ, 128);
        gemm_mma<6><<<dim3(313, 1), 256, GEMM_SMEM>>>(s2h, s2l, wph + LB + 1152 * 128, wpl + LB + 1152 * 128,
                                                      bf2 + i * 128, PQ, PT2, nullptr, nullptr, nullptr, NQ, 128);
        if (i == 0)
            ln_kernel<4><<<NQ, 128>>>(PT2, lng + 1 * 128, lnb + 1 * 128, PQ, nullptr, nullptr, qp16, bpos);  // fp16(q+pos)
        else
            ln_kernel<3><<<NQ, 128>>>(PT2, lng + 3 * 128, lnb + 3 * 128, PQ, nullptr, nullptr, q16, nullptr); // fp16(q)
    }

    // --- conv head ---
    conv1_f16_kernel<<<313, 256, CONV1_SMEM>>>(q16, w16, PH1);
    bn_stats_kernel<<<64, 128>>>(PH1, PPART, 128);
    bn_finalize_kernel<<<1, 128>>>(PPART, g1, b1, PSCALE, PSHIFT, 128);
    bn_apply_split_kernel<<<(NQ * 128 + 255) / 256, 256>>>(PH1, PSCALE, PSHIFT, s1h, s1l, 128, 128, NQ * 128);

    conv_mma_kernel<18, 2, 128><<<313, 256, CONV_SMEM>>>(s1h, s1l, wch + WC2_OFF, wcl + WC2_OFF, PH2, 64);
    bn_stats_kernel<<<64, 64>>>(PH2, PPART, 64);
    bn_finalize_kernel<<<1, 64>>>(PPART, g2, b2, PSCALE, PSHIFT, 64);
    bn_apply_split_kernel<<<(NQ * 64 + 255) / 256, 256>>>(PH2, PSCALE, PSHIFT, s2h, s2l, 64, 64, NQ * 64);

    conv_mma_kernel<9, 1, 64><<<313, 256, CONV_SMEM>>>(s2h, s2l, wch + WC3_OFF, wcl + WC3_OFF, PH3, 48);
    bn_stats_kernel<<<64, 48>>>(PH3, PPART, 48);
    bn_finalize_kernel<<<1, 48>>>(PPART, g3, b3, PSCALE, PSHIFT, 48);
    bn_apply_split_kernel<<<(NQ * 64 + 255) / 256, 256>>>(PH3, PSCALE, PSHIFT, s1h, s1l, 48, 64, NQ * 64);

    conv_mma_kernel<9, 1, 64><<<313, 256, CONV_SMEM>>>(s1h, s1l, wch + WC4_OFF, wcl + WC4_OFF, PH4, 48);
    bn_stats_kernel<<<64, 48>>>(PH4, PPART, 48);
    bn_finalize_kernel<<<1, 48>>>(PPART, g4, b4, PSCALE, PSHIFT, 48);
    head_conv_kernel<<<(NQ + 255) / 256, 256>>>(PH4, PSCALE, PSHIFT, objw, objb, out);
}

// round 9
// speedup vs baseline: 2.7556x; 1.0886x over previous
#include <cuda_runtime.h>
#include <cuda_bf16.h>
#include <cuda_fp16.h>
#include <cstdint>
#include <climits>

// ---------------- problem constants ----------------
constexpr int NQ = 40000;        // 200*200
constexpr int ED = 128;
constexpr int NV = 43520;        // sum of level sizes
constexpr int HEADS = 8;
constexpr int NPART = 320;       // bn partial blocks

// ---------------- scratch layout (floats) ----------------
constexpr size_t OFF_Q    = 0;
constexpr size_t SZ_Q     = (size_t)NQ * ED;
constexpr size_t OFF_T1   = OFF_Q + SZ_Q;
constexpr size_t OFF_T2   = OFF_T1 + SZ_Q;
constexpr size_t OFF_H1   = OFF_T2 + SZ_Q;
constexpr size_t SZ_H1    = (size_t)NQ * 128;
constexpr size_t OFF_H2   = OFF_H1 + SZ_H1;
constexpr size_t SZ_H2    = (size_t)NQ * 64;
constexpr size_t OFF_H3   = OFF_H2 + SZ_H2;
constexpr size_t SZ_H3    = (size_t)NQ * 48;
constexpr size_t OFF_H4   = OFF_H3 + SZ_H3;
constexpr size_t OFF_PART = OFF_H4 + SZ_H3;
constexpr size_t SZ_PART  = (size_t)NPART * 2 * 128;
constexpr size_t OFF_SCALE= OFF_PART + SZ_PART;
constexpr size_t OFF_SHIFT= OFF_SCALE + 128;
constexpr size_t OFF_BIAS = OFF_SHIFT + 128;       // 2 layers x 768 packed bias
constexpr size_t SCRATCH_TOTAL = OFF_BIAS + 2 * 768;

__device__ float g_scratch[SCRATCH_TOTAL];
__device__ int   g_maxv;

// ---------------- bf16 / fp16 buffers ----------------
constexpr int W1CHUNKS = 98;                 // conv1: 49 taps * 2 ci-halves
__device__ __align__(16) __nv_bfloat16 g_s1h[(size_t)NQ * 128];
__device__ __align__(16) __nv_bfloat16 g_s1l[(size_t)NQ * 128];
__device__ __align__(16) __nv_bfloat16 g_s2h[(size_t)NQ * 128];
__device__ __align__(16) __nv_bfloat16 g_s2l[(size_t)NQ * 128];
__device__ __align__(16) __half        g_vx[(size_t)NV * 128];    // fp16 V for deform
__device__ __align__(16) __nv_bfloat16 g_vh[(size_t)NV * 128];
__device__ __align__(16) __nv_bfloat16 g_vl[(size_t)NV * 128];
__device__ __align__(16) __half        g_q16[(size_t)NQ * 128];   // fp16 q for conv1
__device__ __align__(16) __half        g_qp16[(size_t)NQ * 128];  // fp16 q+pos for OA gemm
__device__ __align__(16) __half        g_oa16[(size_t)NQ * 768];  // fp16 offsets+logits
// packed encoder weights (bf16x3 path): per layer 1280 cols x 128 k ([n][k])
__device__ __align__(16) __nv_bfloat16 g_wph[(size_t)2 * 1280 * 128];
__device__ __align__(16) __nv_bfloat16 g_wpl[(size_t)2 * 1280 * 128];
// OA weights fp16: per layer 768 x 128
__device__ __align__(16) __half g_woa16[(size_t)2 * 768 * 128];
// conv1 weights [chunk][co 128][k 64] fp16
__device__ __align__(16) __half g_w16[(size_t)W1CHUNKS * 128 * 64];
// convs 2-4 weights
constexpr int WC2_OFF = 0, WC3_OFF = 73728, WC4_OFF = 110592, WC_TOTAL = 147456;
__device__ __align__(16) __nv_bfloat16 g_wch[WC_TOTAL];
__device__ __align__(16) __nv_bfloat16 g_wcl[WC_TOTAL];

// ---------------- small helpers ----------------
__device__ __forceinline__ uint32_t smem_u32(const void* p) {
    return (uint32_t)__cvta_generic_to_shared(p);
}
__device__ __forceinline__ void cpasync16(uint32_t dst, const void* src, bool valid) {
    asm volatile("cp.async.cg.shared.global [%0], [%1], 16, %2;"
                 :: "r"(dst), "l"(src), "r"(valid ? 16u : 0u));
}
__device__ __forceinline__ void cp_commit() { asm volatile("cp.async.commit_group;"); }
__device__ __forceinline__ void cp_wait1()  { asm volatile("cp.async.wait_group 1;"); }
__device__ __forceinline__ void cp_wait0()  { asm volatile("cp.async.wait_group 0;"); }

__device__ __forceinline__ void ldmx4(uint32_t* r, uint32_t addr) {
    asm volatile("ldmatrix.sync.aligned.m8n8.x4.shared.b16 {%0,%1,%2,%3}, [%4];"
                 : "=r"(r[0]), "=r"(r[1]), "=r"(r[2]), "=r"(r[3]) : "r"(addr));
}
__device__ __forceinline__ void ldmx2(uint32_t* r, uint32_t addr) {
    asm volatile("ldmatrix.sync.aligned.m8n8.x2.shared.b16 {%0,%1}, [%2];"
                 : "=r"(r[0]), "=r"(r[1]) : "r"(addr));
}
__device__ __forceinline__ void mma_bf16(float* c, const uint32_t* a, const uint32_t* b) {
    asm volatile("mma.sync.aligned.m16n8k16.row.col.f32.bf16.bf16.f32 "
                 "{%0,%1,%2,%3}, {%4,%5,%6,%7}, {%8,%9}, {%0,%1,%2,%3};"
                 : "+f"(c[0]), "+f"(c[1]), "+f"(c[2]), "+f"(c[3])
                 : "r"(a[0]), "r"(a[1]), "r"(a[2]), "r"(a[3]), "r"(b[0]), "r"(b[1]));
}
__device__ __forceinline__ void mma_f16(float* c, const uint32_t* a, const uint32_t* b) {
    asm volatile("mma.sync.aligned.m16n8k16.row.col.f32.f16.f16.f32 "
                 "{%0,%1,%2,%3}, {%4,%5,%6,%7}, {%8,%9}, {%0,%1,%2,%3};"
                 : "+f"(c[0]), "+f"(c[1]), "+f"(c[2]), "+f"(c[3])
                 : "r"(a[0]), "r"(a[1]), "r"(a[2]), "r"(a[3]), "r"(b[0]), "r"(b[1]));
}
__device__ __forceinline__ void split2(float v, __nv_bfloat16& h, __nv_bfloat16& l) {
    h = __float2bfloat16(v);
    l = __float2bfloat16(v - __bfloat162float(h));
}

// ---------------- elementwise helpers ----------------
__global__ void init_max_kernel(int* gm) { *gm = INT_MIN; }

__global__ void reduce_max_kernel(const int* __restrict__ p, int* gm) {
    int v = INT_MIN;
    for (int k = blockIdx.x * blockDim.x + threadIdx.x; k < NQ; k += gridDim.x * blockDim.x)
        v = max(v, p[k]);
    #pragma unroll
    for (int o = 16; o > 0; o >>= 1) v = max(v, __shfl_xor_sync(0xffffffffu, v, o));
    __shared__ int sm[8];
    int w = threadIdx.x >> 5;
    if ((threadIdx.x & 31) == 0) sm[w] = v;
    __syncthreads();
    if (threadIdx.x == 0) {
        int bv = sm[0];
        for (int i = 1; i < (int)(blockDim.x >> 5); i++) bv = max(bv, sm[i]);
        atomicMax(gm, bv);
    }
}

__global__ void write_mask_kernel(const int* __restrict__ p, const int* __restrict__ gm,
                                  float* __restrict__ out) {
    int i = blockIdx.x * blockDim.x + threadIdx.x;
    if (i < NQ) out[i] = (p[i] < *gm) ? 1.0f : 0.0f;
}

__global__ void split_kernel(const float* __restrict__ X, __nv_bfloat16* __restrict__ hi,
                             __nv_bfloat16* __restrict__ lo, int n)
{
    int i = blockIdx.x * blockDim.x + threadIdx.x;
    if (i < n) split2(X[i], hi[i], lo[i]);
}

// q+pos -> fp16
__global__ void add_f16_kernel(const float* __restrict__ A, const float* __restrict__ B,
                               __half* __restrict__ o, int n)
{
    int i = blockIdx.x * blockDim.x + threadIdx.x;
    if (i < n) o[i] = __float2half_rn(A[i] + B[i]);
}

// pack encoder weight W [128][N] (k-major) -> hi/lo [N][128]
__global__ void packw_kernel(const float* __restrict__ W, __nv_bfloat16* __restrict__ hi,
                             __nv_bfloat16* __restrict__ lo, int N)
{
    int i = blockIdx.x * blockDim.x + threadIdx.x;
    if (i >= N * 128) return;
    int k = i & 127, n = i >> 7;
    split2(W[(size_t)k * N + n], hi[i], lo[i]);
}

// pack weight W [128][N] -> fp16 [N][128]
__global__ void packwf16_kernel(const float* __restrict__ W, __half* __restrict__ o, int N)
{
    int i = blockIdx.x * blockDim.x + threadIdx.x;
    if (i >= N * 128) return;
    int k = i & 127, n = i >> 7;
    o[i] = __float2half_rn(W[(size_t)k * N + n]);
}

__global__ void packbias_kernel(const float* __restrict__ boff, const float* __restrict__ battn,
                                float* __restrict__ dst)
{
    int i = threadIdx.x + blockIdx.x * blockDim.x;
    if (i < 768) dst[i] = (i < 512) ? boff[i] : battn[i - 512];
}

__global__ void packcw_kernel(const float* __restrict__ W, __nv_bfloat16* __restrict__ hi,
                              __nv_bfloat16* __restrict__ lo, int CO, int CI, int CIN_CH, int total)
{
    int i = blockIdx.x * blockDim.x + threadIdx.x;
    if (i >= total) return;
    int k = i & 63, co = (i >> 6) & 63, c = i >> 12;
    int e = c / CIN_CH, cih = c % CIN_CH;
    int ci = cih * 64 + k;
    float v = (co < CO && ci < CI) ? W[(((size_t)co * CI + ci) * 3 + e / 3) * 3 + e % 3] : 0.f;
    split2(v, hi[i], lo[i]);
}

// conv1 weight -> fp16 [chunk][co][k]
__global__ void wsplit16_kernel(const float* __restrict__ W, __half* __restrict__ w16)
{
    int i = blockIdx.x * blockDim.x + threadIdx.x;
    if (i >= W1CHUNKS * 128 * 64) return;
    int k  = i & 63;
    int co = (i >> 6) & 127;
    int c  = i >> 13;
    int e = c >> 1, ci = ((c & 1) << 6) + k;
    int ky = e / 7, kx = e % 7;
    w16[i] = __float2half_rn(W[(((size_t)co * 128 + ci) * 7 + ky) * 7 + kx]);
}

// ---------------- generic bf16x3 GEMM: C[M,N] = A[M,128] * B[N,128]^T ----------------
// FLAGS: 1 relu, 2 residual, 4 write fp32 C, 8 write split C, 16 write fp16 C
constexpr int GROWB = 272;
constexpr int GTILE = 128 * GROWB;
constexpr int GEMM_SMEM = 4 * GTILE;

template<int FLAGS>
__global__ void __launch_bounds__(256, 1) gemm_mma(
    const __nv_bfloat16* __restrict__ Ah, const __nv_bfloat16* __restrict__ Al,
    const __nv_bfloat16* __restrict__ Bh, const __nv_bfloat16* __restrict__ Bl,
    const float* __restrict__ bias, const float* __restrict__ R,
    float* __restrict__ Cf, __nv_bfloat16* __restrict__ Ch, __nv_bfloat16* __restrict__ Cl,
    __half* __restrict__ Cx, int M, int N)
{
    extern __shared__ char smem[];
    const int tid = threadIdx.x;
    const int wid = tid >> 5, lane = tid & 31;
    const int warp_m = wid >> 2, warp_n = wid & 3;
    const uint32_t sb = smem_u32(smem);
    const int bm = blockIdx.x * 128, bn = blockIdx.y * 128;

    {
        const int lrow = tid >> 1, lhalf = tid & 1;
        const bool aval = (bm + lrow) < M;
        const uint32_t sa = sb + (uint32_t)lrow * GROWB + (uint32_t)lhalf * 128;
        const char* agh = (const char*)(Ah + (size_t)(aval ? (bm + lrow) : 0) * 128 + lhalf * 64);
        const char* agl = (const char*)(Al + (size_t)(aval ? (bm + lrow) : 0) * 128 + lhalf * 64);
        const char* bgh = (const char*)(Bh + (size_t)(bn + lrow) * 128 + lhalf * 64);
        const char* bgl = (const char*)(Bl + (size_t)(bn + lrow) * 128 + lhalf * 64);
        #pragma unroll
        for (int i = 0; i < 8; i++) {
            cpasync16(sa + i * 16,             agh + i * 16, aval);
            cpasync16(sa + GTILE + i * 16,     agl + i * 16, aval);
            cpasync16(sa + 2 * GTILE + i * 16, bgh + i * 16, true);
            cpasync16(sa + 3 * GTILE + i * 16, bgl + i * 16, true);
        }
        cp_commit();
        cp_wait0();
        __syncthreads();
    }

    float acc[4][4][4];
    #pragma unroll
    for (int mt = 0; mt < 4; mt++)
        #pragma unroll
        for (int nt = 0; nt < 4; nt++)
            #pragma unroll
            for (int d = 0; d < 4; d++) acc[mt][nt][d] = 0.f;

    const uint32_t a_base = sb + (uint32_t)(warp_m * 64 + (lane & 15)) * GROWB + (uint32_t)(lane >> 4) * 16;
    const uint32_t b_base = sb + 2 * GTILE + (uint32_t)(warp_n * 32 + (lane & 7)) * GROWB
                          + (uint32_t)((lane >> 3) & 1) * 16;

    #pragma unroll
    for (int ks = 0; ks < 8; ks++) {
        const uint32_t kbyte = (uint32_t)ks * 32;
        uint32_t bh[4][2], bl[4][2];
        #pragma unroll
        for (int nt = 0; nt < 4; nt++) {
            ldmx2(bh[nt], b_base + (uint32_t)nt * 8 * GROWB + kbyte);
            ldmx2(bl[nt], b_base + GTILE + (uint32_t)nt * 8 * GROWB + kbyte);
        }
        #pragma unroll
        for (int mt = 0; mt < 4; mt++) {
            uint32_t ah[4], al[4];
            ldmx4(ah, a_base + (uint32_t)mt * 16 * GROWB + kbyte);
            ldmx4(al, a_base + GTILE + (uint32_t)mt * 16 * GROWB + kbyte);
            #pragma unroll
            for (int nt = 0; nt < 4; nt++) {
                mma_bf16(acc[mt][nt], ah, bh[nt]);
                mma_bf16(acc[mt][nt], ah, bl[nt]);
                mma_bf16(acc[mt][nt], al, bh[nt]);
            }
        }
    }

    const int g = lane >> 2, tg = lane & 3;
    #pragma unroll
    for (int mt = 0; mt < 4; mt++) {
        const int r0 = bm + warp_m * 64 + mt * 16 + g;
        #pragma unroll
        for (int nt = 0; nt < 4; nt++) {
            const int col = bn + warp_n * 32 + nt * 8 + tg * 2;
            float2 bb = *(const float2*)&bias[col];
            float v[4] = {acc[mt][nt][0] + bb.x, acc[mt][nt][1] + bb.y,
                          acc[mt][nt][2] + bb.x, acc[mt][nt][3] + bb.y};
            #pragma unroll
            for (int half = 0; half < 2; half++) {
                const int r = r0 + half * 8;
                if (r >= M) continue;
                float a0 = v[half * 2], a1 = v[half * 2 + 1];
                if (FLAGS & 2) {
                    float2 rr = *(const float2*)&R[(size_t)r * N + col];
                    a0 += rr.x; a1 += rr.y;
                }
                if (FLAGS & 1) { a0 = fmaxf(a0, 0.f); a1 = fmaxf(a1, 0.f); }
                if (FLAGS & 4)
                    *(float2*)&Cf[(size_t)r * N + col] = make_float2(a0, a1);
                if (FLAGS & 8) {
                    __nv_bfloat16 h0, l0, h1, l1;
                    split2(a0, h0, l0); split2(a1, h1, l1);
                    *(__nv_bfloat162*)&Ch[(size_t)r * N + col] = __nv_bfloat162(h0, h1);
                    *(__nv_bfloat162*)&Cl[(size_t)r * N + col] = __nv_bfloat162(l0, l1);
                }
                if (FLAGS & 16)
                    *(__half2*)&Cx[(size_t)r * N + col] = __floats2half2_rn(a0, a1);
            }
        }
    }
}

// ---------------- fp16 single GEMM (OA): C[M,N] = A[M,128] * B[N,128]^T + bias -> fp16 ----------------
constexpr int F16GEMM_SMEM = 2 * GTILE;   // A + B

__global__ void __launch_bounds__(256, 2) gemm_f16_kernel(
    const __half* __restrict__ A, const __half* __restrict__ B,
    const float* __restrict__ bias, __half* __restrict__ Cx, int M, int N)
{
    extern __shared__ char smem[];
    const int tid = threadIdx.x;
    const int wid = tid >> 5, lane = tid & 31;
    const int warp_m = wid >> 2, warp_n = wid & 3;
    const uint32_t sb = smem_u32(smem);
    const int bm = blockIdx.x * 128, bn = blockIdx.y * 128;

    {
        const int lrow = tid >> 1, lhalf = tid & 1;
        const bool aval = (bm + lrow) < M;
        const uint32_t sa = sb + (uint32_t)lrow * GROWB + (uint32_t)lhalf * 128;
        const char* ag = (const char*)(A + (size_t)(aval ? (bm + lrow) : 0) * 128 + lhalf * 64);
        const char* bg = (const char*)(B + (size_t)(bn + lrow) * 128 + lhalf * 64);
        #pragma unroll
        for (int i = 0; i < 8; i++) {
            cpasync16(sa + i * 16,         ag + i * 16, aval);
            cpasync16(sa + GTILE + i * 16, bg + i * 16, true);
        }
        cp_commit();
        cp_wait0();
        __syncthreads();
    }

    float acc[4][4][4];
    #pragma unroll
    for (int mt = 0; mt < 4; mt++)
        #pragma unroll
        for (int nt = 0; nt < 4; nt++)
            #pragma unroll
            for (int d = 0; d < 4; d++) acc[mt][nt][d] = 0.f;

    const uint32_t a_base = sb + (uint32_t)(warp_m * 64 + (lane & 15)) * GROWB + (uint32_t)(lane >> 4) * 16;
    const uint32_t b_base = sb + GTILE + (uint32_t)(warp_n * 32 + (lane & 7)) * GROWB
                          + (uint32_t)((lane >> 3) & 1) * 16;

    #pragma unroll
    for (int ks = 0; ks < 8; ks++) {
        const uint32_t kbyte = (uint32_t)ks * 32;
        uint32_t bfr[4][2];
        #pragma unroll
        for (int nt = 0; nt < 4; nt++)
            ldmx2(bfr[nt], b_base + (uint32_t)nt * 8 * GROWB + kbyte);
        #pragma unroll
        for (int mt = 0; mt < 4; mt++) {
            uint32_t afr[4];
            ldmx4(afr, a_base + (uint32_t)mt * 16 * GROWB + kbyte);
            #pragma unroll
            for (int nt = 0; nt < 4; nt++)
                mma_f16(acc[mt][nt], afr, bfr[nt]);
        }
    }

    const int g = lane >> 2, tg = lane & 3;
    #pragma unroll
    for (int mt = 0; mt < 4; mt++) {
        const int r0 = bm + warp_m * 64 + mt * 16 + g;
        #pragma unroll
        for (int nt = 0; nt < 4; nt++) {
            const int col = bn + warp_n * 32 + nt * 8 + tg * 2;
            float2 bb = *(const float2*)&bias[col];
            #pragma unroll
            for (int half = 0; half < 2; half++) {
                const int r = r0 + half * 8;
                if (r >= M) continue;
                *(__half2*)&Cx[(size_t)r * N + col] =
                    __floats2half2_rn(acc[mt][nt][half * 2] + bb.x, acc[mt][nt][half * 2 + 1] + bb.y);
            }
        }
    }
}

// ---------------- deformable attention sampling (fp16 V + fp16 OA, fused softmax) ----------------
__global__ void __launch_bounds__(256) deform_kernel(
    const __half* __restrict__ VX, const __half* __restrict__ OA,
    __nv_bfloat16* __restrict__ OH, __nv_bfloat16* __restrict__ OL)
{
    int t = blockIdx.x * 256 + threadIdx.x;
    if (t >= NQ * HEADS) return;
    const int n = t >> 3, h = t & 7;
    const float rx = ((float)(n % 200) + 0.5f) * (1.f / 200.f);
    const float ry = ((float)(n / 200) + 0.5f) * (1.f / 200.f);
    const __half* op = OA + (size_t)n * 768 + h * 64;
    const __half* ap = OA + (size_t)n * 768 + 512 + h * 32;

    // in-register softmax over the 32 logits (vectorized fp16 loads)
    float e[32];
    {
        const uint4* apv = (const uint4*)ap;
        #pragma unroll
        for (int q = 0; q < 4; q++) {
            uint4 u = apv[q];
            uint32_t wv[4] = {u.x, u.y, u.z, u.w};
            #pragma unroll
            for (int d = 0; d < 4; d++) {
                float2 f2 = __half22float2(*(const __half2*)&wv[d]);
                e[q * 8 + d * 2 + 0] = f2.x;
                e[q * 8 + d * 2 + 1] = f2.y;
            }
        }
        float m = -1e30f;
        #pragma unroll
        for (int k = 0; k < 32; k++) m = fmaxf(m, e[k]);
        float s = 0.f;
        #pragma unroll
        for (int k = 0; k < 32; k++) { e[k] = expf(e[k] - m); s += e[k]; }
        float inv = 1.f / s;
        #pragma unroll
        for (int k = 0; k < 32; k++) e[k] *= inv;
    }

    float acc[16];
    #pragma unroll
    for (int d = 0; d < 16; d++) acc[d] = 0.f;

    const int stc[4] = {0, 32768, 40960, 43008};
    const int Wc[4]  = {256, 128, 64, 32};
    const int Hc[4]  = {128, 64, 32, 16};

    #pragma unroll
    for (int l = 0; l < 4; l++) {
        const int W = Wc[l], H = Hc[l], st = stc[l];
        const float Wf = (float)W, Hf = (float)H;
        for (int p = 0; p < 8; p++) {
            float2 off2 = __half22float2(*(const __half2*)(op + (l * 8 + p) * 2));
            float aw = e[l * 8 + p];
            float x = (rx + off2.x / Wf) * Wf - 0.5f;
            float y = (ry + off2.y / Hf) * Hf - 0.5f;
            float xf = floorf(x), yf = floorf(y);
            int x0 = (int)xf, y0 = (int)yf;
            float fx = x - xf, fy = y - yf;
            float wx[2] = {1.f - fx, fx};
            float wy[2] = {1.f - fy, fy};
            #pragma unroll
            for (int c = 0; c < 4; c++) {
                int xi = x0 + (c & 1), yi = y0 + (c >> 1);
                float wgt = wx[c & 1] * wy[c >> 1];
                if (xi >= 0 && xi < W && yi >= 0 && yi < H && wgt != 0.f) {
                    const uint4* gp = (const uint4*)(VX + ((size_t)(st + yi * W + xi)) * 128 + h * 16);
                    uint4 u0 = gp[0];
                    uint4 u1 = gp[1];
                    uint32_t wv[8] = {u0.x, u0.y, u0.z, u0.w, u1.x, u1.y, u1.z, u1.w};
                    float cw = aw * wgt;
                    #pragma unroll
                    for (int d = 0; d < 8; d++) {
                        float2 g2 = __half22float2(*(const __half2*)&wv[d]);
                        acc[d * 2 + 0] += cw * g2.x;
                        acc[d * 2 + 1] += cw * g2.y;
                    }
                }
            }
        }
    }
    __nv_bfloat162* oh = (__nv_bfloat162*)(OH + (size_t)n * 128 + h * 16);
    __nv_bfloat162* ol = (__nv_bfloat162*)(OL + (size_t)n * 128 + h * 16);
    #pragma unroll
    for (int d = 0; d < 8; d++) {
        __nv_bfloat16 h0, l0, h1, l1;
        split2(acc[d * 2], h0, l0); split2(acc[d * 2 + 1], h1, l1);
        oh[d] = __nv_bfloat162(h0, h1);
        ol[d] = __nv_bfloat162(l0, l1);
    }
}

// ---------------- layernorm over 128 per row ----------------
// MODE: 0 fp32 only, 1 + split(y), 3 + fp16(y), 4 + fp16(y + pos)
template<int MODE>
__global__ void ln_kernel(const float* __restrict__ X, const float* __restrict__ g,
                          const float* __restrict__ b, float* __restrict__ Y,
                          __nv_bfloat16* __restrict__ Yh, __nv_bfloat16* __restrict__ Yl,
                          __half* __restrict__ Yx, const float* __restrict__ pos)
{
    int r = blockIdx.x;
    int t = threadIdx.x;
    float x = X[(size_t)r * 128 + t];
    float s = x;
    #pragma unroll
    for (int o = 16; o > 0; o >>= 1) s += __shfl_xor_sync(0xffffffffu, s, o);
    __shared__ float sm[4], sm2[4];
    int w = t >> 5, lane = t & 31;
    if (lane == 0) sm[w] = s;
    __syncthreads();
    float m = (sm[0] + sm[1] + sm[2] + sm[3]) * (1.f / 128.f);
    float d = x - m;
    float q = d * d;
    #pragma unroll
    for (int o = 16; o > 0; o >>= 1) q += __shfl_xor_sync(0xffffffffu, q, o);
    if (lane == 0) sm2[w] = q;
    __syncthreads();
    float var = (sm2[0] + sm2[1] + sm2[2] + sm2[3]) * (1.f / 128.f);
    float y = d * rsqrtf(var + 1e-5f) * g[t] + b[t];
    Y[(size_t)r * 128 + t] = y;
    if (MODE == 1) {
        __nv_bfloat16 hh, ll;
        split2(y, hh, ll);
        Yh[(size_t)r * 128 + t] = hh;
        Yl[(size_t)r * 128 + t] = ll;
    }
    if (MODE == 3)
        Yx[(size_t)r * 128 + t] = __float2half_rn(y);
    if (MODE == 4)
        Yx[(size_t)r * 128 + t] = __float2half_rn(y + pos[(size_t)r * 128 + t]);
}

// ---------------- conv1 (7x7, 128->128) via mma.sync fp16 single ----------------
constexpr int ROWB = 144;
constexpr int C1TILE = 128 * ROWB;     // 18432
constexpr int C1BUF  = 2 * C1TILE;     // A + B
constexpr int CONV1_SMEM = 2 * C1BUF;  // 73728

__global__ void __launch_bounds__(256, 2) conv1_f16_kernel(
    const __half* __restrict__ q16, const __half* __restrict__ w16,
    float* __restrict__ Out)
{
    extern __shared__ char smem[];
    const int tid = threadIdx.x;
    const int wid = tid >> 5, lane = tid & 31;
    const int warp_m = wid >> 2, warp_n = wid & 3;
    const uint32_t sb = smem_u32(smem);
    const int bm = blockIdx.x * 128;

    const int lrow = tid >> 1, lhalf = tid & 1;
    const int pm = bm + lrow;
    const int py = pm / 200, px = pm % 200;
    const bool prow_ok = pm < NQ;
    const uint32_t s_arow = sb + (uint32_t)lrow * ROWB + (uint32_t)lhalf * 64;
    const uint32_t s_brow = s_arow + C1TILE;

    const uint32_t a_base = sb + (uint32_t)(warp_m * 64 + (lane & 15)) * ROWB + (uint32_t)(lane >> 4) * 16;
    const uint32_t b_base = sb + C1TILE + (uint32_t)(warp_n * 32 + (lane & 7)) * ROWB
                          + (uint32_t)((lane >> 3) & 1) * 16;

    float acc[4][4][4];
    #pragma unroll
    for (int mt = 0; mt < 4; mt++)
        #pragma unroll
        for (int nt = 0; nt < 4; nt++)
            #pragma unroll
            for (int d = 0; d < 4; d++) acc[mt][nt][d] = 0.f;

    auto load_chunk = [&](int c, int buf) {
        const int e = c >> 1, ch = c & 1;
        const int qy = py + e / 7 - 3;
        const int qx = px + e % 7 - 3;
        const bool val = prow_ok && qy >= 0 && qy < 200 && qx >= 0 && qx < 200;
        const size_t aoff = (size_t)(val ? (qy * 200 + qx) : 0) * 128 + (size_t)ch * 64 + (size_t)lhalf * 32;
        const char* ag = (const char*)(q16 + aoff);
        const size_t boff = ((size_t)c * 128 + lrow) * 64 + (size_t)lhalf * 32;
        const char* bg = (const char*)(w16 + boff);
        const uint32_t sa = s_arow + (uint32_t)buf * C1BUF;
        const uint32_t sbr = s_brow + (uint32_t)buf * C1BUF;
        #pragma unroll
        for (int i = 0; i < 4; i++) {
            cpasync16(sa + i * 16,  ag + i * 16, val);
            cpasync16(sbr + i * 16, bg + i * 16, true);
        }
    };

    load_chunk(0, 0); cp_commit();
    load_chunk(1, 1); cp_commit();

    for (int c = 0; c < W1CHUNKS; c++) {
        const int buf = c & 1;
        cp_wait1();
        __syncthreads();

        const uint32_t ab = a_base + (uint32_t)buf * C1BUF;
        const uint32_t bb = b_base + (uint32_t)buf * C1BUF;
        #pragma unroll
        for (int ks = 0; ks < 4; ks++) {
            const uint32_t kbyte = (uint32_t)ks * 32;
            uint32_t bfr[4][2];
            #pragma unroll
            for (int nt = 0; nt < 4; nt++)
                ldmx2(bfr[nt], bb + (uint32_t)nt * 8 * ROWB + kbyte);
            #pragma unroll
            for (int mt = 0; mt < 4; mt++) {
                uint32_t afr[4];
                ldmx4(afr, ab + (uint32_t)mt * 16 * ROWB + kbyte);
                #pragma unroll
                for (int nt = 0; nt < 4; nt++)
                    mma_f16(acc[mt][nt], afr, bfr[nt]);
            }
        }
        __syncthreads();
        if (c + 2 < W1CHUNKS) load_chunk(c + 2, buf);
        cp_commit();
    }

    const int g = lane >> 2, tg = lane & 3;
    #pragma unroll
    for (int mt = 0; mt < 4; mt++) {
        const int r0 = bm + warp_m * 64 + mt * 16 + g;
        #pragma unroll
        for (int nt = 0; nt < 4; nt++) {
            const int col = warp_n * 32 + nt * 8 + tg * 2;
            if (r0 < NQ)
                *(float2*)&Out[(size_t)r0 * 128 + col] = make_float2(acc[mt][nt][0], acc[mt][nt][1]);
            if (r0 + 8 < NQ)
                *(float2*)&Out[(size_t)(r0 + 8) * 128 + col] = make_float2(acc[mt][nt][2], acc[mt][nt][3]);
        }
    }
}

// ---------------- convs 2-4 (3x3) via mma.sync bf16x3, 128x64 tile ----------------
constexpr int CATILE = 128 * ROWB;
constexpr int CBTILE = 64 * ROWB;
constexpr int CBUF = 2 * CATILE + 2 * CBTILE;
constexpr int CONV_SMEM = 2 * CBUF;

template<int CHUNKS, int CIN_CH, int CST>
__global__ void __launch_bounds__(256, 2) conv_mma_kernel(
    const __nv_bfloat16* __restrict__ inh, const __nv_bfloat16* __restrict__ inl,
    const __nv_bfloat16* __restrict__ wh, const __nv_bfloat16* __restrict__ wl,
    float* __restrict__ Out, int COUT)
{
    extern __shared__ char smem[];
    const int tid = threadIdx.x;
    const int wid = tid >> 5, lane = tid & 31;
    const int warp_m = wid >> 1, warp_n = wid & 1;
    const uint32_t sb = smem_u32(smem);
    const int bm = blockIdx.x * 128;

    const int lrow = tid >> 1, lhalf = tid & 1;
    const int pm = bm + lrow;
    const int py = pm / 200, px = pm % 200;
    const bool prow_ok = pm < NQ;
    const uint32_t s_arow = sb + (uint32_t)lrow * ROWB + (uint32_t)lhalf * 64;
    const int brow = tid >> 2, bq = tid & 3;
    const uint32_t s_brow = sb + 2 * CATILE + (uint32_t)brow * ROWB + (uint32_t)bq * 32;

    const uint32_t a_base = sb + (uint32_t)(warp_m * 32 + (lane & 15)) * ROWB + (uint32_t)(lane >> 4) * 16;
    const uint32_t b_base = sb + 2 * CATILE + (uint32_t)(warp_n * 32 + (lane & 7)) * ROWB
                          + (uint32_t)((lane >> 3) & 1) * 16;

    float acc[2][4][4];
    #pragma unroll
    for (int mt = 0; mt < 2; mt++)
        #pragma unroll
        for (int nt = 0; nt < 4; nt++)
            #pragma unroll
            for (int d = 0; d < 4; d++) acc[mt][nt][d] = 0.f;

    auto load_chunk = [&](int c, int buf) {
        const int e = c / CIN_CH, cih = c % CIN_CH;
        const int qy = py + e / 3 - 1;
        const int qx = px + e % 3 - 1;
        const bool val = prow_ok && qy >= 0 && qy < 200 && qx >= 0 && qx < 200;
        const size_t aoff = (size_t)(val ? (qy * 200 + qx) : 0) * CST + (size_t)cih * 64 + (size_t)lhalf * 32;
        const char* agh = (const char*)(inh + aoff);
        const char* agl = (const char*)(inl + aoff);
        const size_t boff = ((size_t)c * 64 + brow) * 64 + (size_t)bq * 16;
        const char* bgh = (const char*)(wh + boff);
        const char* bgl = (const char*)(wl + boff);
        const uint32_t sa = s_arow + (uint32_t)buf * CBUF;
        const uint32_t sbr = s_brow + (uint32_t)buf * CBUF;
        #pragma unroll
        for (int i = 0; i < 4; i++) {
            cpasync16(sa + i * 16,           agh + i * 16, val);
            cpasync16(sa + CATILE + i * 16,  agl + i * 16, val);
        }
        #pragma unroll
        for (int i = 0; i < 2; i++) {
            cpasync16(sbr + i * 16,          bgh + i * 16, true);
            cpasync16(sbr + CBTILE + i * 16, bgl + i * 16, true);
        }
    };

    load_chunk(0, 0); cp_commit();
    load_chunk(1, 1); cp_commit();

    for (int c = 0; c < CHUNKS; c++) {
        const int buf = c & 1;
        cp_wait1();
        __syncthreads();

        const uint32_t ab = a_base + (uint32_t)buf * CBUF;
        const uint32_t bb = b_base + (uint32_t)buf * CBUF;
        #pragma unroll
        for (int ks = 0; ks < 4; ks++) {
            const uint32_t kbyte = (uint32_t)ks * 32;
            uint32_t bh[4][2], bl[4][2];
            #pragma unroll
            for (int nt = 0; nt < 4; nt++) {
                ldmx2(bh[nt], bb + (uint32_t)nt * 8 * ROWB + kbyte);
                ldmx2(bl[nt], bb + CBTILE + (uint32_t)nt * 8 * ROWB + kbyte);
            }
            #pragma unroll
            for (int mt = 0; mt < 2; mt++) {
                uint32_t ah[4], al[4];
                ldmx4(ah, ab + (uint32_t)mt * 16 * ROWB + kbyte);
                ldmx4(al, ab + CATILE + (uint32_t)mt * 16 * ROWB + kbyte);
                #pragma unroll
                for (int nt = 0; nt < 4; nt++) {
                    mma_bf16(acc[mt][nt], ah, bh[nt]);
                    mma_bf16(acc[mt][nt], ah, bl[nt]);
                    mma_bf16(acc[mt][nt], al, bh[nt]);
                }
            }
        }
        __syncthreads();
        if (c + 2 < CHUNKS) load_chunk(c + 2, buf);
        cp_commit();
    }

    const int g = lane >> 2, tg = lane & 3;
    #pragma unroll
    for (int mt = 0; mt < 2; mt++) {
        const int r0 = bm + warp_m * 32 + mt * 16 + g;
        #pragma unroll
        for (int nt = 0; nt < 4; nt++) {
            const int col = warp_n * 32 + nt * 8 + tg * 2;
            if (col >= COUT) continue;
            if (r0 < NQ)
                *(float2*)&Out[(size_t)r0 * COUT + col] = make_float2(acc[mt][nt][0], acc[mt][nt][1]);
            if (r0 + 8 < NQ)
                *(float2*)&Out[(size_t)(r0 + 8) * COUT + col] = make_float2(acc[mt][nt][2], acc[mt][nt][3]);
        }
    }
}

// ---------------- batchnorm (320-way parallel partials, deterministic) ----------------
__global__ void bn_stats_kernel(const float* __restrict__ X, float* __restrict__ part, int C)
{
    int c = threadIdx.x;
    int g = blockIdx.x;
    const int per = (NQ + NPART - 1) / NPART;
    int p0 = g * per;
    int p1 = min(NQ, p0 + per);
    float s = 0.f, q = 0.f;
    for (int p = p0; p < p1; p++) {
        float x = X[(size_t)p * C + c];
        s += x; q += x * x;
    }
    part[(size_t)g * 2 * C + c] = s;
    part[(size_t)g * 2 * C + C + c] = q;
}

__global__ void bn_finalize_kernel(const float* __restrict__ part,
                                   const float* __restrict__ gamma, const float* __restrict__ beta,
                                   float* __restrict__ scale, float* __restrict__ shift, int C)
{
    int c = threadIdx.x;
    float s = 0.f, q = 0.f;
    for (int g = 0; g < NPART; g++) {
        s += part[(size_t)g * 2 * C + c];
        q += part[(size_t)g * 2 * C + C + c];
    }
    const float invP = 1.f / (float)NQ;
    float m = s * invP;
    float v = q * invP - m * m;
    float sc = gamma[c] * rsqrtf(v + 1e-5f);
    scale[c] = sc;
    shift[c] = beta[c] - m * sc;
}

__global__ void bn_apply_split_kernel(const float* __restrict__ X, const float* __restrict__ scale,
                                      const float* __restrict__ shift,
                                      __nv_bfloat16* __restrict__ hi, __nv_bfloat16* __restrict__ lo,
                                      int C, int CST, int total)
{
    int i = blockIdx.x * blockDim.x + threadIdx.x;
    if (i >= total) return;
    int c = i % CST;
    int p = i / CST;
    float v = 0.f;
    if (c < C) v = fmaxf(0.f, fmaf(X[(size_t)p * C + c], scale[c], shift[c]));
    split2(v, hi[i], lo[i]);
}

// ---------------- head: fused BN4+ReLU + 1x1 conv 48 -> 21, output NCHW ----------------
__global__ void head_conv_kernel(const float* __restrict__ H4raw, const float* __restrict__ scale,
                                 const float* __restrict__ shift,
                                 const float* __restrict__ Wo, const float* __restrict__ bo,
                                 float* __restrict__ out)
{
    int p = blockIdx.x * blockDim.x + threadIdx.x;
    if (p >= NQ) return;
    float x[48];
    const float4* hp = (const float4*)(H4raw + (size_t)p * 48);
    #pragma unroll
    for (int i = 0; i < 12; i++) {
        float4 v = hp[i];
        x[i * 4 + 0] = v.x; x[i * 4 + 1] = v.y; x[i * 4 + 2] = v.z; x[i * 4 + 3] = v.w;
    }
    #pragma unroll
    for (int ci = 0; ci < 48; ci++)
        x[ci] = fmaxf(0.f, fmaf(x[ci], scale[ci], shift[ci]));
    for (int co = 0; co < 21; co++) {
        float s = bo[co];
        const float* w = Wo + co * 48;
        #pragma unroll
        for (int ci = 0; ci < 48; ci++) s = fmaf(x[ci], w[ci], s);
        out[(size_t)co * NQ + p] = s;
    }
}

// ---------------- launch ----------------
extern "C" void kernel_launch(void* const* d_in, const int* in_sizes, int n_in,
                              void* d_out, int out_size)
{
    const float* value = (const float*)d_in[0];
    const float* bq    = (const float*)d_in[1];
    const float* bpos  = (const float*)d_in[2];
    const int*   proj  = (const int*)d_in[3];
    const float* Wv    = (const float*)d_in[4];
    const float* bv    = (const float*)d_in[5];
    const float* Woff  = (const float*)d_in[6];
    const float* boff  = (const float*)d_in[7];
    const float* Wattn = (const float*)d_in[8];
    const float* battn = (const float*)d_in[9];
    const float* Wout  = (const float*)d_in[10];
    const float* bout  = (const float*)d_in[11];
    const float* Wf1   = (const float*)d_in[12];
    const float* bf1   = (const float*)d_in[13];
    const float* Wf2   = (const float*)d_in[14];
    const float* bf2   = (const float*)d_in[15];
    const float* lng   = (const float*)d_in[16];
    const float* lnb   = (const float*)d_in[17];
    const float* cw1   = (const float*)d_in[18];
    const float* g1    = (const float*)d_in[19];
    const float* b1    = (const float*)d_in[20];
    const float* cw2   = (const float*)d_in[21];
    const float* g2    = (const float*)d_in[22];
    const float* b2    = (const float*)d_in[23];
    const float* cw3   = (const float*)d_in[24];
    const float* g3    = (const float*)d_in[25];
    const float* b3    = (const float*)d_in[26];
    const float* cw4   = (const float*)d_in[27];
    const float* g4    = (const float*)d_in[28];
    const float* b4    = (const float*)d_in[29];
    const float* objw  = (const float*)d_in[30];
    const float* objb  = (const float*)d_in[31];
    float* out = (float*)d_out;

    float* S = nullptr;
    cudaGetSymbolAddress((void**)&S, g_scratch);
    int* gm = nullptr;
    cudaGetSymbolAddress((void**)&gm, g_maxv);
    __nv_bfloat16 *s1h, *s1l, *s2h, *s2l, *vh, *vl, *wph, *wpl, *wch, *wcl;
    __half *vx, *q16, *qp16, *w16, *woa16, *oa16;
    cudaGetSymbolAddress((void**)&s1h, g_s1h);
    cudaGetSymbolAddress((void**)&s1l, g_s1l);
    cudaGetSymbolAddress((void**)&s2h, g_s2h);
    cudaGetSymbolAddress((void**)&s2l, g_s2l);
    cudaGetSymbolAddress((void**)&vh,  g_vh);
    cudaGetSymbolAddress((void**)&vl,  g_vl);
    cudaGetSymbolAddress((void**)&vx,  g_vx);
    cudaGetSymbolAddress((void**)&q16, g_q16);
    cudaGetSymbolAddress((void**)&qp16, g_qp16);
    cudaGetSymbolAddress((void**)&w16, g_w16);
    cudaGetSymbolAddress((void**)&woa16, g_woa16);
    cudaGetSymbolAddress((void**)&oa16, g_oa16);
    cudaGetSymbolAddress((void**)&wph, g_wph);
    cudaGetSymbolAddress((void**)&wpl, g_wpl);
    cudaGetSymbolAddress((void**)&wch, g_wch);
    cudaGetSymbolAddress((void**)&wcl, g_wcl);

    float* PQ    = S + OFF_Q;
    float* PT1   = S + OFF_T1;
    float* PT2   = S + OFF_T2;
    float* PH1   = S + OFF_H1;
    float* PH2   = S + OFF_H2;
    float* PH3   = S + OFF_H3;
    float* PH4   = S + OFF_H4;
    float* PPART = S + OFF_PART;
    float* PSCALE= S + OFF_SCALE;
    float* PSHIFT= S + OFF_SHIFT;
    float* PBIAS = S + OFF_BIAS;

    cudaFuncSetAttribute(conv1_f16_kernel, cudaFuncAttributeMaxDynamicSharedMemorySize, CONV1_SMEM);
    cudaFuncSetAttribute(gemm_f16_kernel,  cudaFuncAttributeMaxDynamicSharedMemorySize, F16GEMM_SMEM);
    cudaFuncSetAttribute(gemm_mma<6>,  cudaFuncAttributeMaxDynamicSharedMemorySize, GEMM_SMEM);
    cudaFuncSetAttribute(gemm_mma<9>,  cudaFuncAttributeMaxDynamicSharedMemorySize, GEMM_SMEM);
    cudaFuncSetAttribute(gemm_mma<16>, cudaFuncAttributeMaxDynamicSharedMemorySize, GEMM_SMEM);
    cudaFuncSetAttribute((conv_mma_kernel<18, 2, 128>), cudaFuncAttributeMaxDynamicSharedMemorySize, CONV_SMEM);
    cudaFuncSetAttribute((conv_mma_kernel<9, 1, 64>),   cudaFuncAttributeMaxDynamicSharedMemorySize, CONV_SMEM);

    // --- observed_masks ---
    init_max_kernel<<<1, 1>>>(gm);
    reduce_max_kernel<<<40, 256>>>(proj, gm);
    write_mask_kernel<<<(NQ + 255) / 256, 256>>>(proj, gm, out + 21 * NQ);

    // --- weight prep ---
    wsplit16_kernel<<<(W1CHUNKS * 128 * 64 + 255) / 256, 256>>>(cw1, w16);
    packcw_kernel<<<(18 * 4096 + 255) / 256, 256>>>(cw2, wch + WC2_OFF, wcl + WC2_OFF, 64, 128, 2, 18 * 4096);
    packcw_kernel<<<(9 * 4096 + 255) / 256, 256>>>(cw3, wch + WC3_OFF, wcl + WC3_OFF, 48, 64, 1, 9 * 4096);
    packcw_kernel<<<(9 * 4096 + 255) / 256, 256>>>(cw4, wch + WC4_OFF, wcl + WC4_OFF, 48, 48, 1, 9 * 4096);
    for (int i = 0; i < 2; i++) {
        size_t LB = (size_t)i * 1280 * 128;
        size_t LO = (size_t)i * 768 * 128;
        packw_kernel<<<(128 * 128 + 255) / 256, 256>>>(Wv   + (size_t)i * 128 * 128, wph + LB,              wpl + LB,              128);
        packwf16_kernel<<<(512 * 128 + 255) / 256, 256>>>(Woff + (size_t)i * 128 * 512, woa16 + LO,             512);
        packwf16_kernel<<<(256 * 128 + 255) / 256, 256>>>(Wattn+ (size_t)i * 128 * 256, woa16 + LO + 512 * 128, 256);
        packw_kernel<<<(128 * 128 + 255) / 256, 256>>>(Wout + (size_t)i * 128 * 128, wph + LB + 896 * 128,  wpl + LB + 896 * 128,  128);
        packw_kernel<<<(128 * 128 + 255) / 256, 256>>>(Wf1  + (size_t)i * 128 * 128, wph + LB + 1024 * 128, wpl + LB + 1024 * 128, 128);
        packw_kernel<<<(128 * 128 + 255) / 256, 256>>>(Wf2  + (size_t)i * 128 * 128, wph + LB + 1152 * 128, wpl + LB + 1152 * 128, 128);
        packbias_kernel<<<3, 256>>>(boff + i * 512, battn + i * 256, PBIAS + i * 768);
    }
    split_kernel<<<(NV * 128 + 255) / 256, 256>>>(value, vh, vl, NV * 128);

    // --- q init ---
    cudaMemcpyAsync(PQ, bq, (size_t)NQ * ED * sizeof(float), cudaMemcpyDeviceToDevice);

    // --- 2 encoder layers ---
    add_f16_kernel<<<(NQ * ED + 255) / 256, 256>>>(PQ, bpos, qp16, NQ * ED);
    for (int i = 0; i < 2; i++) {
        size_t LB = (size_t)i * 1280 * 128;
        size_t LO = (size_t)i * 768 * 128;
        // V projection -> fp16 V for deform (bf16x3 for accuracy on the value path)
        gemm_mma<16><<<dim3(340, 1), 256, GEMM_SMEM>>>(vh, vl, wph + LB, wpl + LB,
                                                       bv + i * 128, nullptr, nullptr, nullptr, nullptr, vx, NV, 128);
        // combined Woff+Wattn: fp16 single-MMA GEMM -> fp16 OA buffer
        gemm_f16_kernel<<<dim3(313, 6), 256, F16GEMM_SMEM>>>(qp16, woa16 + LO, PBIAS + i * 768, oa16, NQ, 768);
        deform_kernel<<<(NQ * HEADS + 255) / 256, 256>>>(vx, oa16, s2h, s2l);
        gemm_mma<6><<<dim3(313, 1), 256, GEMM_SMEM>>>(s2h, s2l, wph + LB + 896 * 128, wpl + LB + 896 * 128,
                                                      bout + i * 128, PQ, PT1, nullptr, nullptr, nullptr, NQ, 128);
        ln_kernel<1><<<NQ, 128>>>(PT1, lng + (i * 2 + 0) * 128, lnb + (i * 2 + 0) * 128, PQ, s1h, s1l, nullptr, nullptr);
        gemm_mma<9><<<dim3(313, 1), 256, GEMM_SMEM>>>(s1h, s1l, wph + LB + 1024 * 128, wpl + LB + 1024 * 128,
                                                      bf1 + i * 128, nullptr, nullptr, s2h, s2l, nullptr, NQ, 128);
        gemm_mma<6><<<dim3(313, 1), 256, GEMM_SMEM>>>(s2h, s2l, wph + LB + 1152 * 128, wpl + LB + 1152 * 128,
                                                      bf2 + i * 128, PQ, PT2, nullptr, nullptr, nullptr, NQ, 128);
        if (i == 0)
            ln_kernel<4><<<NQ, 128>>>(PT2, lng + 1 * 128, lnb + 1 * 128, PQ, nullptr, nullptr, qp16, bpos);  // fp16(q+pos)
        else
            ln_kernel<3><<<NQ, 128>>>(PT2, lng + 3 * 128, lnb + 3 * 128, PQ, nullptr, nullptr, q16, nullptr); // fp16(q)
    }

    // --- conv head ---
    conv1_f16_kernel<<<313, 256, CONV1_SMEM>>>(q16, w16, PH1);
    bn_stats_kernel<<<NPART, 128>>>(PH1, PPART, 128);
    bn_finalize_kernel<<<1, 128>>>(PPART, g1, b1, PSCALE, PSHIFT, 128);
    bn_apply_split_kernel<<<(NQ * 128 + 255) / 256, 256>>>(PH1, PSCALE, PSHIFT, s1h, s1l, 128, 128, NQ * 128);

    conv_mma_kernel<18, 2, 128><<<313, 256, CONV_SMEM>>>(s1h, s1l, wch + WC2_OFF, wcl + WC2_OFF, PH2, 64);
    bn_stats_kernel<<<NPART, 64>>>(PH2, PPART, 64);
    bn_finalize_kernel<<<1, 64>>>(PPART, g2, b2, PSCALE, PSHIFT, 64);
    bn_apply_split_kernel<<<(NQ * 64 + 255) / 256, 256>>>(PH2, PSCALE, PSHIFT, s2h, s2l, 64, 64, NQ * 64);

    conv_mma_kernel<9, 1, 64><<<313, 256, CONV_SMEM>>>(s2h, s2l, wch + WC3_OFF, wcl + WC3_OFF, PH3, 48);
    bn_stats_kernel<<<NPART, 48>>>(PH3, PPART, 48);
    bn_finalize_kernel<<<1, 48>>>(PPART, g3, b3, PSCALE, PSHIFT, 48);
    bn_apply_split_kernel<<<(NQ * 64 + 255) / 256, 256>>>(PH3, PSCALE, PSHIFT, s1h, s1l, 48, 64, NQ * 64);

    conv_mma_kernel<9, 1, 64><<<313, 256, CONV_SMEM>>>(s1h, s1l, wch + WC4_OFF, wcl + WC4_OFF, PH4, 48);
    bn_stats_kernel<<<NPART, 48>>>(PH4, PPART, 48);
    bn_finalize_kernel<<<1, 48>>>(PPART, g4, b4, PSCALE, PSHIFT, 48);
    head_conv_kernel<<<(NQ + 255) / 256, 256>>>(PH4, PSCALE, PSHIFT, objw, objb, out);
}

// round 10
// speedup vs baseline: 2.9344x; 1.0649x over previous
#include <cuda_runtime.h>
#include <cuda_bf16.h>
#include <cuda_fp16.h>
#include <cstdint>
#include <climits>

// ---------------- problem constants ----------------
constexpr int NQ = 40000;        // 200*200
constexpr int ED = 128;
constexpr int NV = 43520;        // sum of level sizes
constexpr int HEADS = 8;
constexpr int NPART = 320;       // bn partial blocks

// ---------------- scratch layout (floats) ----------------
constexpr size_t OFF_Q    = 0;
constexpr size_t SZ_Q     = (size_t)NQ * ED;
constexpr size_t OFF_T1   = OFF_Q + SZ_Q;
constexpr size_t OFF_T2   = OFF_T1 + SZ_Q;
constexpr size_t OFF_H1   = OFF_T2 + SZ_Q;
constexpr size_t SZ_H1    = (size_t)NQ * 128;
constexpr size_t OFF_H2   = OFF_H1 + SZ_H1;
constexpr size_t SZ_H2    = (size_t)NQ * 64;
constexpr size_t OFF_H3   = OFF_H2 + SZ_H2;
constexpr size_t SZ_H3    = (size_t)NQ * 48;
constexpr size_t OFF_H4   = OFF_H3 + SZ_H3;
constexpr size_t OFF_PART = OFF_H4 + SZ_H3;
constexpr size_t SZ_PART  = (size_t)NPART * 2 * 128;
constexpr size_t OFF_SCALE= OFF_PART + SZ_PART;
constexpr size_t OFF_SHIFT= OFF_SCALE + 128;
constexpr size_t OFF_BIAS = OFF_SHIFT + 128;       // 2 layers x 768 packed bias
constexpr size_t SCRATCH_TOTAL = OFF_BIAS + 2 * 768;

__device__ float g_scratch[SCRATCH_TOTAL];
__device__ int   g_maxv;

// ---------------- bf16 / fp16 buffers ----------------
constexpr int W1CHUNKS = 98;                 // conv1: 49 taps * 2 ci-halves
__device__ __align__(16) __nv_bfloat16 g_s1h[(size_t)NQ * 128];
__device__ __align__(16) __nv_bfloat16 g_s1l[(size_t)NQ * 128];
__device__ __align__(16) __nv_bfloat16 g_s2h[(size_t)NQ * 128];
__device__ __align__(16) __nv_bfloat16 g_s2l[(size_t)NQ * 128];
__device__ __align__(16) __half        g_vx[(size_t)NV * 128];    // fp16 V for deform
__device__ __align__(16) __half        g_vin16[(size_t)NV * 128]; // fp16 value input
__device__ __align__(16) __half        g_q16[(size_t)NQ * 128];   // fp16 q (LN1 out / final q)
__device__ __align__(16) __half        g_qp16[(size_t)NQ * 128];  // fp16 q+pos / FFN hidden
__device__ __align__(16) __half        g_oa16[(size_t)NQ * 768];  // fp16 offsets+logits
// Wout (bf16x3) per layer 128 x 128
__device__ __align__(16) __nv_bfloat16 g_wph[(size_t)2 * 128 * 128];
__device__ __align__(16) __nv_bfloat16 g_wpl[(size_t)2 * 128 * 128];
// fp16 weights per layer: [OA 768][Wv 128][Wf1 128][Wf2 128] x 128 k
__device__ __align__(16) __half g_wf16[(size_t)2 * 1152 * 128];
// conv1 weights [chunk][co 128][k 64] fp16
__device__ __align__(16) __half g_w16[(size_t)W1CHUNKS * 128 * 64];
// convs 2-4 weights
constexpr int WC2_OFF = 0, WC3_OFF = 73728, WC4_OFF = 110592, WC_TOTAL = 147456;
__device__ __align__(16) __nv_bfloat16 g_wch[WC_TOTAL];
__device__ __align__(16) __nv_bfloat16 g_wcl[WC_TOTAL];

// ---------------- small helpers ----------------
__device__ __forceinline__ uint32_t smem_u32(const void* p) {
    return (uint32_t)__cvta_generic_to_shared(p);
}
__device__ __forceinline__ void cpasync16(uint32_t dst, const void* src, bool valid) {
    asm volatile("cp.async.cg.shared.global [%0], [%1], 16, %2;"
                 :: "r"(dst), "l"(src), "r"(valid ? 16u : 0u));
}
__device__ __forceinline__ void cp_commit() { asm volatile("cp.async.commit_group;"); }
__device__ __forceinline__ void cp_wait1()  { asm volatile("cp.async.wait_group 1;"); }
__device__ __forceinline__ void cp_wait0()  { asm volatile("cp.async.wait_group 0;"); }

__device__ __forceinline__ void ldmx4(uint32_t* r, uint32_t addr) {
    asm volatile("ldmatrix.sync.aligned.m8n8.x4.shared.b16 {%0,%1,%2,%3}, [%4];"
                 : "=r"(r[0]), "=r"(r[1]), "=r"(r[2]), "=r"(r[3]) : "r"(addr));
}
__device__ __forceinline__ void ldmx2(uint32_t* r, uint32_t addr) {
    asm volatile("ldmatrix.sync.aligned.m8n8.x2.shared.b16 {%0,%1}, [%2];"
                 : "=r"(r[0]), "=r"(r[1]) : "r"(addr));
}
__device__ __forceinline__ void mma_bf16(float* c, const uint32_t* a, const uint32_t* b) {
    asm volatile("mma.sync.aligned.m16n8k16.row.col.f32.bf16.bf16.f32 "
                 "{%0,%1,%2,%3}, {%4,%5,%6,%7}, {%8,%9}, {%0,%1,%2,%3};"
                 : "+f"(c[0]), "+f"(c[1]), "+f"(c[2]), "+f"(c[3])
                 : "r"(a[0]), "r"(a[1]), "r"(a[2]), "r"(a[3]), "r"(b[0]), "r"(b[1]));
}
__device__ __forceinline__ void mma_f16(float* c, const uint32_t* a, const uint32_t* b) {
    asm volatile("mma.sync.aligned.m16n8k16.row.col.f32.f16.f16.f32 "
                 "{%0,%1,%2,%3}, {%4,%5,%6,%7}, {%8,%9}, {%0,%1,%2,%3};"
                 : "+f"(c[0]), "+f"(c[1]), "+f"(c[2]), "+f"(c[3])
                 : "r"(a[0]), "r"(a[1]), "r"(a[2]), "r"(a[3]), "r"(b[0]), "r"(b[1]));
}
__device__ __forceinline__ void split2(float v, __nv_bfloat16& h, __nv_bfloat16& l) {
    h = __float2bfloat16(v);
    l = __float2bfloat16(v - __bfloat162float(h));
}

// ---------------- elementwise helpers ----------------
__global__ void init_max_kernel(int* gm) { *gm = INT_MIN; }

__global__ void reduce_max_kernel(const int* __restrict__ p, int* gm) {
    int v = INT_MIN;
    for (int k = blockIdx.x * blockDim.x + threadIdx.x; k < NQ; k += gridDim.x * blockDim.x)
        v = max(v, p[k]);
    #pragma unroll
    for (int o = 16; o > 0; o >>= 1) v = max(v, __shfl_xor_sync(0xffffffffu, v, o));
    __shared__ int sm[8];
    int w = threadIdx.x >> 5;
    if ((threadIdx.x & 31) == 0) sm[w] = v;
    __syncthreads();
    if (threadIdx.x == 0) {
        int bv = sm[0];
        for (int i = 1; i < (int)(blockDim.x >> 5); i++) bv = max(bv, sm[i]);
        atomicMax(gm, bv);
    }
}

__global__ void write_mask_kernel(const int* __restrict__ p, const int* __restrict__ gm,
                                  float* __restrict__ out) {
    int i = blockIdx.x * blockDim.x + threadIdx.x;
    if (i < NQ) out[i] = (p[i] < *gm) ? 1.0f : 0.0f;
}

// fp32 -> fp16
__global__ void tof16_kernel(const float* __restrict__ X, __half* __restrict__ o, int n)
{
    int i = blockIdx.x * blockDim.x + threadIdx.x;
    if (i < n) o[i] = __float2half_rn(X[i]);
}

// q+pos -> fp16
__global__ void add_f16_kernel(const float* __restrict__ A, const float* __restrict__ B,
                               __half* __restrict__ o, int n)
{
    int i = blockIdx.x * blockDim.x + threadIdx.x;
    if (i < n) o[i] = __float2half_rn(A[i] + B[i]);
}

// pack encoder weight W [128][N] (k-major) -> hi/lo [N][128]
__global__ void packw_kernel(const float* __restrict__ W, __nv_bfloat16* __restrict__ hi,
                             __nv_bfloat16* __restrict__ lo, int N)
{
    int i = blockIdx.x * blockDim.x + threadIdx.x;
    if (i >= N * 128) return;
    int k = i & 127, n = i >> 7;
    split2(W[(size_t)k * N + n], hi[i], lo[i]);
}

// pack weight W [128][N] -> fp16 [N][128]
__global__ void packwf16_kernel(const float* __restrict__ W, __half* __restrict__ o, int N)
{
    int i = blockIdx.x * blockDim.x + threadIdx.x;
    if (i >= N * 128) return;
    int k = i & 127, n = i >> 7;
    o[i] = __float2half_rn(W[(size_t)k * N + n]);
}

__global__ void packbias_kernel(const float* __restrict__ boff, const float* __restrict__ battn,
                                float* __restrict__ dst)
{
    int i = threadIdx.x + blockIdx.x * blockDim.x;
    if (i < 768) dst[i] = (i < 512) ? boff[i] : battn[i - 512];
}

__global__ void packcw_kernel(const float* __restrict__ W, __nv_bfloat16* __restrict__ hi,
                              __nv_bfloat16* __restrict__ lo, int CO, int CI, int CIN_CH, int total)
{
    int i = blockIdx.x * blockDim.x + threadIdx.x;
    if (i >= total) return;
    int k = i & 63, co = (i >> 6) & 63, c = i >> 12;
    int e = c / CIN_CH, cih = c % CIN_CH;
    int ci = cih * 64 + k;
    float v = (co < CO && ci < CI) ? W[(((size_t)co * CI + ci) * 3 + e / 3) * 3 + e % 3] : 0.f;
    split2(v, hi[i], lo[i]);
}

// conv1 weight -> fp16 [chunk][co][k]
__global__ void wsplit16_kernel(const float* __restrict__ W, __half* __restrict__ w16)
{
    int i = blockIdx.x * blockDim.x + threadIdx.x;
    if (i >= W1CHUNKS * 128 * 64) return;
    int k  = i & 63;
    int co = (i >> 6) & 127;
    int c  = i >> 13;
    int e = c >> 1, ci = ((c & 1) << 6) + k;
    int ky = e / 7, kx = e % 7;
    w16[i] = __float2half_rn(W[(((size_t)co * 128 + ci) * 7 + ky) * 7 + kx]);
}

// ---------------- generic bf16x3 GEMM (Wout only): residual + fp32 out ----------------
constexpr int GROWB = 272;
constexpr int GTILE = 128 * GROWB;
constexpr int GEMM_SMEM = 4 * GTILE;

__global__ void __launch_bounds__(256, 1) gemm_mma6(
    const __nv_bfloat16* __restrict__ Ah, const __nv_bfloat16* __restrict__ Al,
    const __nv_bfloat16* __restrict__ Bh, const __nv_bfloat16* __restrict__ Bl,
    const float* __restrict__ bias, const float* __restrict__ R,
    float* __restrict__ Cf, int M, int N)
{
    extern __shared__ char smem[];
    const int tid = threadIdx.x;
    const int wid = tid >> 5, lane = tid & 31;
    const int warp_m = wid >> 2, warp_n = wid & 3;
    const uint32_t sb = smem_u32(smem);
    const int bm = blockIdx.x * 128, bn = blockIdx.y * 128;

    {
        const int lrow = tid >> 1, lhalf = tid & 1;
        const bool aval = (bm + lrow) < M;
        const uint32_t sa = sb + (uint32_t)lrow * GROWB + (uint32_t)lhalf * 128;
        const char* agh = (const char*)(Ah + (size_t)(aval ? (bm + lrow) : 0) * 128 + lhalf * 64);
        const char* agl = (const char*)(Al + (size_t)(aval ? (bm + lrow) : 0) * 128 + lhalf * 64);
        const char* bgh = (const char*)(Bh + (size_t)(bn + lrow) * 128 + lhalf * 64);
        const char* bgl = (const char*)(Bl + (size_t)(bn + lrow) * 128 + lhalf * 64);
        #pragma unroll
        for (int i = 0; i < 8; i++) {
            cpasync16(sa + i * 16,             agh + i * 16, aval);
            cpasync16(sa + GTILE + i * 16,     agl + i * 16, aval);
            cpasync16(sa + 2 * GTILE + i * 16, bgh + i * 16, true);
            cpasync16(sa + 3 * GTILE + i * 16, bgl + i * 16, true);
        }
        cp_commit();
        cp_wait0();
        __syncthreads();
    }

    float acc[4][4][4];
    #pragma unroll
    for (int mt = 0; mt < 4; mt++)
        #pragma unroll
        for (int nt = 0; nt < 4; nt++)
            #pragma unroll
            for (int d = 0; d < 4; d++) acc[mt][nt][d] = 0.f;

    const uint32_t a_base = sb + (uint32_t)(warp_m * 64 + (lane & 15)) * GROWB + (uint32_t)(lane >> 4) * 16;
    const uint32_t b_base = sb + 2 * GTILE + (uint32_t)(warp_n * 32 + (lane & 7)) * GROWB
                          + (uint32_t)((lane >> 3) & 1) * 16;

    #pragma unroll
    for (int ks = 0; ks < 8; ks++) {
        const uint32_t kbyte = (uint32_t)ks * 32;
        uint32_t bh[4][2], bl[4][2];
        #pragma unroll
        for (int nt = 0; nt < 4; nt++) {
            ldmx2(bh[nt], b_base + (uint32_t)nt * 8 * GROWB + kbyte);
            ldmx2(bl[nt], b_base + GTILE + (uint32_t)nt * 8 * GROWB + kbyte);
        }
        #pragma unroll
        for (int mt = 0; mt < 4; mt++) {
            uint32_t ah[4], al[4];
            ldmx4(ah, a_base + (uint32_t)mt * 16 * GROWB + kbyte);
            ldmx4(al, a_base + GTILE + (uint32_t)mt * 16 * GROWB + kbyte);
            #pragma unroll
            for (int nt = 0; nt < 4; nt++) {
                mma_bf16(acc[mt][nt], ah, bh[nt]);
                mma_bf16(acc[mt][nt], ah, bl[nt]);
                mma_bf16(acc[mt][nt], al, bh[nt]);
            }
        }
    }

    const int g = lane >> 2, tg = lane & 3;
    #pragma unroll
    for (int mt = 0; mt < 4; mt++) {
        const int r0 = bm + warp_m * 64 + mt * 16 + g;
        #pragma unroll
        for (int nt = 0; nt < 4; nt++) {
            const int col = bn + warp_n * 32 + nt * 8 + tg * 2;
            float2 bb = *(const float2*)&bias[col];
            #pragma unroll
            for (int half = 0; half < 2; half++) {
                const int r = r0 + half * 8;
                if (r >= M) continue;
                float2 rr = *(const float2*)&R[(size_t)r * N + col];
                *(float2*)&Cf[(size_t)r * N + col] =
                    make_float2(acc[mt][nt][half * 2] + bb.x + rr.x,
                                acc[mt][nt][half * 2 + 1] + bb.y + rr.y);
            }
        }
    }
}

// ---------------- fp16 single GEMM: C[M,N] = A[M,128] * B[N,128]^T + bias ----------------
// FLAGS: 1 relu, 2 residual (fp32 R), 4 fp32 out, 8 fp16 out
constexpr int F16GEMM_SMEM = 2 * GTILE;   // A + B

template<int FLAGS>
__global__ void __launch_bounds__(256, 2) gemm_f16(
    const __half* __restrict__ A, const __half* __restrict__ B,
    const float* __restrict__ bias, const float* __restrict__ R,
    float* __restrict__ Cf, __half* __restrict__ Cx, int M, int N)
{
    extern __shared__ char smem[];
    const int tid = threadIdx.x;
    const int wid = tid >> 5, lane = tid & 31;
    const int warp_m = wid >> 2, warp_n = wid & 3;
    const uint32_t sb = smem_u32(smem);
    const int bm = blockIdx.x * 128, bn = blockIdx.y * 128;

    {
        const int lrow = tid >> 1, lhalf = tid & 1;
        const bool aval = (bm + lrow) < M;
        const uint32_t sa = sb + (uint32_t)lrow * GROWB + (uint32_t)lhalf * 128;
        const char* ag = (const char*)(A + (size_t)(aval ? (bm + lrow) : 0) * 128 + lhalf * 64);
        const char* bg = (const char*)(B + (size_t)(bn + lrow) * 128 + lhalf * 64);
        #pragma unroll
        for (int i = 0; i < 8; i++) {
            cpasync16(sa + i * 16,         ag + i * 16, aval);
            cpasync16(sa + GTILE + i * 16, bg + i * 16, true);
        }
        cp_commit();
        cp_wait0();
        __syncthreads();
    }

    float acc[4][4][4];
    #pragma unroll
    for (int mt = 0; mt < 4; mt++)
        #pragma unroll
        for (int nt = 0; nt < 4; nt++)
            #pragma unroll
            for (int d = 0; d < 4; d++) acc[mt][nt][d] = 0.f;

    const uint32_t a_base = sb + (uint32_t)(warp_m * 64 + (lane & 15)) * GROWB + (uint32_t)(lane >> 4) * 16;
    const uint32_t b_base = sb + GTILE + (uint32_t)(warp_n * 32 + (lane & 7)) * GROWB
                          + (uint32_t)((lane >> 3) & 1) * 16;

    #pragma unroll
    for (int ks = 0; ks < 8; ks++) {
        const uint32_t kbyte = (uint32_t)ks * 32;
        uint32_t bfr[4][2];
        #pragma unroll
        for (int nt = 0; nt < 4; nt++)
            ldmx2(bfr[nt], b_base + (uint32_t)nt * 8 * GROWB + kbyte);
        #pragma unroll
        for (int mt = 0; mt < 4; mt++) {
            uint32_t afr[4];
            ldmx4(afr, a_base + (uint32_t)mt * 16 * GROWB + kbyte);
            #pragma unroll
            for (int nt = 0; nt < 4; nt++)
                mma_f16(acc[mt][nt], afr, bfr[nt]);
        }
    }

    const int g = lane >> 2, tg = lane & 3;
    #pragma unroll
    for (int mt = 0; mt < 4; mt++) {
        const int r0 = bm + warp_m * 64 + mt * 16 + g;
        #pragma unroll
        for (int nt = 0; nt < 4; nt++) {
            const int col = bn + warp_n * 32 + nt * 8 + tg * 2;
            float2 bb = *(const float2*)&bias[col];
            #pragma unroll
            for (int half = 0; half < 2; half++) {
                const int r = r0 + half * 8;
                if (r >= M) continue;
                float a0 = acc[mt][nt][half * 2] + bb.x;
                float a1 = acc[mt][nt][half * 2 + 1] + bb.y;
                if (FLAGS & 2) {
                    float2 rr = *(const float2*)&R[(size_t)r * N + col];
                    a0 += rr.x; a1 += rr.y;
                }
                if (FLAGS & 1) { a0 = fmaxf(a0, 0.f); a1 = fmaxf(a1, 0.f); }
                if (FLAGS & 4)
                    *(float2*)&Cf[(size_t)r * N + col] = make_float2(a0, a1);
                if (FLAGS & 8)
                    *(__half2*)&Cx[(size_t)r * N + col] = __floats2half2_rn(a0, a1);
            }
        }
    }
}

// ---------------- deformable attention sampling (fp16 V + fp16 OA, fused softmax) ----------------
__global__ void __launch_bounds__(256) deform_kernel(
    const __half* __restrict__ VX, const __half* __restrict__ OA,
    __nv_bfloat16* __restrict__ OH, __nv_bfloat16* __restrict__ OL)
{
    int t = blockIdx.x * 256 + threadIdx.x;
    if (t >= NQ * HEADS) return;
    const int n = t >> 3, h = t & 7;
    const float rx = ((float)(n % 200) + 0.5f) * (1.f / 200.f);
    const float ry = ((float)(n / 200) + 0.5f) * (1.f / 200.f);
    const __half* op = OA + (size_t)n * 768 + h * 64;
    const __half* ap = OA + (size_t)n * 768 + 512 + h * 32;

    float e[32];
    {
        const uint4* apv = (const uint4*)ap;
        #pragma unroll
        for (int q = 0; q < 4; q++) {
            uint4 u = apv[q];
            uint32_t wv[4] = {u.x, u.y, u.z, u.w};
            #pragma unroll
            for (int d = 0; d < 4; d++) {
                float2 f2 = __half22float2(*(const __half2*)&wv[d]);
                e[q * 8 + d * 2 + 0] = f2.x;
                e[q * 8 + d * 2 + 1] = f2.y;
            }
        }
        float m = -1e30f;
        #pragma unroll
        for (int k = 0; k < 32; k++) m = fmaxf(m, e[k]);
        float s = 0.f;
        #pragma unroll
        for (int k = 0; k < 32; k++) { e[k] = expf(e[k] - m); s += e[k]; }
        float inv = 1.f / s;
        #pragma unroll
        for (int k = 0; k < 32; k++) e[k] *= inv;
    }

    float acc[16];
    #pragma unroll
    for (int d = 0; d < 16; d++) acc[d] = 0.f;

    const int stc[4] = {0, 32768, 40960, 43008};
    const int Wc[4]  = {256, 128, 64, 32};
    const int Hc[4]  = {128, 64, 32, 16};

    #pragma unroll
    for (int l = 0; l < 4; l++) {
        const int W = Wc[l], H = Hc[l], st = stc[l];
        const float Wf = (float)W, Hf = (float)H;
        for (int p = 0; p < 8; p++) {
            float2 off2 = __half22float2(*(const __half2*)(op + (l * 8 + p) * 2));
            float aw = e[l * 8 + p];
            float x = (rx + off2.x / Wf) * Wf - 0.5f;
            float y = (ry + off2.y / Hf) * Hf - 0.5f;
            float xf = floorf(x), yf = floorf(y);
            int x0 = (int)xf, y0 = (int)yf;
            float fx = x - xf, fy = y - yf;
            float wx[2] = {1.f - fx, fx};
            float wy[2] = {1.f - fy, fy};
            #pragma unroll
            for (int c = 0; c < 4; c++) {
                int xi = x0 + (c & 1), yi = y0 + (c >> 1);
                float wgt = wx[c & 1] * wy[c >> 1];
                if (xi >= 0 && xi < W && yi >= 0 && yi < H && wgt != 0.f) {
                    const uint4* gp = (const uint4*)(VX + ((size_t)(st + yi * W + xi)) * 128 + h * 16);
                    uint4 u0 = gp[0];
                    uint4 u1 = gp[1];
                    uint32_t wv[8] = {u0.x, u0.y, u0.z, u0.w, u1.x, u1.y, u1.z, u1.w};
                    float cw = aw * wgt;
                    #pragma unroll
                    for (int d = 0; d < 8; d++) {
                        float2 g2 = __half22float2(*(const __half2*)&wv[d]);
                        acc[d * 2 + 0] += cw * g2.x;
                        acc[d * 2 + 1] += cw * g2.y;
                    }
                }
            }
        }
    }
    __nv_bfloat162* oh = (__nv_bfloat162*)(OH + (size_t)n * 128 + h * 16);
    __nv_bfloat162* ol = (__nv_bfloat162*)(OL + (size_t)n * 128 + h * 16);
    #pragma unroll
    for (int d = 0; d < 8; d++) {
        __nv_bfloat16 h0, l0, h1, l1;
        split2(acc[d * 2], h0, l0); split2(acc[d * 2 + 1], h1, l1);
        oh[d] = __nv_bfloat162(h0, h1);
        ol[d] = __nv_bfloat162(l0, l1);
    }
}

// ---------------- layernorm over 128 per row ----------------
// MODE: 3 fp32 + fp16(y), 4 fp32 + fp16(y + pos)
template<int MODE>
__global__ void ln_kernel(const float* __restrict__ X, const float* __restrict__ g,
                          const float* __restrict__ b, float* __restrict__ Y,
                          __half* __restrict__ Yx, const float* __restrict__ pos)
{
    int r = blockIdx.x;
    int t = threadIdx.x;
    float x = X[(size_t)r * 128 + t];
    float s = x;
    #pragma unroll
    for (int o = 16; o > 0; o >>= 1) s += __shfl_xor_sync(0xffffffffu, s, o);
    __shared__ float sm[4], sm2[4];
    int w = t >> 5, lane = t & 31;
    if (lane == 0) sm[w] = s;
    __syncthreads();
    float m = (sm[0] + sm[1] + sm[2] + sm[3]) * (1.f / 128.f);
    float d = x - m;
    float q = d * d;
    #pragma unroll
    for (int o = 16; o > 0; o >>= 1) q += __shfl_xor_sync(0xffffffffu, q, o);
    if (lane == 0) sm2[w] = q;
    __syncthreads();
    float var = (sm2[0] + sm2[1] + sm2[2] + sm2[3]) * (1.f / 128.f);
    float y = d * rsqrtf(var + 1e-5f) * g[t] + b[t];
    Y[(size_t)r * 128 + t] = y;
    if (MODE == 3)
        Yx[(size_t)r * 128 + t] = __float2half_rn(y);
    if (MODE == 4)
        Yx[(size_t)r * 128 + t] = __float2half_rn(y + pos[(size_t)r * 128 + t]);
}

// ---------------- conv1 (7x7, 128->128) via mma.sync fp16 single ----------------
constexpr int ROWB = 144;
constexpr int C1TILE = 128 * ROWB;     // 18432
constexpr int C1BUF  = 2 * C1TILE;     // A + B
constexpr int CONV1_SMEM = 2 * C1BUF;  // 73728

__global__ void __launch_bounds__(256, 2) conv1_f16_kernel(
    const __half* __restrict__ q16, const __half* __restrict__ w16,
    float* __restrict__ Out)
{
    extern __shared__ char smem[];
    const int tid = threadIdx.x;
    const int wid = tid >> 5, lane = tid & 31;
    const int warp_m = wid >> 2, warp_n = wid & 3;
    const uint32_t sb = smem_u32(smem);
    const int bm = blockIdx.x * 128;

    const int lrow = tid >> 1, lhalf = tid & 1;
    const int pm = bm + lrow;
    const int py = pm / 200, px = pm % 200;
    const bool prow_ok = pm < NQ;
    const uint32_t s_arow = sb + (uint32_t)lrow * ROWB + (uint32_t)lhalf * 64;
    const uint32_t s_brow = s_arow + C1TILE;

    const uint32_t a_base = sb + (uint32_t)(warp_m * 64 + (lane & 15)) * ROWB + (uint32_t)(lane >> 4) * 16;
    const uint32_t b_base = sb + C1TILE + (uint32_t)(warp_n * 32 + (lane & 7)) * ROWB
                          + (uint32_t)((lane >> 3) & 1) * 16;

    float acc[4][4][4];
    #pragma unroll
    for (int mt = 0; mt < 4; mt++)
        #pragma unroll
        for (int nt = 0; nt < 4; nt++)
            #pragma unroll
            for (int d = 0; d < 4; d++) acc[mt][nt][d] = 0.f;

    auto load_chunk = [&](int c, int buf) {
        const int e = c >> 1, ch = c & 1;
        const int qy = py + e / 7 - 3;
        const int qx = px + e % 7 - 3;
        const bool val = prow_ok && qy >= 0 && qy < 200 && qx >= 0 && qx < 200;
        const size_t aoff = (size_t)(val ? (qy * 200 + qx) : 0) * 128 + (size_t)ch * 64 + (size_t)lhalf * 32;
        const char* ag = (const char*)(q16 + aoff);
        const size_t boff = ((size_t)c * 128 + lrow) * 64 + (size_t)lhalf * 32;
        const char* bg = (const char*)(w16 + boff);
        const uint32_t sa = s_arow + (uint32_t)buf * C1BUF;
        const uint32_t sbr = s_brow + (uint32_t)buf * C1BUF;
        #pragma unroll
        for (int i = 0; i < 4; i++) {
            cpasync16(sa + i * 16,  ag + i * 16, val);
            cpasync16(sbr + i * 16, bg + i * 16, true);
        }
    };

    load_chunk(0, 0); cp_commit();
    load_chunk(1, 1); cp_commit();

    for (int c = 0; c < W1CHUNKS; c++) {
        const int buf = c & 1;
        cp_wait1();
        __syncthreads();

        const uint32_t ab = a_base + (uint32_t)buf * C1BUF;
        const uint32_t bb = b_base + (uint32_t)buf * C1BUF;
        #pragma unroll
        for (int ks = 0; ks < 4; ks++) {
            const uint32_t kbyte = (uint32_t)ks * 32;
            uint32_t bfr[4][2];
            #pragma unroll
            for (int nt = 0; nt < 4; nt++)
                ldmx2(bfr[nt], bb + (uint32_t)nt * 8 * ROWB + kbyte);
            #pragma unroll
            for (int mt = 0; mt < 4; mt++) {
                uint32_t afr[4];
                ldmx4(afr, ab + (uint32_t)mt * 16 * ROWB + kbyte);
                #pragma unroll
                for (int nt = 0; nt < 4; nt++)
                    mma_f16(acc[mt][nt], afr, bfr[nt]);
            }
        }
        __syncthreads();
        if (c + 2 < W1CHUNKS) load_chunk(c + 2, buf);
        cp_commit();
    }

    const int g = lane >> 2, tg = lane & 3;
    #pragma unroll
    for (int mt = 0; mt < 4; mt++) {
        const int r0 = bm + warp_m * 64 + mt * 16 + g;
        #pragma unroll
        for (int nt = 0; nt < 4; nt++) {
            const int col = warp_n * 32 + nt * 8 + tg * 2;
            if (r0 < NQ)
                *(float2*)&Out[(size_t)r0 * 128 + col] = make_float2(acc[mt][nt][0], acc[mt][nt][1]);
            if (r0 + 8 < NQ)
                *(float2*)&Out[(size_t)(r0 + 8) * 128 + col] = make_float2(acc[mt][nt][2], acc[mt][nt][3]);
        }
    }
}

// ---------------- convs 2-4 (3x3) via mma.sync bf16x3, 128x64 tile ----------------
constexpr int CATILE = 128 * ROWB;
constexpr int CBTILE = 64 * ROWB;
constexpr int CBUF = 2 * CATILE + 2 * CBTILE;
constexpr int CONV_SMEM = 2 * CBUF;

template<int CHUNKS, int CIN_CH, int CST>
__global__ void __launch_bounds__(256, 2) conv_mma_kernel(
    const __nv_bfloat16* __restrict__ inh, const __nv_bfloat16* __restrict__ inl,
    const __nv_bfloat16* __restrict__ wh, const __nv_bfloat16* __restrict__ wl,
    float* __restrict__ Out, int COUT)
{
    extern __shared__ char smem[];
    const int tid = threadIdx.x;
    const int wid = tid >> 5, lane = tid & 31;
    const int warp_m = wid >> 1, warp_n = wid & 1;
    const uint32_t sb = smem_u32(smem);
    const int bm = blockIdx.x * 128;

    const int lrow = tid >> 1, lhalf = tid & 1;
    const int pm = bm + lrow;
    const int py = pm / 200, px = pm % 200;
    const bool prow_ok = pm < NQ;
    const uint32_t s_arow = sb + (uint32_t)lrow * ROWB + (uint32_t)lhalf * 64;
    const int brow = tid >> 2, bq = tid & 3;
    const uint32_t s_brow = sb + 2 * CATILE + (uint32_t)brow * ROWB + (uint32_t)bq * 32;

    const uint32_t a_base = sb + (uint32_t)(warp_m * 32 + (lane & 15)) * ROWB + (uint32_t)(lane >> 4) * 16;
    const uint32_t b_base = sb + 2 * CATILE + (uint32_t)(warp_n * 32 + (lane & 7)) * ROWB
                          + (uint32_t)((lane >> 3) & 1) * 16;

    float acc[2][4][4];
    #pragma unroll
    for (int mt = 0; mt < 2; mt++)
        #pragma unroll
        for (int nt = 0; nt < 4; nt++)
            #pragma unroll
            for (int d = 0; d < 4; d++) acc[mt][nt][d] = 0.f;

    auto load_chunk = [&](int c, int buf) {
        const int e = c / CIN_CH, cih = c % CIN_CH;
        const int qy = py + e / 3 - 1;
        const int qx = px + e % 3 - 1;
        const bool val = prow_ok && qy >= 0 && qy < 200 && qx >= 0 && qx < 200;
        const size_t aoff = (size_t)(val ? (qy * 200 + qx) : 0) * CST + (size_t)cih * 64 + (size_t)lhalf * 32;
        const char* agh = (const char*)(inh + aoff);
        const char* agl = (const char*)(inl + aoff);
        const size_t boff = ((size_t)c * 64 + brow) * 64 + (size_t)bq * 16;
        const char* bgh = (const char*)(wh + boff);
        const char* bgl = (const char*)(wl + boff);
        const uint32_t sa = s_arow + (uint32_t)buf * CBUF;
        const uint32_t sbr = s_brow + (uint32_t)buf * CBUF;
        #pragma unroll
        for (int i = 0; i < 4; i++) {
            cpasync16(sa + i * 16,           agh + i * 16, val);
            cpasync16(sa + CATILE + i * 16,  agl + i * 16, val);
        }
        #pragma unroll
        for (int i = 0; i < 2; i++) {
            cpasync16(sbr + i * 16,          bgh + i * 16, true);
            cpasync16(sbr + CBTILE + i * 16, bgl + i * 16, true);
        }
    };

    load_chunk(0, 0); cp_commit();
    load_chunk(1, 1); cp_commit();

    for (int c = 0; c < CHUNKS; c++) {
        const int buf = c & 1;
        cp_wait1();
        __syncthreads();

        const uint32_t ab = a_base + (uint32_t)buf * CBUF;
        const uint32_t bb = b_base + (uint32_t)buf * CBUF;
        #pragma unroll
        for (int ks = 0; ks < 4; ks++) {
            const uint32_t kbyte = (uint32_t)ks * 32;
            uint32_t bh[4][2], bl[4][2];
            #pragma unroll
            for (int nt = 0; nt < 4; nt++) {
                ldmx2(bh[nt], bb + (uint32_t)nt * 8 * ROWB + kbyte);
                ldmx2(bl[nt], bb + CBTILE + (uint32_t)nt * 8 * ROWB + kbyte);
            }
            #pragma unroll
            for (int mt = 0; mt < 2; mt++) {
                uint32_t ah[4], al[4];
                ldmx4(ah, ab + (uint32_t)mt * 16 * ROWB + kbyte);
                ldmx4(al, ab + CATILE + (uint32_t)mt * 16 * ROWB + kbyte);
                #pragma unroll
                for (int nt = 0; nt < 4; nt++) {
                    mma_bf16(acc[mt][nt], ah, bh[nt]);
                    mma_bf16(acc[mt][nt], ah, bl[nt]);
                    mma_bf16(acc[mt][nt], al, bh[nt]);
                }
            }
        }
        __syncthreads();
        if (c + 2 < CHUNKS) load_chunk(c + 2, buf);
        cp_commit();
    }

    const int g = lane >> 2, tg = lane & 3;
    #pragma unroll
    for (int mt = 0; mt < 2; mt++) {
        const int r0 = bm + warp_m * 32 + mt * 16 + g;
        #pragma unroll
        for (int nt = 0; nt < 4; nt++) {
            const int col = warp_n * 32 + nt * 8 + tg * 2;
            if (col >= COUT) continue;
            if (r0 < NQ)
                *(float2*)&Out[(size_t)r0 * COUT + col] = make_float2(acc[mt][nt][0], acc[mt][nt][1]);
            if (r0 + 8 < NQ)
                *(float2*)&Out[(size_t)(r0 + 8) * COUT + col] = make_float2(acc[mt][nt][2], acc[mt][nt][3]);
        }
    }
}

// ---------------- batchnorm (320-way parallel partials, deterministic) ----------------
__global__ void bn_stats_kernel(const float* __restrict__ X, float* __restrict__ part, int C)
{
    int c = threadIdx.x;
    int g = blockIdx.x;
    const int per = (NQ + NPART - 1) / NPART;
    int p0 = g * per;
    int p1 = min(NQ, p0 + per);
    float s = 0.f, q = 0.f;
    for (int p = p0; p < p1; p++) {
        float x = X[(size_t)p * C + c];
        s += x; q += x * x;
    }
    part[(size_t)g * 2 * C + c] = s;
    part[(size_t)g * 2 * C + C + c] = q;
}

__global__ void bn_finalize_kernel(const float* __restrict__ part,
                                   const float* __restrict__ gamma, const float* __restrict__ beta,
                                   float* __restrict__ scale, float* __restrict__ shift, int C)
{
    int c = threadIdx.x;
    float s = 0.f, q = 0.f;
    for (int g = 0; g < NPART; g++) {
        s += part[(size_t)g * 2 * C + c];
        q += part[(size_t)g * 2 * C + C + c];
    }
    const float invP = 1.f / (float)NQ;
    float m = s * invP;
    float v = q * invP - m * m;
    float sc = gamma[c] * rsqrtf(v + 1e-5f);
    scale[c] = sc;
    shift[c] = beta[c] - m * sc;
}

__global__ void bn_apply_split_kernel(const float* __restrict__ X, const float* __restrict__ scale,
                                      const float* __restrict__ shift,
                                      __nv_bfloat16* __restrict__ hi, __nv_bfloat16* __restrict__ lo,
                                      int C, int CST, int total)
{
    int i = blockIdx.x * blockDim.x + threadIdx.x;
    if (i >= total) return;
    int c = i % CST;
    int p = i / CST;
    float v = 0.f;
    if (c < C) v = fmaxf(0.f, fmaf(X[(size_t)p * C + c], scale[c], shift[c]));
    split2(v, hi[i], lo[i]);
}

// ---------------- head: fused BN4+ReLU + 1x1 conv 48 -> 21, output NCHW ----------------
__global__ void head_conv_kernel(const float* __restrict__ H4raw, const float* __restrict__ scale,
                                 const float* __restrict__ shift,
                                 const float* __restrict__ Wo, const float* __restrict__ bo,
                                 float* __restrict__ out)
{
    int p = blockIdx.x * blockDim.x + threadIdx.x;
    if (p >= NQ) return;
    float x[48];
    const float4* hp = (const float4*)(H4raw + (size_t)p * 48);
    #pragma unroll
    for (int i = 0; i < 12; i++) {
        float4 v = hp[i];
        x[i * 4 + 0] = v.x; x[i * 4 + 1] = v.y; x[i * 4 + 2] = v.z; x[i * 4 + 3] = v.w;
    }
    #pragma unroll
    for (int ci = 0; ci < 48; ci++)
        x[ci] = fmaxf(0.f, fmaf(x[ci], scale[ci], shift[ci]));
    for (int co = 0; co < 21; co++) {
        float s = bo[co];
        const float* w = Wo + co * 48;
        #pragma unroll
        for (int ci = 0; ci < 48; ci++) s = fmaf(x[ci], w[ci], s);
        out[(size_t)co * NQ + p] = s;
    }
}

// ---------------- launch ----------------
extern "C" void kernel_launch(void* const* d_in, const int* in_sizes, int n_in,
                              void* d_out, int out_size)
{
    const float* value = (const float*)d_in[0];
    const float* bq    = (const float*)d_in[1];
    const float* bpos  = (const float*)d_in[2];
    const int*   proj  = (const int*)d_in[3];
    const float* Wv    = (const float*)d_in[4];
    const float* bv    = (const float*)d_in[5];
    const float* Woff  = (const float*)d_in[6];
    const float* boff  = (const float*)d_in[7];
    const float* Wattn = (const float*)d_in[8];
    const float* battn = (const float*)d_in[9];
    const float* Wout  = (const float*)d_in[10];
    const float* bout  = (const float*)d_in[11];
    const float* Wf1   = (const float*)d_in[12];
    const float* bf1   = (const float*)d_in[13];
    const float* Wf2   = (const float*)d_in[14];
    const float* bf2   = (const float*)d_in[15];
    const float* lng   = (const float*)d_in[16];
    const float* lnb   = (const float*)d_in[17];
    const float* cw1   = (const float*)d_in[18];
    const float* g1    = (const float*)d_in[19];
    const float* b1    = (const float*)d_in[20];
    const float* cw2   = (const float*)d_in[21];
    const float* g2    = (const float*)d_in[22];
    const float* b2    = (const float*)d_in[23];
    const float* cw3   = (const float*)d_in[24];
    const float* g3    = (const float*)d_in[25];
    const float* b3    = (const float*)d_in[26];
    const float* cw4   = (const float*)d_in[27];
    const float* g4    = (const float*)d_in[28];
    const float* b4    = (const float*)d_in[29];
    const float* objw  = (const float*)d_in[30];
    const float* objb  = (const float*)d_in[31];
    float* out = (float*)d_out;

    float* S = nullptr;
    cudaGetSymbolAddress((void**)&S, g_scratch);
    int* gm = nullptr;
    cudaGetSymbolAddress((void**)&gm, g_maxv);
    __nv_bfloat16 *s1h, *s1l, *s2h, *s2l, *wph, *wpl, *wch, *wcl;
    __half *vx, *vin16, *q16, *qp16, *w16, *wf16, *oa16;
    cudaGetSymbolAddress((void**)&s1h, g_s1h);
    cudaGetSymbolAddress((void**)&s1l, g_s1l);
    cudaGetSymbolAddress((void**)&s2h, g_s2h);
    cudaGetSymbolAddress((void**)&s2l, g_s2l);
    cudaGetSymbolAddress((void**)&vx,  g_vx);
    cudaGetSymbolAddress((void**)&vin16, g_vin16);
    cudaGetSymbolAddress((void**)&q16, g_q16);
    cudaGetSymbolAddress((void**)&qp16, g_qp16);
    cudaGetSymbolAddress((void**)&w16, g_w16);
    cudaGetSymbolAddress((void**)&wf16, g_wf16);
    cudaGetSymbolAddress((void**)&oa16, g_oa16);
    cudaGetSymbolAddress((void**)&wph, g_wph);
    cudaGetSymbolAddress((void**)&wpl, g_wpl);
    cudaGetSymbolAddress((void**)&wch, g_wch);
    cudaGetSymbolAddress((void**)&wcl, g_wcl);

    float* PQ    = S + OFF_Q;
    float* PT1   = S + OFF_T1;
    float* PT2   = S + OFF_T2;
    float* PH1   = S + OFF_H1;
    float* PH2   = S + OFF_H2;
    float* PH3   = S + OFF_H3;
    float* PH4   = S + OFF_H4;
    float* PPART = S + OFF_PART;
    float* PSCALE= S + OFF_SCALE;
    float* PSHIFT= S + OFF_SHIFT;
    float* PBIAS = S + OFF_BIAS;

    cudaFuncSetAttribute(conv1_f16_kernel, cudaFuncAttributeMaxDynamicSharedMemorySize, CONV1_SMEM);
    cudaFuncSetAttribute(gemm_f16<8>,    cudaFuncAttributeMaxDynamicSharedMemorySize, F16GEMM_SMEM);
    cudaFuncSetAttribute(gemm_f16<9>,    cudaFuncAttributeMaxDynamicSharedMemorySize, F16GEMM_SMEM);
    cudaFuncSetAttribute(gemm_f16<6>,    cudaFuncAttributeMaxDynamicSharedMemorySize, F16GEMM_SMEM);
    cudaFuncSetAttribute(gemm_mma6,      cudaFuncAttributeMaxDynamicSharedMemorySize, GEMM_SMEM);
    cudaFuncSetAttribute((conv_mma_kernel<18, 2, 128>), cudaFuncAttributeMaxDynamicSharedMemorySize, CONV_SMEM);
    cudaFuncSetAttribute((conv_mma_kernel<9, 1, 64>),   cudaFuncAttributeMaxDynamicSharedMemorySize, CONV_SMEM);

    // --- observed_masks ---
    init_max_kernel<<<1, 1>>>(gm);
    reduce_max_kernel<<<40, 256>>>(proj, gm);
    write_mask_kernel<<<(NQ + 255) / 256, 256>>>(proj, gm, out + 21 * NQ);

    // --- weight prep ---
    wsplit16_kernel<<<(W1CHUNKS * 128 * 64 + 255) / 256, 256>>>(cw1, w16);
    packcw_kernel<<<(18 * 4096 + 255) / 256, 256>>>(cw2, wch + WC2_OFF, wcl + WC2_OFF, 64, 128, 2, 18 * 4096);
    packcw_kernel<<<(9 * 4096 + 255) / 256, 256>>>(cw3, wch + WC3_OFF, wcl + WC3_OFF, 48, 64, 1, 9 * 4096);
    packcw_kernel<<<(9 * 4096 + 255) / 256, 256>>>(cw4, wch + WC4_OFF, wcl + WC4_OFF, 48, 48, 1, 9 * 4096);
    for (int i = 0; i < 2; i++) {
        size_t LW = (size_t)i * 1152 * 128;
        packwf16_kernel<<<(512 * 128 + 255) / 256, 256>>>(Woff + (size_t)i * 128 * 512, wf16 + LW,             512);
        packwf16_kernel<<<(256 * 128 + 255) / 256, 256>>>(Wattn+ (size_t)i * 128 * 256, wf16 + LW + 512 * 128, 256);
        packwf16_kernel<<<(128 * 128 + 255) / 256, 256>>>(Wv   + (size_t)i * 128 * 128, wf16 + LW + 768 * 128, 128);
        packwf16_kernel<<<(128 * 128 + 255) / 256, 256>>>(Wf1  + (size_t)i * 128 * 128, wf16 + LW + 896 * 128, 128);
        packwf16_kernel<<<(128 * 128 + 255) / 256, 256>>>(Wf2  + (size_t)i * 128 * 128, wf16 + LW + 1024 * 128, 128);
        packw_kernel<<<(128 * 128 + 255) / 256, 256>>>(Wout + (size_t)i * 128 * 128,
                                                       wph + (size_t)i * 128 * 128, wpl + (size_t)i * 128 * 128, 128);
        packbias_kernel<<<3, 256>>>(boff + i * 512, battn + i * 256, PBIAS + i * 768);
    }
    tof16_kernel<<<(NV * 128 + 255) / 256, 256>>>(value, vin16, NV * 128);

    // --- q init ---
    cudaMemcpyAsync(PQ, bq, (size_t)NQ * ED * sizeof(float), cudaMemcpyDeviceToDevice);

    // --- 2 encoder layers ---
    add_f16_kernel<<<(NQ * ED + 255) / 256, 256>>>(PQ, bpos, qp16, NQ * ED);
    for (int i = 0; i < 2; i++) {
        size_t LW = (size_t)i * 1152 * 128;
        // V projection (fp16) -> fp16 V for deform
        gemm_f16<8><<<dim3(340, 1), 256, F16GEMM_SMEM>>>(vin16, wf16 + LW + 768 * 128,
                                                         bv + i * 128, nullptr, nullptr, vx, NV, 128);
        // combined Woff+Wattn (fp16) -> fp16 OA buffer
        gemm_f16<8><<<dim3(313, 6), 256, F16GEMM_SMEM>>>(qp16, wf16 + LW,
                                                         PBIAS + i * 768, nullptr, nullptr, oa16, NQ, 768);
        deform_kernel<<<(NQ * HEADS + 255) / 256, 256>>>(vx, oa16, s2h, s2l);
        // Wout (bf16x3) + residual -> PT1
        gemm_mma6<<<dim3(313, 1), 256, GEMM_SMEM>>>(s2h, s2l, wph + (size_t)i * 128 * 128, wpl + (size_t)i * 128 * 128,
                                                    bout + i * 128, PQ, PT1, NQ, 128);
        // LN1 -> fp32 PQ + fp16 q16
        ln_kernel<3><<<NQ, 128>>>(PT1, lng + (i * 2 + 0) * 128, lnb + (i * 2 + 0) * 128, PQ, q16, nullptr);
        // FFN: Wf1 fp16 + relu -> fp16 h (qp16), Wf2 fp16 + residual -> fp32 PT2
        gemm_f16<9><<<dim3(313, 1), 256, F16GEMM_SMEM>>>(q16, wf16 + LW + 896 * 128,
                                                         bf1 + i * 128, nullptr, nullptr, qp16, NQ, 128);
        gemm_f16<6><<<dim3(313, 1), 256, F16GEMM_SMEM>>>(qp16, wf16 + LW + 1024 * 128,
                                                         bf2 + i * 128, PQ, PT2, nullptr, NQ, 128);
        if (i == 0)
            ln_kernel<4><<<NQ, 128>>>(PT2, lng + 1 * 128, lnb + 1 * 128, PQ, qp16, bpos);  // fp16(q+pos)
        else
            ln_kernel<3><<<NQ, 128>>>(PT2, lng + 3 * 128, lnb + 3 * 128, PQ, q16, nullptr); // fp16(q)
    }

    // --- conv head ---
    conv1_f16_kernel<<<313, 256, CONV1_SMEM>>>(q16, w16, PH1);
    bn_stats_kernel<<<NPART, 128>>>(PH1, PPART, 128);
    bn_finalize_kernel<<<1, 128>>>(PPART, g1, b1, PSCALE, PSHIFT, 128);
    bn_apply_split_kernel<<<(NQ * 128 + 255) / 256, 256>>>(PH1, PSCALE, PSHIFT, s1h, s1l, 128, 128, NQ * 128);

    conv_mma_kernel<18, 2, 128><<<313, 256, CONV_SMEM>>>(s1h, s1l, wch + WC2_OFF, wcl + WC2_OFF, PH2, 64);
    bn_stats_kernel<<<NPART, 64>>>(PH2, PPART, 64);
    bn_finalize_kernel<<<1, 64>>>(PPART, g2, b2, PSCALE, PSHIFT, 64);
    bn_apply_split_kernel<<<(NQ * 64 + 255) / 256, 256>>>(PH2, PSCALE, PSHIFT, s2h, s2l, 64, 64, NQ * 64);

    conv_mma_kernel<9, 1, 64><<<313, 256, CONV_SMEM>>>(s2h, s2l, wch + WC3_OFF, wcl + WC3_OFF, PH3, 48);
    bn_stats_kernel<<<NPART, 48>>>(PH3, PPART, 48);
    bn_finalize_kernel<<<1, 48>>>(PPART, g3, b3, PSCALE, PSHIFT, 48);
    bn_apply_split_kernel<<<(NQ * 64 + 255) / 256, 256>>>(PH3, PSCALE, PSHIFT, s1h, s1l, 48, 64, NQ * 64);

    conv_mma_kernel<9, 1, 64><<<313, 256, CONV_SMEM>>>(s1h, s1l, wch + WC4_OFF, wcl + WC4_OFF, PH4, 48);
    bn_stats_kernel<<<NPART, 48>>>(PH4, PPART, 48);
    bn_finalize_kernel<<<1, 48>>>(PPART, g4, b4, PSCALE, PSHIFT, 48);
    head_conv_kernel<<<(NQ + 255) / 256, 256>>>(PH4, PSCALE, PSHIFT, objw, objb, out);
}

// round 12
// speedup vs baseline: 3.0033x; 1.0235x over previous
#include <cuda_runtime.h>
#include <cuda_bf16.h>
#include <cuda_fp16.h>
#include <cstdint>
#include <climits>

// ---------------- problem constants ----------------
constexpr int NQ = 40000;        // 200*200
constexpr int ED = 128;
constexpr int NV = 43520;        // sum of level sizes
constexpr int HEADS = 8;
constexpr int NPART = 320;       // bn partial blocks

// ---------------- scratch layout (floats) ----------------
constexpr size_t OFF_Q    = 0;
constexpr size_t SZ_Q     = (size_t)NQ * ED;
constexpr size_t OFF_T1   = OFF_Q + SZ_Q;
constexpr size_t OFF_T2   = OFF_T1 + SZ_Q;
constexpr size_t OFF_H1   = OFF_T2 + SZ_Q;
constexpr size_t SZ_H1    = (size_t)NQ * 128;
constexpr size_t OFF_H2   = OFF_H1 + SZ_H1;
constexpr size_t SZ_H2    = (size_t)NQ * 64;
constexpr size_t OFF_H3   = OFF_H2 + SZ_H2;
constexpr size_t SZ_H3    = (size_t)NQ * 48;
constexpr size_t OFF_H4   = OFF_H3 + SZ_H3;
constexpr size_t OFF_PART = OFF_H4 + SZ_H3;
constexpr size_t SZ_PART  = (size_t)NPART * 2 * 128;
constexpr size_t OFF_SCALE= OFF_PART + SZ_PART;
constexpr size_t OFF_SHIFT= OFF_SCALE + 128;
constexpr size_t OFF_BIAS = OFF_SHIFT + 128;       // 2 layers x 768 packed bias
constexpr size_t SCRATCH_TOTAL = OFF_BIAS + 2 * 768;

__device__ float g_scratch[SCRATCH_TOTAL];
__device__ int   g_maxv;

// ---------------- bf16 / fp16 buffers ----------------
constexpr int W1CHUNKS = 98;                 // conv1: 49 taps * 2 ci-halves
__device__ __align__(16) __nv_bfloat16 g_s1h[(size_t)NQ * 128];
__device__ __align__(16) __nv_bfloat16 g_s1l[(size_t)NQ * 128];
__device__ __align__(16) __nv_bfloat16 g_s2h[(size_t)NQ * 128];
__device__ __align__(16) __nv_bfloat16 g_s2l[(size_t)NQ * 128];
__device__ __align__(16) __half        g_vx[(size_t)NV * 128];    // fp16 V for deform
__device__ __align__(16) __half        g_vin16[(size_t)NV * 128]; // fp16 value input
__device__ __align__(16) __half        g_q16[(size_t)NQ * 128];   // fp16 scratch
__device__ __align__(16) __half        g_qp16[(size_t)NQ * 128];  // fp16 scratch
__device__ __align__(16) __half        g_oa16[(size_t)NQ * 768];  // fp16 offsets+logits
// Wout (bf16x3) per layer 128 x 128
__device__ __align__(16) __nv_bfloat16 g_wph[(size_t)2 * 128 * 128];
__device__ __align__(16) __nv_bfloat16 g_wpl[(size_t)2 * 128 * 128];
// fp16 weights per layer: [OA 768][Wv 128][Wf1 128][Wf2 128] x 128 k
__device__ __align__(16) __half g_wf16[(size_t)2 * 1152 * 128];
// conv1 weights [chunk][co 128][k 64] fp16
__device__ __align__(16) __half g_w16[(size_t)W1CHUNKS * 128 * 64];
// convs 2-4 bf16 split weights
constexpr int WC2_OFF = 0, WC3_OFF = 73728, WC4_OFF = 110592, WC_TOTAL = 147456;
__device__ __align__(16) __nv_bfloat16 g_wch[WC_TOTAL];
__device__ __align__(16) __nv_bfloat16 g_wcl[WC_TOTAL];

// ---------------- small helpers ----------------
__device__ __forceinline__ uint32_t smem_u32(const void* p) {
    return (uint32_t)__cvta_generic_to_shared(p);
}
__device__ __forceinline__ void cpasync16(uint32_t dst, const void* src, bool valid) {
    asm volatile("cp.async.cg.shared.global [%0], [%1], 16, %2;"
                 :: "r"(dst), "l"(src), "r"(valid ? 16u : 0u));
}
__device__ __forceinline__ void cp_commit() { asm volatile("cp.async.commit_group;"); }
__device__ __forceinline__ void cp_wait1()  { asm volatile("cp.async.wait_group 1;"); }
__device__ __forceinline__ void cp_wait0()  { asm volatile("cp.async.wait_group 0;"); }

__device__ __forceinline__ void ldmx4(uint32_t* r, uint32_t addr) {
    asm volatile("ldmatrix.sync.aligned.m8n8.x4.shared.b16 {%0,%1,%2,%3}, [%4];"
                 : "=r"(r[0]), "=r"(r[1]), "=r"(r[2]), "=r"(r[3]) : "r"(addr));
}
__device__ __forceinline__ void ldmx2(uint32_t* r, uint32_t addr) {
    asm volatile("ldmatrix.sync.aligned.m8n8.x2.shared.b16 {%0,%1}, [%2];"
                 : "=r"(r[0]), "=r"(r[1]) : "r"(addr));
}
__device__ __forceinline__ void mma_bf16(float* c, const uint32_t* a, const uint32_t* b) {
    asm volatile("mma.sync.aligned.m16n8k16.row.col.f32.bf16.bf16.f32 "
                 "{%0,%1,%2,%3}, {%4,%5,%6,%7}, {%8,%9}, {%0,%1,%2,%3};"
                 : "+f"(c[0]), "+f"(c[1]), "+f"(c[2]), "+f"(c[3])
                 : "r"(a[0]), "r"(a[1]), "r"(a[2]), "r"(a[3]), "r"(b[0]), "r"(b[1]));
}
__device__ __forceinline__ void mma_f16(float* c, const uint32_t* a, const uint32_t* b) {
    asm volatile("mma.sync.aligned.m16n8k16.row.col.f32.f16.f16.f32 "
                 "{%0,%1,%2,%3}, {%4,%5,%6,%7}, {%8,%9}, {%0,%1,%2,%3};"
                 : "+f"(c[0]), "+f"(c[1]), "+f"(c[2]), "+f"(c[3])
                 : "r"(a[0]), "r"(a[1]), "r"(a[2]), "r"(a[3]), "r"(b[0]), "r"(b[1]));
}
__device__ __forceinline__ void split2(float v, __nv_bfloat16& h, __nv_bfloat16& l) {
    h = __float2bfloat16(v);
    l = __float2bfloat16(v - __bfloat162float(h));
}

// ---------------- elementwise helpers ----------------
__global__ void init_max_kernel(int* gm) { *gm = INT_MIN; }

__global__ void reduce_max_kernel(const int* __restrict__ p, int* gm) {
    int v = INT_MIN;
    for (int k = blockIdx.x * blockDim.x + threadIdx.x; k < NQ; k += gridDim.x * blockDim.x)
        v = max(v, p[k]);
    #pragma unroll
    for (int o = 16; o > 0; o >>= 1) v = max(v, __shfl_xor_sync(0xffffffffu, v, o));
    __shared__ int sm[8];
    int w = threadIdx.x >> 5;
    if ((threadIdx.x & 31) == 0) sm[w] = v;
    __syncthreads();
    if (threadIdx.x == 0) {
        int bv = sm[0];
        for (int i = 1; i < (int)(blockDim.x >> 5); i++) bv = max(bv, sm[i]);
        atomicMax(gm, bv);
    }
}

__global__ void write_mask_kernel(const int* __restrict__ p, const int* __restrict__ gm,
                                  float* __restrict__ out) {
    int i = blockIdx.x * blockDim.x + threadIdx.x;
    if (i < NQ) out[i] = (p[i] < *gm) ? 1.0f : 0.0f;
}

// fp32 -> fp16
__global__ void tof16_kernel(const float* __restrict__ X, __half* __restrict__ o, int n)
{
    int i = blockIdx.x * blockDim.x + threadIdx.x;
    if (i < n) o[i] = __float2half_rn(X[i]);
}

// q+pos -> fp16
__global__ void add_f16_kernel(const float* __restrict__ A, const float* __restrict__ B,
                               __half* __restrict__ o, int n)
{
    int i = blockIdx.x * blockDim.x + threadIdx.x;
    if (i < n) o[i] = __float2half_rn(A[i] + B[i]);
}

// ---------------- fused weight prep: all packing in one launch ----------------
constexpr int Q0 = 802816;            // conv1 fp16 [chunk][co][k]
constexpr int Q1 = Q0 + 73728;        // conv2 bf16 split
constexpr int Q2 = Q1 + 36864;        // conv3 bf16 split
constexpr int Q3 = Q2 + 36864;        // conv4 bf16 split
constexpr int Q4 = Q3 + 2 * 98304;    // OA fp16 (Woff|Wattn), both layers
constexpr int Q5 = Q4 + 2 * 16384;    // Wv fp16
constexpr int Q6 = Q5 + 2 * 16384;    // Wf1 fp16
constexpr int Q7 = Q6 + 2 * 16384;    // Wf2 fp16
constexpr int Q8 = Q7 + 2 * 16384;    // Wout bf16 split
constexpr int Q9 = Q8 + 2 * 768;      // bias pack

__global__ void prep_kernel(
    const float* __restrict__ cw1, const float* __restrict__ cw2,
    const float* __restrict__ cw3, const float* __restrict__ cw4,
    const float* __restrict__ Woff, const float* __restrict__ Wattn,
    const float* __restrict__ Wv, const float* __restrict__ Wf1,
    const float* __restrict__ Wf2, const float* __restrict__ Wout,
    const float* __restrict__ boff, const float* __restrict__ battn,
    __half* __restrict__ w16, __nv_bfloat16* __restrict__ wch, __nv_bfloat16* __restrict__ wcl,
    __half* __restrict__ wf16,
    __nv_bfloat16* __restrict__ wph, __nv_bfloat16* __restrict__ wpl,
    float* __restrict__ bias_out)
{
    int i = blockIdx.x * blockDim.x + threadIdx.x;
    if (i >= Q9) return;
    if (i < Q0) {
        int k = i & 63, co = (i >> 6) & 127, c = i >> 13;
        int e = c >> 1, ci = ((c & 1) << 6) + k;
        w16[i] = __float2half_rn(cw1[(((size_t)co * 128 + ci) * 7 + e / 7) * 7 + e % 7]);
    } else if (i < Q3) {
        const float* W; int CO, CI, CIN_CH, base, j;
        if (i < Q1)      { j = i - Q0; W = cw2; CO = 64; CI = 128; CIN_CH = 2; base = WC2_OFF; }
        else if (i < Q2) { j = i - Q1; W = cw3; CO = 48; CI = 64;  CIN_CH = 1; base = WC3_OFF; }
        else             { j = i - Q2; W = cw4; CO = 48; CI = 48;  CIN_CH = 1; base = WC4_OFF; }
        int k = j & 63, co = (j >> 6) & 63, c = j >> 12;
        int e = c / CIN_CH, ci = (c % CIN_CH) * 64 + k;
        float v = (co < CO && ci < CI) ? W[(((size_t)co * CI + ci) * 3 + e / 3) * 3 + e % 3] : 0.f;
        split2(v, wch[base + j], wcl[base + j]);
    } else if (i < Q4) {
        int j = i - Q3, l = j / 98304, r = j % 98304;
        int n = r >> 7, k = r & 127;
        float v = (n < 512) ? Woff[((size_t)l * 128 + k) * 512 + n]
                            : Wattn[((size_t)l * 128 + k) * 256 + (n - 512)];
        wf16[(size_t)l * 147456 + r] = __float2half_rn(v);
    } else if (i < Q7) {
        const float* W; int off, j;
        if (i < Q5)      { j = i - Q4; W = Wv;  off = 768 * 128; }
        else if (i < Q6) { j = i - Q5; W = Wf1; off = 896 * 128; }
        else             { j = i - Q6; W = Wf2; off = 1024 * 128; }
        int l = j >> 14, r = j & 16383;
        int n = r >> 7, k = r & 127;
        wf16[(size_t)l * 147456 + off + r] = __float2half_rn(W[((size_t)l * 128 + k) * 128 + n]);
    } else if (i < Q8) {
        int j = i - Q7, l = j >> 14, r = j & 16383;
        int n = r >> 7, k = r & 127;
        split2(Wout[((size_t)l * 128 + k) * 128 + n], wph[(size_t)l * 16384 + r], wpl[(size_t)l * 16384 + r]);
    } else {
        int j = i - Q8, l = j / 768, n = j % 768;
        bias_out[(size_t)l * 768 + n] = (n < 512) ? boff[(size_t)l * 512 + n] : battn[(size_t)l * 256 + n - 512];
    }
}

// ---------------- bf16x3 GEMM (Wout only): residual + fp32 out ----------------
constexpr int GROWB = 272;
constexpr int GTILE = 128 * GROWB;
constexpr int GEMM_SMEM = 4 * GTILE;

__global__ void __launch_bounds__(256, 1) gemm_mma6(
    const __nv_bfloat16* __restrict__ Ah, const __nv_bfloat16* __restrict__ Al,
    const __nv_bfloat16* __restrict__ Bh, const __nv_bfloat16* __restrict__ Bl,
    const float* __restrict__ bias, const float* __restrict__ R,
    float* __restrict__ Cf, int M, int N)
{
    extern __shared__ char smem[];
    const int tid = threadIdx.x;
    const int wid = tid >> 5, lane = tid & 31;
    const int warp_m = wid >> 2, warp_n = wid & 3;
    const uint32_t sb = smem_u32(smem);
    const int bm = blockIdx.x * 128, bn = blockIdx.y * 128;

    {
        const int lrow = tid >> 1, lhalf = tid & 1;
        const bool aval = (bm + lrow) < M;
        const uint32_t sa = sb + (uint32_t)lrow * GROWB + (uint32_t)lhalf * 128;
        const char* agh = (const char*)(Ah + (size_t)(aval ? (bm + lrow) : 0) * 128 + lhalf * 64);
        const char* agl = (const char*)(Al + (size_t)(aval ? (bm + lrow) : 0) * 128 + lhalf * 64);
        const char* bgh = (const char*)(Bh + (size_t)(bn + lrow) * 128 + lhalf * 64);
        const char* bgl = (const char*)(Bl + (size_t)(bn + lrow) * 128 + lhalf * 64);
        #pragma unroll
        for (int i = 0; i < 8; i++) {
            cpasync16(sa + i * 16,             agh + i * 16, aval);
            cpasync16(sa + GTILE + i * 16,     agl + i * 16, aval);
            cpasync16(sa + 2 * GTILE + i * 16, bgh + i * 16, true);
            cpasync16(sa + 3 * GTILE + i * 16, bgl + i * 16, true);
        }
        cp_commit();
        cp_wait0();
        __syncthreads();
    }

    float acc[4][4][4];
    #pragma unroll
    for (int mt = 0; mt < 4; mt++)
        #pragma unroll
        for (int nt = 0; nt < 4; nt++)
            #pragma unroll
            for (int d = 0; d < 4; d++) acc[mt][nt][d] = 0.f;

    const uint32_t a_base = sb + (uint32_t)(warp_m * 64 + (lane & 15)) * GROWB + (uint32_t)(lane >> 4) * 16;
    const uint32_t b_base = sb + 2 * GTILE + (uint32_t)(warp_n * 32 + (lane & 7)) * GROWB
                          + (uint32_t)((lane >> 3) & 1) * 16;

    #pragma unroll
    for (int ks = 0; ks < 8; ks++) {
        const uint32_t kbyte = (uint32_t)ks * 32;
        uint32_t bh[4][2], bl[4][2];
        #pragma unroll
        for (int nt = 0; nt < 4; nt++) {
            ldmx2(bh[nt], b_base + (uint32_t)nt * 8 * GROWB + kbyte);
            ldmx2(bl[nt], b_base + GTILE + (uint32_t)nt * 8 * GROWB + kbyte);
        }
        #pragma unroll
        for (int mt = 0; mt < 4; mt++) {
            uint32_t ah[4], al[4];
            ldmx4(ah, a_base + (uint32_t)mt * 16 * GROWB + kbyte);
            ldmx4(al, a_base + GTILE + (uint32_t)mt * 16 * GROWB + kbyte);
            #pragma unroll
            for (int nt = 0; nt < 4; nt++) {
                mma_bf16(acc[mt][nt], ah, bh[nt]);
                mma_bf16(acc[mt][nt], ah, bl[nt]);
                mma_bf16(acc[mt][nt], al, bh[nt]);
            }
        }
    }

    const int g = lane >> 2, tg = lane & 3;
    #pragma unroll
    for (int mt = 0; mt < 4; mt++) {
        const int r0 = bm + warp_m * 64 + mt * 16 + g;
        #pragma unroll
        for (int nt = 0; nt < 4; nt++) {
            const int col = bn + warp_n * 32 + nt * 8 + tg * 2;
            float2 bb = *(const float2*)&bias[col];
            #pragma unroll
            for (int half = 0; half < 2; half++) {
                const int r = r0 + half * 8;
                if (r >= M) continue;
                float2 rr = *(const float2*)&R[(size_t)r * N + col];
                *(float2*)&Cf[(size_t)r * N + col] =
                    make_float2(acc[mt][nt][half * 2] + bb.x + rr.x,
                                acc[mt][nt][half * 2 + 1] + bb.y + rr.y);
            }
        }
    }
}

// ---------------- fp16 single GEMM ----------------
// FLAGS: 1 relu, 2 residual (fp32 R), 4 fp32 out, 8 fp16 out
constexpr int F16GEMM_SMEM = 2 * GTILE;

template<int FLAGS>
__global__ void __launch_bounds__(256, 2) gemm_f16(
    const __half* __restrict__ A, const __half* __restrict__ B,
    const float* __restrict__ bias, const float* __restrict__ R,
    float* __restrict__ Cf, __half* __restrict__ Cx, int M, int N)
{
    extern __shared__ char smem[];
    const int tid = threadIdx.x;
    const int wid = tid >> 5, lane = tid & 31;
    const int warp_m = wid >> 2, warp_n = wid & 3;
    const uint32_t sb = smem_u32(smem);
    const int bm = blockIdx.x * 128, bn = blockIdx.y * 128;

    {
        const int lrow = tid >> 1, lhalf = tid & 1;
        const bool aval = (bm + lrow) < M;
        const uint32_t sa = sb + (uint32_t)lrow * GROWB + (uint32_t)lhalf * 128;
        const char* ag = (const char*)(A + (size_t)(aval ? (bm + lrow) : 0) * 128 + lhalf * 64);
        const char* bg = (const char*)(B + (size_t)(bn + lrow) * 128 + lhalf * 64);
        #pragma unroll
        for (int i = 0; i < 8; i++) {
            cpasync16(sa + i * 16,         ag + i * 16, aval);
            cpasync16(sa + GTILE + i * 16, bg + i * 16, true);
        }
        cp_commit();
        cp_wait0();
        __syncthreads();
    }

    float acc[4][4][4];
    #pragma unroll
    for (int mt = 0; mt < 4; mt++)
        #pragma unroll
        for (int nt = 0; nt < 4; nt++)
            #pragma unroll
            for (int d = 0; d < 4; d++) acc[mt][nt][d] = 0.f;

    const uint32_t a_base = sb + (uint32_t)(warp_m * 64 + (lane & 15)) * GROWB + (uint32_t)(lane >> 4) * 16;
    const uint32_t b_base = sb + GTILE + (uint32_t)(warp_n * 32 + (lane & 7)) * GROWB
                          + (uint32_t)((lane >> 3) & 1) * 16;

    #pragma unroll
    for (int ks = 0; ks < 8; ks++) {
        const uint32_t kbyte = (uint32_t)ks * 32;
        uint32_t bfr[4][2];
        #pragma unroll
        for (int nt = 0; nt < 4; nt++)
            ldmx2(bfr[nt], b_base + (uint32_t)nt * 8 * GROWB + kbyte);
        #pragma unroll
        for (int mt = 0; mt < 4; mt++) {
            uint32_t afr[4];
            ldmx4(afr, a_base + (uint32_t)mt * 16 * GROWB + kbyte);
            #pragma unroll
            for (int nt = 0; nt < 4; nt++)
                mma_f16(acc[mt][nt], afr, bfr[nt]);
        }
    }

    const int g = lane >> 2, tg = lane & 3;
    #pragma unroll
    for (int mt = 0; mt < 4; mt++) {
        const int r0 = bm + warp_m * 64 + mt * 16 + g;
        #pragma unroll
        for (int nt = 0; nt < 4; nt++) {
            const int col = bn + warp_n * 32 + nt * 8 + tg * 2;
            float2 bb = *(const float2*)&bias[col];
            #pragma unroll
            for (int half = 0; half < 2; half++) {
                const int r = r0 + half * 8;
                if (r >= M) continue;
                float a0 = acc[mt][nt][half * 2] + bb.x;
                float a1 = acc[mt][nt][half * 2 + 1] + bb.y;
                if (FLAGS & 2) {
                    float2 rr = *(const float2*)&R[(size_t)r * N + col];
                    a0 += rr.x; a1 += rr.y;
                }
                if (FLAGS & 1) { a0 = fmaxf(a0, 0.f); a1 = fmaxf(a1, 0.f); }
                if (FLAGS & 4)
                    *(float2*)&Cf[(size_t)r * N + col] = make_float2(a0, a1);
                if (FLAGS & 8)
                    *(__half2*)&Cx[(size_t)r * N + col] = __floats2half2_rn(a0, a1);
            }
        }
    }
}

// ---------------- deformable attention sampling (fp16 V + fp16 OA, fused softmax) ----------------
__global__ void __launch_bounds__(256) deform_kernel(
    const __half* __restrict__ VX, const __half* __restrict__ OA,
    __nv_bfloat16* __restrict__ OH, __nv_bfloat16* __restrict__ OL)
{
    int t = blockIdx.x * 256 + threadIdx.x;
    if (t >= NQ * HEADS) return;
    const int n = t >> 3, h = t & 7;
    const float rx = ((float)(n % 200) + 0.5f) * (1.f / 200.f);
    const float ry = ((float)(n / 200) + 0.5f) * (1.f / 200.f);
    const __half* op = OA + (size_t)n * 768 + h * 64;
    const __half* ap = OA + (size_t)n * 768 + 512 + h * 32;

    float e[32];
    {
        const uint4* apv = (const uint4*)ap;
        #pragma unroll
        for (int q = 0; q < 4; q++) {
            uint4 u = apv[q];
            uint32_t wv[4] = {u.x, u.y, u.z, u.w};
            #pragma unroll
            for (int d = 0; d < 4; d++) {
                float2 f2 = __half22float2(*(const __half2*)&wv[d]);
                e[q * 8 + d * 2 + 0] = f2.x;
                e[q * 8 + d * 2 + 1] = f2.y;
            }
        }
        float m = -1e30f;
        #pragma unroll
        for (int k = 0; k < 32; k++) m = fmaxf(m, e[k]);
        float s = 0.f;
        #pragma unroll
        for (int k = 0; k < 32; k++) { e[k] = expf(e[k] - m); s += e[k]; }
        float inv = 1.f / s;
        #pragma unroll
        for (int k = 0; k < 32; k++) e[k] *= inv;
    }

    float acc[16];
    #pragma unroll
    for (int d = 0; d < 16; d++) acc[d] = 0.f;

    const int stc[4] = {0, 32768, 40960, 43008};
    const int Wc[4]  = {256, 128, 64, 32};
    const int Hc[4]  = {128, 64, 32, 16};

    #pragma unroll
    for (int l = 0; l < 4; l++) {
        const int W = Wc[l], H = Hc[l], st = stc[l];
        const float Wf = (float)W, Hf = (float)H;
        for (int p = 0; p < 8; p++) {
            float2 off2 = __half22float2(*(const __half2*)(op + (l * 8 + p) * 2));
            float aw = e[l * 8 + p];
            float x = (rx + off2.x / Wf) * Wf - 0.5f;
            float y = (ry + off2.y / Hf) * Hf - 0.5f;
            float xf = floorf(x), yf = floorf(y);
            int x0 = (int)xf, y0 = (int)yf;
            float fx = x - xf, fy = y - yf;
            float wx[2] = {1.f - fx, fx};
            float wy[2] = {1.f - fy, fy};
            #pragma unroll
            for (int c = 0; c < 4; c++) {
                int xi = x0 + (c & 1), yi = y0 + (c >> 1);
                float wgt = wx[c & 1] * wy[c >> 1];
                if (xi >= 0 && xi < W && yi >= 0 && yi < H && wgt != 0.f) {
                    const uint4* gp = (const uint4*)(VX + ((size_t)(st + yi * W + xi)) * 128 + h * 16);
                    uint4 u0 = gp[0];
                    uint4 u1 = gp[1];
                    uint32_t wv[8] = {u0.x, u0.y, u0.z, u0.w, u1.x, u1.y, u1.z, u1.w};
                    float cw = aw * wgt;
                    #pragma unroll
                    for (int d = 0; d < 8; d++) {
                        float2 g2 = __half22float2(*(const __half2*)&wv[d]);
                        acc[d * 2 + 0] += cw * g2.x;
                        acc[d * 2 + 1] += cw * g2.y;
                    }
                }
            }
        }
    }
    __nv_bfloat162* oh = (__nv_bfloat162*)(OH + (size_t)n * 128 + h * 16);
    __nv_bfloat162* ol = (__nv_bfloat162*)(OL + (size_t)n * 128 + h * 16);
    #pragma unroll
    for (int d = 0; d < 8; d++) {
        __nv_bfloat16 h0, l0, h1, l1;
        split2(acc[d * 2], h0, l0); split2(acc[d * 2 + 1], h1, l1);
        oh[d] = __nv_bfloat162(h0, h1);
        ol[d] = __nv_bfloat162(l0, l1);
    }
}

// ---------------- layernorm over 128 per row ----------------
// MODE: 3 fp32 + fp16(y), 4 fp32 + fp16(y + pos)
template<int MODE>
__global__ void ln_kernel(const float* __restrict__ X, const float* __restrict__ g,
                          const float* __restrict__ b, float* __restrict__ Y,
                          __half* __restrict__ Yx, const float* __restrict__ pos)
{
    int r = blockIdx.x;
    int t = threadIdx.x;
    float x = X[(size_t)r * 128 + t];
    float s = x;
    #pragma unroll
    for (int o = 16; o > 0; o >>= 1) s += __shfl_xor_sync(0xffffffffu, s, o);
    __shared__ float sm[4], sm2[4];
    int w = t >> 5, lane = t & 31;
    if (lane == 0) sm[w] = s;
    __syncthreads();
    float m = (sm[0] + sm[1] + sm[2] + sm[3]) * (1.f / 128.f);
    float d = x - m;
    float q = d * d;
    #pragma unroll
    for (int o = 16; o > 0; o >>= 1) q += __shfl_xor_sync(0xffffffffu, q, o);
    if (lane == 0) sm2[w] = q;
    __syncthreads();
    float var = (sm2[0] + sm2[1] + sm2[2] + sm2[3]) * (1.f / 128.f);
    float y = d * rsqrtf(var + 1e-5f) * g[t] + b[t];
    Y[(size_t)r * 128 + t] = y;
    if (MODE == 3)
        Yx[(size_t)r * 128 + t] = __float2half_rn(y);
    if (MODE == 4)
        Yx[(size_t)r * 128 + t] = __float2half_rn(y + pos[(size_t)r * 128 + t]);
}

// ---------------- conv1 (7x7, 128->128) via mma.sync fp16 single ----------------
constexpr int ROWB = 144;
constexpr int C1TILE = 128 * ROWB;
constexpr int C1BUF  = 2 * C1TILE;
constexpr int CONV1_SMEM = 2 * C1BUF;

__global__ void __launch_bounds__(256, 2) conv1_f16_kernel(
    const __half* __restrict__ q16, const __half* __restrict__ w16,
    float* __restrict__ Out)
{
    extern __shared__ char smem[];
    const int tid = threadIdx.x;
    const int wid = tid >> 5, lane = tid & 31;
    const int warp_m = wid >> 2, warp_n = wid & 3;
    const uint32_t sb = smem_u32(smem);
    const int bm = blockIdx.x * 128;

    const int lrow = tid >> 1, lhalf = tid & 1;
    const int pm = bm + lrow;
    const int py = pm / 200, px = pm % 200;
    const bool prow_ok = pm < NQ;
    const uint32_t s_arow = sb + (uint32_t)lrow * ROWB + (uint32_t)lhalf * 64;
    const uint32_t s_brow = s_arow + C1TILE;

    const uint32_t a_base = sb + (uint32_t)(warp_m * 64 + (lane & 15)) * ROWB + (uint32_t)(lane >> 4) * 16;
    const uint32_t b_base = sb + C1TILE + (uint32_t)(warp_n * 32 + (lane & 7)) * ROWB
                          + (uint32_t)((lane >> 3) & 1) * 16;

    float acc[4][4][4];
    #pragma unroll
    for (int mt = 0; mt < 4; mt++)
        #pragma unroll
        for (int nt = 0; nt < 4; nt++)
            #pragma unroll
            for (int d = 0; d < 4; d++) acc[mt][nt][d] = 0.f;

    auto load_chunk = [&](int c, int buf) {
        const int e = c >> 1, ch = c & 1;
        const int qy = py + e / 7 - 3;
        const int qx = px + e % 7 - 3;
        const bool val = prow_ok && qy >= 0 && qy < 200 && qx >= 0 && qx < 200;
        const size_t aoff = (size_t)(val ? (qy * 200 + qx) : 0) * 128 + (size_t)ch * 64 + (size_t)lhalf * 32;
        const char* ag = (const char*)(q16 + aoff);
        const size_t boff = ((size_t)c * 128 + lrow) * 64 + (size_t)lhalf * 32;
        const char* bg = (const char*)(w16 + boff);
        const uint32_t sa = s_arow + (uint32_t)buf * C1BUF;
        const uint32_t sbr = s_brow + (uint32_t)buf * C1BUF;
        #pragma unroll
        for (int i = 0; i < 4; i++) {
            cpasync16(sa + i * 16,  ag + i * 16, val);
            cpasync16(sbr + i * 16, bg + i * 16, true);
        }
    };

    load_chunk(0, 0); cp_commit();
    load_chunk(1, 1); cp_commit();

    for (int c = 0; c < W1CHUNKS; c++) {
        const int buf = c & 1;
        cp_wait1();
        __syncthreads();

        const uint32_t ab = a_base + (uint32_t)buf * C1BUF;
        const uint32_t bb = b_base + (uint32_t)buf * C1BUF;
        #pragma unroll
        for (int ks = 0; ks < 4; ks++) {
            const uint32_t kbyte = (uint32_t)ks * 32;
            uint32_t bfr[4][2];
            #pragma unroll
            for (int nt = 0; nt < 4; nt++)
                ldmx2(bfr[nt], bb + (uint32_t)nt * 8 * ROWB + kbyte);
            #pragma unroll
            for (int mt = 0; mt < 4; mt++) {
                uint32_t afr[4];
                ldmx4(afr, ab + (uint32_t)mt * 16 * ROWB + kbyte);
                #pragma unroll
                for (int nt = 0; nt < 4; nt++)
                    mma_f16(acc[mt][nt], afr, bfr[nt]);
            }
        }
        __syncthreads();
        if (c + 2 < W1CHUNKS) load_chunk(c + 2, buf);
        cp_commit();
    }

    const int g = lane >> 2, tg = lane & 3;
    #pragma unroll
    for (int mt = 0; mt < 4; mt++) {
        const int r0 = bm + warp_m * 64 + mt * 16 + g;
        #pragma unroll
        for (int nt = 0; nt < 4; nt++) {
            const int col = warp_n * 32 + nt * 8 + tg * 2;
            if (r0 < NQ)
                *(float2*)&Out[(size_t)r0 * 128 + col] = make_float2(acc[mt][nt][0], acc[mt][nt][1]);
            if (r0 + 8 < NQ)
                *(float2*)&Out[(size_t)(r0 + 8) * 128 + col] = make_float2(acc[mt][nt][2], acc[mt][nt][3]);
        }
    }
}

// ---------------- convs 2-4 (3x3) via mma.sync bf16x3, 128x64 tile ----------------
constexpr int CATILE = 128 * ROWB;
constexpr int CBTILE = 64 * ROWB;
constexpr int CBUF = 2 * CATILE + 2 * CBTILE;
constexpr int CONV_SMEM = 2 * CBUF;

template<int CHUNKS, int CIN_CH, int CST>
__global__ void __launch_bounds__(256, 2) conv_mma_kernel(
    const __nv_bfloat16* __restrict__ inh, const __nv_bfloat16* __restrict__ inl,
    const __nv_bfloat16* __restrict__ wh, const __nv_bfloat16* __restrict__ wl,
    float* __restrict__ Out, int COUT)
{
    extern __shared__ char smem[];
    const int tid = threadIdx.x;
    const int wid = tid >> 5, lane = tid & 31;
    const int warp_m = wid >> 1, warp_n = wid & 1;
    const uint32_t sb = smem_u32(smem);
    const int bm = blockIdx.x * 128;

    const int lrow = tid >> 1, lhalf = tid & 1;
    const int pm = bm + lrow;
    const int py = pm / 200, px = pm % 200;
    const bool prow_ok = pm < NQ;
    const uint32_t s_arow = sb + (uint32_t)lrow * ROWB + (uint32_t)lhalf * 64;
    const int brow = tid >> 2, bq = tid & 3;
    const uint32_t s_brow = sb + 2 * CATILE + (uint32_t)brow * ROWB + (uint32_t)bq * 32;

    const uint32_t a_base = sb + (uint32_t)(warp_m * 32 + (lane & 15)) * ROWB + (uint32_t)(lane >> 4) * 16;
    const uint32_t b_base = sb + 2 * CATILE + (uint32_t)(warp_n * 32 + (lane & 7)) * ROWB
                          + (uint32_t)((lane >> 3) & 1) * 16;

    float acc[2][4][4];
    #pragma unroll
    for (int mt = 0; mt < 2; mt++)
        #pragma unroll
        for (int nt = 0; nt < 4; nt++)
            #pragma unroll
            for (int d = 0; d < 4; d++) acc[mt][nt][d] = 0.f;

    auto load_chunk = [&](int c, int buf) {
        const int e = c / CIN_CH, cih = c % CIN_CH;
        const int qy = py + e / 3 - 1;
        const int qx = px + e % 3 - 1;
        const bool val = prow_ok && qy >= 0 && qy < 200 && qx >= 0 && qx < 200;
        const size_t aoff = (size_t)(val ? (qy * 200 + qx) : 0) * CST + (size_t)cih * 64 + (size_t)lhalf * 32;
        const char* agh = (const char*)(inh + aoff);
        const char* agl = (const char*)(inl + aoff);
        const size_t boff = ((size_t)c * 64 + brow) * 64 + (size_t)bq * 16;
        const char* bgh = (const char*)(wh + boff);
        const char* bgl = (const char*)(wl + boff);
        const uint32_t sa = s_arow + (uint32_t)buf * CBUF;
        const uint32_t sbr = s_brow + (uint32_t)buf * CBUF;
        #pragma unroll
        for (int i = 0; i < 4; i++) {
            cpasync16(sa + i * 16,           agh + i * 16, val);
            cpasync16(sa + CATILE + i * 16,  agl + i * 16, val);
        }
        #pragma unroll
        for (int i = 0; i < 2; i++) {
            cpasync16(sbr + i * 16,          bgh + i * 16, true);
            cpasync16(sbr + CBTILE + i * 16, bgl + i * 16, true);
        }
    };

    load_chunk(0, 0); cp_commit();
    load_chunk(1, 1); cp_commit();

    for (int c = 0; c < CHUNKS; c++) {
        const int buf = c & 1;
        cp_wait1();
        __syncthreads();

        const uint32_t ab = a_base + (uint32_t)buf * CBUF;
        const uint32_t bb = b_base + (uint32_t)buf * CBUF;
        #pragma unroll
        for (int ks = 0; ks < 4; ks++) {
            const uint32_t kbyte = (uint32_t)ks * 32;
            uint32_t bh[4][2], bl[4][2];
            #pragma unroll
            for (int nt = 0; nt < 4; nt++) {
                ldmx2(bh[nt], bb + (uint32_t)nt * 8 * ROWB + kbyte);
                ldmx2(bl[nt], bb + CBTILE + (uint32_t)nt * 8 * ROWB + kbyte);
            }
            #pragma unroll
            for (int mt = 0; mt < 2; mt++) {
                uint32_t ah[4], al[4];
                ldmx4(ah, ab + (uint32_t)mt * 16 * ROWB + kbyte);
                ldmx4(al, ab + CATILE + (uint32_t)mt * 16 * ROWB + kbyte);
                #pragma unroll
                for (int nt = 0; nt < 4; nt++) {
                    mma_bf16(acc[mt][nt], ah, bh[nt]);
                    mma_bf16(acc[mt][nt], ah, bl[nt]);
                    mma_bf16(acc[mt][nt], al, bh[nt]);
                }
            }
        }
        __syncthreads();
        if (c + 2 < CHUNKS) load_chunk(c + 2, buf);
        cp_commit();
    }

    const int g = lane >> 2, tg = lane & 3;
    #pragma unroll
    for (int mt = 0; mt < 2; mt++) {
        const int r0 = bm + warp_m * 32 + mt * 16 + g;
        #pragma unroll
        for (int nt = 0; nt < 4; nt++) {
            const int col = warp_n * 32 + nt * 8 + tg * 2;
            if (col >= COUT) continue;
            if (r0 < NQ)
                *(float2*)&Out[(size_t)r0 * COUT + col] = make_float2(acc[mt][nt][0], acc[mt][nt][1]);
            if (r0 + 8 < NQ)
                *(float2*)&Out[(size_t)(r0 + 8) * COUT + col] = make_float2(acc[mt][nt][2], acc[mt][nt][3]);
        }
    }
}

// ---------------- batchnorm (320-way parallel partials, deterministic) ----------------
__global__ void bn_stats_kernel(const float* __restrict__ X, float* __restrict__ part, int C)
{
    int c = threadIdx.x;
    int g = blockIdx.x;
    const int per = (NQ + NPART - 1) / NPART;
    int p0 = g * per;
    int p1 = min(NQ, p0 + per);
    float s = 0.f, q = 0.f;
    for (int p = p0; p < p1; p++) {
        float x = X[(size_t)p * C + c];
        s += x; q += x * x;
    }
    part[(size_t)g * 2 * C + c] = s;
    part[(size_t)g * 2 * C + C + c] = q;
}

__global__ void bn_finalize_kernel(const float* __restrict__ part,
                                   const float* __restrict__ gamma, const float* __restrict__ beta,
                                   float* __restrict__ scale, float* __restrict__ shift, int C)
{
    int c = threadIdx.x;
    float s = 0.f, q = 0.f;
    for (int g = 0; g < NPART; g++) {
        s += part[(size_t)g * 2 * C + c];
        q += part[(size_t)g * 2 * C + C + c];
    }
    const float invP = 1.f / (float)NQ;
    float m = s * invP;
    float v = q * invP - m * m;
    float sc = gamma[c] * rsqrtf(v + 1e-5f);
    scale[c] = sc;
    shift[c] = beta[c] - m * sc;
}

__global__ void bn_apply_split_kernel(const float* __restrict__ X, const float* __restrict__ scale,
                                      const float* __restrict__ shift,
                                      __nv_bfloat16* __restrict__ hi, __nv_bfloat16* __restrict__ lo,
                                      int C, int CST, int total)
{
    int i = blockIdx.x * blockDim.x + threadIdx.x;
    if (i >= total) return;
    int c = i % CST;
    int p = i / CST;
    float v = 0.f;
    if (c < C) v = fmaxf(0.f, fmaf(X[(size_t)p * C + c], scale[c], shift[c]));
    split2(v, hi[i], lo[i]);
}

// ---------------- head: fused BN4+ReLU + 1x1 conv 48 -> 21, output NCHW ----------------
__global__ void head_conv_kernel(const float* __restrict__ H4raw, const float* __restrict__ scale,
                                 const float* __restrict__ shift,
                                 const float* __restrict__ Wo, const float* __restrict__ bo,
                                 float* __restrict__ out)
{
    int p = blockIdx.x * blockDim.x + threadIdx.x;
    if (p >= NQ) return;
    float x[48];
    const float4* hp = (const float4*)(H4raw + (size_t)p * 48);
    #pragma unroll
    for (int i = 0; i < 12; i++) {
        float4 v = hp[i];
        x[i * 4 + 0] = v.x; x[i * 4 + 1] = v.y; x[i * 4 + 2] = v.z; x[i * 4 + 3] = v.w;
    }
    #pragma unroll
    for (int ci = 0; ci < 48; ci++)
        x[ci] = fmaxf(0.f, fmaf(x[ci], scale[ci], shift[ci]));
    for (int co = 0; co < 21; co++) {
        float s = bo[co];
        const float* w = Wo + co * 48;
        #pragma unroll
        for (int ci = 0; ci < 48; ci++) s = fmaf(x[ci], w[ci], s);
        out[(size_t)co * NQ + p] = s;
    }
}

// ---------------- launch ----------------
extern "C" void kernel_launch(void* const* d_in, const int* in_sizes, int n_in,
                              void* d_out, int out_size)
{
    const float* value = (const float*)d_in[0];
    const float* bq    = (const float*)d_in[1];
    const float* bpos  = (const float*)d_in[2];
    const int*   proj  = (const int*)d_in[3];
    const float* Wv    = (const float*)d_in[4];
    const float* bv    = (const float*)d_in[5];
    const float* Woff  = (const float*)d_in[6];
    const float* boff  = (const float*)d_in[7];
    const float* Wattn = (const float*)d_in[8];
    const float* battn = (const float*)d_in[9];
    const float* Wout  = (const float*)d_in[10];
    const float* bout  = (const float*)d_in[11];
    const float* Wf1   = (const float*)d_in[12];
    const float* bf1   = (const float*)d_in[13];
    const float* Wf2   = (const float*)d_in[14];
    const float* bf2   = (const float*)d_in[15];
    const float* lng   = (const float*)d_in[16];
    const float* lnb   = (const float*)d_in[17];
    const float* cw1   = (const float*)d_in[18];
    const float* g1    = (const float*)d_in[19];
    const float* b1    = (const float*)d_in[20];
    const float* cw2   = (const float*)d_in[21];
    const float* g2    = (const float*)d_in[22];
    const float* b2    = (const float*)d_in[23];
    const float* cw3   = (const float*)d_in[24];
    const float* g3    = (const float*)d_in[25];
    const float* b3    = (const float*)d_in[26];
    const float* cw4   = (const float*)d_in[27];
    const float* g4    = (const float*)d_in[28];
    const float* b4    = (const float*)d_in[29];
    const float* objw  = (const float*)d_in[30];
    const float* objb  = (const float*)d_in[31];
    float* out = (float*)d_out;

    float* S = nullptr;
    cudaGetSymbolAddress((void**)&S, g_scratch);
    int* gm = nullptr;
    cudaGetSymbolAddress((void**)&gm, g_maxv);
    __nv_bfloat16 *s1h, *s1l, *s2h, *s2l, *wph, *wpl, *wch, *wcl;
    __half *vx, *vin16, *q16, *qp16, *w16, *wf16, *oa16;
    cudaGetSymbolAddress((void**)&s1h, g_s1h);
    cudaGetSymbolAddress((void**)&s1l, g_s1l);
    cudaGetSymbolAddress((void**)&s2h, g_s2h);
    cudaGetSymbolAddress((void**)&s2l, g_s2l);
    cudaGetSymbolAddress((void**)&vx,  g_vx);
    cudaGetSymbolAddress((void**)&vin16, g_vin16);
    cudaGetSymbolAddress((void**)&q16, g_q16);
    cudaGetSymbolAddress((void**)&qp16, g_qp16);
    cudaGetSymbolAddress((void**)&w16, g_w16);
    cudaGetSymbolAddress((void**)&wf16, g_wf16);
    cudaGetSymbolAddress((void**)&oa16, g_oa16);
    cudaGetSymbolAddress((void**)&wph, g_wph);
    cudaGetSymbolAddress((void**)&wpl, g_wpl);
    cudaGetSymbolAddress((void**)&wch, g_wch);
    cudaGetSymbolAddress((void**)&wcl, g_wcl);

    float* PQ    = S + OFF_Q;
    float* PT1   = S + OFF_T1;
    float* PT2   = S + OFF_T2;
    float* PH1   = S + OFF_H1;
    float* PH2   = S + OFF_H2;
    float* PH3   = S + OFF_H3;
    float* PH4   = S + OFF_H4;
    float* PPART = S + OFF_PART;
    float* PSCALE= S + OFF_SCALE;
    float* PSHIFT= S + OFF_SHIFT;
    float* PBIAS = S + OFF_BIAS;

    cudaFuncSetAttribute(conv1_f16_kernel, cudaFuncAttributeMaxDynamicSharedMemorySize, CONV1_SMEM);
    cudaFuncSetAttribute(gemm_f16<8>,    cudaFuncAttributeMaxDynamicSharedMemorySize, F16GEMM_SMEM);
    cudaFuncSetAttribute(gemm_f16<9>,    cudaFuncAttributeMaxDynamicSharedMemorySize, F16GEMM_SMEM);
    cudaFuncSetAttribute(gemm_f16<6>,    cudaFuncAttributeMaxDynamicSharedMemorySize, F16GEMM_SMEM);
    cudaFuncSetAttribute(gemm_mma6,      cudaFuncAttributeMaxDynamicSharedMemorySize, GEMM_SMEM);
    cudaFuncSetAttribute((conv_mma_kernel<18, 2, 128>), cudaFuncAttributeMaxDynamicSharedMemorySize, CONV_SMEM);
    cudaFuncSetAttribute((conv_mma_kernel<9, 1, 64>),   cudaFuncAttributeMaxDynamicSharedMemorySize, CONV_SMEM);

    // --- observed_masks ---
    init_max_kernel<<<1, 1>>>(gm);
    reduce_max_kernel<<<40, 256>>>(proj, gm);
    write_mask_kernel<<<(NQ + 255) / 256, 256>>>(proj, gm, out + 21 * NQ);

    // --- fused weight prep (single launch) + value fp16 ---
    prep_kernel<<<(Q9 + 255) / 256, 256>>>(cw1, cw2, cw3, cw4, Woff, Wattn, Wv, Wf1, Wf2, Wout,
                                           boff, battn, w16, wch, wcl, wf16, wph, wpl, PBIAS);
    tof16_kernel<<<(NV * 128 + 255) / 256, 256>>>(value, vin16, NV * 128);

    // --- q init ---
    cudaMemcpyAsync(PQ, bq, (size_t)NQ * ED * sizeof(float), cudaMemcpyDeviceToDevice);

    // --- 2 encoder layers ---
    add_f16_kernel<<<(NQ * ED + 255) / 256, 256>>>(PQ, bpos, qp16, NQ * ED);
    for (int i = 0; i < 2; i++) {
        size_t LW = (size_t)i * 1152 * 128;
        gemm_f16<8><<<dim3(340, 1), 256, F16GEMM_SMEM>>>(vin16, wf16 + LW + 768 * 128,
                                                         bv + i * 128, nullptr, nullptr, vx, NV, 128);
        gemm_f16<8><<<dim3(313, 6), 256, F16GEMM_SMEM>>>(qp16, wf16 + LW,
                                                         PBIAS + i * 768, nullptr, nullptr, oa16, NQ, 768);
        deform_kernel<<<(NQ * HEADS + 255) / 256, 256>>>(vx, oa16, s2h, s2l);
        gemm_mma6<<<dim3(313, 1), 256, GEMM_SMEM>>>(s2h, s2l, wph + (size_t)i * 128 * 128, wpl + (size_t)i * 128 * 128,
                                                    bout + i * 128, PQ, PT1, NQ, 128);
        ln_kernel<3><<<NQ, 128>>>(PT1, lng + (i * 2 + 0) * 128, lnb + (i * 2 + 0) * 128, PQ, q16, nullptr);
        gemm_f16<9><<<dim3(313, 1), 256, F16GEMM_SMEM>>>(q16, wf16 + LW + 896 * 128,
                                                         bf1 + i * 128, nullptr, nullptr, qp16, NQ, 128);
        gemm_f16<6><<<dim3(313, 1), 256, F16GEMM_SMEM>>>(qp16, wf16 + LW + 1024 * 128,
                                                         bf2 + i * 128, PQ, PT2, nullptr, NQ, 128);
        if (i == 0)
            ln_kernel<4><<<NQ, 128>>>(PT2, lng + 1 * 128, lnb + 1 * 128, PQ, qp16, bpos);   // fp16(q+pos)
        else
            ln_kernel<3><<<NQ, 128>>>(PT2, lng + 3 * 128, lnb + 3 * 128, PQ, q16, nullptr); // fp16(q)
    }

    // --- conv head ---
    conv1_f16_kernel<<<313, 256, CONV1_SMEM>>>(q16, w16, PH1);
    bn_stats_kernel<<<NPART, 128>>>(PH1, PPART, 128);
    bn_finalize_kernel<<<1, 128>>>(PPART, g1, b1, PSCALE, PSHIFT, 128);
    bn_apply_split_kernel<<<(NQ * 128 + 255) / 256, 256>>>(PH1, PSCALE, PSHIFT, s1h, s1l, 128, 128, NQ * 128);

    conv_mma_kernel<18, 2, 128><<<313, 256, CONV_SMEM>>>(s1h, s1l, wch + WC2_OFF, wcl + WC2_OFF, PH2, 64);
    bn_stats_kernel<<<NPART, 64>>>(PH2, PPART, 64);
    bn_finalize_kernel<<<1, 64>>>(PPART, g2, b2, PSCALE, PSHIFT, 64);
    bn_apply_split_kernel<<<(NQ * 64 + 255) / 256, 256>>>(PH2, PSCALE, PSHIFT, s2h, s2l, 64, 64, NQ * 64);

    conv_mma_kernel<9, 1, 64><<<313, 256, CONV_SMEM>>>(s2h, s2l, wch + WC3_OFF, wcl + WC3_OFF, PH3, 48);
    bn_stats_kernel<<<NPART, 48>>>(PH3, PPART, 48);
    bn_finalize_kernel<<<1, 48>>>(PPART, g3, b3, PSCALE, PSHIFT, 48);
    bn_apply_split_kernel<<<(NQ * 64 + 255) / 256, 256>>>(PH3, PSCALE, PSHIFT, s1h, s1l, 48, 64, NQ * 64);

    conv_mma_kernel<9, 1, 64><<<313, 256, CONV_SMEM>>>(s1h, s1l, wch + WC4_OFF, wcl + WC4_OFF, PH4, 48);
    bn_stats_kernel<<<NPART, 48>>>(PH4, PPART, 48);
    bn_finalize_kernel<<<1, 48>>>(PPART, g4, b4, PSCALE, PSHIFT, 48);
    head_conv_kernel<<<(NQ + 255) / 256, 256>>>(PH4, PSCALE, PSHIFT, objw, objb, out);
}